// round 1
// baseline (speedup 1.0000x reference)
#include <cuda_runtime.h>
#include <math.h>

// ---------------- problem constants ----------------
#define BB   2
#define NN   2048
#define DD   768
#define HH   12
#define DHH  64
#define MM   266          // random features
#define MP   272          // padded to 8*34
#define FFD  3072
#define ROWS (BB*NN)      // 4096
#define RIDS (BB*HH*NN)   // 49152

#define DN_SCALE   0.35355339059327f   // 64^-0.25
#define RATIO_SC   0.061313689f        // 266^-0.5
#define EPS_KER    1e-4f
#define EPS_DEN    1e-6f

// ---------------- scratch (static device allocations) ----------------
__device__ float g_h1[ROWS*DD];
__device__ float g_q [ROWS*DD];
__device__ float g_k [ROWS*DD];
__device__ float g_v [ROWS*DD];
__device__ float g_o [ROWS*DD];
__device__ float g_x1[ROWS*DD];
__device__ float g_h2[ROWS*DD];
__device__ float g_ff[ROWS*FFD];
__device__ float g_qp[(size_t)RIDS*MP];
__device__ float g_kp[(size_t)RIDS*MP];
__device__ float g_kdiag[RIDS];
__device__ unsigned g_kmax_u;

// monotonic float<->uint encoding for atomicMax over signed floats
__device__ __forceinline__ unsigned enc_f(float f){
    unsigned u = __float_as_uint(f);
    return (u & 0x80000000u) ? ~u : (u | 0x80000000u);
}
__device__ __forceinline__ float dec_f(unsigned u){
    return (u & 0x80000000u) ? __uint_as_float(u ^ 0x80000000u) : __uint_as_float(~u);
}

__global__ void init_k(){ g_kmax_u = 0x00800000u; /* enc(-FLT_MAX) */ }

// ---------------- LayerNorm ----------------
__global__ void ln_k(const float* __restrict__ X, const float* __restrict__ G,
                     const float* __restrict__ Bv, float* __restrict__ Y){
    int row = blockIdx.x, tid = threadIdx.x;
    const float* x = X + (size_t)row*DD;
    float v0 = x[tid], v1 = x[tid+256], v2 = x[tid+512];
    float s = v0+v1+v2, ss = v0*v0 + v1*v1 + v2*v2;
    __shared__ float rs[8], rss[8], stat[2];
    for (int o=16;o;o>>=1){ s += __shfl_xor_sync(0xffffffffu,s,o); ss += __shfl_xor_sync(0xffffffffu,ss,o); }
    if ((tid&31)==0){ rs[tid>>5]=s; rss[tid>>5]=ss; }
    __syncthreads();
    if (tid==0){
        float S=0,SS=0;
        #pragma unroll
        for (int i=0;i<8;i++){ S+=rs[i]; SS+=rss[i]; }
        float mu = S*(1.0f/DD);
        float var = SS*(1.0f/DD) - mu*mu;
        stat[0]=mu; stat[1]=rsqrtf(var + 1e-5f);
    }
    __syncthreads();
    float mu = stat[0], rstd = stat[1];
    float* y = Y + (size_t)row*DD;
    y[tid]     = (v0-mu)*rstd*G[tid]     + Bv[tid];
    y[tid+256] = (v1-mu)*rstd*G[tid+256] + Bv[tid+256];
    y[tid+512] = (v2-mu)*rstd*G[tid+512] + Bv[tid+512];
}

// ---------------- SGEMM: C = A[MrxK] @ W[KxNC] + bias (+gelu | +residual) ----------------
// EPI: 0 = bias, 1 = bias+gelu(exact), 2 = bias+residual
template<int EPI>
__global__ void gemm_k(const float* __restrict__ A, const float* __restrict__ W,
                       const float* __restrict__ bias, const float* __restrict__ R,
                       float* __restrict__ C, int K, int NC){
    __shared__ __align__(16) float Ast[16][68];   // [k][m]
    __shared__ __align__(16) float Bs [16][64];   // [k][n]
    int tid = threadIdx.x;
    int m0 = blockIdx.y*64, n0 = blockIdx.x*64;
    int ra = tid>>2,  ca = (tid&3)<<2;
    int rb = tid>>4,  cb = (tid&15)<<2;
    int ty = tid>>4,  tx = tid&15;
    float acc[4][4] = {};
    const float* Ap = A + (size_t)(m0+ra)*K + ca;
    const float* Wp = W + (size_t)rb*NC + n0 + cb;
    for (int kb=0; kb<K; kb+=16){
        float4 av = *(const float4*)(Ap + kb);
        float4 bv = *(const float4*)(Wp + (size_t)kb*NC);
        Ast[ca+0][ra]=av.x; Ast[ca+1][ra]=av.y; Ast[ca+2][ra]=av.z; Ast[ca+3][ra]=av.w;
        *(float4*)&Bs[rb][cb] = bv;
        __syncthreads();
        #pragma unroll
        for (int kk=0; kk<16; kk++){
            float4 a4 = *(const float4*)&Ast[kk][ty*4];
            float4 b4 = *(const float4*)&Bs [kk][tx*4];
            float a[4] = {a4.x,a4.y,a4.z,a4.w};
            float b[4] = {b4.x,b4.y,b4.z,b4.w};
            #pragma unroll
            for (int i=0;i<4;i++)
                #pragma unroll
                for (int j=0;j<4;j++) acc[i][j] += a[i]*b[j];
        }
        __syncthreads();
    }
    #pragma unroll
    for (int i=0;i<4;i++){
        int m = m0 + ty*4 + i;
        #pragma unroll
        for (int j=0;j<4;j++){
            int n = n0 + tx*4 + j;
            float vv = acc[i][j] + bias[n];
            if (EPI==1) vv = 0.5f*vv*(1.0f + erff(vv*0.70710678118654752f));
            if (EPI==2) vv += R[(size_t)m*NC + n];
            C[(size_t)m*NC + n] = vv;
        }
    }
}

// ---------------- FAVOR+ feature maps ----------------
// query: per-row max (fused)
__global__ void featq_k(const float* __restrict__ Q, const float* __restrict__ proj,
                        float* __restrict__ QP){
    int rid = blockIdx.x;                 // rid = (b*H+h)*N + n
    int b = rid/(HH*NN); int rem = rid%(HH*NN); int h = rem/NN; int n = rem%NN;
    int bn = b*NN + n;
    __shared__ float data[64];
    __shared__ float dd[MM];
    __shared__ float wmax[4], smax;
    int tid = threadIdx.x;
    if (tid < 64) data[tid] = Q[(size_t)bn*DD + h*64 + tid];
    __syncthreads();
    float ssq = 0.f;
    #pragma unroll 16
    for (int d=0; d<64; d++) ssq += data[d]*data[d];
    float diag = ssq * 0.0625f;           // 0.5 * dn^2
    for (int m=tid; m<MM; m+=128){
        const float* pr = proj + (size_t)m*64;
        float acc = 0.f;
        #pragma unroll 16
        for (int d=0; d<64; d++) acc += data[d]*pr[d];
        dd[m] = acc * DN_SCALE;
    }
    __syncthreads();
    float mx = -3.4e38f;
    for (int m=tid; m<MM; m+=128) mx = fmaxf(mx, dd[m]);
    for (int o=16;o;o>>=1) mx = fmaxf(mx, __shfl_xor_sync(0xffffffffu,mx,o));
    if ((tid&31)==0) wmax[tid>>5] = mx;
    __syncthreads();
    if (tid==0) smax = fmaxf(fmaxf(wmax[0],wmax[1]), fmaxf(wmax[2],wmax[3]));
    __syncthreads();
    float M0 = smax;
    float* out = QP + (size_t)rid*MP;
    for (int m=tid; m<MP; m+=128)
        out[m] = (m<MM) ? RATIO_SC*(expf(dd[m]-diag-M0) + EPS_KER) : 0.f;
}

// key pass 1: raw dd + diag + global atomic max
__global__ void featk1_k(const float* __restrict__ K, const float* __restrict__ proj,
                         float* __restrict__ KP, float* __restrict__ KD){
    int rid = blockIdx.x;
    int b = rid/(HH*NN); int rem = rid%(HH*NN); int h = rem/NN; int n = rem%NN;
    int bn = b*NN + n;
    __shared__ float data[64];
    __shared__ float wmax[4];
    int tid = threadIdx.x;
    if (tid < 64) data[tid] = K[(size_t)bn*DD + h*64 + tid];
    __syncthreads();
    float ssq = 0.f;
    #pragma unroll 16
    for (int d=0; d<64; d++) ssq += data[d]*data[d];
    float diag = ssq * 0.0625f;
    float mx = -3.4e38f;
    float* out = KP + (size_t)rid*MP;
    for (int m=tid; m<MM; m+=128){
        const float* pr = proj + (size_t)m*64;
        float acc = 0.f;
        #pragma unroll 16
        for (int d=0; d<64; d++) acc += data[d]*pr[d];
        float ddv = acc * DN_SCALE;
        out[m] = ddv;
        mx = fmaxf(mx, ddv);
    }
    for (int o=16;o;o>>=1) mx = fmaxf(mx, __shfl_xor_sync(0xffffffffu,mx,o));
    if ((tid&31)==0) wmax[tid>>5] = mx;
    __syncthreads();
    if (tid==0){
        KD[rid] = diag;
        float m2 = fmaxf(fmaxf(wmax[0],wmax[1]), fmaxf(wmax[2],wmax[3]));
        atomicMax(&g_kmax_u, enc_f(m2));
    }
}

// key pass 2: apply exp with global max
__global__ void featk2_k(float* __restrict__ KP, const float* __restrict__ KD){
    size_t idx = (size_t)blockIdx.x*256 + threadIdx.x;
    const size_t total = (size_t)RIDS*MP;
    if (idx >= total) return;
    int rid = (int)(idx / MP);
    int m   = (int)(idx % MP);
    float vv = 0.f;
    if (m < MM){
        float gmax = dec_f(g_kmax_u);
        vv = RATIO_SC*(expf(KP[idx] - KD[rid] - gmax) + EPS_KER);
    }
    KP[idx] = vv;
}

// ---------------- causal linear attention scan ----------------
__device__ __forceinline__ void cpasync16(void* smem, const void* gmem){
    unsigned s = (unsigned)__cvta_generic_to_shared(smem);
    asm volatile("cp.async.ca.shared.global [%0], [%1], 16;\n" :: "r"(s), "l"(gmem));
}
#define CP_COMMIT asm volatile("cp.async.commit_group;\n" ::: "memory")
#define CP_WAIT0  asm volatile("cp.async.wait_group 0;\n" ::: "memory")

__global__ __launch_bounds__(512) void scan_k(const float* __restrict__ QP,
                                              const float* __restrict__ KP,
                                              const float* __restrict__ V,
                                              float* __restrict__ O){
    int bh = blockIdx.x;                // b*H + h
    int b = bh / HH, h = bh % HH;
    int tid = threadIdx.x;
    int g = tid >> 6, e = tid & 63;
    const int m0 = g*34;
    float S[34];
    #pragma unroll
    for (int i=0;i<34;i++) S[i]=0.f;

    __shared__ __align__(16) float qbuf[2][MP];
    __shared__ __align__(16) float kbuf[2][MP];
    __shared__ __align__(16) float vbuf[2][64];
    __shared__ float zs[MP];
    __shared__ float partials[8][64];
    __shared__ float den_s[2];

    for (int i=tid;i<MP;i+=512) zs[i]=0.f;
    if (tid<2) den_s[tid]=0.f;

    const float* qbase = QP + (size_t)bh*NN*MP;
    const float* kbase = KP + (size_t)bh*NN*MP;
    const float* vbase = V  + (size_t)b*NN*DD + h*64;

    // prefetch token 0 into buffer 0
    if (tid < 68)       cpasync16(&qbuf[0][tid*4],        qbase + tid*4);
    else if (tid < 136) cpasync16(&kbuf[0][(tid-68)*4],   kbase + (tid-68)*4);
    else if (tid < 152) cpasync16(&vbuf[0][(tid-136)*4],  vbase + (tid-136)*4);
    CP_COMMIT;

    for (int t=0; t<NN; t++){
        int cur = t & 1;
        CP_WAIT0;
        __syncthreads();
        // prefetch t+1
        if (t+1 < NN){
            int nb = cur ^ 1;
            const float* qr = qbase + (size_t)(t+1)*MP;
            const float* kr = kbase + (size_t)(t+1)*MP;
            const float* vr = vbase + (size_t)(t+1)*DD;
            if (tid < 68)       cpasync16(&qbuf[nb][tid*4],       qr + tid*4);
            else if (tid < 136) cpasync16(&kbuf[nb][(tid-68)*4],  kr + (tid-68)*4);
            else if (tid < 152) cpasync16(&vbuf[nb][(tid-136)*4], vr + (tid-136)*4);
        }
        CP_COMMIT;

        // z update + denominator partial: den = q . (z_new + EPS_DEN)
        float dp = 0.f;
        if (tid < MP){
            float kv = kbuf[cur][tid];
            float zn = zs[tid] + kv;
            zs[tid] = zn;
            dp = qbuf[cur][tid] * (zn + EPS_DEN);
        }
        for (int o=16;o;o>>=1) dp += __shfl_xor_sync(0xffffffffu, dp, o);
        if ((tid&31)==0) atomicAdd(&den_s[cur], dp);

        // S += k v^T ; acc = q . S  (inclusive)
        float vv = vbuf[cur][e];
        const float* kb_ = kbuf[cur];
        const float* qb_ = qbuf[cur];
        float acc = 0.f;
        #pragma unroll
        for (int i=0;i<34;i++){
            S[i] += kb_[m0+i] * vv;
            acc  += qb_[m0+i] * S[i];
        }
        partials[g][e] = acc;
        __syncthreads();

        if (tid < 64){
            float s = 0.f;
            #pragma unroll
            for (int gg=0; gg<8; gg++) s += partials[gg][tid];
            O[(size_t)(b*NN + t)*DD + h*64 + tid] = s / den_s[cur];
        }
        if (tid == 511) den_s[cur^1] = 0.f;   // next-next slot; ordered by next iter's barrier
    }
}

// ---------------- launch ----------------
extern "C" void kernel_launch(void* const* d_in, const int* in_sizes, int n_in,
                              void* d_out, int out_size){
    (void)in_sizes; (void)n_in; (void)out_size;
    const float* x    = (const float*)d_in[0];
    const float* ln1g = (const float*)d_in[1];
    const float* ln1b = (const float*)d_in[2];
    const float* Wq   = (const float*)d_in[3];
    const float* bq   = (const float*)d_in[4];
    const float* Wk   = (const float*)d_in[5];
    const float* bk   = (const float*)d_in[6];
    const float* Wv   = (const float*)d_in[7];
    const float* bv   = (const float*)d_in[8];
    const float* Wo   = (const float*)d_in[9];
    const float* bo   = (const float*)d_in[10];
    const float* proj = (const float*)d_in[11];
    const float* ln2g = (const float*)d_in[12];
    const float* ln2b = (const float*)d_in[13];
    const float* W1   = (const float*)d_in[14];
    const float* b1   = (const float*)d_in[15];
    const float* W2   = (const float*)d_in[16];
    const float* b2   = (const float*)d_in[17];
    float* out = (float*)d_out;

    float *h1,*q,*k,*v,*qp,*kp,*kd,*o,*x1,*h2,*ff;
    cudaGetSymbolAddress((void**)&h1, g_h1);
    cudaGetSymbolAddress((void**)&q,  g_q);
    cudaGetSymbolAddress((void**)&k,  g_k);
    cudaGetSymbolAddress((void**)&v,  g_v);
    cudaGetSymbolAddress((void**)&qp, g_qp);
    cudaGetSymbolAddress((void**)&kp, g_kp);
    cudaGetSymbolAddress((void**)&kd, g_kdiag);
    cudaGetSymbolAddress((void**)&o,  g_o);
    cudaGetSymbolAddress((void**)&x1, g_x1);
    cudaGetSymbolAddress((void**)&h2, g_h2);
    cudaGetSymbolAddress((void**)&ff, g_ff);

    init_k<<<1,1>>>();
    ln_k<<<ROWS,256>>>(x, ln1g, ln1b, h1);

    dim3 g768(DD/64, ROWS/64);
    gemm_k<0><<<g768,256>>>(h1, Wq, bq, nullptr, q, DD, DD);
    gemm_k<0><<<g768,256>>>(h1, Wk, bk, nullptr, k, DD, DD);
    gemm_k<0><<<g768,256>>>(h1, Wv, bv, nullptr, v, DD, DD);

    featq_k <<<RIDS,128>>>(q, proj, qp);
    featk1_k<<<RIDS,128>>>(k, proj, kp, kd);
    {
        size_t total = (size_t)RIDS*MP;
        featk2_k<<<(unsigned)((total+255)/256),256>>>(kp, kd);
    }

    scan_k<<<BB*HH,512>>>(qp, kp, v, o);

    gemm_k<2><<<g768,256>>>(o, Wo, bo, x, x1, DD, DD);
    ln_k<<<ROWS,256>>>(x1, ln2g, ln2b, h2);

    dim3 gff(FFD/64, ROWS/64);
    gemm_k<1><<<gff,256>>>(h2, W1, b1, nullptr, ff, DD, FFD);
    gemm_k<2><<<g768,256>>>(ff, W2, b2, x1, out, FFD, DD);
}

// round 2
// speedup vs baseline: 1.1812x; 1.1812x over previous
#include <cuda_runtime.h>
#include <math.h>

// ---------------- problem constants ----------------
#define BB   2
#define NN   2048
#define DD   768
#define HH   12
#define MM   266          // random features
#define MP2  288          // padded to 8*36 (36 floats = 9 float4, 16B aligned per group)
#define GM   36           // features per group
#define FFD  3072
#define ROWS (BB*NN)      // 4096
#define RIDS (BB*HH*NN)   // 49152
#define BH   (BB*HH)      // 24
#define CHK  128          // chunk length
#define NC   (NN/CHK)     // 16 chunks per (b,h)
#define NCH  (BH*NC)      // 384 chunk-CTAs
#define TT   8            // tokens per smem tile
#define NTILE (CHK/TT)    // 16 tiles per chunk
#define KVSTRIDE (MP2*64) // 18432

#define DN_SCALE   0.35355339059327f   // 64^-0.25
#define RATIO_SC   0.061313689f        // 266^-0.5
#define EPS_KER    1e-4f
#define EPS_DEN    1e-6f

// ---------------- scratch ----------------
__device__ float g_h1[ROWS*DD];
__device__ float g_q [ROWS*DD];
__device__ float g_k [ROWS*DD];
__device__ float g_v [ROWS*DD];
__device__ float g_o [ROWS*DD];
__device__ float g_x1[ROWS*DD];
__device__ float g_h2[ROWS*DD];
__device__ float g_ff[ROWS*FFD];
__device__ float g_qp[(size_t)RIDS*MP2];
__device__ float g_kp[(size_t)RIDS*MP2];
__device__ float g_kdiag[RIDS];
__device__ float g_Z [(size_t)NCH*MP2];
__device__ float g_KV[(size_t)NCH*KVSTRIDE];
__device__ unsigned g_kmax_u;

__device__ __forceinline__ unsigned enc_f(float f){
    unsigned u = __float_as_uint(f);
    return (u & 0x80000000u) ? ~u : (u | 0x80000000u);
}
__device__ __forceinline__ float dec_f(unsigned u){
    return (u & 0x80000000u) ? __uint_as_float(u ^ 0x80000000u) : __uint_as_float(~u);
}

__global__ void init_k(){ g_kmax_u = 0x00800000u; }

// ---------------- LayerNorm ----------------
__global__ void ln_k(const float* __restrict__ X, const float* __restrict__ G,
                     const float* __restrict__ Bv, float* __restrict__ Y){
    int row = blockIdx.x, tid = threadIdx.x;
    const float* x = X + (size_t)row*DD;
    float v0 = x[tid], v1 = x[tid+256], v2 = x[tid+512];
    float s = v0+v1+v2, ss = v0*v0 + v1*v1 + v2*v2;
    __shared__ float rs[8], rss[8], stat[2];
    for (int o=16;o;o>>=1){ s += __shfl_xor_sync(0xffffffffu,s,o); ss += __shfl_xor_sync(0xffffffffu,ss,o); }
    if ((tid&31)==0){ rs[tid>>5]=s; rss[tid>>5]=ss; }
    __syncthreads();
    if (tid==0){
        float S=0,SS=0;
        #pragma unroll
        for (int i=0;i<8;i++){ S+=rs[i]; SS+=rss[i]; }
        float mu = S*(1.0f/DD);
        float var = SS*(1.0f/DD) - mu*mu;
        stat[0]=mu; stat[1]=rsqrtf(var + 1e-5f);
    }
    __syncthreads();
    float mu = stat[0], rstd = stat[1];
    float* y = Y + (size_t)row*DD;
    y[tid]     = (v0-mu)*rstd*G[tid]     + Bv[tid];
    y[tid+256] = (v1-mu)*rstd*G[tid+256] + Bv[tid+256];
    y[tid+512] = (v2-mu)*rstd*G[tid+512] + Bv[tid+512];
}

// ---------------- SGEMM ----------------
template<int EPI>
__global__ void gemm_k(const float* __restrict__ A, const float* __restrict__ W,
                       const float* __restrict__ bias, const float* __restrict__ R,
                       float* __restrict__ C, int K, int NCc){
    __shared__ __align__(16) float Ast[16][68];
    __shared__ __align__(16) float Bs [16][64];
    int tid = threadIdx.x;
    int m0 = blockIdx.y*64, n0 = blockIdx.x*64;
    int ra = tid>>2,  ca = (tid&3)<<2;
    int rb = tid>>4,  cb = (tid&15)<<2;
    int ty = tid>>4,  tx = tid&15;
    float acc[4][4] = {};
    const float* Ap = A + (size_t)(m0+ra)*K + ca;
    const float* Wp = W + (size_t)rb*NCc + n0 + cb;
    for (int kb=0; kb<K; kb+=16){
        float4 av = *(const float4*)(Ap + kb);
        float4 bv = *(const float4*)(Wp + (size_t)kb*NCc);
        Ast[ca+0][ra]=av.x; Ast[ca+1][ra]=av.y; Ast[ca+2][ra]=av.z; Ast[ca+3][ra]=av.w;
        *(float4*)&Bs[rb][cb] = bv;
        __syncthreads();
        #pragma unroll
        for (int kk=0; kk<16; kk++){
            float4 a4 = *(const float4*)&Ast[kk][ty*4];
            float4 b4 = *(const float4*)&Bs [kk][tx*4];
            float a[4] = {a4.x,a4.y,a4.z,a4.w};
            float b[4] = {b4.x,b4.y,b4.z,b4.w};
            #pragma unroll
            for (int i=0;i<4;i++)
                #pragma unroll
                for (int j=0;j<4;j++) acc[i][j] += a[i]*b[j];
        }
        __syncthreads();
    }
    #pragma unroll
    for (int i=0;i<4;i++){
        int m = m0 + ty*4 + i;
        #pragma unroll
        for (int j=0;j<4;j++){
            int n = n0 + tx*4 + j;
            float vv = acc[i][j] + bias[n];
            if (EPI==1) vv = 0.5f*vv*(1.0f + erff(vv*0.70710678118654752f));
            if (EPI==2) vv += R[(size_t)m*NCc + n];
            C[(size_t)m*NCc + n] = vv;
        }
    }
}

// ---------------- FAVOR+ feature maps ----------------
__global__ void featq_k(const float* __restrict__ Q, const float* __restrict__ proj,
                        float* __restrict__ QP){
    int rid = blockIdx.x;
    int b = rid/(HH*NN); int rem = rid%(HH*NN); int h = rem/NN; int n = rem%NN;
    int bn = b*NN + n;
    __shared__ float data[64];
    __shared__ float dd[MM];
    __shared__ float wmax[4], smax;
    int tid = threadIdx.x;
    if (tid < 64) data[tid] = Q[(size_t)bn*DD + h*64 + tid];
    __syncthreads();
    float ssq = 0.f;
    #pragma unroll 16
    for (int d=0; d<64; d++) ssq += data[d]*data[d];
    float diag = ssq * 0.0625f;
    for (int m=tid; m<MM; m+=128){
        const float* pr = proj + (size_t)m*64;
        float acc = 0.f;
        #pragma unroll 16
        for (int d=0; d<64; d++) acc += data[d]*pr[d];
        dd[m] = acc * DN_SCALE;
    }
    __syncthreads();
    float mx = -3.4e38f;
    for (int m=tid; m<MM; m+=128) mx = fmaxf(mx, dd[m]);
    for (int o=16;o;o>>=1) mx = fmaxf(mx, __shfl_xor_sync(0xffffffffu,mx,o));
    if ((tid&31)==0) wmax[tid>>5] = mx;
    __syncthreads();
    if (tid==0) smax = fmaxf(fmaxf(wmax[0],wmax[1]), fmaxf(wmax[2],wmax[3]));
    __syncthreads();
    float M0 = smax;
    float* out = QP + (size_t)rid*MP2;
    for (int m=tid; m<MP2; m+=128)
        out[m] = (m<MM) ? RATIO_SC*(expf(dd[m]-diag-M0) + EPS_KER) : 0.f;
}

__global__ void featk1_k(const float* __restrict__ K, const float* __restrict__ proj,
                         float* __restrict__ KP, float* __restrict__ KD){
    int rid = blockIdx.x;
    int b = rid/(HH*NN); int rem = rid%(HH*NN); int h = rem/NN; int n = rem%NN;
    int bn = b*NN + n;
    __shared__ float data[64];
    __shared__ float wmax[4];
    int tid = threadIdx.x;
    if (tid < 64) data[tid] = K[(size_t)bn*DD + h*64 + tid];
    __syncthreads();
    float ssq = 0.f;
    #pragma unroll 16
    for (int d=0; d<64; d++) ssq += data[d]*data[d];
    float diag = ssq * 0.0625f;
    float mx = -3.4e38f;
    float* out = KP + (size_t)rid*MP2;
    for (int m=tid; m<MM; m+=128){
        const float* pr = proj + (size_t)m*64;
        float acc = 0.f;
        #pragma unroll 16
        for (int d=0; d<64; d++) acc += data[d]*pr[d];
        float ddv = acc * DN_SCALE;
        out[m] = ddv;
        mx = fmaxf(mx, ddv);
    }
    for (int o=16;o;o>>=1) mx = fmaxf(mx, __shfl_xor_sync(0xffffffffu,mx,o));
    if ((tid&31)==0) wmax[tid>>5] = mx;
    __syncthreads();
    if (tid==0){
        KD[rid] = diag;
        float m2 = fmaxf(fmaxf(wmax[0],wmax[1]), fmaxf(wmax[2],wmax[3]));
        atomicMax(&g_kmax_u, enc_f(m2));
    }
}

__global__ void featk2_k(float* __restrict__ KP, const float* __restrict__ KD){
    size_t idx = (size_t)blockIdx.x*256 + threadIdx.x;
    const size_t total = (size_t)RIDS*MP2;
    if (idx >= total) return;
    int rid = (int)(idx / MP2);
    int m   = (int)(idx % MP2);
    float vv = 0.f;
    if (m < MM){
        float gmax = dec_f(g_kmax_u);
        vv = RATIO_SC*(expf(KP[idx] - KD[rid] - gmax) + EPS_KER);
    }
    KP[idx] = vv;
}

// ---------------- chunked causal linear attention ----------------
__device__ __forceinline__ void cpasync16(void* smem, const void* gmem){
    unsigned s = (unsigned)__cvta_generic_to_shared(smem);
    asm volatile("cp.async.ca.shared.global [%0], [%1], 16;\n" :: "r"(s), "l"(gmem));
}
#define CP_COMMIT asm volatile("cp.async.commit_group;\n" ::: "memory")
#define CP_WAIT0  asm volatile("cp.async.wait_group 0;\n" ::: "memory")

// Phase 1: per-chunk totals  Z_c[m] = sum k,  KV_c[m][e] = sum k v^T
__global__ __launch_bounds__(512) void chunksum_k(const float* __restrict__ KP,
                                                  const float* __restrict__ V,
                                                  float* __restrict__ Z,
                                                  float* __restrict__ KV){
    int bhc = blockIdx.x;
    int bh = bhc / NC, c = bhc % NC;
    int b = bh / HH, h = bh % HH;
    int tid = threadIdx.x, g = tid>>6, e = tid&63;
    const int m0 = g*GM;
    __shared__ __align__(16) float kt[2][TT][MP2];
    __shared__ __align__(16) float vt[2][TT][64];
    float S[GM];
    #pragma unroll
    for (int i=0;i<GM;i++) S[i]=0.f;
    float zacc = 0.f;
    const float* kb = KP + ((size_t)bh*NN + c*CHK)*MP2;
    const float* vb = V  + ((size_t)(b*NN + c*CHK))*DD + h*64;

    auto load = [&](int buf, int tile){
        const float* kb_ = kb + (size_t)tile*TT*MP2;
        const float* vb_ = vb + (size_t)tile*TT*DD;
        for (int idx=tid; idx<704; idx+=512){
            if (idx < 576){ int tok=idx/72, f=(idx%72)*4; cpasync16(&kt[buf][tok][f], kb_ + (size_t)tok*MP2 + f); }
            else { int r=idx-576; int tok=r/16, f=(r%16)*4; cpasync16(&vt[buf][tok][f], vb_ + (size_t)tok*DD + f); }
        }
    };
    load(0,0); CP_COMMIT;
    for (int tile=0; tile<NTILE; tile++){
        int buf = tile&1;
        CP_WAIT0;
        __syncthreads();
        if (tile+1 < NTILE) load(buf^1, tile+1);
        CP_COMMIT;
        #pragma unroll
        for (int tt=0; tt<TT; tt++){
            float vv = vt[buf][tt][e];
            const float4* kr = (const float4*)(&kt[buf][tt][m0]);
            #pragma unroll
            for (int i4=0;i4<9;i4++){
                float4 kk = kr[i4];
                S[i4*4+0] += kk.x*vv;
                S[i4*4+1] += kk.y*vv;
                S[i4*4+2] += kk.z*vv;
                S[i4*4+3] += kk.w*vv;
            }
            if (tid < MP2) zacc += kt[buf][tt][tid];
        }
    }
    if (tid < MP2) Z[(size_t)bhc*MP2 + tid] = zacc;
    float* kvout = KV + (size_t)bhc*KVSTRIDE;
    #pragma unroll
    for (int i=0;i<GM;i++) kvout[(size_t)(m0+i)*64 + e] = S[i];
}

// Phase 2: exclusive prefix over chunks (in place)
__global__ __launch_bounds__(512) void prefix_k(float* __restrict__ Z, float* __restrict__ KV){
    int bh = blockIdx.x;
    int base = bh*NC;
    int tid = threadIdx.x;
    for (int idx=tid; idx<KVSTRIDE; idx+=512){
        float run = 0.f;
        #pragma unroll
        for (int c=0;c<NC;c++){
            float* p = KV + (size_t)(base+c)*KVSTRIDE + idx;
            float t = *p; *p = run; run += t;
        }
    }
    if (tid < MP2){
        float run = 0.f;
        #pragma unroll
        for (int c=0;c<NC;c++){
            float* p = Z + (size_t)(base+c)*MP2 + tid;
            float t = *p; *p = run; run += t;
        }
    }
}

// Phase 3: per-chunk inclusive recurrence with prefix initial state
__global__ __launch_bounds__(512) void chunkout_k(const float* __restrict__ QP,
                                                  const float* __restrict__ KP,
                                                  const float* __restrict__ V,
                                                  const float* __restrict__ Z,
                                                  const float* __restrict__ KV,
                                                  float* __restrict__ O){
    int bhc = blockIdx.x;
    int bh = bhc / NC, c = bhc % NC;
    int b = bh / HH, h = bh % HH;
    int tid = threadIdx.x, g = tid>>6, e = tid&63;
    const int m0 = g*GM;
    __shared__ __align__(16) float kt[2][TT][MP2];
    __shared__ __align__(16) float qt[2][TT][MP2];
    __shared__ __align__(16) float vt[2][TT][64];
    __shared__ float partials[2][8][64];
    __shared__ float dred[2][9];

    float S[GM];
    const float* kvin = KV + (size_t)bhc*KVSTRIDE;
    #pragma unroll
    for (int i=0;i<GM;i++) S[i] = kvin[(size_t)(m0+i)*64 + e];
    float zreg = (tid < MP2) ? Z[(size_t)bhc*MP2 + tid] : 0.f;

    const float* kb = KP + ((size_t)bh*NN + c*CHK)*MP2;
    const float* qb = QP + ((size_t)bh*NN + c*CHK)*MP2;
    const float* vb = V  + ((size_t)(b*NN + c*CHK))*DD + h*64;

    auto load = [&](int buf, int tile){
        const float* kb_ = kb + (size_t)tile*TT*MP2;
        const float* qb_ = qb + (size_t)tile*TT*MP2;
        const float* vb_ = vb + (size_t)tile*TT*DD;
        for (int idx=tid; idx<1280; idx+=512){
            if (idx < 576){ int tok=idx/72, f=(idx%72)*4; cpasync16(&kt[buf][tok][f], kb_ + (size_t)tok*MP2 + f); }
            else if (idx < 1152){ int r=idx-576; int tok=r/72, f=(r%72)*4; cpasync16(&qt[buf][tok][f], qb_ + (size_t)tok*MP2 + f); }
            else { int r=idx-1152; int tok=r/16, f=(r%16)*4; cpasync16(&vt[buf][tok][f], vb_ + (size_t)tok*DD + f); }
        }
    };
    load(0,0); CP_COMMIT;

    for (int tile=0; tile<NTILE; tile++){
        int buf = tile&1;
        CP_WAIT0;
        __syncthreads();
        if (tile+1 < NTILE) load(buf^1, tile+1);
        CP_COMMIT;
        #pragma unroll
        for (int tt=0; tt<TT; tt++){
            int pt = tt & 1;
            // main recurrence: S += k v^T ; acc = q . S (inclusive)
            float vv = vt[buf][tt][e];
            const float4* kr = (const float4*)(&kt[buf][tt][m0]);
            const float4* qr = (const float4*)(&qt[buf][tt][m0]);
            float acc = 0.f;
            #pragma unroll
            for (int i4=0;i4<9;i4++){
                float4 kk = kr[i4];
                float4 qq = qr[i4];
                S[i4*4+0] += kk.x*vv;  acc += qq.x*S[i4*4+0];
                S[i4*4+1] += kk.y*vv;  acc += qq.y*S[i4*4+1];
                S[i4*4+2] += kk.z*vv;  acc += qq.z*S[i4*4+2];
                S[i4*4+3] += kk.w*vv;  acc += qq.w*S[i4*4+3];
            }
            partials[pt][g][e] = acc;
            // denominator: den = q . (z_incl + eps), per-m owned by one thread
            if (tid < MP2){
                float kv = kt[buf][tt][tid];
                zreg += kv;
                float dp = qt[buf][tt][tid]*(zreg + EPS_DEN);
                #pragma unroll
                for (int o=16;o;o>>=1) dp += __shfl_xor_sync(0xffffffffu, dp, o);
                if ((tid&31)==0) dred[pt][tid>>5] = dp;
            }
            __syncthreads();
            if (tid < 64){
                float s = 0.f;
                #pragma unroll
                for (int gg=0; gg<8; gg++) s += partials[pt][gg][tid];
                float den = 0.f;
                #pragma unroll
                for (int w=0; w<9; w++) den += dred[pt][w];
                int t = c*CHK + tile*TT + tt;
                O[((size_t)(b*NN + t))*DD + h*64 + tid] = s / den;
            }
        }
    }
}

// ---------------- launch ----------------
extern "C" void kernel_launch(void* const* d_in, const int* in_sizes, int n_in,
                              void* d_out, int out_size){
    (void)in_sizes; (void)n_in; (void)out_size;
    const float* x    = (const float*)d_in[0];
    const float* ln1g = (const float*)d_in[1];
    const float* ln1b = (const float*)d_in[2];
    const float* Wq   = (const float*)d_in[3];
    const float* bq   = (const float*)d_in[4];
    const float* Wk   = (const float*)d_in[5];
    const float* bk   = (const float*)d_in[6];
    const float* Wv   = (const float*)d_in[7];
    const float* bv   = (const float*)d_in[8];
    const float* Wo   = (const float*)d_in[9];
    const float* bo   = (const float*)d_in[10];
    const float* proj = (const float*)d_in[11];
    const float* ln2g = (const float*)d_in[12];
    const float* ln2b = (const float*)d_in[13];
    const float* W1   = (const float*)d_in[14];
    const float* b1   = (const float*)d_in[15];
    const float* W2   = (const float*)d_in[16];
    const float* b2   = (const float*)d_in[17];
    float* out = (float*)d_out;

    float *h1,*q,*k,*v,*qp,*kp,*kd,*o,*x1,*h2,*ff,*zz,*kv;
    cudaGetSymbolAddress((void**)&h1, g_h1);
    cudaGetSymbolAddress((void**)&q,  g_q);
    cudaGetSymbolAddress((void**)&k,  g_k);
    cudaGetSymbolAddress((void**)&v,  g_v);
    cudaGetSymbolAddress((void**)&qp, g_qp);
    cudaGetSymbolAddress((void**)&kp, g_kp);
    cudaGetSymbolAddress((void**)&kd, g_kdiag);
    cudaGetSymbolAddress((void**)&o,  g_o);
    cudaGetSymbolAddress((void**)&x1, g_x1);
    cudaGetSymbolAddress((void**)&h2, g_h2);
    cudaGetSymbolAddress((void**)&ff, g_ff);
    cudaGetSymbolAddress((void**)&zz, g_Z);
    cudaGetSymbolAddress((void**)&kv, g_KV);

    init_k<<<1,1>>>();
    ln_k<<<ROWS,256>>>(x, ln1g, ln1b, h1);

    dim3 g768(DD/64, ROWS/64);
    gemm_k<0><<<g768,256>>>(h1, Wq, bq, nullptr, q, DD, DD);
    gemm_k<0><<<g768,256>>>(h1, Wk, bk, nullptr, k, DD, DD);
    gemm_k<0><<<g768,256>>>(h1, Wv, bv, nullptr, v, DD, DD);

    featq_k <<<RIDS,128>>>(q, proj, qp);
    featk1_k<<<RIDS,128>>>(k, proj, kp, kd);
    {
        size_t total = (size_t)RIDS*MP2;
        featk2_k<<<(unsigned)((total+255)/256),256>>>(kp, kd);
    }

    chunksum_k<<<NCH,512>>>(kp, v, zz, kv);
    prefix_k  <<<BH, 512>>>(zz, kv);
    chunkout_k<<<NCH,512>>>(qp, kp, v, zz, kv, o);

    gemm_k<2><<<g768,256>>>(o, Wo, bo, x, x1, DD, DD);
    ln_k<<<ROWS,256>>>(x1, ln2g, ln2b, h2);

    dim3 gff(FFD/64, ROWS/64);
    gemm_k<1><<<gff,256>>>(h2, W1, b1, nullptr, ff, DD, FFD);
    gemm_k<2><<<g768,256>>>(ff, W2, b2, x1, out, FFD, DD);
}

// round 3
// speedup vs baseline: 3.9759x; 3.3659x over previous
#include <cuda_runtime.h>
#include <math.h>

// ---------------- problem constants ----------------
#define BB   2
#define NN   2048
#define DD   768
#define HH   12
#define MM   266          // random features
#define MP2  288          // padded to 8*36
#define GM   36           // features per scan group
#define FFD  3072
#define ROWS (BB*NN)      // 4096
#define RIDS (BB*HH*NN)   // 49152
#define BH   (BB*HH)      // 24
#define CHK  128
#define NC   (NN/CHK)     // 16
#define NCH  (BH*NC)      // 384
#define TT   8
#define NTILE (CHK/TT)    // 16
#define KVSTRIDE (MP2*64) // 18432

#define DN_SCALE   0.35355339059327f   // 64^-0.25
#define RATIO_SC   0.061313689f        // 266^-0.5
#define EPS_KER    1e-4f
#define EPS_DEN    1e-6f

// ---------------- scratch ----------------
__device__ float g_h1[ROWS*DD];
__device__ float g_q [ROWS*DD];
__device__ float g_k [ROWS*DD];
__device__ float g_v [ROWS*DD];
__device__ float g_o [ROWS*DD];
__device__ float g_x1[ROWS*DD];
__device__ float g_h2[ROWS*DD];
__device__ float g_ff[ROWS*FFD];
__device__ float g_qp[(size_t)RIDS*MP2];
__device__ float g_kp[(size_t)RIDS*MP2];
__device__ float g_rm[RIDS];
__device__ float g_sc[RIDS];
__device__ float g_Z [(size_t)NCH*MP2];
__device__ float g_KV[(size_t)NCH*KVSTRIDE];
__device__ unsigned g_kmax_u;

__device__ __forceinline__ unsigned enc_f(float f){
    unsigned u = __float_as_uint(f);
    return (u & 0x80000000u) ? ~u : (u | 0x80000000u);
}
__device__ __forceinline__ float dec_f(unsigned u){
    return (u & 0x80000000u) ? __uint_as_float(u ^ 0x80000000u) : __uint_as_float(~u);
}

__global__ void init_k(){ g_kmax_u = 0x00800000u; }

// ---------------- LayerNorm ----------------
__global__ void ln_k(const float* __restrict__ X, const float* __restrict__ G,
                     const float* __restrict__ Bv, float* __restrict__ Y){
    int row = blockIdx.x, tid = threadIdx.x;
    const float* x = X + (size_t)row*DD;
    float v0 = x[tid], v1 = x[tid+256], v2 = x[tid+512];
    float s = v0+v1+v2, ss = v0*v0 + v1*v1 + v2*v2;
    __shared__ float rs[8], rss[8], stat[2];
    for (int o=16;o;o>>=1){ s += __shfl_xor_sync(0xffffffffu,s,o); ss += __shfl_xor_sync(0xffffffffu,ss,o); }
    if ((tid&31)==0){ rs[tid>>5]=s; rss[tid>>5]=ss; }
    __syncthreads();
    if (tid==0){
        float S=0,SS=0;
        #pragma unroll
        for (int i=0;i<8;i++){ S+=rs[i]; SS+=rss[i]; }
        float mu = S*(1.0f/DD);
        float var = SS*(1.0f/DD) - mu*mu;
        stat[0]=mu; stat[1]=rsqrtf(var + 1e-5f);
    }
    __syncthreads();
    float mu = stat[0], rstd = stat[1];
    float* y = Y + (size_t)row*DD;
    y[tid]     = (v0-mu)*rstd*G[tid]     + Bv[tid];
    y[tid+256] = (v1-mu)*rstd*G[tid+256] + Bv[tid+256];
    y[tid+512] = (v2-mu)*rstd*G[tid+512] + Bv[tid+512];
}

// ---------------- SGEMM ----------------
template<int EPI>
__global__ void gemm_k(const float* __restrict__ A, const float* __restrict__ W,
                       const float* __restrict__ bias, const float* __restrict__ R,
                       float* __restrict__ C, int K, int NCc){
    __shared__ __align__(16) float Ast[16][68];
    __shared__ __align__(16) float Bs [16][64];
    int tid = threadIdx.x;
    int m0 = blockIdx.y*64, n0 = blockIdx.x*64;
    int ra = tid>>2,  ca = (tid&3)<<2;
    int rb = tid>>4,  cb = (tid&15)<<2;
    int ty = tid>>4,  tx = tid&15;
    float acc[4][4] = {};
    const float* Ap = A + (size_t)(m0+ra)*K + ca;
    const float* Wp = W + (size_t)rb*NCc + n0 + cb;
    for (int kb=0; kb<K; kb+=16){
        float4 av = *(const float4*)(Ap + kb);
        float4 bv = *(const float4*)(Wp + (size_t)kb*NCc);
        Ast[ca+0][ra]=av.x; Ast[ca+1][ra]=av.y; Ast[ca+2][ra]=av.z; Ast[ca+3][ra]=av.w;
        *(float4*)&Bs[rb][cb] = bv;
        __syncthreads();
        #pragma unroll
        for (int kk=0; kk<16; kk++){
            float4 a4 = *(const float4*)&Ast[kk][ty*4];
            float4 b4 = *(const float4*)&Bs [kk][tx*4];
            float a[4] = {a4.x,a4.y,a4.z,a4.w};
            float b[4] = {b4.x,b4.y,b4.z,b4.w};
            #pragma unroll
            for (int i=0;i<4;i++)
                #pragma unroll
                for (int j=0;j<4;j++) acc[i][j] += a[i]*b[j];
        }
        __syncthreads();
    }
    #pragma unroll
    for (int i=0;i<4;i++){
        int m = m0 + ty*4 + i;
        #pragma unroll
        for (int j=0;j<4;j++){
            int n = n0 + tx*4 + j;
            float vv = acc[i][j] + bias[n];
            if (EPI==1) vv = 0.5f*vv*(1.0f + erff(vv*0.70710678118654752f));
            if (EPI==2) vv += R[(size_t)m*NCc + n];
            C[(size_t)m*NCc + n] = vv;
        }
    }
}

// ---------------- FAVOR+ feature maps as GEMM ----------------
// Block: 32 tokens x 288 features, K=64 (two 32-steps). blockIdx.z: 0=Q, 1=K.
__global__ __launch_bounds__(256) void featgemm_k(const float* __restrict__ Q,
                                                  const float* __restrict__ Kin,
                                                  const float* __restrict__ proj,
                                                  float* __restrict__ QP,
                                                  float* __restrict__ KP,
                                                  float* __restrict__ RM){
    const int isK = blockIdx.z;
    const int bh = blockIdx.y;
    const int n0 = blockIdx.x*32;
    const int b = bh/HH, h = bh%HH;
    const float* A = (isK ? Kin : Q) + (size_t)(b*NN + n0)*DD + h*64;

    __shared__ float Ps[32][292];   // [d][m], padded stride (conflict-free)
    __shared__ float At[32][33];    // [d][t]
    __shared__ float diag_s[32];
    __shared__ float wmx[8];

    int tid = threadIdx.x;
    int tx = tid & 31, ty = tid >> 5;       // warp = one ty (4 tokens), lanes = feature groups
    float acc[4][9];
    #pragma unroll
    for (int i=0;i<4;i++)
        #pragma unroll
        for (int j=0;j<9;j++) acc[i][j]=0.f;

    #pragma unroll
    for (int ks=0; ks<2; ks++){
        // load A tile transposed: token t = tid/8, d4 = (tid%8)*4
        {
            int t = tid>>3, d4 = (tid&7)<<2;
            float4 a4 = *(const float4*)(A + (size_t)t*DD + ks*32 + d4);
            At[d4+0][t]=a4.x; At[d4+1][t]=a4.y; At[d4+2][t]=a4.z; At[d4+3][t]=a4.w;
        }
        // load proj tile transposed: m = tid/8 + it*32, d4 = (tid%8)*4
        {
            int d4 = (tid&7)<<2, mb = tid>>3;
            #pragma unroll
            for (int it=0; it<9; it++){
                int m = mb + it*32;
                float4 p4 = (m < MM) ? *(const float4*)(proj + (size_t)m*64 + ks*32 + d4)
                                     : make_float4(0.f,0.f,0.f,0.f);
                Ps[d4+0][m]=p4.x; Ps[d4+1][m]=p4.y; Ps[d4+2][m]=p4.z; Ps[d4+3][m]=p4.w;
            }
        }
        __syncthreads();
        // diag accumulation (threads 0..31, one token each)
        if (tid < 32){
            float s = (ks==0) ? 0.f : diag_s[tid];
            #pragma unroll
            for (int d=0; d<32; d++){ float a = At[d][tid]; s += a*a; }
            diag_s[tid] = s;
        }
        // main FMA loop
        #pragma unroll
        for (int d=0; d<32; d++){
            float a0 = At[d][ty*4+0];
            float a1 = At[d][ty*4+1];
            float a2 = At[d][ty*4+2];
            float a3 = At[d][ty*4+3];
            #pragma unroll
            for (int j=0;j<9;j++){
                float p = Ps[d][tx*9+j];
                acc[0][j] += a0*p;
                acc[1][j] += a1*p;
                acc[2][j] += a2*p;
                acc[3][j] += a3*p;
            }
        }
        __syncthreads();
    }

    // epilogue: scale, row max, exp
    float mx[4];
    #pragma unroll
    for (int i=0;i<4;i++){
        float m_ = -3.4e38f;
        #pragma unroll
        for (int j=0;j<9;j++){
            float v = acc[i][j]*DN_SCALE;
            acc[i][j] = v;
            if (tx*9+j < MM) m_ = fmaxf(m_, v);
        }
        #pragma unroll
        for (int o=16;o;o>>=1) m_ = fmaxf(m_, __shfl_xor_sync(0xffffffffu, m_, o));
        mx[i] = m_;
    }

    if (!isK){
        #pragma unroll
        for (int i=0;i<4;i++){
            int t = ty*4+i;
            float dg = diag_s[t]*0.0625f;
            float* out = QP + ((size_t)(bh*NN + n0 + t))*MP2;
            #pragma unroll
            for (int j=0;j<9;j++){
                int m = tx*9+j;
                out[m] = (m < MM) ? RATIO_SC*(__expf(acc[i][j]-dg-mx[i]) + EPS_KER) : 0.f;
            }
        }
    } else {
        float bm = -3.4e38f;
        #pragma unroll
        for (int i=0;i<4;i++){
            int t = ty*4+i;
            float dg = diag_s[t]*0.0625f;
            float* out = KP + ((size_t)(bh*NN + n0 + t))*MP2;
            #pragma unroll
            for (int j=0;j<9;j++){
                int m = tx*9+j;
                out[m] = (m < MM) ? __expf(acc[i][j]-dg-mx[i]) : 0.f;
            }
            if (tx==0) RM[bh*NN + n0 + t] = mx[i];
            bm = fmaxf(bm, mx[i]);
        }
        if (tx==0) wmx[ty] = bm;
        __syncthreads();
        if (tid==0){
            float B = wmx[0];
            #pragma unroll
            for (int w=1;w<8;w++) B = fmaxf(B, wmx[w]);
            atomicMax(&g_kmax_u, enc_f(B));
        }
    }
}

// per-row rescale factor exp(rowmax - globalmax)
__global__ void kscale_k(const float* __restrict__ RM, float* __restrict__ SC){
    int rid = blockIdx.x*256 + threadIdx.x;
    if (rid < RIDS) SC[rid] = __expf(RM[rid] - dec_f(g_kmax_u));
}

// KP = ratio*(f*scale + eps)
__global__ void krescale_k(float* __restrict__ KP, const float* __restrict__ SC){
    size_t idx = (size_t)blockIdx.x*256 + threadIdx.x;
    const size_t total = (size_t)RIDS*MP2;
    if (idx >= total) return;
    int rid = (int)(idx / MP2);
    int m   = (int)(idx % MP2);
    float vv = 0.f;
    if (m < MM) vv = RATIO_SC*(KP[idx]*SC[rid] + EPS_KER);
    KP[idx] = vv;
}

// ---------------- chunked causal linear attention ----------------
__device__ __forceinline__ void cpasync16(void* smem, const void* gmem){
    unsigned s = (unsigned)__cvta_generic_to_shared(smem);
    asm volatile("cp.async.ca.shared.global [%0], [%1], 16;\n" :: "r"(s), "l"(gmem));
}
#define CP_COMMIT asm volatile("cp.async.commit_group;\n" ::: "memory")
#define CP_WAIT0  asm volatile("cp.async.wait_group 0;\n" ::: "memory")

__global__ __launch_bounds__(512) void chunksum_k(const float* __restrict__ KP,
                                                  const float* __restrict__ V,
                                                  float* __restrict__ Z,
                                                  float* __restrict__ KV){
    int bhc = blockIdx.x;
    int bh = bhc / NC, c = bhc % NC;
    int b = bh / HH, h = bh % HH;
    int tid = threadIdx.x, g = tid>>6, e = tid&63;
    const int m0 = g*GM;
    __shared__ __align__(16) float kt[2][TT][MP2];
    __shared__ __align__(16) float vt[2][TT][64];
    float S[GM];
    #pragma unroll
    for (int i=0;i<GM;i++) S[i]=0.f;
    float zacc = 0.f;
    const float* kb = KP + ((size_t)bh*NN + c*CHK)*MP2;
    const float* vb = V  + ((size_t)(b*NN + c*CHK))*DD + h*64;

    auto load = [&](int buf, int tile){
        const float* kb_ = kb + (size_t)tile*TT*MP2;
        const float* vb_ = vb + (size_t)tile*TT*DD;
        for (int idx=tid; idx<704; idx+=512){
            if (idx < 576){ int tok=idx/72, f=(idx%72)*4; cpasync16(&kt[buf][tok][f], kb_ + (size_t)tok*MP2 + f); }
            else { int r=idx-576; int tok=r/16, f=(r%16)*4; cpasync16(&vt[buf][tok][f], vb_ + (size_t)tok*DD + f); }
        }
    };
    load(0,0); CP_COMMIT;
    for (int tile=0; tile<NTILE; tile++){
        int buf = tile&1;
        CP_WAIT0;
        __syncthreads();
        if (tile+1 < NTILE) load(buf^1, tile+1);
        CP_COMMIT;
        #pragma unroll
        for (int tt=0; tt<TT; tt++){
            float vv = vt[buf][tt][e];
            const float4* kr = (const float4*)(&kt[buf][tt][m0]);
            #pragma unroll
            for (int i4=0;i4<9;i4++){
                float4 kk = kr[i4];
                S[i4*4+0] += kk.x*vv;
                S[i4*4+1] += kk.y*vv;
                S[i4*4+2] += kk.z*vv;
                S[i4*4+3] += kk.w*vv;
            }
            if (tid < MP2) zacc += kt[buf][tt][tid];
        }
    }
    if (tid < MP2) Z[(size_t)bhc*MP2 + tid] = zacc;
    float* kvout = KV + (size_t)bhc*KVSTRIDE;
    #pragma unroll
    for (int i=0;i<GM;i++) kvout[(size_t)(m0+i)*64 + e] = S[i];
}

__global__ __launch_bounds__(512) void prefix_k(float* __restrict__ Z, float* __restrict__ KV){
    int bh = blockIdx.x;
    int base = bh*NC;
    int tid = threadIdx.x;
    for (int idx=tid; idx<KVSTRIDE; idx+=512){
        float run = 0.f;
        #pragma unroll
        for (int c=0;c<NC;c++){
            float* p = KV + (size_t)(base+c)*KVSTRIDE + idx;
            float t = *p; *p = run; run += t;
        }
    }
    if (tid < MP2){
        float run = 0.f;
        #pragma unroll
        for (int c=0;c<NC;c++){
            float* p = Z + (size_t)(base+c)*MP2 + tid;
            float t = *p; *p = run; run += t;
        }
    }
}

__global__ __launch_bounds__(512) void chunkout_k(const float* __restrict__ QP,
                                                  const float* __restrict__ KP,
                                                  const float* __restrict__ V,
                                                  const float* __restrict__ Z,
                                                  const float* __restrict__ KV,
                                                  float* __restrict__ O){
    int bhc = blockIdx.x;
    int bh = bhc / NC, c = bhc % NC;
    int b = bh / HH, h = bh % HH;
    int tid = threadIdx.x, g = tid>>6, e = tid&63;
    const int m0 = g*GM;
    __shared__ __align__(16) float kt[2][TT][MP2];
    __shared__ __align__(16) float qt[2][TT][MP2];
    __shared__ __align__(16) float vt[2][TT][64];
    __shared__ float partials[2][8][64];
    __shared__ float dred[2][9];

    float S[GM];
    const float* kvin = KV + (size_t)bhc*KVSTRIDE;
    #pragma unroll
    for (int i=0;i<GM;i++) S[i] = kvin[(size_t)(m0+i)*64 + e];
    float zreg = (tid < MP2) ? Z[(size_t)bhc*MP2 + tid] : 0.f;

    const float* kb = KP + ((size_t)bh*NN + c*CHK)*MP2;
    const float* qb = QP + ((size_t)bh*NN + c*CHK)*MP2;
    const float* vb = V  + ((size_t)(b*NN + c*CHK))*DD + h*64;

    auto load = [&](int buf, int tile){
        const float* kb_ = kb + (size_t)tile*TT*MP2;
        const float* qb_ = qb + (size_t)tile*TT*MP2;
        const float* vb_ = vb + (size_t)tile*TT*DD;
        for (int idx=tid; idx<1280; idx+=512){
            if (idx < 576){ int tok=idx/72, f=(idx%72)*4; cpasync16(&kt[buf][tok][f], kb_ + (size_t)tok*MP2 + f); }
            else if (idx < 1152){ int r=idx-576; int tok=r/72, f=(r%72)*4; cpasync16(&qt[buf][tok][f], qb_ + (size_t)tok*MP2 + f); }
            else { int r=idx-1152; int tok=r/16, f=(r%16)*4; cpasync16(&vt[buf][tok][f], vb_ + (size_t)tok*DD + f); }
        }
    };
    load(0,0); CP_COMMIT;

    for (int tile=0; tile<NTILE; tile++){
        int buf = tile&1;
        CP_WAIT0;
        __syncthreads();
        if (tile+1 < NTILE) load(buf^1, tile+1);
        CP_COMMIT;
        #pragma unroll
        for (int tt=0; tt<TT; tt++){
            int pt = tt & 1;
            float vv = vt[buf][tt][e];
            const float4* kr = (const float4*)(&kt[buf][tt][m0]);
            const float4* qr = (const float4*)(&qt[buf][tt][m0]);
            float acc = 0.f;
            #pragma unroll
            for (int i4=0;i4<9;i4++){
                float4 kk = kr[i4];
                float4 qq = qr[i4];
                S[i4*4+0] += kk.x*vv;  acc += qq.x*S[i4*4+0];
                S[i4*4+1] += kk.y*vv;  acc += qq.y*S[i4*4+1];
                S[i4*4+2] += kk.z*vv;  acc += qq.z*S[i4*4+2];
                S[i4*4+3] += kk.w*vv;  acc += qq.w*S[i4*4+3];
            }
            partials[pt][g][e] = acc;
            if (tid < MP2){
                float kv = kt[buf][tt][tid];
                zreg += kv;
                float dp = qt[buf][tt][tid]*(zreg + EPS_DEN);
                #pragma unroll
                for (int o=16;o;o>>=1) dp += __shfl_xor_sync(0xffffffffu, dp, o);
                if ((tid&31)==0) dred[pt][tid>>5] = dp;
            }
            __syncthreads();
            if (tid < 64){
                float s = 0.f;
                #pragma unroll
                for (int gg=0; gg<8; gg++) s += partials[pt][gg][tid];
                float den = 0.f;
                #pragma unroll
                for (int w=0; w<9; w++) den += dred[pt][w];
                int t = c*CHK + tile*TT + tt;
                O[((size_t)(b*NN + t))*DD + h*64 + tid] = s / den;
            }
        }
    }
}

// ---------------- launch ----------------
extern "C" void kernel_launch(void* const* d_in, const int* in_sizes, int n_in,
                              void* d_out, int out_size){
    (void)in_sizes; (void)n_in; (void)out_size;
    const float* x    = (const float*)d_in[0];
    const float* ln1g = (const float*)d_in[1];
    const float* ln1b = (const float*)d_in[2];
    const float* Wq   = (const float*)d_in[3];
    const float* bq   = (const float*)d_in[4];
    const float* Wk   = (const float*)d_in[5];
    const float* bk   = (const float*)d_in[6];
    const float* Wv   = (const float*)d_in[7];
    const float* bv   = (const float*)d_in[8];
    const float* Wo   = (const float*)d_in[9];
    const float* bo   = (const float*)d_in[10];
    const float* proj = (const float*)d_in[11];
    const float* ln2g = (const float*)d_in[12];
    const float* ln2b = (const float*)d_in[13];
    const float* W1   = (const float*)d_in[14];
    const float* b1   = (const float*)d_in[15];
    const float* W2   = (const float*)d_in[16];
    const float* b2   = (const float*)d_in[17];
    float* out = (float*)d_out;

    float *h1,*q,*k,*v,*qp,*kp,*rm,*sc,*o,*x1,*h2,*ff,*zz,*kv;
    cudaGetSymbolAddress((void**)&h1, g_h1);
    cudaGetSymbolAddress((void**)&q,  g_q);
    cudaGetSymbolAddress((void**)&k,  g_k);
    cudaGetSymbolAddress((void**)&v,  g_v);
    cudaGetSymbolAddress((void**)&qp, g_qp);
    cudaGetSymbolAddress((void**)&kp, g_kp);
    cudaGetSymbolAddress((void**)&rm, g_rm);
    cudaGetSymbolAddress((void**)&sc, g_sc);
    cudaGetSymbolAddress((void**)&o,  g_o);
    cudaGetSymbolAddress((void**)&x1, g_x1);
    cudaGetSymbolAddress((void**)&h2, g_h2);
    cudaGetSymbolAddress((void**)&ff, g_ff);
    cudaGetSymbolAddress((void**)&zz, g_Z);
    cudaGetSymbolAddress((void**)&kv, g_KV);

    init_k<<<1,1>>>();
    ln_k<<<ROWS,256>>>(x, ln1g, ln1b, h1);

    dim3 g768(DD/64, ROWS/64);
    gemm_k<0><<<g768,256>>>(h1, Wq, bq, nullptr, q, DD, DD);
    gemm_k<0><<<g768,256>>>(h1, Wk, bk, nullptr, k, DD, DD);
    gemm_k<0><<<g768,256>>>(h1, Wv, bv, nullptr, v, DD, DD);

    dim3 gfeat(NN/32, BH, 2);
    featgemm_k<<<gfeat,256>>>(q, k, proj, qp, kp, rm);
    kscale_k<<<(RIDS+255)/256,256>>>(rm, sc);
    {
        size_t total = (size_t)RIDS*MP2;
        krescale_k<<<(unsigned)((total+255)/256),256>>>(kp, sc);
    }

    chunksum_k<<<NCH,512>>>(kp, v, zz, kv);
    prefix_k  <<<BH, 512>>>(zz, kv);
    chunkout_k<<<NCH,512>>>(qp, kp, v, zz, kv, o);

    gemm_k<2><<<g768,256>>>(o, Wo, bo, x, x1, DD, DD);
    ln_k<<<ROWS,256>>>(x1, ln2g, ln2b, h2);

    dim3 gff(FFD/64, ROWS/64);
    gemm_k<1><<<gff,256>>>(h2, W1, b1, nullptr, ff, DD, FFD);
    gemm_k<2><<<g768,256>>>(ff, W2, b2, x1, out, FFD, DD);
}

// round 4
// speedup vs baseline: 4.3368x; 1.0908x over previous
#include <cuda_runtime.h>
#include <math.h>

// ---------------- problem constants ----------------
#define BB   2
#define NN   2048
#define DD   768
#define HH   12
#define MM   266
#define MP2  288
#define GM   36
#define FFD  3072
#define ROWS (BB*NN)
#define RIDS (BB*HH*NN)
#define BH   (BB*HH)
#define CHK  128
#define NC   (NN/CHK)
#define NCH  (BH*NC)
#define TT   8
#define NTILE (CHK/TT)
#define KVSTRIDE (MP2*64)

#define DN_SCALE   0.35355339059327f
#define RATIO_SC   0.061313689f
#define EPS_KER    1e-4f
#define EPS_DEN    1e-6f

// ---------------- scratch ----------------
__device__ float g_h1[ROWS*DD];
__device__ float g_q [ROWS*DD];
__device__ float g_k [ROWS*DD];
__device__ float g_v [ROWS*DD];
__device__ float g_o [ROWS*DD];
__device__ float g_x1[ROWS*DD];
__device__ float g_h2[ROWS*DD];
__device__ float g_ff[ROWS*FFD];
__device__ float g_qp[(size_t)RIDS*MP2];
__device__ float g_kp[(size_t)RIDS*MP2];
__device__ float g_rm[RIDS];
__device__ float g_sc[RIDS];
__device__ float g_Z [(size_t)NCH*MP2];
__device__ float g_KV[(size_t)NCH*KVSTRIDE];
__device__ unsigned g_kmax_u;

__device__ __forceinline__ unsigned enc_f(float f){
    unsigned u = __float_as_uint(f);
    return (u & 0x80000000u) ? ~u : (u | 0x80000000u);
}
__device__ __forceinline__ float dec_f(unsigned u){
    return (u & 0x80000000u) ? __uint_as_float(u ^ 0x80000000u) : __uint_as_float(~u);
}

__global__ void init_k(){ g_kmax_u = 0x00800000u; }

// ---------------- LayerNorm ----------------
__global__ void ln_k(const float* __restrict__ X, const float* __restrict__ G,
                     const float* __restrict__ Bv, float* __restrict__ Y){
    int row = blockIdx.x, tid = threadIdx.x;
    const float* x = X + (size_t)row*DD;
    float v0 = x[tid], v1 = x[tid+256], v2 = x[tid+512];
    float s = v0+v1+v2, ss = v0*v0 + v1*v1 + v2*v2;
    __shared__ float rs[8], rss[8], stat[2];
    for (int o=16;o;o>>=1){ s += __shfl_xor_sync(0xffffffffu,s,o); ss += __shfl_xor_sync(0xffffffffu,ss,o); }
    if ((tid&31)==0){ rs[tid>>5]=s; rss[tid>>5]=ss; }
    __syncthreads();
    if (tid==0){
        float S=0,SS=0;
        #pragma unroll
        for (int i=0;i<8;i++){ S+=rs[i]; SS+=rss[i]; }
        float mu = S*(1.0f/DD);
        float var = SS*(1.0f/DD) - mu*mu;
        stat[0]=mu; stat[1]=rsqrtf(var + 1e-5f);
    }
    __syncthreads();
    float mu = stat[0], rstd = stat[1];
    float* y = Y + (size_t)row*DD;
    y[tid]     = (v0-mu)*rstd*G[tid]     + Bv[tid];
    y[tid+256] = (v1-mu)*rstd*G[tid+256] + Bv[tid+256];
    y[tid+512] = (v2-mu)*rstd*G[tid+512] + Bv[tid+512];
}

// ---------------- cp.async helpers ----------------
__device__ __forceinline__ void cpasync16(void* smem, const void* gmem){
    unsigned s = (unsigned)__cvta_generic_to_shared(smem);
    asm volatile("cp.async.ca.shared.global [%0], [%1], 16;\n" :: "r"(s), "l"(gmem));
}
#define CP_COMMIT asm volatile("cp.async.commit_group;\n" ::: "memory")
#define CP_WAIT0  asm volatile("cp.async.wait_group 0;\n" ::: "memory")

// ---------------- SGEMM 128x128, 8x8 microtile, BK=8, double-buffered ----------------
// EPI: 0 = bias, 1 = bias+gelu(exact), 2 = bias+residual
template<int EPI>
__global__ __launch_bounds__(256) void gemm_k(const float* __restrict__ A,
                                              const float* __restrict__ W,
                                              const float* __restrict__ bias,
                                              const float* __restrict__ R,
                                              float* __restrict__ C, int K, int N){
    __shared__ __align__(16) float As[2][8][128];   // [k][m]
    __shared__ __align__(16) float Bs[2][8][128];   // [k][n]
    const int tid = threadIdx.x;
    const int m0 = blockIdx.y*128, n0 = blockIdx.x*128;
    const int tx = tid & 15, ty = tid >> 4;          // 16x16
    const int arow = tid >> 1, akc = (tid & 1) << 2; // A load: row 0..127, k 0/4
    const int brow = tid >> 5, bcol = (tid & 31) << 2;

    const float* Ap = A + (size_t)(m0 + arow)*K + akc;
    const float* Wp = W + (size_t)brow*N + n0 + bcol;

    float acc[8][8];
    #pragma unroll
    for (int i=0;i<8;i++)
        #pragma unroll
        for (int j=0;j<8;j++) acc[i][j]=0.f;

    float4 areg;
    // prologue: stage 0
    areg = *(const float4*)(Ap);
    cpasync16(&Bs[0][brow][bcol], Wp);
    CP_COMMIT;
    {
        As[0][akc+0][arow]=areg.x; As[0][akc+1][arow]=areg.y;
        As[0][akc+2][arow]=areg.z; As[0][akc+3][arow]=areg.w;
    }

    int st = 0;
    for (int kb=0; kb<K; kb+=8, st^=1){
        const bool hasNext = (kb+8 < K);
        if (hasNext) areg = *(const float4*)(Ap + kb + 8);
        CP_WAIT0;
        __syncthreads();
        if (hasNext){
            cpasync16(&Bs[st^1][brow][bcol], Wp + (size_t)(kb+8)*N);
            CP_COMMIT;
        }
        #pragma unroll
        for (int kk=0; kk<8; kk++){
            float4 a0 = *(const float4*)&As[st][kk][ty*4];
            float4 a1 = *(const float4*)&As[st][kk][64+ty*4];
            float4 b0 = *(const float4*)&Bs[st][kk][tx*4];
            float4 b1 = *(const float4*)&Bs[st][kk][64+tx*4];
            float a[8] = {a0.x,a0.y,a0.z,a0.w,a1.x,a1.y,a1.z,a1.w};
            float b[8] = {b0.x,b0.y,b0.z,b0.w,b1.x,b1.y,b1.z,b1.w};
            #pragma unroll
            for (int i=0;i<8;i++)
                #pragma unroll
                for (int j=0;j<8;j++) acc[i][j] += a[i]*b[j];
        }
        if (hasNext){
            int nb = st^1;
            As[nb][akc+0][arow]=areg.x; As[nb][akc+1][arow]=areg.y;
            As[nb][akc+2][arow]=areg.z; As[nb][akc+3][arow]=areg.w;
        }
    }

    // epilogue
    #pragma unroll
    for (int i=0;i<8;i++){
        int m = m0 + ((i<4) ? (ty*4+i) : (64+ty*4+i-4));
        #pragma unroll
        for (int half=0; half<2; half++){
            int n = n0 + half*64 + tx*4;
            float4 vv;
            float* pv = &vv.x;
            #pragma unroll
            for (int j=0;j<4;j++){
                float v = acc[i][half*4+j] + bias[n+j];
                if (EPI==1) v = 0.5f*v*(1.0f + erff(v*0.70710678118654752f));
                pv[j] = v;
            }
            if (EPI==2){
                float4 r4 = *(const float4*)(R + (size_t)m*N + n);
                vv.x += r4.x; vv.y += r4.y; vv.z += r4.z; vv.w += r4.w;
            }
            *(float4*)(C + (size_t)m*N + n) = vv;
        }
    }
}

// ---------------- FAVOR+ feature maps as GEMM ----------------
__global__ __launch_bounds__(256) void featgemm_k(const float* __restrict__ Q,
                                                  const float* __restrict__ Kin,
                                                  const float* __restrict__ proj,
                                                  float* __restrict__ QP,
                                                  float* __restrict__ KP,
                                                  float* __restrict__ RM){
    const int isK = blockIdx.z;
    const int bh = blockIdx.y;
    const int n0 = blockIdx.x*32;
    const int b = bh/HH, h = bh%HH;
    const float* A = (isK ? Kin : Q) + (size_t)(b*NN + n0)*DD + h*64;

    __shared__ float Ps[32][292];
    __shared__ float At[32][33];
    __shared__ float diag_s[32];
    __shared__ float wmx[8];

    int tid = threadIdx.x;
    int tx = tid & 31, ty = tid >> 5;
    float acc[4][9];
    #pragma unroll
    for (int i=0;i<4;i++)
        #pragma unroll
        for (int j=0;j<9;j++) acc[i][j]=0.f;

    #pragma unroll
    for (int ks=0; ks<2; ks++){
        {
            int t = tid>>3, d4 = (tid&7)<<2;
            float4 a4 = *(const float4*)(A + (size_t)t*DD + ks*32 + d4);
            At[d4+0][t]=a4.x; At[d4+1][t]=a4.y; At[d4+2][t]=a4.z; At[d4+3][t]=a4.w;
        }
        {
            int d4 = (tid&7)<<2, mb = tid>>3;
            #pragma unroll
            for (int it=0; it<9; it++){
                int m = mb + it*32;
                float4 p4 = (m < MM) ? *(const float4*)(proj + (size_t)m*64 + ks*32 + d4)
                                     : make_float4(0.f,0.f,0.f,0.f);
                Ps[d4+0][m]=p4.x; Ps[d4+1][m]=p4.y; Ps[d4+2][m]=p4.z; Ps[d4+3][m]=p4.w;
            }
        }
        __syncthreads();
        if (tid < 32){
            float s = (ks==0) ? 0.f : diag_s[tid];
            #pragma unroll
            for (int d=0; d<32; d++){ float a = At[d][tid]; s += a*a; }
            diag_s[tid] = s;
        }
        #pragma unroll
        for (int d=0; d<32; d++){
            float a0 = At[d][ty*4+0];
            float a1 = At[d][ty*4+1];
            float a2 = At[d][ty*4+2];
            float a3 = At[d][ty*4+3];
            #pragma unroll
            for (int j=0;j<9;j++){
                float p = Ps[d][tx*9+j];
                acc[0][j] += a0*p;
                acc[1][j] += a1*p;
                acc[2][j] += a2*p;
                acc[3][j] += a3*p;
            }
        }
        __syncthreads();
    }

    float mx[4];
    #pragma unroll
    for (int i=0;i<4;i++){
        float m_ = -3.4e38f;
        #pragma unroll
        for (int j=0;j<9;j++){
            float v = acc[i][j]*DN_SCALE;
            acc[i][j] = v;
            if (tx*9+j < MM) m_ = fmaxf(m_, v);
        }
        #pragma unroll
        for (int o=16;o;o>>=1) m_ = fmaxf(m_, __shfl_xor_sync(0xffffffffu, m_, o));
        mx[i] = m_;
    }

    if (!isK){
        #pragma unroll
        for (int i=0;i<4;i++){
            int t = ty*4+i;
            float dg = diag_s[t]*0.0625f;
            float* out = QP + ((size_t)(bh*NN + n0 + t))*MP2;
            #pragma unroll
            for (int j=0;j<9;j++){
                int m = tx*9+j;
                out[m] = (m < MM) ? RATIO_SC*(__expf(acc[i][j]-dg-mx[i]) + EPS_KER) : 0.f;
            }
        }
    } else {
        float bm = -3.4e38f;
        #pragma unroll
        for (int i=0;i<4;i++){
            int t = ty*4+i;
            float dg = diag_s[t]*0.0625f;
            float* out = KP + ((size_t)(bh*NN + n0 + t))*MP2;
            #pragma unroll
            for (int j=0;j<9;j++){
                int m = tx*9+j;
                out[m] = (m < MM) ? __expf(acc[i][j]-dg-mx[i]) : 0.f;
            }
            if (tx==0) RM[bh*NN + n0 + t] = mx[i];
            bm = fmaxf(bm, mx[i]);
        }
        if (tx==0) wmx[ty] = bm;
        __syncthreads();
        if (tid==0){
            float B = wmx[0];
            #pragma unroll
            for (int w=1;w<8;w++) B = fmaxf(B, wmx[w]);
            atomicMax(&g_kmax_u, enc_f(B));
        }
    }
}

__global__ void kscale_k(const float* __restrict__ RM, float* __restrict__ SC){
    int rid = blockIdx.x*256 + threadIdx.x;
    if (rid < RIDS) SC[rid] = __expf(RM[rid] - dec_f(g_kmax_u));
}

__global__ void krescale_k(float* __restrict__ KP, const float* __restrict__ SC){
    size_t idx = (size_t)blockIdx.x*256 + threadIdx.x;
    const size_t total = (size_t)RIDS*MP2;
    if (idx >= total) return;
    int rid = (int)(idx / MP2);
    int m   = (int)(idx % MP2);
    float vv = 0.f;
    if (m < MM) vv = RATIO_SC*(KP[idx]*SC[rid] + EPS_KER);
    KP[idx] = vv;
}

// ---------------- chunked causal linear attention ----------------
__global__ __launch_bounds__(512) void chunksum_k(const float* __restrict__ KP,
                                                  const float* __restrict__ V,
                                                  float* __restrict__ Z,
                                                  float* __restrict__ KV){
    int bhc = blockIdx.x;
    int bh = bhc / NC, c = bhc % NC;
    int b = bh / HH, h = bh % HH;
    int tid = threadIdx.x, g = tid>>6, e = tid&63;
    const int m0 = g*GM;
    __shared__ __align__(16) float kt[2][TT][MP2];
    __shared__ __align__(16) float vt[2][TT][64];
    float S[GM];
    #pragma unroll
    for (int i=0;i<GM;i++) S[i]=0.f;
    float zacc = 0.f;
    const float* kb = KP + ((size_t)bh*NN + c*CHK)*MP2;
    const float* vb = V  + ((size_t)(b*NN + c*CHK))*DD + h*64;

    auto load = [&](int buf, int tile){
        const float* kb_ = kb + (size_t)tile*TT*MP2;
        const float* vb_ = vb + (size_t)tile*TT*DD;
        for (int idx=tid; idx<704; idx+=512){
            if (idx < 576){ int tok=idx/72, f=(idx%72)*4; cpasync16(&kt[buf][tok][f], kb_ + (size_t)tok*MP2 + f); }
            else { int r=idx-576; int tok=r/16, f=(r%16)*4; cpasync16(&vt[buf][tok][f], vb_ + (size_t)tok*DD + f); }
        }
    };
    load(0,0); CP_COMMIT;
    for (int tile=0; tile<NTILE; tile++){
        int buf = tile&1;
        CP_WAIT0;
        __syncthreads();
        if (tile+1 < NTILE) load(buf^1, tile+1);
        CP_COMMIT;
        #pragma unroll
        for (int tt=0; tt<TT; tt++){
            float vv = vt[buf][tt][e];
            const float4* kr = (const float4*)(&kt[buf][tt][m0]);
            #pragma unroll
            for (int i4=0;i4<9;i4++){
                float4 kk = kr[i4];
                S[i4*4+0] += kk.x*vv;
                S[i4*4+1] += kk.y*vv;
                S[i4*4+2] += kk.z*vv;
                S[i4*4+3] += kk.w*vv;
            }
            if (tid < MP2) zacc += kt[buf][tt][tid];
        }
    }
    if (tid < MP2) Z[(size_t)bhc*MP2 + tid] = zacc;
    float* kvout = KV + (size_t)bhc*KVSTRIDE;
    #pragma unroll
    for (int i=0;i<GM;i++) kvout[(size_t)(m0+i)*64 + e] = S[i];
}

__global__ __launch_bounds__(512) void prefix_k(float* __restrict__ Z, float* __restrict__ KV){
    int bh = blockIdx.x;
    int base = bh*NC;
    int tid = threadIdx.x;
    for (int idx=tid; idx<KVSTRIDE; idx+=512){
        float run = 0.f;
        #pragma unroll
        for (int c=0;c<NC;c++){
            float* p = KV + (size_t)(base+c)*KVSTRIDE + idx;
            float t = *p; *p = run; run += t;
        }
    }
    if (tid < MP2){
        float run = 0.f;
        #pragma unroll
        for (int c=0;c<NC;c++){
            float* p = Z + (size_t)(base+c)*MP2 + tid;
            float t = *p; *p = run; run += t;
        }
    }
}

__global__ __launch_bounds__(512) void chunkout_k(const float* __restrict__ QP,
                                                  const float* __restrict__ KP,
                                                  const float* __restrict__ V,
                                                  const float* __restrict__ Z,
                                                  const float* __restrict__ KV,
                                                  float* __restrict__ O){
    int bhc = blockIdx.x;
    int bh = bhc / NC, c = bhc % NC;
    int b = bh / HH, h = bh % HH;
    int tid = threadIdx.x, g = tid>>6, e = tid&63;
    const int m0 = g*GM;
    __shared__ __align__(16) float kt[2][TT][MP2];
    __shared__ __align__(16) float qt[2][TT][MP2];
    __shared__ __align__(16) float vt[2][TT][64];
    __shared__ float partials[2][8][64];
    __shared__ float dred[2][9];

    float S[GM];
    const float* kvin = KV + (size_t)bhc*KVSTRIDE;
    #pragma unroll
    for (int i=0;i<GM;i++) S[i] = kvin[(size_t)(m0+i)*64 + e];
    float zreg = (tid < MP2) ? Z[(size_t)bhc*MP2 + tid] : 0.f;

    const float* kb = KP + ((size_t)bh*NN + c*CHK)*MP2;
    const float* qb = QP + ((size_t)bh*NN + c*CHK)*MP2;
    const float* vb = V  + ((size_t)(b*NN + c*CHK))*DD + h*64;

    auto load = [&](int buf, int tile){
        const float* kb_ = kb + (size_t)tile*TT*MP2;
        const float* qb_ = qb + (size_t)tile*TT*MP2;
        const float* vb_ = vb + (size_t)tile*TT*DD;
        for (int idx=tid; idx<1280; idx+=512){
            if (idx < 576){ int tok=idx/72, f=(idx%72)*4; cpasync16(&kt[buf][tok][f], kb_ + (size_t)tok*MP2 + f); }
            else if (idx < 1152){ int r=idx-576; int tok=r/72, f=(r%72)*4; cpasync16(&qt[buf][tok][f], qb_ + (size_t)tok*MP2 + f); }
            else { int r=idx-1152; int tok=r/16, f=(r%16)*4; cpasync16(&vt[buf][tok][f], vb_ + (size_t)tok*DD + f); }
        }
    };
    load(0,0); CP_COMMIT;

    for (int tile=0; tile<NTILE; tile++){
        int buf = tile&1;
        CP_WAIT0;
        __syncthreads();
        if (tile+1 < NTILE) load(buf^1, tile+1);
        CP_COMMIT;
        #pragma unroll
        for (int tt=0; tt<TT; tt++){
            int pt = tt & 1;
            float vv = vt[buf][tt][e];
            const float4* kr = (const float4*)(&kt[buf][tt][m0]);
            const float4* qr = (const float4*)(&qt[buf][tt][m0]);
            float acc = 0.f;
            #pragma unroll
            for (int i4=0;i4<9;i4++){
                float4 kk = kr[i4];
                float4 qq = qr[i4];
                S[i4*4+0] += kk.x*vv;  acc += qq.x*S[i4*4+0];
                S[i4*4+1] += kk.y*vv;  acc += qq.y*S[i4*4+1];
                S[i4*4+2] += kk.z*vv;  acc += qq.z*S[i4*4+2];
                S[i4*4+3] += kk.w*vv;  acc += qq.w*S[i4*4+3];
            }
            partials[pt][g][e] = acc;
            if (tid < MP2){
                float kv = kt[buf][tt][tid];
                zreg += kv;
                float dp = qt[buf][tt][tid]*(zreg + EPS_DEN);
                #pragma unroll
                for (int o=16;o;o>>=1) dp += __shfl_xor_sync(0xffffffffu, dp, o);
                if ((tid&31)==0) dred[pt][tid>>5] = dp;
            }
            __syncthreads();
            if (tid < 64){
                float s = 0.f;
                #pragma unroll
                for (int gg=0; gg<8; gg++) s += partials[pt][gg][tid];
                float den = 0.f;
                #pragma unroll
                for (int w=0; w<9; w++) den += dred[pt][w];
                int t = c*CHK + tile*TT + tt;
                O[((size_t)(b*NN + t))*DD + h*64 + tid] = s / den;
            }
        }
    }
}

// ---------------- launch ----------------
extern "C" void kernel_launch(void* const* d_in, const int* in_sizes, int n_in,
                              void* d_out, int out_size){
    (void)in_sizes; (void)n_in; (void)out_size;
    const float* x    = (const float*)d_in[0];
    const float* ln1g = (const float*)d_in[1];
    const float* ln1b = (const float*)d_in[2];
    const float* Wq   = (const float*)d_in[3];
    const float* bq   = (const float*)d_in[4];
    const float* Wk   = (const float*)d_in[5];
    const float* bk   = (const float*)d_in[6];
    const float* Wv   = (const float*)d_in[7];
    const float* bv   = (const float*)d_in[8];
    const float* Wo   = (const float*)d_in[9];
    const float* bo   = (const float*)d_in[10];
    const float* proj = (const float*)d_in[11];
    const float* ln2g = (const float*)d_in[12];
    const float* ln2b = (const float*)d_in[13];
    const float* W1   = (const float*)d_in[14];
    const float* b1   = (const float*)d_in[15];
    const float* W2   = (const float*)d_in[16];
    const float* b2   = (const float*)d_in[17];
    float* out = (float*)d_out;

    float *h1,*q,*k,*v,*qp,*kp,*rm,*sc,*o,*x1,*h2,*ff,*zz,*kv;
    cudaGetSymbolAddress((void**)&h1, g_h1);
    cudaGetSymbolAddress((void**)&q,  g_q);
    cudaGetSymbolAddress((void**)&k,  g_k);
    cudaGetSymbolAddress((void**)&v,  g_v);
    cudaGetSymbolAddress((void**)&qp, g_qp);
    cudaGetSymbolAddress((void**)&kp, g_kp);
    cudaGetSymbolAddress((void**)&rm, g_rm);
    cudaGetSymbolAddress((void**)&sc, g_sc);
    cudaGetSymbolAddress((void**)&o,  g_o);
    cudaGetSymbolAddress((void**)&x1, g_x1);
    cudaGetSymbolAddress((void**)&h2, g_h2);
    cudaGetSymbolAddress((void**)&ff, g_ff);
    cudaGetSymbolAddress((void**)&zz, g_Z);
    cudaGetSymbolAddress((void**)&kv, g_KV);

    init_k<<<1,1>>>();
    ln_k<<<ROWS,256>>>(x, ln1g, ln1b, h1);

    dim3 g768(DD/128, ROWS/128);      // (6, 32)
    gemm_k<0><<<g768,256>>>(h1, Wq, bq, nullptr, q, DD, DD);
    gemm_k<0><<<g768,256>>>(h1, Wk, bk, nullptr, k, DD, DD);
    gemm_k<0><<<g768,256>>>(h1, Wv, bv, nullptr, v, DD, DD);

    dim3 gfeat(NN/32, BH, 2);
    featgemm_k<<<gfeat,256>>>(q, k, proj, qp, kp, rm);
    kscale_k<<<(RIDS+255)/256,256>>>(rm, sc);
    {
        size_t total = (size_t)RIDS*MP2;
        krescale_k<<<(unsigned)((total+255)/256),256>>>(kp, sc);
    }

    chunksum_k<<<NCH,512>>>(kp, v, zz, kv);
    prefix_k  <<<BH, 512>>>(zz, kv);
    chunkout_k<<<NCH,512>>>(qp, kp, v, zz, kv, o);

    gemm_k<2><<<g768,256>>>(o, Wo, bo, x, x1, DD, DD);
    ln_k<<<ROWS,256>>>(x1, ln2g, ln2b, h2);

    dim3 gff(FFD/128, ROWS/128);      // (24, 32)
    gemm_k<1><<<gff,256>>>(h2, W1, b1, nullptr, ff, DD, FFD);
    gemm_k<2><<<g768,256>>>(ff, W2, b2, x1, out, FFD, DD);
}

// round 5
// speedup vs baseline: 5.2885x; 1.2195x over previous
#include <cuda_runtime.h>
#include <math.h>
#include <stdint.h>

// ---------------- problem constants ----------------
#define BB   2
#define NN   2048
#define DD   768
#define HH   12
#define MM   266
#define MP2  288
#define GM   36
#define FFD  3072
#define ROWS (BB*NN)
#define RIDS (BB*HH*NN)
#define BH   (BB*HH)
#define CHK  128
#define NC   (NN/CHK)
#define NCH  (BH*NC)
#define TT   8
#define NTILE (CHK/TT)
#define KVSTRIDE (MP2*64)
#define QKVS 2304

#define DN_SCALE   0.35355339059327f
#define RATIO_SC   0.061313689f
#define EPS_KER    1e-4f
#define EPS_DEN    1e-6f

// ---------------- scratch ----------------
__device__ float g_h1[ROWS*DD];
__device__ float g_qkv[(size_t)ROWS*QKVS];
__device__ float g_o [ROWS*DD];
__device__ float g_x1[ROWS*DD];
__device__ float g_h2[ROWS*DD];
__device__ float g_ff[ROWS*FFD];
__device__ float g_qp[(size_t)RIDS*MP2];
__device__ float g_kp[(size_t)RIDS*MP2];
__device__ float g_rm[RIDS];
__device__ float g_sc[RIDS];
__device__ float g_Z [(size_t)NCH*MP2];
__device__ float g_KV[(size_t)NCH*KVSTRIDE];
__device__ unsigned g_kmax_u;
__device__ float g_bqkv[QKVS];
// fragment-ordered tf32 hi/lo buffers
__device__ unsigned g_afh[(size_t)(ROWS/16)*(FFD/8)*128];
__device__ unsigned g_afl[(size_t)(ROWS/16)*(FFD/8)*128];
__device__ unsigned g_wfh[(size_t)(FFD/8)*(DD/8)*64];
__device__ unsigned g_wfl[(size_t)(FFD/8)*(DD/8)*64];

__device__ __forceinline__ unsigned enc_f(float f){
    unsigned u = __float_as_uint(f);
    return (u & 0x80000000u) ? ~u : (u | 0x80000000u);
}
__device__ __forceinline__ float dec_f(unsigned u){
    return (u & 0x80000000u) ? __uint_as_float(u ^ 0x80000000u) : __uint_as_float(~u);
}

__global__ void init_k(){ g_kmax_u = 0x00800000u; }

__device__ __forceinline__ unsigned tf32h(float f){
    unsigned r; asm("cvt.rna.tf32.f32 %0, %1;" : "=r"(r) : "f"(f)); return r;
}

// ---------------- LayerNorm ----------------
__global__ void ln_k(const float* __restrict__ X, const float* __restrict__ G,
                     const float* __restrict__ Bv, float* __restrict__ Y){
    int row = blockIdx.x, tid = threadIdx.x;
    const float* x = X + (size_t)row*DD;
    float v0 = x[tid], v1 = x[tid+256], v2 = x[tid+512];
    float s = v0+v1+v2, ss = v0*v0 + v1*v1 + v2*v2;
    __shared__ float rs[8], rss[8], stat[2];
    for (int o=16;o;o>>=1){ s += __shfl_xor_sync(0xffffffffu,s,o); ss += __shfl_xor_sync(0xffffffffu,ss,o); }
    if ((tid&31)==0){ rs[tid>>5]=s; rss[tid>>5]=ss; }
    __syncthreads();
    if (tid==0){
        float S=0,SS=0;
        #pragma unroll
        for (int i=0;i<8;i++){ S+=rs[i]; SS+=rss[i]; }
        float mu = S*(1.0f/DD);
        float var = SS*(1.0f/DD) - mu*mu;
        stat[0]=mu; stat[1]=rsqrtf(var + 1e-5f);
    }
    __syncthreads();
    float mu = stat[0], rstd = stat[1];
    float* y = Y + (size_t)row*DD;
    y[tid]     = (v0-mu)*rstd*G[tid]     + Bv[tid];
    y[tid+256] = (v1-mu)*rstd*G[tid+256] + Bv[tid+256];
    y[tid+512] = (v2-mu)*rstd*G[tid+512] + Bv[tid+512];
}

// ---------------- tf32 split kernels (fragment-ordered) ----------------
// A[R][C] -> per-atom (16x8) fragment order: [(am*C8+ak)*32+lane] uint4
__global__ void splitA_k(const float* __restrict__ X, unsigned* __restrict__ H,
                         unsigned* __restrict__ L, int R, int Ccols){
    int idx = blockIdx.x*256 + threadIdx.x;
    int C8 = Ccols>>3;
    int total = (R>>4)*C8*32;
    if (idx >= total) return;
    int lane = idx & 31, atom = idx >> 5;
    int am = atom / C8, ak = atom % C8;
    int g = lane>>2, l = lane&3;
    const float* p = X + (size_t)(am*16+g)*Ccols + ak*8 + l;
    float a0 = p[0], a1 = p[(size_t)8*Ccols], a2 = p[4], a3 = p[(size_t)8*Ccols+4];
    uint4 h, lo;
    h.x = tf32h(a0); lo.x = tf32h(a0 - __uint_as_float(h.x));
    h.y = tf32h(a1); lo.y = tf32h(a1 - __uint_as_float(h.y));
    h.z = tf32h(a2); lo.z = tf32h(a2 - __uint_as_float(h.z));
    h.w = tf32h(a3); lo.w = tf32h(a3 - __uint_as_float(h.w));
    ((uint4*)H)[idx] = h;
    ((uint4*)L)[idx] = lo;
}

// W[K][N] -> B-fragment (8k x 8n, col-major frag) order: [((anBase+an)*K8+ak)*32+lane] uint2
__global__ void splitB_k(const float* __restrict__ W, unsigned* __restrict__ H,
                         unsigned* __restrict__ L, int K, int N, int anBase){
    int idx = blockIdx.x*256 + threadIdx.x;
    int K8 = K>>3;
    int total = K8*(N>>3)*32;
    if (idx >= total) return;
    int lane = idx & 31, atom = idx >> 5;
    int an = atom / K8, ak = atom % K8;
    int g = lane>>2, l = lane&3;
    const float* p = W + (size_t)(ak*8+l)*N + an*8 + g;
    float b0 = p[0], b1 = p[(size_t)4*N];
    uint2 h, lo;
    h.x = tf32h(b0); lo.x = tf32h(b0 - __uint_as_float(h.x));
    h.y = tf32h(b1); lo.y = tf32h(b1 - __uint_as_float(h.y));
    int outi = ((anBase + an)*K8 + ak)*32 + lane;
    ((uint2*)H)[outi] = h;
    ((uint2*)L)[outi] = lo;
}

__global__ void packb_k(const float* __restrict__ bq, const float* __restrict__ bk,
                        const float* __restrict__ bv, float* __restrict__ o){
    int i = blockIdx.x*256 + threadIdx.x;
    if (i < DD){ o[i]=bq[i]; o[DD+i]=bk[i]; o[2*DD+i]=bv[i]; }
}

// ---------------- cp.async helpers ----------------
__device__ __forceinline__ void cpasync16(void* smem, const void* gmem){
    unsigned s = (unsigned)__cvta_generic_to_shared(smem);
    asm volatile("cp.async.ca.shared.global [%0], [%1], 16;\n" :: "r"(s), "l"(gmem));
}
#define CP_COMMIT asm volatile("cp.async.commit_group;\n" ::: "memory")
#define CP_WAIT0  asm volatile("cp.async.wait_group 0;\n" ::: "memory")

// ---------------- tf32 tensor-core GEMM ----------------
__device__ __forceinline__ void mma8(float* d, const unsigned* a, const unsigned* b){
    asm volatile("mma.sync.aligned.m16n8k8.row.col.f32.tf32.tf32.f32 "
        "{%0,%1,%2,%3},{%4,%5,%6,%7},{%8,%9},{%0,%1,%2,%3};"
        : "+f"(d[0]),"+f"(d[1]),"+f"(d[2]),"+f"(d[3])
        : "r"(a[0]),"r"(a[1]),"r"(a[2]),"r"(a[3]),"r"(b[0]),"r"(b[1]));
}

// CTA tile 128x128, 8 warps (2x4), warp tile 64x32, BK=32 (4 k-atoms), 2-stage.
// EPI: 0=bias, 1=bias+gelu, 2=bias+residual
template<int EPI>
__global__ __launch_bounds__(256) void gemm_tc(const unsigned* __restrict__ Ah,
                                               const unsigned* __restrict__ Al,
                                               const unsigned* __restrict__ Bh,
                                               const unsigned* __restrict__ Bl,
                                               const float* __restrict__ bias,
                                               const float* __restrict__ R,
                                               float* __restrict__ C, int K8, int N){
    extern __shared__ float smem[];
    const int tid = threadIdx.x, lane = tid & 31, warp = tid >> 5;
    const int wm = warp >> 2, wn = warp & 3;
    const int bm = blockIdx.y, bn = blockIdx.x;

    float acc[4][4][4];
    #pragma unroll
    for (int a=0;a<4;a++)
        #pragma unroll
        for (int b=0;b<4;b++)
            #pragma unroll
            for (int c=0;c<4;c++) acc[a][b][c]=0.f;

    auto stage_copy = [&](int s, int kb){
        float* dA = smem + s*8192;
        float* dB = smem + 16384 + s*8192;
        #pragma unroll
        for (int i=0;i<4;i++){
            int j = tid + i*256;
            int ma = j>>7, r = j&127;
            size_t ga = ((size_t)(bm*8+ma)*K8 + kb)*128 + r*4;
            cpasync16(dA + ma*512 + r*4,        Ah + ga);
            cpasync16(dA + 4096 + ma*512 + r*4, Al + ga);
            int na = j>>6, rb = j&63;
            size_t gb = ((size_t)(bn*16+na)*K8 + kb)*64 + rb*4;
            cpasync16(dB + na*256 + rb*4,        Bh + gb);
            cpasync16(dB + 4096 + na*256 + rb*4, Bl + gb);
        }
    };

    stage_copy(0, 0); CP_COMMIT;
    const int nk = K8 >> 2;
    int st = 0;
    for (int ks=0; ks<nk; ks++, st^=1){
        CP_WAIT0;
        __syncthreads();
        if (ks+1 < nk){ stage_copy(st^1, (ks+1)*4); CP_COMMIT; }
        const unsigned* sA = (const unsigned*)(smem + st*8192);
        const unsigned* sB = (const unsigned*)(smem + 16384 + st*8192);
        #pragma unroll
        for (int ka=0; ka<4; ka++){
            uint4 Afh[4], Afl[4];
            uint2 Bfh[4], Bfl[4];
            #pragma unroll
            for (int mi=0;mi<4;mi++){
                int off = ((wm*4+mi)*4 + ka)*128 + lane*4;
                Afh[mi] = *(const uint4*)(sA + off);
                Afl[mi] = *(const uint4*)(sA + 4096 + off);
            }
            #pragma unroll
            for (int ni=0;ni<4;ni++){
                int off = ((wn*4+ni)*4 + ka)*64 + lane*2;
                Bfh[ni] = *(const uint2*)(sB + off);
                Bfl[ni] = *(const uint2*)(sB + 4096 + off);
            }
            #pragma unroll
            for (int mi=0;mi<4;mi++)
                #pragma unroll
                for (int ni=0;ni<4;ni++){
                    mma8(acc[mi][ni], (const unsigned*)&Afh[mi], (const unsigned*)&Bfh[ni]);
                    mma8(acc[mi][ni], (const unsigned*)&Afh[mi], (const unsigned*)&Bfl[ni]);
                    mma8(acc[mi][ni], (const unsigned*)&Afl[mi], (const unsigned*)&Bfh[ni]);
                }
        }
    }

    const int g = lane>>2, l = lane&3;
    #pragma unroll
    for (int mi=0;mi<4;mi++){
        int row = bm*128 + wm*64 + mi*16 + g;
        #pragma unroll
        for (int ni=0;ni<4;ni++){
            int col = bn*128 + wn*32 + ni*8 + 2*l;
            float b0 = bias[col], b1 = bias[col+1];
            float v0 = acc[mi][ni][0]+b0, v1 = acc[mi][ni][1]+b1;
            float v2 = acc[mi][ni][2]+b0, v3 = acc[mi][ni][3]+b1;
            if (EPI==1){
                v0 = 0.5f*v0*(1.0f + erff(v0*0.70710678118654752f));
                v1 = 0.5f*v1*(1.0f + erff(v1*0.70710678118654752f));
                v2 = 0.5f*v2*(1.0f + erff(v2*0.70710678118654752f));
                v3 = 0.5f*v3*(1.0f + erff(v3*0.70710678118654752f));
            }
            if (EPI==2){
                float2 r0 = *(const float2*)(R + (size_t)row*N + col);
                float2 r1 = *(const float2*)(R + (size_t)(row+8)*N + col);
                v0 += r0.x; v1 += r0.y; v2 += r1.x; v3 += r1.y;
            }
            *(float2*)(C + (size_t)row*N + col)     = make_float2(v0, v1);
            *(float2*)(C + (size_t)(row+8)*N + col) = make_float2(v2, v3);
        }
    }
}

// ---------------- FAVOR+ feature maps as GEMM (reads packed QKV) ----------------
__global__ __launch_bounds__(256) void featgemm_k(const float* __restrict__ QKV,
                                                  const float* __restrict__ proj,
                                                  float* __restrict__ QP,
                                                  float* __restrict__ KP,
                                                  float* __restrict__ RM){
    const int isK = blockIdx.z;
    const int bh = blockIdx.y;
    const int n0 = blockIdx.x*32;
    const int b = bh/HH, h = bh%HH;
    const float* A = QKV + (size_t)(b*NN + n0)*QKVS + (isK ? DD : 0) + h*64;

    __shared__ float Ps[32][292];
    __shared__ float At[32][33];
    __shared__ float diag_s[32];
    __shared__ float wmx[8];

    int tid = threadIdx.x;
    int tx = tid & 31, ty = tid >> 5;
    float acc[4][9];
    #pragma unroll
    for (int i=0;i<4;i++)
        #pragma unroll
        for (int j=0;j<9;j++) acc[i][j]=0.f;

    #pragma unroll
    for (int ks=0; ks<2; ks++){
        {
            int t = tid>>3, d4 = (tid&7)<<2;
            float4 a4 = *(const float4*)(A + (size_t)t*QKVS + ks*32 + d4);
            At[d4+0][t]=a4.x; At[d4+1][t]=a4.y; At[d4+2][t]=a4.z; At[d4+3][t]=a4.w;
        }
        {
            int d4 = (tid&7)<<2, mb = tid>>3;
            #pragma unroll
            for (int it=0; it<9; it++){
                int m = mb + it*32;
                float4 p4 = (m < MM) ? *(const float4*)(proj + (size_t)m*64 + ks*32 + d4)
                                     : make_float4(0.f,0.f,0.f,0.f);
                Ps[d4+0][m]=p4.x; Ps[d4+1][m]=p4.y; Ps[d4+2][m]=p4.z; Ps[d4+3][m]=p4.w;
            }
        }
        __syncthreads();
        if (tid < 32){
            float s = (ks==0) ? 0.f : diag_s[tid];
            #pragma unroll
            for (int d=0; d<32; d++){ float a = At[d][tid]; s += a*a; }
            diag_s[tid] = s;
        }
        #pragma unroll
        for (int d=0; d<32; d++){
            float a0 = At[d][ty*4+0];
            float a1 = At[d][ty*4+1];
            float a2 = At[d][ty*4+2];
            float a3 = At[d][ty*4+3];
            #pragma unroll
            for (int j=0;j<9;j++){
                float p = Ps[d][tx*9+j];
                acc[0][j] += a0*p;
                acc[1][j] += a1*p;
                acc[2][j] += a2*p;
                acc[3][j] += a3*p;
            }
        }
        __syncthreads();
    }

    float mx[4];
    #pragma unroll
    for (int i=0;i<4;i++){
        float m_ = -3.4e38f;
        #pragma unroll
        for (int j=0;j<9;j++){
            float v = acc[i][j]*DN_SCALE;
            acc[i][j] = v;
            if (tx*9+j < MM) m_ = fmaxf(m_, v);
        }
        #pragma unroll
        for (int o=16;o;o>>=1) m_ = fmaxf(m_, __shfl_xor_sync(0xffffffffu, m_, o));
        mx[i] = m_;
    }

    if (!isK){
        #pragma unroll
        for (int i=0;i<4;i++){
            int t = ty*4+i;
            float dg = diag_s[t]*0.0625f;
            float* out = QP + ((size_t)(bh*NN + n0 + t))*MP2;
            #pragma unroll
            for (int j=0;j<9;j++){
                int m = tx*9+j;
                out[m] = (m < MM) ? RATIO_SC*(__expf(acc[i][j]-dg-mx[i]) + EPS_KER) : 0.f;
            }
        }
    } else {
        float bm_ = -3.4e38f;
        #pragma unroll
        for (int i=0;i<4;i++){
            int t = ty*4+i;
            float dg = diag_s[t]*0.0625f;
            float* out = KP + ((size_t)(bh*NN + n0 + t))*MP2;
            #pragma unroll
            for (int j=0;j<9;j++){
                int m = tx*9+j;
                out[m] = (m < MM) ? __expf(acc[i][j]-dg-mx[i]) : 0.f;
            }
            if (tx==0) RM[bh*NN + n0 + t] = mx[i];
            bm_ = fmaxf(bm_, mx[i]);
        }
        if (tx==0) wmx[ty] = bm_;
        __syncthreads();
        if (tid==0){
            float B = wmx[0];
            #pragma unroll
            for (int w=1;w<8;w++) B = fmaxf(B, wmx[w]);
            atomicMax(&g_kmax_u, enc_f(B));
        }
    }
}

__global__ void kscale_k(const float* __restrict__ RM, float* __restrict__ SC){
    int rid = blockIdx.x*256 + threadIdx.x;
    if (rid < RIDS) SC[rid] = __expf(RM[rid] - dec_f(g_kmax_u));
}

__global__ void krescale_k(float* __restrict__ KP, const float* __restrict__ SC){
    size_t idx = (size_t)blockIdx.x*256 + threadIdx.x;
    const size_t total = (size_t)RIDS*MP2;
    if (idx >= total) return;
    int rid = (int)(idx / MP2);
    int m   = (int)(idx % MP2);
    float vv = 0.f;
    if (m < MM) vv = RATIO_SC*(KP[idx]*SC[rid] + EPS_KER);
    KP[idx] = vv;
}

// ---------------- chunked causal linear attention (V from packed QKV) ----------------
__global__ __launch_bounds__(512) void chunksum_k(const float* __restrict__ KP,
                                                  const float* __restrict__ QKV,
                                                  float* __restrict__ Z,
                                                  float* __restrict__ KV){
    int bhc = blockIdx.x;
    int bh = bhc / NC, c = bhc % NC;
    int b = bh / HH, h = bh % HH;
    int tid = threadIdx.x, g = tid>>6, e = tid&63;
    const int m0 = g*GM;
    __shared__ __align__(16) float kt[2][TT][MP2];
    __shared__ __align__(16) float vt[2][TT][64];
    float S[GM];
    #pragma unroll
    for (int i=0;i<GM;i++) S[i]=0.f;
    float zacc = 0.f;
    const float* kb = KP + ((size_t)bh*NN + c*CHK)*MP2;
    const float* vb = QKV + (size_t)(b*NN + c*CHK)*QKVS + 2*DD + h*64;

    auto load = [&](int buf, int tile){
        const float* kb_ = kb + (size_t)tile*TT*MP2;
        const float* vb_ = vb + (size_t)tile*TT*QKVS;
        for (int idx=tid; idx<704; idx+=512){
            if (idx < 576){ int tok=idx/72, f=(idx%72)*4; cpasync16(&kt[buf][tok][f], kb_ + (size_t)tok*MP2 + f); }
            else { int r=idx-576; int tok=r/16, f=(r%16)*4; cpasync16(&vt[buf][tok][f], vb_ + (size_t)tok*QKVS + f); }
        }
    };
    load(0,0); CP_COMMIT;
    for (int tile=0; tile<NTILE; tile++){
        int buf = tile&1;
        CP_WAIT0;
        __syncthreads();
        if (tile+1 < NTILE) load(buf^1, tile+1);
        CP_COMMIT;
        #pragma unroll
        for (int tt=0; tt<TT; tt++){
            float vv = vt[buf][tt][e];
            const float4* kr = (const float4*)(&kt[buf][tt][m0]);
            #pragma unroll
            for (int i4=0;i4<9;i4++){
                float4 kk = kr[i4];
                S[i4*4+0] += kk.x*vv;
                S[i4*4+1] += kk.y*vv;
                S[i4*4+2] += kk.z*vv;
                S[i4*4+3] += kk.w*vv;
            }
            if (tid < MP2) zacc += kt[buf][tt][tid];
        }
    }
    if (tid < MP2) Z[(size_t)bhc*MP2 + tid] = zacc;
    float* kvout = KV + (size_t)bhc*KVSTRIDE;
    #pragma unroll
    for (int i=0;i<GM;i++) kvout[(size_t)(m0+i)*64 + e] = S[i];
}

__global__ __launch_bounds__(512) void prefix_k(float* __restrict__ Z, float* __restrict__ KV){
    int bh = blockIdx.x;
    int base = bh*NC;
    int tid = threadIdx.x;
    for (int idx=tid; idx<KVSTRIDE; idx+=512){
        float run = 0.f;
        #pragma unroll
        for (int c=0;c<NC;c++){
            float* p = KV + (size_t)(base+c)*KVSTRIDE + idx;
            float t = *p; *p = run; run += t;
        }
    }
    if (tid < MP2){
        float run = 0.f;
        #pragma unroll
        for (int c=0;c<NC;c++){
            float* p = Z + (size_t)(base+c)*MP2 + tid;
            float t = *p; *p = run; run += t;
        }
    }
}

__global__ __launch_bounds__(512) void chunkout_k(const float* __restrict__ QP,
                                                  const float* __restrict__ KP,
                                                  const float* __restrict__ QKV,
                                                  const float* __restrict__ Z,
                                                  const float* __restrict__ KV,
                                                  float* __restrict__ O){
    int bhc = blockIdx.x;
    int bh = bhc / NC, c = bhc % NC;
    int b = bh / HH, h = bh % HH;
    int tid = threadIdx.x, g = tid>>6, e = tid&63;
    const int m0 = g*GM;
    __shared__ __align__(16) float kt[2][TT][MP2];
    __shared__ __align__(16) float qt[2][TT][MP2];
    __shared__ __align__(16) float vt[2][TT][64];
    __shared__ float partials[2][8][64];
    __shared__ float dred[2][9];

    float S[GM];
    const float* kvin = KV + (size_t)bhc*KVSTRIDE;
    #pragma unroll
    for (int i=0;i<GM;i++) S[i] = kvin[(size_t)(m0+i)*64 + e];
    float zreg = (tid < MP2) ? Z[(size_t)bhc*MP2 + tid] : 0.f;

    const float* kb = KP + ((size_t)bh*NN + c*CHK)*MP2;
    const float* qb = QP + ((size_t)bh*NN + c*CHK)*MP2;
    const float* vb = QKV + (size_t)(b*NN + c*CHK)*QKVS + 2*DD + h*64;

    auto load = [&](int buf, int tile){
        const float* kb_ = kb + (size_t)tile*TT*MP2;
        const float* qb_ = qb + (size_t)tile*TT*MP2;
        const float* vb_ = vb + (size_t)tile*TT*QKVS;
        for (int idx=tid; idx<1280; idx+=512){
            if (idx < 576){ int tok=idx/72, f=(idx%72)*4; cpasync16(&kt[buf][tok][f], kb_ + (size_t)tok*MP2 + f); }
            else if (idx < 1152){ int r=idx-576; int tok=r/72, f=(r%72)*4; cpasync16(&qt[buf][tok][f], qb_ + (size_t)tok*MP2 + f); }
            else { int r=idx-1152; int tok=r/16, f=(r%16)*4; cpasync16(&vt[buf][tok][f], vb_ + (size_t)tok*QKVS + f); }
        }
    };
    load(0,0); CP_COMMIT;

    for (int tile=0; tile<NTILE; tile++){
        int buf = tile&1;
        CP_WAIT0;
        __syncthreads();
        if (tile+1 < NTILE) load(buf^1, tile+1);
        CP_COMMIT;
        #pragma unroll
        for (int tt=0; tt<TT; tt++){
            int pt = tt & 1;
            float vv = vt[buf][tt][e];
            const float4* kr = (const float4*)(&kt[buf][tt][m0]);
            const float4* qr = (const float4*)(&qt[buf][tt][m0]);
            float acc = 0.f;
            #pragma unroll
            for (int i4=0;i4<9;i4++){
                float4 kk = kr[i4];
                float4 qq = qr[i4];
                S[i4*4+0] += kk.x*vv;  acc += qq.x*S[i4*4+0];
                S[i4*4+1] += kk.y*vv;  acc += qq.y*S[i4*4+1];
                S[i4*4+2] += kk.z*vv;  acc += qq.z*S[i4*4+2];
                S[i4*4+3] += kk.w*vv;  acc += qq.w*S[i4*4+3];
            }
            partials[pt][g][e] = acc;
            if (tid < MP2){
                float kv = kt[buf][tt][tid];
                zreg += kv;
                float dp = qt[buf][tt][tid]*(zreg + EPS_DEN);
                #pragma unroll
                for (int o=16;o;o>>=1) dp += __shfl_xor_sync(0xffffffffu, dp, o);
                if ((tid&31)==0) dred[pt][tid>>5] = dp;
            }
            __syncthreads();
            if (tid < 64){
                float s = 0.f;
                #pragma unroll
                for (int gg=0; gg<8; gg++) s += partials[pt][gg][tid];
                float den = 0.f;
                #pragma unroll
                for (int w=0; w<9; w++) den += dred[pt][w];
                int t = c*CHK + tile*TT + tt;
                O[((size_t)(b*NN + t))*DD + h*64 + tid] = s / den;
            }
        }
    }
}

// ---------------- launch ----------------
#define GEMM_SMEM 131072

extern "C" void kernel_launch(void* const* d_in, const int* in_sizes, int n_in,
                              void* d_out, int out_size){
    (void)in_sizes; (void)n_in; (void)out_size;
    const float* x    = (const float*)d_in[0];
    const float* ln1g = (const float*)d_in[1];
    const float* ln1b = (const float*)d_in[2];
    const float* Wq   = (const float*)d_in[3];
    const float* bq   = (const float*)d_in[4];
    const float* Wk   = (const float*)d_in[5];
    const float* bk   = (const float*)d_in[6];
    const float* Wv   = (const float*)d_in[7];
    const float* bv   = (const float*)d_in[8];
    const float* Wo   = (const float*)d_in[9];
    const float* bo   = (const float*)d_in[10];
    const float* proj = (const float*)d_in[11];
    const float* ln2g = (const float*)d_in[12];
    const float* ln2b = (const float*)d_in[13];
    const float* W1   = (const float*)d_in[14];
    const float* b1   = (const float*)d_in[15];
    const float* W2   = (const float*)d_in[16];
    const float* b2   = (const float*)d_in[17];
    float* out = (float*)d_out;

    float *h1,*qkv,*qp,*kp,*rm,*sc,*o,*x1,*h2,*ff,*zz,*kv,*bqkv;
    unsigned *afh,*afl,*wfh,*wfl;
    cudaGetSymbolAddress((void**)&h1,  g_h1);
    cudaGetSymbolAddress((void**)&qkv, g_qkv);
    cudaGetSymbolAddress((void**)&qp,  g_qp);
    cudaGetSymbolAddress((void**)&kp,  g_kp);
    cudaGetSymbolAddress((void**)&rm,  g_rm);
    cudaGetSymbolAddress((void**)&sc,  g_sc);
    cudaGetSymbolAddress((void**)&o,   g_o);
    cudaGetSymbolAddress((void**)&x1,  g_x1);
    cudaGetSymbolAddress((void**)&h2,  g_h2);
    cudaGetSymbolAddress((void**)&ff,  g_ff);
    cudaGetSymbolAddress((void**)&zz,  g_Z);
    cudaGetSymbolAddress((void**)&kv,  g_KV);
    cudaGetSymbolAddress((void**)&bqkv,g_bqkv);
    cudaGetSymbolAddress((void**)&afh, g_afh);
    cudaGetSymbolAddress((void**)&afl, g_afl);
    cudaGetSymbolAddress((void**)&wfh, g_wfh);
    cudaGetSymbolAddress((void**)&wfl, g_wfl);

    cudaFuncSetAttribute(gemm_tc<0>, cudaFuncAttributeMaxDynamicSharedMemorySize, GEMM_SMEM);
    cudaFuncSetAttribute(gemm_tc<1>, cudaFuncAttributeMaxDynamicSharedMemorySize, GEMM_SMEM);
    cudaFuncSetAttribute(gemm_tc<2>, cudaFuncAttributeMaxDynamicSharedMemorySize, GEMM_SMEM);

    init_k<<<1,1>>>();
    ln_k<<<ROWS,256>>>(x, ln1g, ln1b, h1);

    // ---- QKV fused GEMM (tf32 3x) ----
    splitA_k<<<3072,256>>>(h1, afh, afl, ROWS, DD);
    splitB_k<<<1152,256>>>(Wq, wfh, wfl, DD, DD, 0);
    splitB_k<<<1152,256>>>(Wk, wfh, wfl, DD, DD, DD/8);
    splitB_k<<<1152,256>>>(Wv, wfh, wfl, DD, DD, 2*DD/8);
    packb_k<<<3,256>>>(bq, bk, bv, bqkv);
    {
        dim3 gq(QKVS/128, ROWS/128);
        gemm_tc<0><<<gq,256,GEMM_SMEM>>>(afh, afl, wfh, wfl, bqkv, nullptr, qkv, DD/8, QKVS);
    }

    // ---- feature maps ----
    dim3 gfeat(NN/32, BH, 2);
    featgemm_k<<<gfeat,256>>>(qkv, proj, qp, kp, rm);
    kscale_k<<<(RIDS+255)/256,256>>>(rm, sc);
    {
        size_t total = (size_t)RIDS*MP2;
        krescale_k<<<(unsigned)((total+255)/256),256>>>(kp, sc);
    }

    // ---- scan ----
    chunksum_k<<<NCH,512>>>(kp, qkv, zz, kv);
    prefix_k  <<<BH, 512>>>(zz, kv);
    chunkout_k<<<NCH,512>>>(qp, kp, qkv, zz, kv, o);

    // ---- Wo GEMM + residual ----
    splitA_k<<<3072,256>>>(o, afh, afl, ROWS, DD);
    splitB_k<<<1152,256>>>(Wo, wfh, wfl, DD, DD, 0);
    {
        dim3 gg(DD/128, ROWS/128);
        gemm_tc<2><<<gg,256,GEMM_SMEM>>>(afh, afl, wfh, wfl, bo, x, x1, DD/8, DD);
    }

    ln_k<<<ROWS,256>>>(x1, ln2g, ln2b, h2);

    // ---- FFN ----
    splitA_k<<<3072,256>>>(h2, afh, afl, ROWS, DD);
    splitB_k<<<4608,256>>>(W1, wfh, wfl, DD, FFD, 0);
    {
        dim3 gg(FFD/128, ROWS/128);
        gemm_tc<1><<<gg,256,GEMM_SMEM>>>(afh, afl, wfh, wfl, b1, nullptr, ff, DD/8, FFD);
    }
    splitA_k<<<12288,256>>>(ff, afh, afl, ROWS, FFD);
    splitB_k<<<4608,256>>>(W2, wfh, wfl, FFD, DD, 0);
    {
        dim3 gg(DD/128, ROWS/128);
        gemm_tc<2><<<gg,256,GEMM_SMEM>>>(afh, afl, wfh, wfl, b2, x1, out, FFD/8, DD);
    }
}

// round 6
// speedup vs baseline: 7.7315x; 1.4620x over previous
#include <cuda_runtime.h>
#include <cuda_bf16.h>
#include <math.h>
#include <stdint.h>

// ---------------- problem constants ----------------
#define BB   2
#define NN   2048
#define DD   768
#define HH   12
#define MM   266
#define MP2  288
#define GM   36
#define FFD  3072
#define ROWS (BB*NN)
#define RIDS (BB*HH*NN)
#define BH   (BB*HH)
#define CHK  128
#define NC   (NN/CHK)
#define NCH  (BH*NC)
#define TT   8
#define NTILE (CHK/TT)
#define KVSTRIDE (MP2*64)
#define QKVS 2304

#define DN_SCALE   0.35355339059327f
#define RATIO_SC   0.061313689f
#define EPS_KER    1e-4f
#define EPS_DEN    1e-6f

// ---------------- scratch ----------------
__device__ float g_h1[ROWS*DD];
__device__ float g_qkv[(size_t)ROWS*QKVS];
__device__ float g_o [ROWS*DD];
__device__ float g_x1[ROWS*DD];
__device__ float g_h2[ROWS*DD];
__device__ float g_ff[ROWS*FFD];
__device__ float g_qp[(size_t)RIDS*MP2];
__device__ float g_kp[(size_t)RIDS*MP2];
__device__ float g_rm[RIDS];
__device__ float g_Z [(size_t)NCH*MP2];
__device__ float g_KV[(size_t)NCH*KVSTRIDE];
__device__ unsigned g_kmax_u;
__device__ float g_bqkv[QKVS];
// fragment-ordered bf16 hi/lo buffers
__device__ uint4 g_afh[(size_t)(ROWS/16)*(FFD/16)*32];
__device__ uint4 g_afl[(size_t)(ROWS/16)*(FFD/16)*32];
__device__ uint2 g_wfh[(size_t)(FFD/16)*(FFD/8)*32];
__device__ uint2 g_wfl[(size_t)(FFD/16)*(FFD/8)*32];

__device__ __forceinline__ unsigned enc_f(float f){
    unsigned u = __float_as_uint(f);
    return (u & 0x80000000u) ? ~u : (u | 0x80000000u);
}
__device__ __forceinline__ float dec_f(unsigned u){
    return (u & 0x80000000u) ? __uint_as_float(u ^ 0x80000000u) : __uint_as_float(~u);
}

__global__ void init_k(){ g_kmax_u = 0x00800000u; }

// split a float pair into bf16x2 hi + bf16x2 lo (residual)
__device__ __forceinline__ void pack2(float x, float y, unsigned &h, unsigned &l){
    __nv_bfloat162 hv = __floats2bfloat162_rn(x, y);
    float hx = __low2float(hv), hy = __high2float(hv);
    __nv_bfloat162 lv = __floats2bfloat162_rn(x - hx, y - hy);
    h = *reinterpret_cast<unsigned*>(&hv);
    l = *reinterpret_cast<unsigned*>(&lv);
}

// ---------------- LayerNorm ----------------
__global__ void ln_k(const float* __restrict__ X, const float* __restrict__ G,
                     const float* __restrict__ Bv, float* __restrict__ Y){
    int row = blockIdx.x, tid = threadIdx.x;
    const float* x = X + (size_t)row*DD;
    float v0 = x[tid], v1 = x[tid+256], v2 = x[tid+512];
    float s = v0+v1+v2, ss = v0*v0 + v1*v1 + v2*v2;
    __shared__ float rs[8], rss[8], stat[2];
    for (int o=16;o;o>>=1){ s += __shfl_xor_sync(0xffffffffu,s,o); ss += __shfl_xor_sync(0xffffffffu,ss,o); }
    if ((tid&31)==0){ rs[tid>>5]=s; rss[tid>>5]=ss; }
    __syncthreads();
    if (tid==0){
        float S=0,SS=0;
        #pragma unroll
        for (int i=0;i<8;i++){ S+=rs[i]; SS+=rss[i]; }
        float mu = S*(1.0f/DD);
        float var = SS*(1.0f/DD) - mu*mu;
        stat[0]=mu; stat[1]=rsqrtf(var + 1e-5f);
    }
    __syncthreads();
    float mu = stat[0], rstd = stat[1];
    float* y = Y + (size_t)row*DD;
    y[tid]     = (v0-mu)*rstd*G[tid]     + Bv[tid];
    y[tid+256] = (v1-mu)*rstd*G[tid+256] + Bv[tid+256];
    y[tid+512] = (v2-mu)*rstd*G[tid+512] + Bv[tid+512];
}

// ---------------- bf16 split kernels (fragment-ordered, m16n8k16) ----------------
// A[R][C] -> atom (am,ak) 16x16; lane g=lane>>2,l=lane&3 holds pairs:
//   (g,2l),(g,2l+1) | (g+8,2l),(g+8,2l+1) | (g,2l+8),(g,2l+9) | (g+8,2l+8),(g+8,2l+9)
__global__ void splitA_k(const float* __restrict__ X, uint4* __restrict__ H,
                         uint4* __restrict__ L, int R, int C){
    int idx = blockIdx.x*256 + threadIdx.x;
    int K16 = C>>4;
    int total = (R>>4)*K16*32;
    if (idx >= total) return;
    int lane = idx & 31, atom = idx >> 5;
    int am = atom / K16, ak = atom % K16;
    int g = lane>>2, l = lane&3;
    const float* p = X + (size_t)(am*16+g)*C + ak*16 + 2*l;
    float2 v0 = *(const float2*)(p);
    float2 v1 = *(const float2*)(p + (size_t)8*C);
    float2 v2 = *(const float2*)(p + 8);
    float2 v3 = *(const float2*)(p + (size_t)8*C + 8);
    uint4 h, lo;
    pack2(v0.x, v0.y, h.x, lo.x);
    pack2(v1.x, v1.y, h.y, lo.y);
    pack2(v2.x, v2.y, h.z, lo.z);
    pack2(v3.x, v3.y, h.w, lo.w);
    H[idx] = h; L[idx] = lo;
}

// W[K][N] -> B atom (an,ak) 16(K)x8(N); lane holds (2l,g),(2l+1,g) | (2l+8,g),(2l+9,g)
__global__ void splitB_k(const float* __restrict__ W, uint2* __restrict__ H,
                         uint2* __restrict__ L, int K, int N, int anBase){
    int idx = blockIdx.x*256 + threadIdx.x;
    int K16 = K>>4;
    int total = K16*(N>>3)*32;
    if (idx >= total) return;
    int lane = idx & 31, atom = idx >> 5;
    int an = atom / K16, ak = atom % K16;
    int g = lane>>2, l = lane&3;
    const float* p = W + (size_t)(ak*16 + 2*l)*N + an*8 + g;
    float b00 = p[0],            b01 = p[N];
    float b10 = p[(size_t)8*N],  b11 = p[(size_t)9*N];
    uint2 h, lo;
    pack2(b00, b01, h.x, lo.x);
    pack2(b10, b11, h.y, lo.y);
    int outi = ((anBase + an)*K16 + ak)*32 + lane;
    H[outi] = h; L[outi] = lo;
}

__global__ void packb_k(const float* __restrict__ bq, const float* __restrict__ bk,
                        const float* __restrict__ bv, float* __restrict__ o){
    int i = blockIdx.x*256 + threadIdx.x;
    if (i < DD){ o[i]=bq[i]; o[DD+i]=bk[i]; o[2*DD+i]=bv[i]; }
}

// ---------------- cp.async helpers ----------------
__device__ __forceinline__ void cpasync16(void* smem, const void* gmem){
    unsigned s = (unsigned)__cvta_generic_to_shared(smem);
    asm volatile("cp.async.ca.shared.global [%0], [%1], 16;\n" :: "r"(s), "l"(gmem));
}
#define CP_COMMIT asm volatile("cp.async.commit_group;\n" ::: "memory")
#define CP_WAIT0  asm volatile("cp.async.wait_group 0;\n" ::: "memory")

// ---------------- bf16x3 tensor-core GEMM ----------------
__device__ __forceinline__ void mma16(float* d, const uint4& a, const uint2& b){
    asm volatile("mma.sync.aligned.m16n8k16.row.col.f32.bf16.bf16.f32 "
        "{%0,%1,%2,%3},{%4,%5,%6,%7},{%8,%9},{%0,%1,%2,%3};"
        : "+f"(d[0]),"+f"(d[1]),"+f"(d[2]),"+f"(d[3])
        : "r"(a.x),"r"(a.y),"r"(a.z),"r"(a.w),"r"(b.x),"r"(b.y));
}

// CTA tile 128x128, 8 warps (2x4), warp tile 64x32, BK=32 (2 k16-atoms), 2-stage 64KB.
// EPI: 0=bias, 1=bias+gelu, 2=bias+residual
template<int EPI>
__global__ __launch_bounds__(256) void gemm_tc(const uint4* __restrict__ Ah,
                                               const uint4* __restrict__ Al,
                                               const uint2* __restrict__ Bh,
                                               const uint2* __restrict__ Bl,
                                               const float* __restrict__ bias,
                                               const float* __restrict__ R,
                                               float* __restrict__ C, int K16, int N){
    extern __shared__ char smem[];
    const int tid = threadIdx.x, lane = tid & 31, warp = tid >> 5;
    const int wm = warp >> 2, wn = warp & 3;
    const int bm = blockIdx.y, bn = blockIdx.x;

    float acc[4][4][4];
    #pragma unroll
    for (int a=0;a<4;a++)
        #pragma unroll
        for (int b=0;b<4;b++)
            #pragma unroll
            for (int c=0;c<4;c++) acc[a][b][c]=0.f;

    // stage layout (32KB): A-hi[0,8K) A-lo[8K,16K) B-hi[16K,24K) B-lo[24K,32K)
    auto stage_copy = [&](int s, int kb){
        char* base = smem + s*32768;
        #pragma unroll
        for (int i=0;i<2;i++){
            int e = tid + i*256;                 // 0..511
            // A: e = ma*64 + ka*32 + lane
            int ma = e>>6, ra = e&63;
            int ka = ra>>5, ln = ra&31;
            size_t ga = ((size_t)(bm*8+ma)*K16 + kb + ka)*32 + ln;
            cpasync16(base + e*16,         Ah + ga);
            cpasync16(base + 8192 + e*16,  Al + ga);
            // B: e = na*32 + kb2*16 + lp  (lp = lane pair)
            int na = e>>5, rb = e&31;
            int kb2 = rb>>4, lp = rb&15;
            size_t gb = ((size_t)(bn*16+na)*K16 + kb + kb2)*32 + lp*2;  // uint2 idx
            cpasync16(base + 16384 + e*16, Bh + gb);
            cpasync16(base + 24576 + e*16, Bl + gb);
        }
    };

    stage_copy(0, 0); CP_COMMIT;
    const int nk = K16 >> 1;
    int st = 0;
    for (int ks=0; ks<nk; ks++, st^=1){
        CP_WAIT0;
        __syncthreads();
        if (ks+1 < nk){ stage_copy(st^1, (ks+1)*2); CP_COMMIT; }
        const uint4* sAh = (const uint4*)(smem + st*32768);
        const uint4* sAl = (const uint4*)(smem + st*32768 + 8192);
        const uint2* sBh = (const uint2*)(smem + st*32768 + 16384);
        const uint2* sBl = (const uint2*)(smem + st*32768 + 24576);
        #pragma unroll
        for (int ka=0; ka<2; ka++){
            uint4 Afh[4], Afl[4];
            uint2 Bfh[4], Bfl[4];
            #pragma unroll
            for (int mi=0;mi<4;mi++){
                int off = ((wm*4+mi)*2 + ka)*32 + lane;
                Afh[mi] = sAh[off];
                Afl[mi] = sAl[off];
            }
            #pragma unroll
            for (int ni=0;ni<4;ni++){
                int off = ((wn*4+ni)*2 + ka)*32 + lane;
                Bfh[ni] = sBh[off];
                Bfl[ni] = sBl[off];
            }
            #pragma unroll
            for (int mi=0;mi<4;mi++)
                #pragma unroll
                for (int ni=0;ni<4;ni++){
                    mma16(acc[mi][ni], Afh[mi], Bfh[ni]);
                    mma16(acc[mi][ni], Afh[mi], Bfl[ni]);
                    mma16(acc[mi][ni], Afl[mi], Bfh[ni]);
                }
        }
    }

    const int g = lane>>2, l = lane&3;
    #pragma unroll
    for (int mi=0;mi<4;mi++){
        int row = bm*128 + wm*64 + mi*16 + g;
        #pragma unroll
        for (int ni=0;ni<4;ni++){
            int col = bn*128 + wn*32 + ni*8 + 2*l;
            float b0 = bias[col], b1 = bias[col+1];
            float v0 = acc[mi][ni][0]+b0, v1 = acc[mi][ni][1]+b1;
            float v2 = acc[mi][ni][2]+b0, v3 = acc[mi][ni][3]+b1;
            if (EPI==1){
                v0 = 0.5f*v0*(1.0f + erff(v0*0.70710678118654752f));
                v1 = 0.5f*v1*(1.0f + erff(v1*0.70710678118654752f));
                v2 = 0.5f*v2*(1.0f + erff(v2*0.70710678118654752f));
                v3 = 0.5f*v3*(1.0f + erff(v3*0.70710678118654752f));
            }
            if (EPI==2){
                float2 r0 = *(const float2*)(R + (size_t)row*N + col);
                float2 r1 = *(const float2*)(R + (size_t)(row+8)*N + col);
                v0 += r0.x; v1 += r0.y; v2 += r1.x; v3 += r1.y;
            }
            *(float2*)(C + (size_t)row*N + col)     = make_float2(v0, v1);
            *(float2*)(C + (size_t)(row+8)*N + col) = make_float2(v2, v3);
        }
    }
}

// ---------------- FAVOR+ feature maps as GEMM (reads packed QKV) ----------------
__global__ __launch_bounds__(256) void featgemm_k(const float* __restrict__ QKV,
                                                  const float* __restrict__ proj,
                                                  float* __restrict__ QP,
                                                  float* __restrict__ KP,
                                                  float* __restrict__ RM){
    const int isK = blockIdx.z;
    const int bh = blockIdx.y;
    const int n0 = blockIdx.x*32;
    const int b = bh/HH, h = bh%HH;
    const float* A = QKV + (size_t)(b*NN + n0)*QKVS + (isK ? DD : 0) + h*64;

    __shared__ float Ps[32][292];
    __shared__ float At[32][33];
    __shared__ float diag_s[32];
    __shared__ float wmx[8];

    int tid = threadIdx.x;
    int tx = tid & 31, ty = tid >> 5;
    float acc[4][9];
    #pragma unroll
    for (int i=0;i<4;i++)
        #pragma unroll
        for (int j=0;j<9;j++) acc[i][j]=0.f;

    #pragma unroll
    for (int ks=0; ks<2; ks++){
        {
            int t = tid>>3, d4 = (tid&7)<<2;
            float4 a4 = *(const float4*)(A + (size_t)t*QKVS + ks*32 + d4);
            At[d4+0][t]=a4.x; At[d4+1][t]=a4.y; At[d4+2][t]=a4.z; At[d4+3][t]=a4.w;
        }
        {
            int d4 = (tid&7)<<2, mb = tid>>3;
            #pragma unroll
            for (int it=0; it<9; it++){
                int m = mb + it*32;
                float4 p4 = (m < MM) ? *(const float4*)(proj + (size_t)m*64 + ks*32 + d4)
                                     : make_float4(0.f,0.f,0.f,0.f);
                Ps[d4+0][m]=p4.x; Ps[d4+1][m]=p4.y; Ps[d4+2][m]=p4.z; Ps[d4+3][m]=p4.w;
            }
        }
        __syncthreads();
        if (tid < 32){
            float s = (ks==0) ? 0.f : diag_s[tid];
            #pragma unroll
            for (int d=0; d<32; d++){ float a = At[d][tid]; s += a*a; }
            diag_s[tid] = s;
        }
        #pragma unroll
        for (int d=0; d<32; d++){
            float a0 = At[d][ty*4+0];
            float a1 = At[d][ty*4+1];
            float a2 = At[d][ty*4+2];
            float a3 = At[d][ty*4+3];
            #pragma unroll
            for (int j=0;j<9;j++){
                float p = Ps[d][tx*9+j];
                acc[0][j] += a0*p;
                acc[1][j] += a1*p;
                acc[2][j] += a2*p;
                acc[3][j] += a3*p;
            }
        }
        __syncthreads();
    }

    float mx[4];
    #pragma unroll
    for (int i=0;i<4;i++){
        float m_ = -3.4e38f;
        #pragma unroll
        for (int j=0;j<9;j++){
            float v = acc[i][j]*DN_SCALE;
            acc[i][j] = v;
            if (tx*9+j < MM) m_ = fmaxf(m_, v);
        }
        #pragma unroll
        for (int o=16;o;o>>=1) m_ = fmaxf(m_, __shfl_xor_sync(0xffffffffu, m_, o));
        mx[i] = m_;
    }

    if (!isK){
        #pragma unroll
        for (int i=0;i<4;i++){
            int t = ty*4+i;
            float dg = diag_s[t]*0.0625f;
            float* out = QP + ((size_t)(bh*NN + n0 + t))*MP2;
            #pragma unroll
            for (int j=0;j<9;j++){
                int m = tx*9+j;
                out[m] = (m < MM) ? RATIO_SC*(__expf(acc[i][j]-dg-mx[i]) + EPS_KER) : 0.f;
            }
        }
    } else {
        float bm_ = -3.4e38f;
        #pragma unroll
        for (int i=0;i<4;i++){
            int t = ty*4+i;
            float dg = diag_s[t]*0.0625f;
            float* out = KP + ((size_t)(bh*NN + n0 + t))*MP2;
            #pragma unroll
            for (int j=0;j<9;j++){
                int m = tx*9+j;
                out[m] = (m < MM) ? __expf(acc[i][j]-dg-mx[i]) : 0.f;
            }
            if (tx==0) RM[bh*NN + n0 + t] = mx[i];
            bm_ = fmaxf(bm_, mx[i]);
        }
        if (tx==0) wmx[ty] = bm_;
        __syncthreads();
        if (tid==0){
            float B = wmx[0];
            #pragma unroll
            for (int w=1;w<8;w++) B = fmaxf(B, wmx[w]);
            atomicMax(&g_kmax_u, enc_f(B));
        }
    }
}

// ---------------- chunked causal linear attention (fused k-rescale) ----------------
__global__ __launch_bounds__(512) void chunksum_k(const float* __restrict__ KP,
                                                  const float* __restrict__ QKV,
                                                  const float* __restrict__ RM,
                                                  float* __restrict__ Z,
                                                  float* __restrict__ KV){
    int bhc = blockIdx.x;
    int bh = bhc / NC, c = bhc % NC;
    int b = bh / HH, h = bh % HH;
    int tid = threadIdx.x, g = tid>>6, e = tid&63;
    const int m0 = g*GM;
    __shared__ __align__(16) float kt[2][TT][MP2];
    __shared__ __align__(16) float vt[2][TT][64];
    __shared__ float scs[CHK];
    float S[GM];
    #pragma unroll
    for (int i=0;i<GM;i++) S[i]=0.f;
    float zacc = 0.f;
    const float* kb = KP + ((size_t)bh*NN + c*CHK)*MP2;
    const float* vb = QKV + (size_t)(b*NN + c*CHK)*QKVS + 2*DD + h*64;

    float gmax = dec_f(g_kmax_u);
    for (int i=tid; i<CHK; i+=512)
        scs[i] = __expf(RM[bh*NN + c*CHK + i] - gmax);

    auto load = [&](int buf, int tile){
        const float* kb_ = kb + (size_t)tile*TT*MP2;
        const float* vb_ = vb + (size_t)tile*TT*QKVS;
        for (int idx=tid; idx<704; idx+=512){
            if (idx < 576){ int tok=idx/72, f=(idx%72)*4; cpasync16(&kt[buf][tok][f], kb_ + (size_t)tok*MP2 + f); }
            else { int r=idx-576; int tok=r/16, f=(r%16)*4; cpasync16(&vt[buf][tok][f], vb_ + (size_t)tok*QKVS + f); }
        }
    };
    load(0,0); CP_COMMIT;
    for (int tile=0; tile<NTILE; tile++){
        int buf = tile&1;
        CP_WAIT0;
        __syncthreads();
        if (tile+1 < NTILE) load(buf^1, tile+1);
        CP_COMMIT;
        // apply k rescale in place
        {
            const int tb = tile*TT;
            for (int idx=tid; idx<TT*MP2; idx+=512){
                int tok = idx/MP2, m = idx - tok*MP2;
                float f = kt[buf][tok][m];
                kt[buf][tok][m] = (m < MM) ? RATIO_SC*(f*scs[tb+tok] + EPS_KER) : 0.f;
            }
        }
        __syncthreads();
        #pragma unroll
        for (int tt=0; tt<TT; tt++){
            float vv = vt[buf][tt][e];
            const float4* kr = (const float4*)(&kt[buf][tt][m0]);
            #pragma unroll
            for (int i4=0;i4<9;i4++){
                float4 kk = kr[i4];
                S[i4*4+0] += kk.x*vv;
                S[i4*4+1] += kk.y*vv;
                S[i4*4+2] += kk.z*vv;
                S[i4*4+3] += kk.w*vv;
            }
            if (tid < MP2) zacc += kt[buf][tt][tid];
        }
    }
    if (tid < MP2) Z[(size_t)bhc*MP2 + tid] = zacc;
    float* kvout = KV + (size_t)bhc*KVSTRIDE;
    #pragma unroll
    for (int i=0;i<GM;i++) kvout[(size_t)(m0+i)*64 + e] = S[i];
}

__global__ __launch_bounds__(512) void prefix_k(float* __restrict__ Z, float* __restrict__ KV){
    int bh = blockIdx.x;
    int base = bh*NC;
    int tid = threadIdx.x;
    for (int idx=tid; idx<KVSTRIDE; idx+=512){
        float run = 0.f;
        #pragma unroll
        for (int c=0;c<NC;c++){
            float* p = KV + (size_t)(base+c)*KVSTRIDE + idx;
            float t = *p; *p = run; run += t;
        }
    }
    if (tid < MP2){
        float run = 0.f;
        #pragma unroll
        for (int c=0;c<NC;c++){
            float* p = Z + (size_t)(base+c)*MP2 + tid;
            float t = *p; *p = run; run += t;
        }
    }
}

__global__ __launch_bounds__(512) void chunkout_k(const float* __restrict__ QP,
                                                  const float* __restrict__ KP,
                                                  const float* __restrict__ QKV,
                                                  const float* __restrict__ RM,
                                                  const float* __restrict__ Z,
                                                  const float* __restrict__ KV,
                                                  float* __restrict__ O){
    int bhc = blockIdx.x;
    int bh = bhc / NC, c = bhc % NC;
    int b = bh / HH, h = bh % HH;
    int tid = threadIdx.x, g = tid>>6, e = tid&63;
    const int m0 = g*GM;
    __shared__ __align__(16) float kt[2][TT][MP2];
    __shared__ __align__(16) float qt[2][TT][MP2];
    __shared__ __align__(16) float vt[2][TT][64];
    __shared__ float partials[2][8][64];
    __shared__ float dred[2][9];
    __shared__ float scs[CHK];

    float S[GM];
    const float* kvin = KV + (size_t)bhc*KVSTRIDE;
    #pragma unroll
    for (int i=0;i<GM;i++) S[i] = kvin[(size_t)(m0+i)*64 + e];
    float zreg = (tid < MP2) ? Z[(size_t)bhc*MP2 + tid] : 0.f;

    const float* kb = KP + ((size_t)bh*NN + c*CHK)*MP2;
    const float* qb = QP + ((size_t)bh*NN + c*CHK)*MP2;
    const float* vb = QKV + (size_t)(b*NN + c*CHK)*QKVS + 2*DD + h*64;

    float gmax = dec_f(g_kmax_u);
    for (int i=tid; i<CHK; i+=512)
        scs[i] = __expf(RM[bh*NN + c*CHK + i] - gmax);

    auto load = [&](int buf, int tile){
        const float* kb_ = kb + (size_t)tile*TT*MP2;
        const float* qb_ = qb + (size_t)tile*TT*MP2;
        const float* vb_ = vb + (size_t)tile*TT*QKVS;
        for (int idx=tid; idx<1280; idx+=512){
            if (idx < 576){ int tok=idx/72, f=(idx%72)*4; cpasync16(&kt[buf][tok][f], kb_ + (size_t)tok*MP2 + f); }
            else if (idx < 1152){ int r=idx-576; int tok=r/72, f=(r%72)*4; cpasync16(&qt[buf][tok][f], qb_ + (size_t)tok*MP2 + f); }
            else { int r=idx-1152; int tok=r/16, f=(r%16)*4; cpasync16(&vt[buf][tok][f], vb_ + (size_t)tok*QKVS + f); }
        }
    };
    load(0,0); CP_COMMIT;

    for (int tile=0; tile<NTILE; tile++){
        int buf = tile&1;
        CP_WAIT0;
        __syncthreads();
        if (tile+1 < NTILE) load(buf^1, tile+1);
        CP_COMMIT;
        // apply k rescale in place
        {
            const int tb = tile*TT;
            for (int idx=tid; idx<TT*MP2; idx+=512){
                int tok = idx/MP2, m = idx - tok*MP2;
                float f = kt[buf][tok][m];
                kt[buf][tok][m] = (m < MM) ? RATIO_SC*(f*scs[tb+tok] + EPS_KER) : 0.f;
            }
        }
        __syncthreads();
        #pragma unroll
        for (int tt=0; tt<TT; tt++){
            int pt = tt & 1;
            float vv = vt[buf][tt][e];
            const float4* kr = (const float4*)(&kt[buf][tt][m0]);
            const float4* qr = (const float4*)(&qt[buf][tt][m0]);
            float acc = 0.f;
            #pragma unroll
            for (int i4=0;i4<9;i4++){
                float4 kk = kr[i4];
                float4 qq = qr[i4];
                S[i4*4+0] += kk.x*vv;  acc += qq.x*S[i4*4+0];
                S[i4*4+1] += kk.y*vv;  acc += qq.y*S[i4*4+1];
                S[i4*4+2] += kk.z*vv;  acc += qq.z*S[i4*4+2];
                S[i4*4+3] += kk.w*vv;  acc += qq.w*S[i4*4+3];
            }
            partials[pt][g][e] = acc;
            if (tid < MP2){
                float kv = kt[buf][tt][tid];
                zreg += kv;
                float dp = qt[buf][tt][tid]*(zreg + EPS_DEN);
                #pragma unroll
                for (int o=16;o;o>>=1) dp += __shfl_xor_sync(0xffffffffu, dp, o);
                if ((tid&31)==0) dred[pt][tid>>5] = dp;
            }
            __syncthreads();
            if (tid < 64){
                float s = 0.f;
                #pragma unroll
                for (int gg=0; gg<8; gg++) s += partials[pt][gg][tid];
                float den = 0.f;
                #pragma unroll
                for (int w=0; w<9; w++) den += dred[pt][w];
                int t = c*CHK + tile*TT + tt;
                O[((size_t)(b*NN + t))*DD + h*64 + tid] = s / den;
            }
        }
    }
}

// ---------------- launch ----------------
#define GEMM_SMEM 65536

extern "C" void kernel_launch(void* const* d_in, const int* in_sizes, int n_in,
                              void* d_out, int out_size){
    (void)in_sizes; (void)n_in; (void)out_size;
    const float* x    = (const float*)d_in[0];
    const float* ln1g = (const float*)d_in[1];
    const float* ln1b = (const float*)d_in[2];
    const float* Wq   = (const float*)d_in[3];
    const float* bq   = (const float*)d_in[4];
    const float* Wk   = (const float*)d_in[5];
    const float* bk   = (const float*)d_in[6];
    const float* Wv   = (const float*)d_in[7];
    const float* bv   = (const float*)d_in[8];
    const float* Wo   = (const float*)d_in[9];
    const float* bo   = (const float*)d_in[10];
    const float* proj = (const float*)d_in[11];
    const float* ln2g = (const float*)d_in[12];
    const float* ln2b = (const float*)d_in[13];
    const float* W1   = (const float*)d_in[14];
    const float* b1   = (const float*)d_in[15];
    const float* W2   = (const float*)d_in[16];
    const float* b2   = (const float*)d_in[17];
    float* out = (float*)d_out;

    float *h1,*qkv,*qp,*kp,*rm,*o,*x1,*h2,*ff,*zz,*kv,*bqkv;
    uint4 *afh,*afl;
    uint2 *wfh,*wfl;
    cudaGetSymbolAddress((void**)&h1,  g_h1);
    cudaGetSymbolAddress((void**)&qkv, g_qkv);
    cudaGetSymbolAddress((void**)&qp,  g_qp);
    cudaGetSymbolAddress((void**)&kp,  g_kp);
    cudaGetSymbolAddress((void**)&rm,  g_rm);
    cudaGetSymbolAddress((void**)&o,   g_o);
    cudaGetSymbolAddress((void**)&x1,  g_x1);
    cudaGetSymbolAddress((void**)&h2,  g_h2);
    cudaGetSymbolAddress((void**)&ff,  g_ff);
    cudaGetSymbolAddress((void**)&zz,  g_Z);
    cudaGetSymbolAddress((void**)&kv,  g_KV);
    cudaGetSymbolAddress((void**)&bqkv,g_bqkv);
    cudaGetSymbolAddress((void**)&afh, g_afh);
    cudaGetSymbolAddress((void**)&afl, g_afl);
    cudaGetSymbolAddress((void**)&wfh, g_wfh);
    cudaGetSymbolAddress((void**)&wfl, g_wfl);

    cudaFuncSetAttribute(gemm_tc<0>, cudaFuncAttributeMaxDynamicSharedMemorySize, GEMM_SMEM);
    cudaFuncSetAttribute(gemm_tc<1>, cudaFuncAttributeMaxDynamicSharedMemorySize, GEMM_SMEM);
    cudaFuncSetAttribute(gemm_tc<2>, cudaFuncAttributeMaxDynamicSharedMemorySize, GEMM_SMEM);

    init_k<<<1,1>>>();
    ln_k<<<ROWS,256>>>(x, ln1g, ln1b, h1);

    // ---- QKV fused GEMM (bf16 3x) ----
    splitA_k<<<1536,256>>>(h1, afh, afl, ROWS, DD);
    splitB_k<<<576,256>>>(Wq, wfh, wfl, DD, DD, 0);
    splitB_k<<<576,256>>>(Wk, wfh, wfl, DD, DD, DD/8);
    splitB_k<<<576,256>>>(Wv, wfh, wfl, DD, DD, 2*DD/8);
    packb_k<<<3,256>>>(bq, bk, bv, bqkv);
    {
        dim3 gq(QKVS/128, ROWS/128);
        gemm_tc<0><<<gq,256,GEMM_SMEM>>>(afh, afl, wfh, wfl, bqkv, nullptr, qkv, DD/16, QKVS);
    }

    // ---- feature maps ----
    dim3 gfeat(NN/32, BH, 2);
    featgemm_k<<<gfeat,256>>>(qkv, proj, qp, kp, rm);

    // ---- scan (k-rescale fused) ----
    chunksum_k<<<NCH,512>>>(kp, qkv, rm, zz, kv);
    prefix_k  <<<BH, 512>>>(zz, kv);
    chunkout_k<<<NCH,512>>>(qp, kp, qkv, rm, zz, kv, o);

    // ---- Wo GEMM + residual ----
    splitA_k<<<1536,256>>>(o, afh, afl, ROWS, DD);
    splitB_k<<<576,256>>>(Wo, wfh, wfl, DD, DD, 0);
    {
        dim3 gg(DD/128, ROWS/128);
        gemm_tc<2><<<gg,256,GEMM_SMEM>>>(afh, afl, wfh, wfl, bo, x, x1, DD/16, DD);
    }

    ln_k<<<ROWS,256>>>(x1, ln2g, ln2b, h2);

    // ---- FFN ----
    splitA_k<<<1536,256>>>(h2, afh, afl, ROWS, DD);
    splitB_k<<<2304,256>>>(W1, wfh, wfl, DD, FFD, 0);
    {
        dim3 gg(FFD/128, ROWS/128);
        gemm_tc<1><<<gg,256,GEMM_SMEM>>>(afh, afl, wfh, wfl, b1, nullptr, ff, DD/16, FFD);
    }
    splitA_k<<<6144,256>>>(ff, afh, afl, ROWS, FFD);
    splitB_k<<<2304,256>>>(W2, wfh, wfl, FFD, DD, 0);
    {
        dim3 gg(DD/128, ROWS/128);
        gemm_tc<2><<<gg,256,GEMM_SMEM>>>(afh, afl, wfh, wfl, b2, x1, out, FFD/16, DD);
    }
}

// round 7
// speedup vs baseline: 8.0103x; 1.0360x over previous
#include <cuda_runtime.h>
#include <cuda_bf16.h>
#include <math.h>
#include <stdint.h>

// ---------------- problem constants ----------------
#define BB   2
#define NN   2048
#define DD   768
#define HH   12
#define MM   266
#define MP2  288
#define GM   36
#define FFD  3072
#define ROWS (BB*NN)
#define RIDS (BB*HH*NN)
#define BH   (BB*HH)
#define CHK  128
#define NC   (NN/CHK)
#define NCH  (BH*NC)
#define TT   8
#define NTILE (CHK/TT)
#define KVSTRIDE (MP2*64)
#define QKVS 2304

#define DN_SCALE   0.35355339059327f
#define RATIO_SC   0.061313689f
#define EPS_KER    1e-4f
#define EPS_DEN    1e-6f

// ---------------- scratch ----------------
__device__ float g_qkv[(size_t)ROWS*QKVS];
__device__ float g_o [ROWS*DD];
__device__ float g_x1[ROWS*DD];
__device__ float g_qp[(size_t)RIDS*MP2];
__device__ float g_kp[(size_t)RIDS*MP2];
__device__ float g_rm[RIDS];
__device__ float g_Z [(size_t)NCH*MP2];
__device__ float g_KV[(size_t)NCH*KVSTRIDE];
__device__ unsigned g_kmax_u;
__device__ float g_bqkv[QKVS];
// fragment-ordered bf16 hi/lo buffers
__device__ uint4 g_afh[(size_t)(ROWS/16)*(DD/16)*32];
__device__ uint4 g_afl[(size_t)(ROWS/16)*(DD/16)*32];
__device__ uint4 g_af2h[(size_t)(ROWS/16)*(FFD/16)*32];
__device__ uint4 g_af2l[(size_t)(ROWS/16)*(FFD/16)*32];
__device__ uint2 g_wfh[(size_t)(FFD/16)*(FFD/8)*32];
__device__ uint2 g_wfl[(size_t)(FFD/16)*(FFD/8)*32];

__device__ __forceinline__ unsigned enc_f(float f){
    unsigned u = __float_as_uint(f);
    return (u & 0x80000000u) ? ~u : (u | 0x80000000u);
}
__device__ __forceinline__ float dec_f(unsigned u){
    return (u & 0x80000000u) ? __uint_as_float(u ^ 0x80000000u) : __uint_as_float(~u);
}

__global__ void init_k(){ g_kmax_u = 0x00800000u; }

__device__ __forceinline__ void pack2(float x, float y, unsigned &h, unsigned &l){
    __nv_bfloat162 hv = __floats2bfloat162_rn(x, y);
    float hx = __low2float(hv), hy = __high2float(hv);
    __nv_bfloat162 lv = __floats2bfloat162_rn(x - hx, y - hy);
    h = *reinterpret_cast<unsigned*>(&hv);
    l = *reinterpret_cast<unsigned*>(&lv);
}

// ---------------- LayerNorm emitting A-fragments (16 rows/CTA) ----------------
__global__ __launch_bounds__(256) void lnfrag_k(const float* __restrict__ X,
                                                const float* __restrict__ G,
                                                const float* __restrict__ Bv,
                                                uint4* __restrict__ H,
                                                uint4* __restrict__ L){
    const int blk = blockIdx.x;             // 16-row group
    const int tid = threadIdx.x;
    const int r = tid >> 4, c16 = tid & 15;
    __shared__ float mu_s[16], rs_s[16];
    const float* xr = X + ((size_t)blk*16 + r)*DD;
    float s = 0.f, ss = 0.f;
    #pragma unroll
    for (int j=0;j<12;j++){
        float4 v = *(const float4*)(xr + c16*4 + j*64);
        s  += v.x+v.y+v.z+v.w;
        ss += v.x*v.x+v.y*v.y+v.z*v.z+v.w*v.w;
    }
    #pragma unroll
    for (int o=8;o;o>>=1){
        s  += __shfl_xor_sync(0xffffffffu, s, o, 16);
        ss += __shfl_xor_sync(0xffffffffu, ss, o, 16);
    }
    if (c16==0){
        float mu = s*(1.0f/DD);
        float var = ss*(1.0f/DD) - mu*mu;
        mu_s[r]=mu; rs_s[r]=rsqrtf(var + 1e-5f);
    }
    __syncthreads();
    // fragment pack: 48 k-atoms x 32 lanes = 1536 items, 6 per thread
    #pragma unroll
    for (int i=0;i<6;i++){
        int it = tid + i*256;
        int ak = it>>5, lane = it&31;
        int g = lane>>2, l = lane&3;
        float mu0 = mu_s[g],  r0 = rs_s[g];
        float mu1 = mu_s[g+8],r1 = rs_s[g+8];
        int c = ak*16 + 2*l;
        const float* row0 = X + ((size_t)blk*16 + g)*DD;
        const float* row1 = X + ((size_t)blk*16 + g + 8)*DD;
        float2 ga = *(const float2*)(G + c),  gb = *(const float2*)(G + c + 8);
        float2 ba = *(const float2*)(Bv + c), bb = *(const float2*)(Bv + c + 8);
        float2 v0 = *(const float2*)(row0 + c);
        float2 v1 = *(const float2*)(row1 + c);
        float2 v2 = *(const float2*)(row0 + c + 8);
        float2 v3 = *(const float2*)(row1 + c + 8);
        uint4 h, lo;
        pack2((v0.x-mu0)*r0*ga.x+ba.x, (v0.y-mu0)*r0*ga.y+ba.y, h.x, lo.x);
        pack2((v1.x-mu1)*r1*ga.x+ba.x, (v1.y-mu1)*r1*ga.y+ba.y, h.y, lo.y);
        pack2((v2.x-mu0)*r0*gb.x+bb.x, (v2.y-mu0)*r0*gb.y+bb.y, h.z, lo.z);
        pack2((v3.x-mu1)*r1*gb.x+bb.x, (v3.y-mu1)*r1*gb.y+bb.y, h.w, lo.w);
        size_t gidx = ((size_t)blk*48 + ak)*32 + lane;
        H[gidx]=h; L[gidx]=lo;
    }
}

// ---------------- bf16 split kernels ----------------
__global__ void splitA_k(const float* __restrict__ X, uint4* __restrict__ H,
                         uint4* __restrict__ L, int R, int C){
    int idx = blockIdx.x*256 + threadIdx.x;
    int K16 = C>>4;
    int total = (R>>4)*K16*32;
    if (idx >= total) return;
    int lane = idx & 31, atom = idx >> 5;
    int am = atom / K16, ak = atom % K16;
    int g = lane>>2, l = lane&3;
    const float* p = X + (size_t)(am*16+g)*C + ak*16 + 2*l;
    float2 v0 = *(const float2*)(p);
    float2 v1 = *(const float2*)(p + (size_t)8*C);
    float2 v2 = *(const float2*)(p + 8);
    float2 v3 = *(const float2*)(p + (size_t)8*C + 8);
    uint4 h, lo;
    pack2(v0.x, v0.y, h.x, lo.x);
    pack2(v1.x, v1.y, h.y, lo.y);
    pack2(v2.x, v2.y, h.z, lo.z);
    pack2(v3.x, v3.y, h.w, lo.w);
    H[idx] = h; L[idx] = lo;
}

__global__ void splitB_k(const float* __restrict__ W, uint2* __restrict__ H,
                         uint2* __restrict__ L, int K, int N, int anBase){
    int idx = blockIdx.x*256 + threadIdx.x;
    int K16 = K>>4;
    int total = K16*(N>>3)*32;
    if (idx >= total) return;
    int lane = idx & 31, atom = idx >> 5;
    int an = atom / K16, ak = atom % K16;
    int g = lane>>2, l = lane&3;
    const float* p = W + (size_t)(ak*16 + 2*l)*N + an*8 + g;
    float b00 = p[0],            b01 = p[N];
    float b10 = p[(size_t)8*N],  b11 = p[(size_t)9*N];
    uint2 h, lo;
    pack2(b00, b01, h.x, lo.x);
    pack2(b10, b11, h.y, lo.y);
    int outi = ((anBase + an)*K16 + ak)*32 + lane;
    H[outi] = h; L[outi] = lo;
}

__global__ void packb_k(const float* __restrict__ bq, const float* __restrict__ bk,
                        const float* __restrict__ bv, float* __restrict__ o){
    int i = blockIdx.x*256 + threadIdx.x;
    if (i < DD){ o[i]=bq[i]; o[DD+i]=bk[i]; o[2*DD+i]=bv[i]; }
}

// ---------------- cp.async helpers ----------------
__device__ __forceinline__ void cpasync16(void* smem, const void* gmem){
    unsigned s = (unsigned)__cvta_generic_to_shared(smem);
    asm volatile("cp.async.ca.shared.global [%0], [%1], 16;\n" :: "r"(s), "l"(gmem));
}
#define CP_COMMIT asm volatile("cp.async.commit_group;\n" ::: "memory")
#define CP_WAIT0  asm volatile("cp.async.wait_group 0;\n" ::: "memory")

// ---------------- bf16x3 tensor-core GEMM ----------------
__device__ __forceinline__ void mma16(float* d, const uint4& a, const uint2& b){
    asm volatile("mma.sync.aligned.m16n8k16.row.col.f32.bf16.bf16.f32 "
        "{%0,%1,%2,%3},{%4,%5,%6,%7},{%8,%9},{%0,%1,%2,%3};"
        : "+f"(d[0]),"+f"(d[1]),"+f"(d[2]),"+f"(d[3])
        : "r"(a.x),"r"(a.y),"r"(a.z),"r"(a.w),"r"(b.x),"r"(b.y));
}

// EPI: 0=bias->float, 1=bias+gelu->FRAGMENTS ONLY, 2=bias+residual->float
template<int EPI>
__global__ __launch_bounds__(256) void gemm_tc(const uint4* __restrict__ Ah,
                                               const uint4* __restrict__ Al,
                                               const uint2* __restrict__ Bh,
                                               const uint2* __restrict__ Bl,
                                               const float* __restrict__ bias,
                                               const float* __restrict__ R,
                                               float* __restrict__ C,
                                               uint4* __restrict__ FH,
                                               uint4* __restrict__ FL,
                                               int K16, int N){
    extern __shared__ char smem[];
    const int tid = threadIdx.x, lane = tid & 31, warp = tid >> 5;
    const int wm = warp >> 2, wn = warp & 3;
    const int bm = blockIdx.y, bn = blockIdx.x;

    float acc[4][4][4];
    #pragma unroll
    for (int a=0;a<4;a++)
        #pragma unroll
        for (int b=0;b<4;b++)
            #pragma unroll
            for (int c=0;c<4;c++) acc[a][b][c]=0.f;

    auto stage_copy = [&](int s, int kb){
        char* base = smem + s*32768;
        #pragma unroll
        for (int i=0;i<2;i++){
            int e = tid + i*256;
            int ma = e>>6, ra = e&63;
            int ka = ra>>5, ln = ra&31;
            size_t ga = ((size_t)(bm*8+ma)*K16 + kb + ka)*32 + ln;
            cpasync16(base + e*16,         Ah + ga);
            cpasync16(base + 8192 + e*16,  Al + ga);
            int na = e>>5, rb = e&31;
            int kb2 = rb>>4, lp = rb&15;
            size_t gb = ((size_t)(bn*16+na)*K16 + kb + kb2)*32 + lp*2;
            cpasync16(base + 16384 + e*16, Bh + gb);
            cpasync16(base + 24576 + e*16, Bl + gb);
        }
    };

    stage_copy(0, 0); CP_COMMIT;
    const int nk = K16 >> 1;
    int st = 0;
    for (int ks=0; ks<nk; ks++, st^=1){
        CP_WAIT0;
        __syncthreads();
        if (ks+1 < nk){ stage_copy(st^1, (ks+1)*2); CP_COMMIT; }
        const uint4* sAh = (const uint4*)(smem + st*32768);
        const uint4* sAl = (const uint4*)(smem + st*32768 + 8192);
        const uint2* sBh = (const uint2*)(smem + st*32768 + 16384);
        const uint2* sBl = (const uint2*)(smem + st*32768 + 24576);
        #pragma unroll
        for (int ka=0; ka<2; ka++){
            uint4 Afh[4], Afl[4];
            uint2 Bfh[4], Bfl[4];
            #pragma unroll
            for (int mi=0;mi<4;mi++){
                int off = ((wm*4+mi)*2 + ka)*32 + lane;
                Afh[mi] = sAh[off];
                Afl[mi] = sAl[off];
            }
            #pragma unroll
            for (int ni=0;ni<4;ni++){
                int off = ((wn*4+ni)*2 + ka)*32 + lane;
                Bfh[ni] = sBh[off];
                Bfl[ni] = sBl[off];
            }
            #pragma unroll
            for (int mi=0;mi<4;mi++)
                #pragma unroll
                for (int ni=0;ni<4;ni++){
                    mma16(acc[mi][ni], Afh[mi], Bfh[ni]);
                    mma16(acc[mi][ni], Afh[mi], Bfl[ni]);
                    mma16(acc[mi][ni], Afl[mi], Bfh[ni]);
                }
        }
    }

    const int g = lane>>2, l = lane&3;
    if (EPI==1){
        // fragment-emitting epilogue: pack 2 adjacent n-atoms into one A k-atom
        const int K16n = N >> 4;
        #pragma unroll
        for (int mi=0;mi<4;mi++){
            int am = bm*8 + wm*4 + mi;
            #pragma unroll
            for (int np=0;np<2;np++){
                float vv[2][4];
                #pragma unroll
                for (int half=0; half<2; half++){
                    int ni = 2*np + half;
                    int col = bn*128 + wn*32 + ni*8 + 2*l;
                    float b0 = bias[col], b1 = bias[col+1];
                    float v0 = acc[mi][ni][0]+b0, v1 = acc[mi][ni][1]+b1;
                    float v2 = acc[mi][ni][2]+b0, v3 = acc[mi][ni][3]+b1;
                    vv[half][0] = 0.5f*v0*(1.0f + erff(v0*0.70710678118654752f));
                    vv[half][1] = 0.5f*v1*(1.0f + erff(v1*0.70710678118654752f));
                    vv[half][2] = 0.5f*v2*(1.0f + erff(v2*0.70710678118654752f));
                    vv[half][3] = 0.5f*v3*(1.0f + erff(v3*0.70710678118654752f));
                }
                uint4 h, lo;
                pack2(vv[0][0], vv[0][1], h.x, lo.x);
                pack2(vv[0][2], vv[0][3], h.y, lo.y);
                pack2(vv[1][0], vv[1][1], h.z, lo.z);
                pack2(vv[1][2], vv[1][3], h.w, lo.w);
                size_t ga = ((size_t)am*K16n + (bn*8 + wn*2 + np))*32 + lane;
                FH[ga] = h; FL[ga] = lo;
            }
        }
    } else {
        #pragma unroll
        for (int mi=0;mi<4;mi++){
            int row = bm*128 + wm*64 + mi*16 + g;
            #pragma unroll
            for (int ni=0;ni<4;ni++){
                int col = bn*128 + wn*32 + ni*8 + 2*l;
                float b0 = bias[col], b1 = bias[col+1];
                float v0 = acc[mi][ni][0]+b0, v1 = acc[mi][ni][1]+b1;
                float v2 = acc[mi][ni][2]+b0, v3 = acc[mi][ni][3]+b1;
                if (EPI==2){
                    float2 r0 = *(const float2*)(R + (size_t)row*N + col);
                    float2 r1 = *(const float2*)(R + (size_t)(row+8)*N + col);
                    v0 += r0.x; v1 += r0.y; v2 += r1.x; v3 += r1.y;
                }
                *(float2*)(C + (size_t)row*N + col)     = make_float2(v0, v1);
                *(float2*)(C + (size_t)(row+8)*N + col) = make_float2(v2, v3);
            }
        }
    }
}

// ---------------- FAVOR+ feature maps as GEMM ----------------
__global__ __launch_bounds__(256) void featgemm_k(const float* __restrict__ QKV,
                                                  const float* __restrict__ proj,
                                                  float* __restrict__ QP,
                                                  float* __restrict__ KP,
                                                  float* __restrict__ RM){
    const int isK = blockIdx.z;
    const int bh = blockIdx.y;
    const int n0 = blockIdx.x*32;
    const int b = bh/HH, h = bh%HH;
    const float* A = QKV + (size_t)(b*NN + n0)*QKVS + (isK ? DD : 0) + h*64;

    __shared__ float Ps[32][292];
    __shared__ float At[32][33];
    __shared__ float diag_s[32];
    __shared__ float wmx[8];

    int tid = threadIdx.x;
    int tx = tid & 31, ty = tid >> 5;
    float acc[4][9];
    #pragma unroll
    for (int i=0;i<4;i++)
        #pragma unroll
        for (int j=0;j<9;j++) acc[i][j]=0.f;

    #pragma unroll
    for (int ks=0; ks<2; ks++){
        {
            int t = tid>>3, d4 = (tid&7)<<2;
            float4 a4 = *(const float4*)(A + (size_t)t*QKVS + ks*32 + d4);
            At[d4+0][t]=a4.x; At[d4+1][t]=a4.y; At[d4+2][t]=a4.z; At[d4+3][t]=a4.w;
        }
        {
            int d4 = (tid&7)<<2, mb = tid>>3;
            #pragma unroll
            for (int it=0; it<9; it++){
                int m = mb + it*32;
                float4 p4 = (m < MM) ? *(const float4*)(proj + (size_t)m*64 + ks*32 + d4)
                                     : make_float4(0.f,0.f,0.f,0.f);
                Ps[d4+0][m]=p4.x; Ps[d4+1][m]=p4.y; Ps[d4+2][m]=p4.z; Ps[d4+3][m]=p4.w;
            }
        }
        __syncthreads();
        if (tid < 32){
            float s = (ks==0) ? 0.f : diag_s[tid];
            #pragma unroll
            for (int d=0; d<32; d++){ float a = At[d][tid]; s += a*a; }
            diag_s[tid] = s;
        }
        #pragma unroll
        for (int d=0; d<32; d++){
            float a0 = At[d][ty*4+0];
            float a1 = At[d][ty*4+1];
            float a2 = At[d][ty*4+2];
            float a3 = At[d][ty*4+3];
            #pragma unroll
            for (int j=0;j<9;j++){
                float p = Ps[d][tx*9+j];
                acc[0][j] += a0*p;
                acc[1][j] += a1*p;
                acc[2][j] += a2*p;
                acc[3][j] += a3*p;
            }
        }
        __syncthreads();
    }

    float mx[4];
    #pragma unroll
    for (int i=0;i<4;i++){
        float m_ = -3.4e38f;
        #pragma unroll
        for (int j=0;j<9;j++){
            float v = acc[i][j]*DN_SCALE;
            acc[i][j] = v;
            if (tx*9+j < MM) m_ = fmaxf(m_, v);
        }
        #pragma unroll
        for (int o=16;o;o>>=1) m_ = fmaxf(m_, __shfl_xor_sync(0xffffffffu, m_, o));
        mx[i] = m_;
    }

    if (!isK){
        #pragma unroll
        for (int i=0;i<4;i++){
            int t = ty*4+i;
            float dg = diag_s[t]*0.0625f;
            float* out = QP + ((size_t)(bh*NN + n0 + t))*MP2;
            #pragma unroll
            for (int j=0;j<9;j++){
                int m = tx*9+j;
                out[m] = (m < MM) ? RATIO_SC*(__expf(acc[i][j]-dg-mx[i]) + EPS_KER) : 0.f;
            }
        }
    } else {
        float bm_ = -3.4e38f;
        #pragma unroll
        for (int i=0;i<4;i++){
            int t = ty*4+i;
            float dg = diag_s[t]*0.0625f;
            float* out = KP + ((size_t)(bh*NN + n0 + t))*MP2;
            #pragma unroll
            for (int j=0;j<9;j++){
                int m = tx*9+j;
                out[m] = (m < MM) ? __expf(acc[i][j]-dg-mx[i]) : 0.f;
            }
            if (tx==0) RM[bh*NN + n0 + t] = mx[i];
            bm_ = fmaxf(bm_, mx[i]);
        }
        if (tx==0) wmx[ty] = bm_;
        __syncthreads();
        if (tid==0){
            float B = wmx[0];
            #pragma unroll
            for (int w=1;w<8;w++) B = fmaxf(B, wmx[w]);
            atomicMax(&g_kmax_u, enc_f(B));
        }
    }
}

// ---------------- chunked causal linear attention ----------------
__global__ __launch_bounds__(512) void chunksum_k(const float* __restrict__ KP,
                                                  const float* __restrict__ QKV,
                                                  const float* __restrict__ RM,
                                                  float* __restrict__ Z,
                                                  float* __restrict__ KV){
    int bhc = blockIdx.x;
    int bh = bhc / NC, c = bhc % NC;
    int b = bh / HH, h = bh % HH;
    int tid = threadIdx.x, g = tid>>6, e = tid&63;
    const int m0 = g*GM;
    __shared__ __align__(16) float kt[2][TT][MP2];
    __shared__ __align__(16) float vt[2][TT][64];
    __shared__ float scs[CHK];
    float S[GM];
    #pragma unroll
    for (int i=0;i<GM;i++) S[i]=0.f;
    float zacc = 0.f;
    const float* kb = KP + ((size_t)bh*NN + c*CHK)*MP2;
    const float* vb = QKV + (size_t)(b*NN + c*CHK)*QKVS + 2*DD + h*64;

    float gmax = dec_f(g_kmax_u);
    for (int i=tid; i<CHK; i+=512)
        scs[i] = __expf(RM[bh*NN + c*CHK + i] - gmax);

    auto load = [&](int buf, int tile){
        const float* kb_ = kb + (size_t)tile*TT*MP2;
        const float* vb_ = vb + (size_t)tile*TT*QKVS;
        for (int idx=tid; idx<704; idx+=512){
            if (idx < 576){ int tok=idx/72, f=(idx%72)*4; cpasync16(&kt[buf][tok][f], kb_ + (size_t)tok*MP2 + f); }
            else { int r=idx-576; int tok=r/16, f=(r%16)*4; cpasync16(&vt[buf][tok][f], vb_ + (size_t)tok*QKVS + f); }
        }
    };
    load(0,0); CP_COMMIT;
    for (int tile=0; tile<NTILE; tile++){
        int buf = tile&1;
        CP_WAIT0;
        __syncthreads();
        if (tile+1 < NTILE) load(buf^1, tile+1);
        CP_COMMIT;
        {
            const int tb = tile*TT;
            for (int idx=tid; idx<TT*MP2; idx+=512){
                int tok = idx/MP2, m = idx - tok*MP2;
                float f = kt[buf][tok][m];
                kt[buf][tok][m] = (m < MM) ? RATIO_SC*(f*scs[tb+tok] + EPS_KER) : 0.f;
            }
        }
        __syncthreads();
        #pragma unroll
        for (int tt=0; tt<TT; tt++){
            float vv = vt[buf][tt][e];
            const float4* kr = (const float4*)(&kt[buf][tt][m0]);
            #pragma unroll
            for (int i4=0;i4<9;i4++){
                float4 kk = kr[i4];
                S[i4*4+0] += kk.x*vv;
                S[i4*4+1] += kk.y*vv;
                S[i4*4+2] += kk.z*vv;
                S[i4*4+3] += kk.w*vv;
            }
            if (tid < MP2) zacc += kt[buf][tt][tid];
        }
    }
    if (tid < MP2) Z[(size_t)bhc*MP2 + tid] = zacc;
    float* kvout = KV + (size_t)bhc*KVSTRIDE;
    #pragma unroll
    for (int i=0;i<GM;i++) kvout[(size_t)(m0+i)*64 + e] = S[i];
}

// parallel exclusive prefix: grid (KVSTRIDE/512, BH)
__global__ __launch_bounds__(512) void prefix_k(float* __restrict__ Z, float* __restrict__ KV){
    int bh = blockIdx.y;
    int base = bh*NC;
    int idx = blockIdx.x*512 + threadIdx.x;
    float run = 0.f;
    #pragma unroll
    for (int c=0;c<NC;c++){
        float* p = KV + (size_t)(base+c)*KVSTRIDE + idx;
        float t = *p; *p = run; run += t;
    }
    if (blockIdx.x==0 && threadIdx.x < MP2){
        float rz = 0.f;
        #pragma unroll
        for (int c=0;c<NC;c++){
            float* p = Z + (size_t)(base+c)*MP2 + threadIdx.x;
            float t = *p; *p = rz; rz += t;
        }
    }
}

__global__ __launch_bounds__(512) void chunkout_k(const float* __restrict__ QP,
                                                  const float* __restrict__ KP,
                                                  const float* __restrict__ QKV,
                                                  const float* __restrict__ RM,
                                                  const float* __restrict__ Z,
                                                  const float* __restrict__ KV,
                                                  float* __restrict__ O){
    int bhc = blockIdx.x;
    int bh = bhc / NC, c = bhc % NC;
    int b = bh / HH, h = bh % HH;
    int tid = threadIdx.x, g = tid>>6, e = tid&63;
    const int m0 = g*GM;
    __shared__ __align__(16) float kt[2][TT][MP2];
    __shared__ __align__(16) float qt[2][TT][MP2];
    __shared__ __align__(16) float vt[2][TT][64];
    __shared__ float partials[2][8][64];
    __shared__ float dred[2][9];
    __shared__ float scs[CHK];

    float S[GM];
    const float* kvin = KV + (size_t)bhc*KVSTRIDE;
    #pragma unroll
    for (int i=0;i<GM;i++) S[i] = kvin[(size_t)(m0+i)*64 + e];
    float zreg = (tid < MP2) ? Z[(size_t)bhc*MP2 + tid] : 0.f;

    const float* kb = KP + ((size_t)bh*NN + c*CHK)*MP2;
    const float* qb = QP + ((size_t)bh*NN + c*CHK)*MP2;
    const float* vb = QKV + (size_t)(b*NN + c*CHK)*QKVS + 2*DD + h*64;

    float gmax = dec_f(g_kmax_u);
    for (int i=tid; i<CHK; i+=512)
        scs[i] = __expf(RM[bh*NN + c*CHK + i] - gmax);

    auto load = [&](int buf, int tile){
        const float* kb_ = kb + (size_t)tile*TT*MP2;
        const float* qb_ = qb + (size_t)tile*TT*MP2;
        const float* vb_ = vb + (size_t)tile*TT*QKVS;
        for (int idx=tid; idx<1280; idx+=512){
            if (idx < 576){ int tok=idx/72, f=(idx%72)*4; cpasync16(&kt[buf][tok][f], kb_ + (size_t)tok*MP2 + f); }
            else if (idx < 1152){ int r=idx-576; int tok=r/72, f=(r%72)*4; cpasync16(&qt[buf][tok][f], qb_ + (size_t)tok*MP2 + f); }
            else { int r=idx-1152; int tok=r/16, f=(r%16)*4; cpasync16(&vt[buf][tok][f], vb_ + (size_t)tok*QKVS + f); }
        }
    };
    load(0,0); CP_COMMIT;

    for (int tile=0; tile<NTILE; tile++){
        int buf = tile&1;
        CP_WAIT0;
        __syncthreads();
        if (tile+1 < NTILE) load(buf^1, tile+1);
        CP_COMMIT;
        {
            const int tb = tile*TT;
            for (int idx=tid; idx<TT*MP2; idx+=512){
                int tok = idx/MP2, m = idx - tok*MP2;
                float f = kt[buf][tok][m];
                kt[buf][tok][m] = (m < MM) ? RATIO_SC*(f*scs[tb+tok] + EPS_KER) : 0.f;
            }
        }
        __syncthreads();
        #pragma unroll
        for (int tt=0; tt<TT; tt++){
            int pt = tt & 1;
            float vv = vt[buf][tt][e];
            const float4* kr = (const float4*)(&kt[buf][tt][m0]);
            const float4* qr = (const float4*)(&qt[buf][tt][m0]);
            float acc = 0.f;
            #pragma unroll
            for (int i4=0;i4<9;i4++){
                float4 kk = kr[i4];
                float4 qq = qr[i4];
                S[i4*4+0] += kk.x*vv;  acc += qq.x*S[i4*4+0];
                S[i4*4+1] += kk.y*vv;  acc += qq.y*S[i4*4+1];
                S[i4*4+2] += kk.z*vv;  acc += qq.z*S[i4*4+2];
                S[i4*4+3] += kk.w*vv;  acc += qq.w*S[i4*4+3];
            }
            partials[pt][g][e] = acc;
            if (tid < MP2){
                float kv = kt[buf][tt][tid];
                zreg += kv;
                float dp = qt[buf][tt][tid]*(zreg + EPS_DEN);
                #pragma unroll
                for (int o=16;o;o>>=1) dp += __shfl_xor_sync(0xffffffffu, dp, o);
                if ((tid&31)==0) dred[pt][tid>>5] = dp;
            }
            __syncthreads();
            if (tid < 64){
                float s = 0.f;
                #pragma unroll
                for (int gg=0; gg<8; gg++) s += partials[pt][gg][tid];
                float den = 0.f;
                #pragma unroll
                for (int w=0; w<9; w++) den += dred[pt][w];
                int t = c*CHK + tile*TT + tt;
                O[((size_t)(b*NN + t))*DD + h*64 + tid] = s / den;
            }
        }
    }
}

// ---------------- launch ----------------
#define GEMM_SMEM 65536

extern "C" void kernel_launch(void* const* d_in, const int* in_sizes, int n_in,
                              void* d_out, int out_size){
    (void)in_sizes; (void)n_in; (void)out_size;
    const float* x    = (const float*)d_in[0];
    const float* ln1g = (const float*)d_in[1];
    const float* ln1b = (const float*)d_in[2];
    const float* Wq   = (const float*)d_in[3];
    const float* bq   = (const float*)d_in[4];
    const float* Wk   = (const float*)d_in[5];
    const float* bk   = (const float*)d_in[6];
    const float* Wv   = (const float*)d_in[7];
    const float* bv   = (const float*)d_in[8];
    const float* Wo   = (const float*)d_in[9];
    const float* bo   = (const float*)d_in[10];
    const float* proj = (const float*)d_in[11];
    const float* ln2g = (const float*)d_in[12];
    const float* ln2b = (const float*)d_in[13];
    const float* W1   = (const float*)d_in[14];
    const float* b1   = (const float*)d_in[15];
    const float* W2   = (const float*)d_in[16];
    const float* b2   = (const float*)d_in[17];
    float* out = (float*)d_out;

    float *qkv,*qp,*kp,*rm,*o,*x1,*zz,*kv,*bqkv;
    uint4 *afh,*afl,*af2h,*af2l;
    uint2 *wfh,*wfl;
    cudaGetSymbolAddress((void**)&qkv, g_qkv);
    cudaGetSymbolAddress((void**)&qp,  g_qp);
    cudaGetSymbolAddress((void**)&kp,  g_kp);
    cudaGetSymbolAddress((void**)&rm,  g_rm);
    cudaGetSymbolAddress((void**)&o,   g_o);
    cudaGetSymbolAddress((void**)&x1,  g_x1);
    cudaGetSymbolAddress((void**)&zz,  g_Z);
    cudaGetSymbolAddress((void**)&kv,  g_KV);
    cudaGetSymbolAddress((void**)&bqkv,g_bqkv);
    cudaGetSymbolAddress((void**)&afh, g_afh);
    cudaGetSymbolAddress((void**)&afl, g_afl);
    cudaGetSymbolAddress((void**)&af2h,g_af2h);
    cudaGetSymbolAddress((void**)&af2l,g_af2l);
    cudaGetSymbolAddress((void**)&wfh, g_wfh);
    cudaGetSymbolAddress((void**)&wfl, g_wfl);

    cudaFuncSetAttribute(gemm_tc<0>, cudaFuncAttributeMaxDynamicSharedMemorySize, GEMM_SMEM);
    cudaFuncSetAttribute(gemm_tc<1>, cudaFuncAttributeMaxDynamicSharedMemorySize, GEMM_SMEM);
    cudaFuncSetAttribute(gemm_tc<2>, cudaFuncAttributeMaxDynamicSharedMemorySize, GEMM_SMEM);

    init_k<<<1,1>>>();

    // ---- LN1 -> fragments, QKV fused GEMM ----
    lnfrag_k<<<ROWS/16,256>>>(x, ln1g, ln1b, afh, afl);
    splitB_k<<<576,256>>>(Wq, wfh, wfl, DD, DD, 0);
    splitB_k<<<576,256>>>(Wk, wfh, wfl, DD, DD, DD/8);
    splitB_k<<<576,256>>>(Wv, wfh, wfl, DD, DD, 2*DD/8);
    packb_k<<<3,256>>>(bq, bk, bv, bqkv);
    {
        dim3 gq(QKVS/128, ROWS/128);
        gemm_tc<0><<<gq,256,GEMM_SMEM>>>(afh, afl, wfh, wfl, bqkv, nullptr, qkv, nullptr, nullptr, DD/16, QKVS);
    }

    // ---- feature maps ----
    dim3 gfeat(NN/32, BH, 2);
    featgemm_k<<<gfeat,256>>>(qkv, proj, qp, kp, rm);

    // ---- scan ----
    chunksum_k<<<NCH,512>>>(kp, qkv, rm, zz, kv);
    {
        dim3 gp(KVSTRIDE/512, BH);
        prefix_k<<<gp,512>>>(zz, kv);
    }
    chunkout_k<<<NCH,512>>>(qp, kp, qkv, rm, zz, kv, o);

    // ---- Wo GEMM + residual ----
    splitA_k<<<1536,256>>>(o, afh, afl, ROWS, DD);
    splitB_k<<<576,256>>>(Wo, wfh, wfl, DD, DD, 0);
    {
        dim3 gg(DD/128, ROWS/128);
        gemm_tc<2><<<gg,256,GEMM_SMEM>>>(afh, afl, wfh, wfl, bo, x, x1, nullptr, nullptr, DD/16, DD);
    }

    // ---- LN2 -> fragments, FFN ----
    lnfrag_k<<<ROWS/16,256>>>(x1, ln2g, ln2b, afh, afl);
    splitB_k<<<2304,256>>>(W1, wfh, wfl, DD, FFD, 0);
    {
        dim3 gg(FFD/128, ROWS/128);
        gemm_tc<1><<<gg,256,GEMM_SMEM>>>(afh, afl, wfh, wfl, b1, nullptr, nullptr, af2h, af2l, DD/16, FFD);
    }
    splitB_k<<<2304,256>>>(W2, wfh, wfl, FFD, DD, 0);
    {
        dim3 gg(DD/128, ROWS/128);
        gemm_tc<2><<<gg,256,GEMM_SMEM>>>(af2h, af2l, wfh, wfl, b2, x1, out, nullptr, nullptr, FFD/16, DD);
    }
}

// round 9
// speedup vs baseline: 8.0637x; 1.0067x over previous
#include <cuda_runtime.h>
#include <cuda_bf16.h>
#include <math.h>
#include <stdint.h>

// ---------------- problem constants ----------------
#define BB   2
#define NN   2048
#define DD   768
#define HH   12
#define MM   266
#define MP2  288
#define GM   36
#define FFD  3072
#define ROWS (BB*NN)
#define RIDS (BB*HH*NN)
#define BH   (BB*HH)
#define CHK  128
#define NC   (NN/CHK)
#define NCH  (BH*NC)
#define TT   8
#define NTILE (CHK/TT)
#define KVSTRIDE (MP2*64)
#define QKVS 2304

#define DN_SCALE   0.35355339059327f
#define RATIO_SC   0.061313689f
#define EPS_KER    1e-4f
#define EPS_DEN    1e-6f

// ---------------- scratch ----------------
__device__ float g_qkv[(size_t)ROWS*QKVS];
__device__ float g_o [ROWS*DD];
__device__ float g_x1[ROWS*DD];
__device__ float g_qp[(size_t)RIDS*MP2];
__device__ float g_kp[(size_t)RIDS*MP2];
__device__ float g_rm[RIDS];
__device__ float g_Z [(size_t)NCH*MP2];
__device__ float g_KV[(size_t)NCH*KVSTRIDE];
__device__ unsigned g_kmax_u;
__device__ float g_bqkv[QKVS];
// fragment-ordered bf16 hi/lo buffers
__device__ uint4 g_afh[(size_t)(ROWS/16)*(DD/16)*32];
__device__ uint4 g_afl[(size_t)(ROWS/16)*(DD/16)*32];
__device__ uint4 g_af2h[(size_t)(ROWS/16)*(FFD/16)*32];
__device__ uint4 g_af2l[(size_t)(ROWS/16)*(FFD/16)*32];
__device__ uint2 g_wfh[(size_t)(FFD/16)*(FFD/8)*32];
__device__ uint2 g_wfl[(size_t)(FFD/16)*(FFD/8)*32];

__device__ __forceinline__ unsigned enc_f(float f){
    unsigned u = __float_as_uint(f);
    return (u & 0x80000000u) ? ~u : (u | 0x80000000u);
}
__device__ __forceinline__ float dec_f(unsigned u){
    return (u & 0x80000000u) ? __uint_as_float(u ^ 0x80000000u) : __uint_as_float(~u);
}

__global__ void init_k(){ g_kmax_u = 0x00800000u; }

__device__ __forceinline__ void pack2(float x, float y, unsigned &h, unsigned &l){
    __nv_bfloat162 hv = __floats2bfloat162_rn(x, y);
    float hx = __low2float(hv), hy = __high2float(hv);
    __nv_bfloat162 lv = __floats2bfloat162_rn(x - hx, y - hy);
    h = *reinterpret_cast<unsigned*>(&hv);
    l = *reinterpret_cast<unsigned*>(&lv);
}

// ---------------- LayerNorm emitting A-fragments (16 rows/CTA) ----------------
__global__ __launch_bounds__(256) void lnfrag_k(const float* __restrict__ X,
                                                const float* __restrict__ G,
                                                const float* __restrict__ Bv,
                                                uint4* __restrict__ H,
                                                uint4* __restrict__ L){
    const int blk = blockIdx.x;
    const int tid = threadIdx.x;
    const int r = tid >> 4, c16 = tid & 15;
    __shared__ float mu_s[16], rs_s[16];
    const float* xr = X + ((size_t)blk*16 + r)*DD;
    float s = 0.f, ss = 0.f;
    #pragma unroll
    for (int j=0;j<12;j++){
        float4 v = *(const float4*)(xr + c16*4 + j*64);
        s  += v.x+v.y+v.z+v.w;
        ss += v.x*v.x+v.y*v.y+v.z*v.z+v.w*v.w;
    }
    #pragma unroll
    for (int o=8;o;o>>=1){
        s  += __shfl_xor_sync(0xffffffffu, s, o, 16);
        ss += __shfl_xor_sync(0xffffffffu, ss, o, 16);
    }
    if (c16==0){
        float mu = s*(1.0f/DD);
        float var = ss*(1.0f/DD) - mu*mu;
        mu_s[r]=mu; rs_s[r]=rsqrtf(var + 1e-5f);
    }
    __syncthreads();
    #pragma unroll
    for (int i=0;i<6;i++){
        int it = tid + i*256;
        int ak = it>>5, lane = it&31;
        int g = lane>>2, l = lane&3;
        float mu0 = mu_s[g],  r0 = rs_s[g];
        float mu1 = mu_s[g+8],r1 = rs_s[g+8];
        int c = ak*16 + 2*l;
        const float* row0 = X + ((size_t)blk*16 + g)*DD;
        const float* row1 = X + ((size_t)blk*16 + g + 8)*DD;
        float2 ga = *(const float2*)(G + c),  gb = *(const float2*)(G + c + 8);
        float2 ba = *(const float2*)(Bv + c), bb = *(const float2*)(Bv + c + 8);
        float2 v0 = *(const float2*)(row0 + c);
        float2 v1 = *(const float2*)(row1 + c);
        float2 v2 = *(const float2*)(row0 + c + 8);
        float2 v3 = *(const float2*)(row1 + c + 8);
        uint4 h, lo;
        pack2((v0.x-mu0)*r0*ga.x+ba.x, (v0.y-mu0)*r0*ga.y+ba.y, h.x, lo.x);
        pack2((v1.x-mu1)*r1*ga.x+ba.x, (v1.y-mu1)*r1*ga.y+ba.y, h.y, lo.y);
        pack2((v2.x-mu0)*r0*gb.x+bb.x, (v2.y-mu0)*r0*gb.y+bb.y, h.z, lo.z);
        pack2((v3.x-mu1)*r1*gb.x+bb.x, (v3.y-mu1)*r1*gb.y+bb.y, h.w, lo.w);
        size_t gidx = ((size_t)blk*48 + ak)*32 + lane;
        H[gidx]=h; L[gidx]=lo;
    }
}

// ---------------- bf16 split kernels ----------------
__global__ void splitA_k(const float* __restrict__ X, uint4* __restrict__ H,
                         uint4* __restrict__ L, int R, int C){
    int idx = blockIdx.x*256 + threadIdx.x;
    int K16 = C>>4;
    int total = (R>>4)*K16*32;
    if (idx >= total) return;
    int lane = idx & 31, atom = idx >> 5;
    int am = atom / K16, ak = atom % K16;
    int g = lane>>2, l = lane&3;
    const float* p = X + (size_t)(am*16+g)*C + ak*16 + 2*l;
    float2 v0 = *(const float2*)(p);
    float2 v1 = *(const float2*)(p + (size_t)8*C);
    float2 v2 = *(const float2*)(p + 8);
    float2 v3 = *(const float2*)(p + (size_t)8*C + 8);
    uint4 h, lo;
    pack2(v0.x, v0.y, h.x, lo.x);
    pack2(v1.x, v1.y, h.y, lo.y);
    pack2(v2.x, v2.y, h.z, lo.z);
    pack2(v3.x, v3.y, h.w, lo.w);
    H[idx] = h; L[idx] = lo;
}

__global__ void splitB_k(const float* __restrict__ W, uint2* __restrict__ H,
                         uint2* __restrict__ L, int K, int N, int anBase){
    int idx = blockIdx.x*256 + threadIdx.x;
    int K16 = K>>4;
    int total = K16*(N>>3)*32;
    if (idx >= total) return;
    int lane = idx & 31, atom = idx >> 5;
    int an = atom / K16, ak = atom % K16;
    int g = lane>>2, l = lane&3;
    const float* p = W + (size_t)(ak*16 + 2*l)*N + an*8 + g;
    float b00 = p[0],            b01 = p[N];
    float b10 = p[(size_t)8*N],  b11 = p[(size_t)9*N];
    uint2 h, lo;
    pack2(b00, b01, h.x, lo.x);
    pack2(b10, b11, h.y, lo.y);
    int outi = ((anBase + an)*K16 + ak)*32 + lane;
    H[outi] = h; L[outi] = lo;
}

__global__ void packb_k(const float* __restrict__ bq, const float* __restrict__ bk,
                        const float* __restrict__ bv, float* __restrict__ o){
    int i = blockIdx.x*256 + threadIdx.x;
    if (i < DD){ o[i]=bq[i]; o[DD+i]=bk[i]; o[2*DD+i]=bv[i]; }
}

// ---------------- cp.async helpers ----------------
__device__ __forceinline__ void cpasync16(void* smem, const void* gmem){
    unsigned s = (unsigned)__cvta_generic_to_shared(smem);
    asm volatile("cp.async.ca.shared.global [%0], [%1], 16;\n" :: "r"(s), "l"(gmem));
}
#define CP_COMMIT asm volatile("cp.async.commit_group;\n" ::: "memory")
#define CP_WAIT0  asm volatile("cp.async.wait_group 0;\n" ::: "memory")

// ---------------- bf16x3 tensor-core GEMM ----------------
__device__ __forceinline__ void mma16(float* d, const uint4& a, const uint2& b){
    asm volatile("mma.sync.aligned.m16n8k16.row.col.f32.bf16.bf16.f32 "
        "{%0,%1,%2,%3},{%4,%5,%6,%7},{%8,%9},{%0,%1,%2,%3};"
        : "+f"(d[0]),"+f"(d[1]),"+f"(d[2]),"+f"(d[3])
        : "r"(a.x),"r"(a.y),"r"(a.z),"r"(a.w),"r"(b.x),"r"(b.y));
}

// EPI: 0=bias->float, 1=bias+gelu->FRAGMENTS ONLY, 2=bias+residual->float
// min-blocks=2: cap regs at 128 so 2 CTAs co-reside per SM (smem 64KB*2 fits)
template<int EPI>
__global__ __launch_bounds__(256, 2) void gemm_tc(const uint4* __restrict__ Ah,
                                               const uint4* __restrict__ Al,
                                               const uint2* __restrict__ Bh,
                                               const uint2* __restrict__ Bl,
                                               const float* __restrict__ bias,
                                               const float* __restrict__ R,
                                               float* __restrict__ C,
                                               uint4* __restrict__ FH,
                                               uint4* __restrict__ FL,
                                               int K16, int N){
    extern __shared__ char smem[];
    const int tid = threadIdx.x, lane = tid & 31, warp = tid >> 5;
    const int wm = warp >> 2, wn = warp & 3;
    const int bm = blockIdx.y, bn = blockIdx.x;

    float acc[4][4][4];
    #pragma unroll
    for (int a=0;a<4;a++)
        #pragma unroll
        for (int b=0;b<4;b++)
            #pragma unroll
            for (int c=0;c<4;c++) acc[a][b][c]=0.f;

    auto stage_copy = [&](int s, int kb){
        char* base = smem + s*32768;
        #pragma unroll
        for (int i=0;i<2;i++){
            int e = tid + i*256;
            int ma = e>>6, ra = e&63;
            int ka = ra>>5, ln = ra&31;
            size_t ga = ((size_t)(bm*8+ma)*K16 + kb + ka)*32 + ln;
            cpasync16(base + e*16,         Ah + ga);
            cpasync16(base + 8192 + e*16,  Al + ga);
            int na = e>>5, rb = e&31;
            int kb2 = rb>>4, lp = rb&15;
            size_t gb = ((size_t)(bn*16+na)*K16 + kb + kb2)*32 + lp*2;
            cpasync16(base + 16384 + e*16, Bh + gb);
            cpasync16(base + 24576 + e*16, Bl + gb);
        }
    };

    stage_copy(0, 0); CP_COMMIT;
    const int nk = K16 >> 1;
    int st = 0;
    for (int ks=0; ks<nk; ks++, st^=1){
        CP_WAIT0;
        __syncthreads();
        if (ks+1 < nk){ stage_copy(st^1, (ks+1)*2); CP_COMMIT; }
        const uint4* sAh = (const uint4*)(smem + st*32768);
        const uint4* sAl = (const uint4*)(smem + st*32768 + 8192);
        const uint2* sBh = (const uint2*)(smem + st*32768 + 16384);
        const uint2* sBl = (const uint2*)(smem + st*32768 + 24576);
        #pragma unroll
        for (int ka=0; ka<2; ka++){
            uint4 Afh[4], Afl[4];
            uint2 Bfh[4], Bfl[4];
            #pragma unroll
            for (int mi=0;mi<4;mi++){
                int off = ((wm*4+mi)*2 + ka)*32 + lane;
                Afh[mi] = sAh[off];
                Afl[mi] = sAl[off];
            }
            #pragma unroll
            for (int ni=0;ni<4;ni++){
                int off = ((wn*4+ni)*2 + ka)*32 + lane;
                Bfh[ni] = sBh[off];
                Bfl[ni] = sBl[off];
            }
            #pragma unroll
            for (int mi=0;mi<4;mi++)
                #pragma unroll
                for (int ni=0;ni<4;ni++){
                    mma16(acc[mi][ni], Afh[mi], Bfh[ni]);
                    mma16(acc[mi][ni], Afh[mi], Bfl[ni]);
                    mma16(acc[mi][ni], Afl[mi], Bfh[ni]);
                }
        }
    }

    const int g = lane>>2, l = lane&3;
    if (EPI==1){
        const int K16n = N >> 4;
        #pragma unroll
        for (int mi=0;mi<4;mi++){
            int am = bm*8 + wm*4 + mi;
            #pragma unroll
            for (int np=0;np<2;np++){
                float vv[2][4];
                #pragma unroll
                for (int half=0; half<2; half++){
                    int ni = 2*np + half;
                    int col = bn*128 + wn*32 + ni*8 + 2*l;
                    float b0 = bias[col], b1 = bias[col+1];
                    float v0 = acc[mi][ni][0]+b0, v1 = acc[mi][ni][1]+b1;
                    float v2 = acc[mi][ni][2]+b0, v3 = acc[mi][ni][3]+b1;
                    vv[half][0] = 0.5f*v0*(1.0f + erff(v0*0.70710678118654752f));
                    vv[half][1] = 0.5f*v1*(1.0f + erff(v1*0.70710678118654752f));
                    vv[half][2] = 0.5f*v2*(1.0f + erff(v2*0.70710678118654752f));
                    vv[half][3] = 0.5f*v3*(1.0f + erff(v3*0.70710678118654752f));
                }
                uint4 h, lo;
                pack2(vv[0][0], vv[0][1], h.x, lo.x);
                pack2(vv[0][2], vv[0][3], h.y, lo.y);
                pack2(vv[1][0], vv[1][1], h.z, lo.z);
                pack2(vv[1][2], vv[1][3], h.w, lo.w);
                size_t ga = ((size_t)am*K16n + (bn*8 + wn*2 + np))*32 + lane;
                FH[ga] = h; FL[ga] = lo;
            }
        }
    } else {
        #pragma unroll
        for (int mi=0;mi<4;mi++){
            int row = bm*128 + wm*64 + mi*16 + g;
            #pragma unroll
            for (int ni=0;ni<4;ni++){
                int col = bn*128 + wn*32 + ni*8 + 2*l;
                float b0 = bias[col], b1 = bias[col+1];
                float v0 = acc[mi][ni][0]+b0, v1 = acc[mi][ni][1]+b1;
                float v2 = acc[mi][ni][2]+b0, v3 = acc[mi][ni][3]+b1;
                if (EPI==2){
                    float2 r0 = *(const float2*)(R + (size_t)row*N + col);
                    float2 r1 = *(const float2*)(R + (size_t)(row+8)*N + col);
                    v0 += r0.x; v1 += r0.y; v2 += r1.x; v3 += r1.y;
                }
                *(float2*)(C + (size_t)row*N + col)     = make_float2(v0, v1);
                *(float2*)(C + (size_t)(row+8)*N + col) = make_float2(v2, v3);
            }
        }
    }
}

// ---------------- FAVOR+ feature maps as GEMM ----------------
__global__ __launch_bounds__(256) void featgemm_k(const float* __restrict__ QKV,
                                                  const float* __restrict__ proj,
                                                  float* __restrict__ QP,
                                                  float* __restrict__ KP,
                                                  float* __restrict__ RM){
    const int isK = blockIdx.z;
    const int bh = blockIdx.y;
    const int n0 = blockIdx.x*32;
    const int b = bh/HH, h = bh%HH;
    const float* A = QKV + (size_t)(b*NN + n0)*QKVS + (isK ? DD : 0) + h*64;

    __shared__ float Ps[32][292];
    __shared__ float At[32][33];
    __shared__ float diag_s[32];
    __shared__ float wmx[8];

    int tid = threadIdx.x;
    int tx = tid & 31, ty = tid >> 5;
    float acc[4][9];
    #pragma unroll
    for (int i=0;i<4;i++)
        #pragma unroll
        for (int j=0;j<9;j++) acc[i][j]=0.f;

    #pragma unroll
    for (int ks=0; ks<2; ks++){
        {
            int t = tid>>3, d4 = (tid&7)<<2;
            float4 a4 = *(const float4*)(A + (size_t)t*QKVS + ks*32 + d4);
            At[d4+0][t]=a4.x; At[d4+1][t]=a4.y; At[d4+2][t]=a4.z; At[d4+3][t]=a4.w;
        }
        {
            int d4 = (tid&7)<<2, mb = tid>>3;
            #pragma unroll
            for (int it=0; it<9; it++){
                int m = mb + it*32;
                float4 p4 = (m < MM) ? *(const float4*)(proj + (size_t)m*64 + ks*32 + d4)
                                     : make_float4(0.f,0.f,0.f,0.f);
                Ps[d4+0][m]=p4.x; Ps[d4+1][m]=p4.y; Ps[d4+2][m]=p4.z; Ps[d4+3][m]=p4.w;
            }
        }
        __syncthreads();
        if (tid < 32){
            float s = (ks==0) ? 0.f : diag_s[tid];
            #pragma unroll
            for (int d=0; d<32; d++){ float a = At[d][tid]; s += a*a; }
            diag_s[tid] = s;
        }
        #pragma unroll
        for (int d=0; d<32; d++){
            float a0 = At[d][ty*4+0];
            float a1 = At[d][ty*4+1];
            float a2 = At[d][ty*4+2];
            float a3 = At[d][ty*4+3];
            #pragma unroll
            for (int j=0;j<9;j++){
                float p = Ps[d][tx*9+j];
                acc[0][j] += a0*p;
                acc[1][j] += a1*p;
                acc[2][j] += a2*p;
                acc[3][j] += a3*p;
            }
        }
        __syncthreads();
    }

    float mx[4];
    #pragma unroll
    for (int i=0;i<4;i++){
        float m_ = -3.4e38f;
        #pragma unroll
        for (int j=0;j<9;j++){
            float v = acc[i][j]*DN_SCALE;
            acc[i][j] = v;
            if (tx*9+j < MM) m_ = fmaxf(m_, v);
        }
        #pragma unroll
        for (int o=16;o;o>>=1) m_ = fmaxf(m_, __shfl_xor_sync(0xffffffffu, m_, o));
        mx[i] = m_;
    }

    if (!isK){
        #pragma unroll
        for (int i=0;i<4;i++){
            int t = ty*4+i;
            float dg = diag_s[t]*0.0625f;
            float* out = QP + ((size_t)(bh*NN + n0 + t))*MP2;
            #pragma unroll
            for (int j=0;j<9;j++){
                int m = tx*9+j;
                out[m] = (m < MM) ? RATIO_SC*(__expf(acc[i][j]-dg-mx[i]) + EPS_KER) : 0.f;
            }
        }
    } else {
        float bm_ = -3.4e38f;
        #pragma unroll
        for (int i=0;i<4;i++){
            int t = ty*4+i;
            float dg = diag_s[t]*0.0625f;
            float* out = KP + ((size_t)(bh*NN + n0 + t))*MP2;
            #pragma unroll
            for (int j=0;j<9;j++){
                int m = tx*9+j;
                out[m] = (m < MM) ? __expf(acc[i][j]-dg-mx[i]) : 0.f;
            }
            if (tx==0) RM[bh*NN + n0 + t] = mx[i];
            bm_ = fmaxf(bm_, mx[i]);
        }
        if (tx==0) wmx[ty] = bm_;
        __syncthreads();
        if (tid==0){
            float B = wmx[0];
            #pragma unroll
            for (int w=1;w<8;w++) B = fmaxf(B, wmx[w]);
            atomicMax(&g_kmax_u, enc_f(B));
        }
    }
}

// ---------------- chunked causal linear attention ----------------
__global__ __launch_bounds__(512) void chunksum_k(const float* __restrict__ KP,
                                                  const float* __restrict__ QKV,
                                                  const float* __restrict__ RM,
                                                  float* __restrict__ Z,
                                                  float* __restrict__ KV){
    int bhc = blockIdx.x;
    int bh = bhc / NC, c = bhc % NC;
    int b = bh / HH, h = bh % HH;
    int tid = threadIdx.x, g = tid>>6, e = tid&63;
    const int m0 = g*GM;
    __shared__ __align__(16) float kt[2][TT][MP2];
    __shared__ __align__(16) float vt[2][TT][64];
    __shared__ float scs[CHK];
    float S[GM];
    #pragma unroll
    for (int i=0;i<GM;i++) S[i]=0.f;
    float zacc = 0.f;
    const float* kb = KP + ((size_t)bh*NN + c*CHK)*MP2;
    const float* vb = QKV + (size_t)(b*NN + c*CHK)*QKVS + 2*DD + h*64;

    float gmax = dec_f(g_kmax_u);
    for (int i=tid; i<CHK; i+=512)
        scs[i] = __expf(RM[bh*NN + c*CHK + i] - gmax);

    auto load = [&](int buf, int tile){
        const float* kb_ = kb + (size_t)tile*TT*MP2;
        const float* vb_ = vb + (size_t)tile*TT*QKVS;
        for (int idx=tid; idx<704; idx+=512){
            if (idx < 576){ int tok=idx/72, f=(idx%72)*4; cpasync16(&kt[buf][tok][f], kb_ + (size_t)tok*MP2 + f); }
            else { int r=idx-576; int tok=r/16, f=(r%16)*4; cpasync16(&vt[buf][tok][f], vb_ + (size_t)tok*QKVS + f); }
        }
    };
    load(0,0); CP_COMMIT;
    for (int tile=0; tile<NTILE; tile++){
        int buf = tile&1;
        CP_WAIT0;
        __syncthreads();
        if (tile+1 < NTILE) load(buf^1, tile+1);
        CP_COMMIT;
        {
            const int tb = tile*TT;
            for (int idx=tid; idx<TT*MP2; idx+=512){
                int tok = idx/MP2, m = idx - tok*MP2;
                float f = kt[buf][tok][m];
                kt[buf][tok][m] = (m < MM) ? RATIO_SC*(f*scs[tb+tok] + EPS_KER) : 0.f;
            }
        }
        __syncthreads();
        #pragma unroll
        for (int tt=0; tt<TT; tt++){
            float vv = vt[buf][tt][e];
            const float4* kr = (const float4*)(&kt[buf][tt][m0]);
            #pragma unroll
            for (int i4=0;i4<9;i4++){
                float4 kk = kr[i4];
                S[i4*4+0] += kk.x*vv;
                S[i4*4+1] += kk.y*vv;
                S[i4*4+2] += kk.z*vv;
                S[i4*4+3] += kk.w*vv;
            }
            if (tid < MP2) zacc += kt[buf][tt][tid];
        }
    }
    if (tid < MP2) Z[(size_t)bhc*MP2 + tid] = zacc;
    float* kvout = KV + (size_t)bhc*KVSTRIDE;
    #pragma unroll
    for (int i=0;i<GM;i++) kvout[(size_t)(m0+i)*64 + e] = S[i];
}

__global__ __launch_bounds__(512) void prefix_k(float* __restrict__ Z, float* __restrict__ KV){
    int bh = blockIdx.y;
    int base = bh*NC;
    int idx = blockIdx.x*512 + threadIdx.x;
    float run = 0.f;
    #pragma unroll
    for (int c=0;c<NC;c++){
        float* p = KV + (size_t)(base+c)*KVSTRIDE + idx;
        float t = *p; *p = run; run += t;
    }
    if (blockIdx.x==0 && threadIdx.x < MP2){
        float rz = 0.f;
        #pragma unroll
        for (int c=0;c<NC;c++){
            float* p = Z + (size_t)(base+c)*MP2 + threadIdx.x;
            float t = *p; *p = rz; rz += t;
        }
    }
}

__global__ __launch_bounds__(512) void chunkout_k(const float* __restrict__ QP,
                                                  const float* __restrict__ KP,
                                                  const float* __restrict__ QKV,
                                                  const float* __restrict__ RM,
                                                  const float* __restrict__ Z,
                                                  const float* __restrict__ KV,
                                                  float* __restrict__ O){
    int bhc = blockIdx.x;
    int bh = bhc / NC, c = bhc % NC;
    int b = bh / HH, h = bh % HH;
    int tid = threadIdx.x, g = tid>>6, e = tid&63;
    const int m0 = g*GM;
    __shared__ __align__(16) float kt[2][TT][MP2];
    __shared__ __align__(16) float qt[2][TT][MP2];
    __shared__ __align__(16) float vt[2][TT][64];
    __shared__ float partials[2][8][64];
    __shared__ float dred[2][9];
    __shared__ float scs[CHK];

    float S[GM];
    const float* kvin = KV + (size_t)bhc*KVSTRIDE;
    #pragma unroll
    for (int i=0;i<GM;i++) S[i] = kvin[(size_t)(m0+i)*64 + e];
    float zreg = (tid < MP2) ? Z[(size_t)bhc*MP2 + tid] : 0.f;

    const float* kb = KP + ((size_t)bh*NN + c*CHK)*MP2;
    const float* qb = QP + ((size_t)bh*NN + c*CHK)*MP2;
    const float* vb = QKV + (size_t)(b*NN + c*CHK)*QKVS + 2*DD + h*64;

    float gmax = dec_f(g_kmax_u);
    for (int i=tid; i<CHK; i+=512)
        scs[i] = __expf(RM[bh*NN + c*CHK + i] - gmax);

    auto load = [&](int buf, int tile){
        const float* kb_ = kb + (size_t)tile*TT*MP2;
        const float* qb_ = qb + (size_t)tile*TT*MP2;
        const float* vb_ = vb + (size_t)tile*TT*QKVS;
        for (int idx=tid; idx<1280; idx+=512){
            if (idx < 576){ int tok=idx/72, f=(idx%72)*4; cpasync16(&kt[buf][tok][f], kb_ + (size_t)tok*MP2 + f); }
            else if (idx < 1152){ int r=idx-576; int tok=r/72, f=(r%72)*4; cpasync16(&qt[buf][tok][f], qb_ + (size_t)tok*MP2 + f); }
            else { int r=idx-1152; int tok=r/16, f=(r%16)*4; cpasync16(&vt[buf][tok][f], vb_ + (size_t)tok*QKVS + f); }
        }
    };
    load(0,0); CP_COMMIT;

    for (int tile=0; tile<NTILE; tile++){
        int buf = tile&1;
        CP_WAIT0;
        __syncthreads();
        if (tile+1 < NTILE) load(buf^1, tile+1);
        CP_COMMIT;
        {
            const int tb = tile*TT;
            for (int idx=tid; idx<TT*MP2; idx+=512){
                int tok = idx/MP2, m = idx - tok*MP2;
                float f = kt[buf][tok][m];
                kt[buf][tok][m] = (m < MM) ? RATIO_SC*(f*scs[tb+tok] + EPS_KER) : 0.f;
            }
        }
        __syncthreads();
        #pragma unroll
        for (int tt=0; tt<TT; tt++){
            int pt = tt & 1;
            float vv = vt[buf][tt][e];
            const float4* kr = (const float4*)(&kt[buf][tt][m0]);
            const float4* qr = (const float4*)(&qt[buf][tt][m0]);
            float acc = 0.f;
            #pragma unroll
            for (int i4=0;i4<9;i4++){
                float4 kk = kr[i4];
                float4 qq = qr[i4];
                S[i4*4+0] += kk.x*vv;  acc += qq.x*S[i4*4+0];
                S[i4*4+1] += kk.y*vv;  acc += qq.y*S[i4*4+1];
                S[i4*4+2] += kk.z*vv;  acc += qq.z*S[i4*4+2];
                S[i4*4+3] += kk.w*vv;  acc += qq.w*S[i4*4+3];
            }
            partials[pt][g][e] = acc;
            if (tid < MP2){
                float kv = kt[buf][tt][tid];
                zreg += kv;
                float dp = qt[buf][tt][tid]*(zreg + EPS_DEN);
                #pragma unroll
                for (int o=16;o;o>>=1) dp += __shfl_xor_sync(0xffffffffu, dp, o);
                if ((tid&31)==0) dred[pt][tid>>5] = dp;
            }
            __syncthreads();
            if (tid < 64){
                float s = 0.f;
                #pragma unroll
                for (int gg=0; gg<8; gg++) s += partials[pt][gg][tid];
                float den = 0.f;
                #pragma unroll
                for (int w=0; w<9; w++) den += dred[pt][w];
                int t = c*CHK + tile*TT + tt;
                O[((size_t)(b*NN + t))*DD + h*64 + tid] = s / den;
            }
        }
    }
}

// ---------------- launch ----------------
#define GEMM_SMEM 65536

extern "C" void kernel_launch(void* const* d_in, const int* in_sizes, int n_in,
                              void* d_out, int out_size){
    (void)in_sizes; (void)n_in; (void)out_size;
    const float* x    = (const float*)d_in[0];
    const float* ln1g = (const float*)d_in[1];
    const float* ln1b = (const float*)d_in[2];
    const float* Wq   = (const float*)d_in[3];
    const float* bq   = (const float*)d_in[4];
    const float* Wk   = (const float*)d_in[5];
    const float* bk   = (const float*)d_in[6];
    const float* Wv   = (const float*)d_in[7];
    const float* bv   = (const float*)d_in[8];
    const float* Wo   = (const float*)d_in[9];
    const float* bo   = (const float*)d_in[10];
    const float* proj = (const float*)d_in[11];
    const float* ln2g = (const float*)d_in[12];
    const float* ln2b = (const float*)d_in[13];
    const float* W1   = (const float*)d_in[14];
    const float* b1   = (const float*)d_in[15];
    const float* W2   = (const float*)d_in[16];
    const float* b2   = (const float*)d_in[17];
    float* out = (float*)d_out;

    float *qkv,*qp,*kp,*rm,*o,*x1,*zz,*kv,*bqkv;
    uint4 *afh,*afl,*af2h,*af2l;
    uint2 *wfh,*wfl;
    cudaGetSymbolAddress((void**)&qkv, g_qkv);
    cudaGetSymbolAddress((void**)&qp,  g_qp);
    cudaGetSymbolAddress((void**)&kp,  g_kp);
    cudaGetSymbolAddress((void**)&rm,  g_rm);
    cudaGetSymbolAddress((void**)&o,   g_o);
    cudaGetSymbolAddress((void**)&x1,  g_x1);
    cudaGetSymbolAddress((void**)&zz,  g_Z);
    cudaGetSymbolAddress((void**)&kv,  g_KV);
    cudaGetSymbolAddress((void**)&bqkv,g_bqkv);
    cudaGetSymbolAddress((void**)&afh, g_afh);
    cudaGetSymbolAddress((void**)&afl, g_afl);
    cudaGetSymbolAddress((void**)&af2h,g_af2h);
    cudaGetSymbolAddress((void**)&af2l,g_af2l);
    cudaGetSymbolAddress((void**)&wfh, g_wfh);
    cudaGetSymbolAddress((void**)&wfl, g_wfl);

    cudaFuncSetAttribute(gemm_tc<0>, cudaFuncAttributeMaxDynamicSharedMemorySize, GEMM_SMEM);
    cudaFuncSetAttribute(gemm_tc<1>, cudaFuncAttributeMaxDynamicSharedMemorySize, GEMM_SMEM);
    cudaFuncSetAttribute(gemm_tc<2>, cudaFuncAttributeMaxDynamicSharedMemorySize, GEMM_SMEM);

    init_k<<<1,1>>>();

    // ---- LN1 -> fragments, QKV fused GEMM ----
    lnfrag_k<<<ROWS/16,256>>>(x, ln1g, ln1b, afh, afl);
    splitB_k<<<576,256>>>(Wq, wfh, wfl, DD, DD, 0);
    splitB_k<<<576,256>>>(Wk, wfh, wfl, DD, DD, DD/8);
    splitB_k<<<576,256>>>(Wv, wfh, wfl, DD, DD, 2*DD/8);
    packb_k<<<3,256>>>(bq, bk, bv, bqkv);
    {
        dim3 gq(QKVS/128, ROWS/128);
        gemm_tc<0><<<gq,256,GEMM_SMEM>>>(afh, afl, wfh, wfl, bqkv, nullptr, qkv, nullptr, nullptr, DD/16, QKVS);
    }

    // ---- feature maps ----
    dim3 gfeat(NN/32, BH, 2);
    featgemm_k<<<gfeat,256>>>(qkv, proj, qp, kp, rm);

    // ---- scan ----
    chunksum_k<<<NCH,512>>>(kp, qkv, rm, zz, kv);
    {
        dim3 gp(KVSTRIDE/512, BH);
        prefix_k<<<gp,512>>>(zz, kv);
    }
    chunkout_k<<<NCH,512>>>(qp, kp, qkv, rm, zz, kv, o);

    // ---- Wo GEMM + residual ----
    splitA_k<<<1536,256>>>(o, afh, afl, ROWS, DD);
    splitB_k<<<576,256>>>(Wo, wfh, wfl, DD, DD, 0);
    {
        dim3 gg(DD/128, ROWS/128);
        gemm_tc<2><<<gg,256,GEMM_SMEM>>>(afh, afl, wfh, wfl, bo, x, x1, nullptr, nullptr, DD/16, DD);
    }

    // ---- LN2 -> fragments, FFN ----
    lnfrag_k<<<ROWS/16,256>>>(x1, ln2g, ln2b, afh, afl);
    splitB_k<<<2304,256>>>(W1, wfh, wfl, DD, FFD, 0);
    {
        dim3 gg(FFD/128, ROWS/128);
        gemm_tc<1><<<gg,256,GEMM_SMEM>>>(afh, afl, wfh, wfl, b1, nullptr, nullptr, af2h, af2l, DD/16, FFD);
    }
    splitB_k<<<2304,256>>>(W2, wfh, wfl, FFD, DD, 0);
    {
        dim3 gg(DD/128, ROWS/128);
        gemm_tc<2><<<gg,256,GEMM_SMEM>>>(af2h, af2l, wfh, wfl, b2, x1, out, nullptr, nullptr, FFD/16, DD);
    }
}

// round 10
// speedup vs baseline: 8.4155x; 1.0436x over previous
#include <cuda_runtime.h>
#include <cuda_bf16.h>
#include <math.h>
#include <stdint.h>

// ---------------- problem constants ----------------
#define BB   2
#define NN   2048
#define DD   768
#define HH   12
#define MM   266
#define MP2  288
#define GM   36
#define FFD  3072
#define ROWS (BB*NN)
#define RIDS (BB*HH*NN)
#define BH   (BB*HH)
#define CHK  128
#define NC   (NN/CHK)
#define NCH  (BH*NC)
#define TT   8
#define NTILE (CHK/TT)
#define KVSTRIDE (MP2*64)
#define QKVS 2304

#define DN_SCALE   0.35355339059327f
#define RATIO_SC   0.061313689f
#define EPS_KER    1e-4f
#define EPS_DEN    1e-6f

// ---------------- scratch ----------------
__device__ float g_qkv[(size_t)ROWS*QKVS];
__device__ float g_o [ROWS*DD];
__device__ float g_x1[ROWS*DD];
__device__ float g_qp[(size_t)RIDS*MP2];
__device__ float g_kp[(size_t)RIDS*MP2];
__device__ float g_rm[RIDS];
__device__ float g_Z [(size_t)NCH*MP2];
__device__ float g_KV[(size_t)NCH*KVSTRIDE];
__device__ unsigned g_kmax_u;
__device__ float g_bqkv[QKVS];
__device__ float g_part[(size_t)4*ROWS*DD];   // k-split partials
// fragment-ordered bf16 hi/lo buffers
__device__ uint4 g_afh[(size_t)(ROWS/16)*(DD/16)*32];
__device__ uint4 g_afl[(size_t)(ROWS/16)*(DD/16)*32];
__device__ uint4 g_af2h[(size_t)(ROWS/16)*(FFD/16)*32];
__device__ uint4 g_af2l[(size_t)(ROWS/16)*(FFD/16)*32];
__device__ uint2 g_wfh[(size_t)(FFD/16)*(FFD/8)*32];
__device__ uint2 g_wfl[(size_t)(FFD/16)*(FFD/8)*32];

__device__ __forceinline__ unsigned enc_f(float f){
    unsigned u = __float_as_uint(f);
    return (u & 0x80000000u) ? ~u : (u | 0x80000000u);
}
__device__ __forceinline__ float dec_f(unsigned u){
    return (u & 0x80000000u) ? __uint_as_float(u ^ 0x80000000u) : __uint_as_float(~u);
}

__global__ void init_k(){ g_kmax_u = 0x00800000u; }

__device__ __forceinline__ void pack2(float x, float y, unsigned &h, unsigned &l){
    __nv_bfloat162 hv = __floats2bfloat162_rn(x, y);
    float hx = __low2float(hv), hy = __high2float(hv);
    __nv_bfloat162 lv = __floats2bfloat162_rn(x - hx, y - hy);
    h = *reinterpret_cast<unsigned*>(&hv);
    l = *reinterpret_cast<unsigned*>(&lv);
}

// ---------------- LayerNorm emitting A-fragments (16 rows/CTA) ----------------
__global__ __launch_bounds__(256) void lnfrag_k(const float* __restrict__ X,
                                                const float* __restrict__ G,
                                                const float* __restrict__ Bv,
                                                uint4* __restrict__ H,
                                                uint4* __restrict__ L){
    const int blk = blockIdx.x;
    const int tid = threadIdx.x;
    const int r = tid >> 4, c16 = tid & 15;
    __shared__ float mu_s[16], rs_s[16];
    const float* xr = X + ((size_t)blk*16 + r)*DD;
    float s = 0.f, ss = 0.f;
    #pragma unroll
    for (int j=0;j<12;j++){
        float4 v = *(const float4*)(xr + c16*4 + j*64);
        s  += v.x+v.y+v.z+v.w;
        ss += v.x*v.x+v.y*v.y+v.z*v.z+v.w*v.w;
    }
    #pragma unroll
    for (int o=8;o;o>>=1){
        s  += __shfl_xor_sync(0xffffffffu, s, o, 16);
        ss += __shfl_xor_sync(0xffffffffu, ss, o, 16);
    }
    if (c16==0){
        float mu = s*(1.0f/DD);
        float var = ss*(1.0f/DD) - mu*mu;
        mu_s[r]=mu; rs_s[r]=rsqrtf(var + 1e-5f);
    }
    __syncthreads();
    #pragma unroll
    for (int i=0;i<6;i++){
        int it = tid + i*256;
        int ak = it>>5, lane = it&31;
        int g = lane>>2, l = lane&3;
        float mu0 = mu_s[g],  r0 = rs_s[g];
        float mu1 = mu_s[g+8],r1 = rs_s[g+8];
        int c = ak*16 + 2*l;
        const float* row0 = X + ((size_t)blk*16 + g)*DD;
        const float* row1 = X + ((size_t)blk*16 + g + 8)*DD;
        float2 ga = *(const float2*)(G + c),  gb = *(const float2*)(G + c + 8);
        float2 ba = *(const float2*)(Bv + c), bb = *(const float2*)(Bv + c + 8);
        float2 v0 = *(const float2*)(row0 + c);
        float2 v1 = *(const float2*)(row1 + c);
        float2 v2 = *(const float2*)(row0 + c + 8);
        float2 v3 = *(const float2*)(row1 + c + 8);
        uint4 h, lo;
        pack2((v0.x-mu0)*r0*ga.x+ba.x, (v0.y-mu0)*r0*ga.y+ba.y, h.x, lo.x);
        pack2((v1.x-mu1)*r1*ga.x+ba.x, (v1.y-mu1)*r1*ga.y+ba.y, h.y, lo.y);
        pack2((v2.x-mu0)*r0*gb.x+bb.x, (v2.y-mu0)*r0*gb.y+bb.y, h.z, lo.z);
        pack2((v3.x-mu1)*r1*gb.x+bb.x, (v3.y-mu1)*r1*gb.y+bb.y, h.w, lo.w);
        size_t gidx = ((size_t)blk*48 + ak)*32 + lane;
        H[gidx]=h; L[gidx]=lo;
    }
}

// ---------------- bf16 split kernels ----------------
__global__ void splitA_k(const float* __restrict__ X, uint4* __restrict__ H,
                         uint4* __restrict__ L, int R, int C){
    int idx = blockIdx.x*256 + threadIdx.x;
    int K16 = C>>4;
    int total = (R>>4)*K16*32;
    if (idx >= total) return;
    int lane = idx & 31, atom = idx >> 5;
    int am = atom / K16, ak = atom % K16;
    int g = lane>>2, l = lane&3;
    const float* p = X + (size_t)(am*16+g)*C + ak*16 + 2*l;
    float2 v0 = *(const float2*)(p);
    float2 v1 = *(const float2*)(p + (size_t)8*C);
    float2 v2 = *(const float2*)(p + 8);
    float2 v3 = *(const float2*)(p + (size_t)8*C + 8);
    uint4 h, lo;
    pack2(v0.x, v0.y, h.x, lo.x);
    pack2(v1.x, v1.y, h.y, lo.y);
    pack2(v2.x, v2.y, h.z, lo.z);
    pack2(v3.x, v3.y, h.w, lo.w);
    H[idx] = h; L[idx] = lo;
}

__device__ __forceinline__ void splitB_core(const float* __restrict__ W,
                                            uint2* __restrict__ H, uint2* __restrict__ L,
                                            int idx, int K, int N, int anBase){
    int lane = idx & 31, atom = idx >> 5;
    int K16 = K>>4;
    int an = atom / K16, ak = atom % K16;
    int g = lane>>2, l = lane&3;
    const float* p = W + (size_t)(ak*16 + 2*l)*N + an*8 + g;
    float b00 = p[0],            b01 = p[N];
    float b10 = p[(size_t)8*N],  b11 = p[(size_t)9*N];
    uint2 h, lo;
    pack2(b00, b01, h.x, lo.x);
    pack2(b10, b11, h.y, lo.y);
    int outi = ((anBase + an)*K16 + ak)*32 + lane;
    H[outi] = h; L[outi] = lo;
}

__global__ void splitB_k(const float* __restrict__ W, uint2* __restrict__ H,
                         uint2* __restrict__ L, int K, int N, int anBase){
    int idx = blockIdx.x*256 + threadIdx.x;
    int total = (K>>4)*(N>>3)*32;
    if (idx >= total) return;
    splitB_core(W, H, L, idx, K, N, anBase);
}

// merged QKV weight split (3 x [768x768])
__global__ void splitB3_k(const float* __restrict__ Wq, const float* __restrict__ Wk,
                          const float* __restrict__ Wv, uint2* __restrict__ H,
                          uint2* __restrict__ L){
    const int per = (DD>>4)*(DD>>3)*32;   // 147456
    int idx = blockIdx.x*256 + threadIdx.x;
    if (idx >= 3*per) return;
    int which = idx / per, rem = idx - which*per;
    const float* W = (which==0)?Wq:(which==1)?Wk:Wv;
    splitB_core(W, H, L, rem, DD, DD, which*(DD>>3));
}

__global__ void packb_k(const float* __restrict__ bq, const float* __restrict__ bk,
                        const float* __restrict__ bv, float* __restrict__ o){
    int i = blockIdx.x*256 + threadIdx.x;
    if (i < DD){ o[i]=bq[i]; o[DD+i]=bk[i]; o[2*DD+i]=bv[i]; }
}

// ---------------- cp.async helpers ----------------
__device__ __forceinline__ void cpasync16(void* smem, const void* gmem){
    unsigned s = (unsigned)__cvta_generic_to_shared(smem);
    asm volatile("cp.async.ca.shared.global [%0], [%1], 16;\n" :: "r"(s), "l"(gmem));
}
#define CP_COMMIT asm volatile("cp.async.commit_group;\n" ::: "memory")
#define CP_WAIT0  asm volatile("cp.async.wait_group 0;\n" ::: "memory")

// ---------------- bf16x3 tensor-core GEMM ----------------
__device__ __forceinline__ void mma16(float* d, const uint4& a, const uint2& b){
    asm volatile("mma.sync.aligned.m16n8k16.row.col.f32.bf16.bf16.f32 "
        "{%0,%1,%2,%3},{%4,%5,%6,%7},{%8,%9},{%0,%1,%2,%3};"
        : "+f"(d[0]),"+f"(d[1]),"+f"(d[2]),"+f"(d[3])
        : "r"(a.x),"r"(a.y),"r"(a.z),"r"(a.w),"r"(b.x),"r"(b.y));
}

// EPI: 0=bias->float, 1=bias+gelu->FRAGMENTS, 2=bias+residual->float, 3=raw partial (k-split)
// grid.z = k-split index; nk16 = k16-atoms per split; K16s = full row stride in k16 units.
template<int EPI>
__global__ __launch_bounds__(256, 2) void gemm_tc(const uint4* __restrict__ Ah,
                                               const uint4* __restrict__ Al,
                                               const uint2* __restrict__ Bh,
                                               const uint2* __restrict__ Bl,
                                               const float* __restrict__ bias,
                                               const float* __restrict__ R,
                                               float* __restrict__ C,
                                               uint4* __restrict__ FH,
                                               uint4* __restrict__ FL,
                                               int K16s, int nk16, int N){
    extern __shared__ char smem[];
    const int tid = threadIdx.x, lane = tid & 31, warp = tid >> 5;
    const int wm = warp >> 2, wn = warp & 3;
    const int bm = blockIdx.y, bn = blockIdx.x;
    const int kz = blockIdx.z * nk16;

    float acc[4][4][4];
    #pragma unroll
    for (int a=0;a<4;a++)
        #pragma unroll
        for (int b=0;b<4;b++)
            #pragma unroll
            for (int c=0;c<4;c++) acc[a][b][c]=0.f;

    auto stage_copy = [&](int s, int kb){
        char* base = smem + s*32768;
        #pragma unroll
        for (int i=0;i<2;i++){
            int e = tid + i*256;
            int ma = e>>6, ra = e&63;
            int ka = ra>>5, ln = ra&31;
            size_t ga = ((size_t)(bm*8+ma)*K16s + kz + kb + ka)*32 + ln;
            cpasync16(base + e*16,         Ah + ga);
            cpasync16(base + 8192 + e*16,  Al + ga);
            int na = e>>5, rb = e&31;
            int kb2 = rb>>4, lp = rb&15;
            size_t gb = ((size_t)(bn*16+na)*K16s + kz + kb + kb2)*32 + lp*2;
            cpasync16(base + 16384 + e*16, Bh + gb);
            cpasync16(base + 24576 + e*16, Bl + gb);
        }
    };

    stage_copy(0, 0); CP_COMMIT;
    const int nk = nk16 >> 1;
    int st = 0;
    for (int ks=0; ks<nk; ks++, st^=1){
        CP_WAIT0;
        __syncthreads();
        if (ks+1 < nk){ stage_copy(st^1, (ks+1)*2); CP_COMMIT; }
        const uint4* sAh = (const uint4*)(smem + st*32768);
        const uint4* sAl = (const uint4*)(smem + st*32768 + 8192);
        const uint2* sBh = (const uint2*)(smem + st*32768 + 16384);
        const uint2* sBl = (const uint2*)(smem + st*32768 + 24576);
        #pragma unroll
        for (int ka=0; ka<2; ka++){
            uint4 Afh[4], Afl[4];
            uint2 Bfh[4], Bfl[4];
            #pragma unroll
            for (int mi=0;mi<4;mi++){
                int off = ((wm*4+mi)*2 + ka)*32 + lane;
                Afh[mi] = sAh[off];
                Afl[mi] = sAl[off];
            }
            #pragma unroll
            for (int ni=0;ni<4;ni++){
                int off = ((wn*4+ni)*2 + ka)*32 + lane;
                Bfh[ni] = sBh[off];
                Bfl[ni] = sBl[off];
            }
            #pragma unroll
            for (int mi=0;mi<4;mi++)
                #pragma unroll
                for (int ni=0;ni<4;ni++){
                    mma16(acc[mi][ni], Afh[mi], Bfh[ni]);
                    mma16(acc[mi][ni], Afh[mi], Bfl[ni]);
                    mma16(acc[mi][ni], Afl[mi], Bfh[ni]);
                }
        }
    }

    const int g = lane>>2, l = lane&3;
    if (EPI==1){
        const int K16n = N >> 4;
        #pragma unroll
        for (int mi=0;mi<4;mi++){
            int am = bm*8 + wm*4 + mi;
            #pragma unroll
            for (int np=0;np<2;np++){
                float vv[2][4];
                #pragma unroll
                for (int half=0; half<2; half++){
                    int ni = 2*np + half;
                    int col = bn*128 + wn*32 + ni*8 + 2*l;
                    float b0 = bias[col], b1 = bias[col+1];
                    float v0 = acc[mi][ni][0]+b0, v1 = acc[mi][ni][1]+b1;
                    float v2 = acc[mi][ni][2]+b0, v3 = acc[mi][ni][3]+b1;
                    vv[half][0] = 0.5f*v0*(1.0f + erff(v0*0.70710678118654752f));
                    vv[half][1] = 0.5f*v1*(1.0f + erff(v1*0.70710678118654752f));
                    vv[half][2] = 0.5f*v2*(1.0f + erff(v2*0.70710678118654752f));
                    vv[half][3] = 0.5f*v3*(1.0f + erff(v3*0.70710678118654752f));
                }
                uint4 h, lo;
                pack2(vv[0][0], vv[0][1], h.x, lo.x);
                pack2(vv[0][2], vv[0][3], h.y, lo.y);
                pack2(vv[1][0], vv[1][1], h.z, lo.z);
                pack2(vv[1][2], vv[1][3], h.w, lo.w);
                size_t ga = ((size_t)am*K16n + (bn*8 + wn*2 + np))*32 + lane;
                FH[ga] = h; FL[ga] = lo;
            }
        }
    } else {
        float* Cp = C;
        if (EPI==3) Cp = C + (size_t)blockIdx.z * (size_t)(gridDim.y*128) * N;
        #pragma unroll
        for (int mi=0;mi<4;mi++){
            int row = bm*128 + wm*64 + mi*16 + g;
            #pragma unroll
            for (int ni=0;ni<4;ni++){
                int col = bn*128 + wn*32 + ni*8 + 2*l;
                float b0 = (EPI==3) ? 0.f : bias[col];
                float b1 = (EPI==3) ? 0.f : bias[col+1];
                float v0 = acc[mi][ni][0]+b0, v1 = acc[mi][ni][1]+b1;
                float v2 = acc[mi][ni][2]+b0, v3 = acc[mi][ni][3]+b1;
                if (EPI==2){
                    float2 r0 = *(const float2*)(R + (size_t)row*N + col);
                    float2 r1 = *(const float2*)(R + (size_t)(row+8)*N + col);
                    v0 += r0.x; v1 += r0.y; v2 += r1.x; v3 += r1.y;
                }
                *(float2*)(Cp + (size_t)row*N + col)     = make_float2(v0, v1);
                *(float2*)(Cp + (size_t)(row+8)*N + col) = make_float2(v2, v3);
            }
        }
    }
}

// ---------------- k-split reduce: C = sum_s P[s] + bias + R ----------------
template<int S>
__global__ void reduceK_k(const float* __restrict__ P, const float* __restrict__ bias,
                          const float* __restrict__ R, float* __restrict__ C, int N){
    const size_t stride4 = (size_t)ROWS*DD/4;
    size_t i = (size_t)blockIdx.x*256 + threadIdx.x;
    if (i >= stride4) return;
    float4 a = ((const float4*)P)[i];
    #pragma unroll
    for (int s=1;s<S;s++){
        float4 b = ((const float4*)P)[s*stride4 + i];
        a.x+=b.x; a.y+=b.y; a.z+=b.z; a.w+=b.w;
    }
    int col4 = (int)(i % (N/4));
    float4 bb = ((const float4*)bias)[col4];
    float4 rr = ((const float4*)R)[i];
    a.x += bb.x + rr.x; a.y += bb.y + rr.y;
    a.z += bb.z + rr.z; a.w += bb.w + rr.w;
    ((float4*)C)[i] = a;
}

// ---------------- FAVOR+ feature maps as GEMM ----------------
__global__ __launch_bounds__(256) void featgemm_k(const float* __restrict__ QKV,
                                                  const float* __restrict__ proj,
                                                  float* __restrict__ QP,
                                                  float* __restrict__ KP,
                                                  float* __restrict__ RM){
    const int isK = blockIdx.z;
    const int bh = blockIdx.y;
    const int n0 = blockIdx.x*32;
    const int b = bh/HH, h = bh%HH;
    const float* A = QKV + (size_t)(b*NN + n0)*QKVS + (isK ? DD : 0) + h*64;

    __shared__ float Ps[32][292];
    __shared__ float At[32][33];
    __shared__ float diag_s[32];
    __shared__ float wmx[8];

    int tid = threadIdx.x;
    int tx = tid & 31, ty = tid >> 5;
    float acc[4][9];
    #pragma unroll
    for (int i=0;i<4;i++)
        #pragma unroll
        for (int j=0;j<9;j++) acc[i][j]=0.f;

    #pragma unroll
    for (int ks=0; ks<2; ks++){
        {
            int t = tid>>3, d4 = (tid&7)<<2;
            float4 a4 = *(const float4*)(A + (size_t)t*QKVS + ks*32 + d4);
            At[d4+0][t]=a4.x; At[d4+1][t]=a4.y; At[d4+2][t]=a4.z; At[d4+3][t]=a4.w;
        }
        {
            int d4 = (tid&7)<<2, mb = tid>>3;
            #pragma unroll
            for (int it=0; it<9; it++){
                int m = mb + it*32;
                float4 p4 = (m < MM) ? *(const float4*)(proj + (size_t)m*64 + ks*32 + d4)
                                     : make_float4(0.f,0.f,0.f,0.f);
                Ps[d4+0][m]=p4.x; Ps[d4+1][m]=p4.y; Ps[d4+2][m]=p4.z; Ps[d4+3][m]=p4.w;
            }
        }
        __syncthreads();
        if (tid < 32){
            float s = (ks==0) ? 0.f : diag_s[tid];
            #pragma unroll
            for (int d=0; d<32; d++){ float a = At[d][tid]; s += a*a; }
            diag_s[tid] = s;
        }
        #pragma unroll
        for (int d=0; d<32; d++){
            float a0 = At[d][ty*4+0];
            float a1 = At[d][ty*4+1];
            float a2 = At[d][ty*4+2];
            float a3 = At[d][ty*4+3];
            #pragma unroll
            for (int j=0;j<9;j++){
                float p = Ps[d][tx*9+j];
                acc[0][j] += a0*p;
                acc[1][j] += a1*p;
                acc[2][j] += a2*p;
                acc[3][j] += a3*p;
            }
        }
        __syncthreads();
    }

    float mx[4];
    #pragma unroll
    for (int i=0;i<4;i++){
        float m_ = -3.4e38f;
        #pragma unroll
        for (int j=0;j<9;j++){
            float v = acc[i][j]*DN_SCALE;
            acc[i][j] = v;
            if (tx*9+j < MM) m_ = fmaxf(m_, v);
        }
        #pragma unroll
        for (int o=16;o;o>>=1) m_ = fmaxf(m_, __shfl_xor_sync(0xffffffffu, m_, o));
        mx[i] = m_;
    }

    if (!isK){
        #pragma unroll
        for (int i=0;i<4;i++){
            int t = ty*4+i;
            float dg = diag_s[t]*0.0625f;
            float* out = QP + ((size_t)(bh*NN + n0 + t))*MP2;
            #pragma unroll
            for (int j=0;j<9;j++){
                int m = tx*9+j;
                out[m] = (m < MM) ? RATIO_SC*(__expf(acc[i][j]-dg-mx[i]) + EPS_KER) : 0.f;
            }
        }
    } else {
        float bm_ = -3.4e38f;
        #pragma unroll
        for (int i=0;i<4;i++){
            int t = ty*4+i;
            float dg = diag_s[t]*0.0625f;
            float* out = KP + ((size_t)(bh*NN + n0 + t))*MP2;
            #pragma unroll
            for (int j=0;j<9;j++){
                int m = tx*9+j;
                out[m] = (m < MM) ? __expf(acc[i][j]-dg-mx[i]) : 0.f;
            }
            if (tx==0) RM[bh*NN + n0 + t] = mx[i];
            bm_ = fmaxf(bm_, mx[i]);
        }
        if (tx==0) wmx[ty] = bm_;
        __syncthreads();
        if (tid==0){
            float B = wmx[0];
            #pragma unroll
            for (int w=1;w<8;w++) B = fmaxf(B, wmx[w]);
            atomicMax(&g_kmax_u, enc_f(B));
        }
    }
}

// ---------------- chunked causal linear attention ----------------
__global__ __launch_bounds__(512) void chunksum_k(const float* __restrict__ KP,
                                                  const float* __restrict__ QKV,
                                                  const float* __restrict__ RM,
                                                  float* __restrict__ Z,
                                                  float* __restrict__ KV){
    int bhc = blockIdx.x;
    int bh = bhc / NC, c = bhc % NC;
    int b = bh / HH, h = bh % HH;
    int tid = threadIdx.x, g = tid>>6, e = tid&63;
    const int m0 = g*GM;
    __shared__ __align__(16) float kt[2][TT][MP2];
    __shared__ __align__(16) float vt[2][TT][64];
    __shared__ float scs[CHK];
    float S[GM];
    #pragma unroll
    for (int i=0;i<GM;i++) S[i]=0.f;
    float zacc = 0.f;
    const float* kb = KP + ((size_t)bh*NN + c*CHK)*MP2;
    const float* vb = QKV + (size_t)(b*NN + c*CHK)*QKVS + 2*DD + h*64;

    float gmax = dec_f(g_kmax_u);
    for (int i=tid; i<CHK; i+=512)
        scs[i] = __expf(RM[bh*NN + c*CHK + i] - gmax);

    auto load = [&](int buf, int tile){
        const float* kb_ = kb + (size_t)tile*TT*MP2;
        const float* vb_ = vb + (size_t)tile*TT*QKVS;
        for (int idx=tid; idx<704; idx+=512){
            if (idx < 576){ int tok=idx/72, f=(idx%72)*4; cpasync16(&kt[buf][tok][f], kb_ + (size_t)tok*MP2 + f); }
            else { int r=idx-576; int tok=r/16, f=(r%16)*4; cpasync16(&vt[buf][tok][f], vb_ + (size_t)tok*QKVS + f); }
        }
    };
    load(0,0); CP_COMMIT;
    for (int tile=0; tile<NTILE; tile++){
        int buf = tile&1;
        CP_WAIT0;
        __syncthreads();
        if (tile+1 < NTILE) load(buf^1, tile+1);
        CP_COMMIT;
        {
            const int tb = tile*TT;
            for (int idx=tid; idx<TT*MP2; idx+=512){
                int tok = idx/MP2, m = idx - tok*MP2;
                float f = kt[buf][tok][m];
                kt[buf][tok][m] = (m < MM) ? RATIO_SC*(f*scs[tb+tok] + EPS_KER) : 0.f;
            }
        }
        __syncthreads();
        #pragma unroll
        for (int tt=0; tt<TT; tt++){
            float vv = vt[buf][tt][e];
            const float4* kr = (const float4*)(&kt[buf][tt][m0]);
            #pragma unroll
            for (int i4=0;i4<9;i4++){
                float4 kk = kr[i4];
                S[i4*4+0] += kk.x*vv;
                S[i4*4+1] += kk.y*vv;
                S[i4*4+2] += kk.z*vv;
                S[i4*4+3] += kk.w*vv;
            }
            if (tid < MP2) zacc += kt[buf][tt][tid];
        }
    }
    if (tid < MP2) Z[(size_t)bhc*MP2 + tid] = zacc;
    float* kvout = KV + (size_t)bhc*KVSTRIDE;
    #pragma unroll
    for (int i=0;i<GM;i++) kvout[(size_t)(m0+i)*64 + e] = S[i];
}

__global__ __launch_bounds__(512) void prefix_k(float* __restrict__ Z, float* __restrict__ KV){
    int bh = blockIdx.y;
    int base = bh*NC;
    int idx = blockIdx.x*512 + threadIdx.x;
    float run = 0.f;
    #pragma unroll
    for (int c=0;c<NC;c++){
        float* p = KV + (size_t)(base+c)*KVSTRIDE + idx;
        float t = *p; *p = run; run += t;
    }
    if (blockIdx.x==0 && threadIdx.x < MP2){
        float rz = 0.f;
        #pragma unroll
        for (int c=0;c<NC;c++){
            float* p = Z + (size_t)(base+c)*MP2 + threadIdx.x;
            float t = *p; *p = rz; rz += t;
        }
    }
}

__global__ __launch_bounds__(512) void chunkout_k(const float* __restrict__ QP,
                                                  const float* __restrict__ KP,
                                                  const float* __restrict__ QKV,
                                                  const float* __restrict__ RM,
                                                  const float* __restrict__ Z,
                                                  const float* __restrict__ KV,
                                                  float* __restrict__ O){
    int bhc = blockIdx.x;
    int bh = bhc / NC, c = bhc % NC;
    int b = bh / HH, h = bh % HH;
    int tid = threadIdx.x, g = tid>>6, e = tid&63;
    const int m0 = g*GM;
    __shared__ __align__(16) float kt[2][TT][MP2];
    __shared__ __align__(16) float qt[2][TT][MP2];
    __shared__ __align__(16) float vt[2][TT][64];
    __shared__ float partials[2][8][64];
    __shared__ float dred[2][9];
    __shared__ float scs[CHK];

    float S[GM];
    const float* kvin = KV + (size_t)bhc*KVSTRIDE;
    #pragma unroll
    for (int i=0;i<GM;i++) S[i] = kvin[(size_t)(m0+i)*64 + e];
    float zreg = (tid < MP2) ? Z[(size_t)bhc*MP2 + tid] : 0.f;

    const float* kb = KP + ((size_t)bh*NN + c*CHK)*MP2;
    const float* qb = QP + ((size_t)bh*NN + c*CHK)*MP2;
    const float* vb = QKV + (size_t)(b*NN + c*CHK)*QKVS + 2*DD + h*64;

    float gmax = dec_f(g_kmax_u);
    for (int i=tid; i<CHK; i+=512)
        scs[i] = __expf(RM[bh*NN + c*CHK + i] - gmax);

    auto load = [&](int buf, int tile){
        const float* kb_ = kb + (size_t)tile*TT*MP2;
        const float* qb_ = qb + (size_t)tile*TT*MP2;
        const float* vb_ = vb + (size_t)tile*TT*QKVS;
        for (int idx=tid; idx<1280; idx+=512){
            if (idx < 576){ int tok=idx/72, f=(idx%72)*4; cpasync16(&kt[buf][tok][f], kb_ + (size_t)tok*MP2 + f); }
            else if (idx < 1152){ int r=idx-576; int tok=r/72, f=(r%72)*4; cpasync16(&qt[buf][tok][f], qb_ + (size_t)tok*MP2 + f); }
            else { int r=idx-1152; int tok=r/16, f=(r%16)*4; cpasync16(&vt[buf][tok][f], vb_ + (size_t)tok*QKVS + f); }
        }
    };
    load(0,0); CP_COMMIT;

    for (int tile=0; tile<NTILE; tile++){
        int buf = tile&1;
        CP_WAIT0;
        __syncthreads();
        if (tile+1 < NTILE) load(buf^1, tile+1);
        CP_COMMIT;
        {
            const int tb = tile*TT;
            for (int idx=tid; idx<TT*MP2; idx+=512){
                int tok = idx/MP2, m = idx - tok*MP2;
                float f = kt[buf][tok][m];
                kt[buf][tok][m] = (m < MM) ? RATIO_SC*(f*scs[tb+tok] + EPS_KER) : 0.f;
            }
        }
        __syncthreads();
        #pragma unroll
        for (int tt=0; tt<TT; tt++){
            int pt = tt & 1;
            float vv = vt[buf][tt][e];
            const float4* kr = (const float4*)(&kt[buf][tt][m0]);
            const float4* qr = (const float4*)(&qt[buf][tt][m0]);
            float acc = 0.f;
            #pragma unroll
            for (int i4=0;i4<9;i4++){
                float4 kk = kr[i4];
                float4 qq = qr[i4];
                S[i4*4+0] += kk.x*vv;  acc += qq.x*S[i4*4+0];
                S[i4*4+1] += kk.y*vv;  acc += qq.y*S[i4*4+1];
                S[i4*4+2] += kk.z*vv;  acc += qq.z*S[i4*4+2];
                S[i4*4+3] += kk.w*vv;  acc += qq.w*S[i4*4+3];
            }
            partials[pt][g][e] = acc;
            if (tid < MP2){
                float kv = kt[buf][tt][tid];
                zreg += kv;
                float dp = qt[buf][tt][tid]*(zreg + EPS_DEN);
                #pragma unroll
                for (int o=16;o;o>>=1) dp += __shfl_xor_sync(0xffffffffu, dp, o);
                if ((tid&31)==0) dred[pt][tid>>5] = dp;
            }
            __syncthreads();
            if (tid < 64){
                float s = 0.f;
                #pragma unroll
                for (int gg=0; gg<8; gg++) s += partials[pt][gg][tid];
                float den = 0.f;
                #pragma unroll
                for (int w=0; w<9; w++) den += dred[pt][w];
                int t = c*CHK + tile*TT + tt;
                O[((size_t)(b*NN + t))*DD + h*64 + tid] = s / den;
            }
        }
    }
}

// ---------------- launch ----------------
#define GEMM_SMEM 65536

extern "C" void kernel_launch(void* const* d_in, const int* in_sizes, int n_in,
                              void* d_out, int out_size){
    (void)in_sizes; (void)n_in; (void)out_size;
    const float* x    = (const float*)d_in[0];
    const float* ln1g = (const float*)d_in[1];
    const float* ln1b = (const float*)d_in[2];
    const float* Wq   = (const float*)d_in[3];
    const float* bq   = (const float*)d_in[4];
    const float* Wk   = (const float*)d_in[5];
    const float* bk   = (const float*)d_in[6];
    const float* Wv   = (const float*)d_in[7];
    const float* bv   = (const float*)d_in[8];
    const float* Wo   = (const float*)d_in[9];
    const float* bo   = (const float*)d_in[10];
    const float* proj = (const float*)d_in[11];
    const float* ln2g = (const float*)d_in[12];
    const float* ln2b = (const float*)d_in[13];
    const float* W1   = (const float*)d_in[14];
    const float* b1   = (const float*)d_in[15];
    const float* W2   = (const float*)d_in[16];
    const float* b2   = (const float*)d_in[17];
    float* out = (float*)d_out;

    float *qkv,*qp,*kp,*rm,*o,*x1,*zz,*kv,*bqkv,*part;
    uint4 *afh,*afl,*af2h,*af2l;
    uint2 *wfh,*wfl;
    cudaGetSymbolAddress((void**)&qkv, g_qkv);
    cudaGetSymbolAddress((void**)&qp,  g_qp);
    cudaGetSymbolAddress((void**)&kp,  g_kp);
    cudaGetSymbolAddress((void**)&rm,  g_rm);
    cudaGetSymbolAddress((void**)&o,   g_o);
    cudaGetSymbolAddress((void**)&x1,  g_x1);
    cudaGetSymbolAddress((void**)&zz,  g_Z);
    cudaGetSymbolAddress((void**)&kv,  g_KV);
    cudaGetSymbolAddress((void**)&bqkv,g_bqkv);
    cudaGetSymbolAddress((void**)&part,g_part);
    cudaGetSymbolAddress((void**)&afh, g_afh);
    cudaGetSymbolAddress((void**)&afl, g_afl);
    cudaGetSymbolAddress((void**)&af2h,g_af2h);
    cudaGetSymbolAddress((void**)&af2l,g_af2l);
    cudaGetSymbolAddress((void**)&wfh, g_wfh);
    cudaGetSymbolAddress((void**)&wfl, g_wfl);

    cudaFuncSetAttribute(gemm_tc<0>, cudaFuncAttributeMaxDynamicSharedMemorySize, GEMM_SMEM);
    cudaFuncSetAttribute(gemm_tc<1>, cudaFuncAttributeMaxDynamicSharedMemorySize, GEMM_SMEM);
    cudaFuncSetAttribute(gemm_tc<2>, cudaFuncAttributeMaxDynamicSharedMemorySize, GEMM_SMEM);
    cudaFuncSetAttribute(gemm_tc<3>, cudaFuncAttributeMaxDynamicSharedMemorySize, GEMM_SMEM);

    // launch order arranged so ncu -s 5 -c 1 captures a kernel that matters:
    // 1:init 2:packb 3:lnfrag 4:splitB3 5:gemm_tc<0> 6:featgemm ...
    init_k<<<1,1>>>();
    packb_k<<<3,256>>>(bq, bk, bv, bqkv);
    lnfrag_k<<<ROWS/16,256>>>(x, ln1g, ln1b, afh, afl);
    splitB3_k<<<1728,256>>>(Wq, Wk, Wv, wfh, wfl);
    {
        dim3 gq(QKVS/128, ROWS/128);
        gemm_tc<0><<<gq,256,GEMM_SMEM>>>(afh, afl, wfh, wfl, bqkv, nullptr, qkv,
                                         nullptr, nullptr, DD/16, DD/16, QKVS);
    }

    // ---- feature maps ----
    dim3 gfeat(NN/32, BH, 2);
    featgemm_k<<<gfeat,256>>>(qkv, proj, qp, kp, rm);

    // ---- scan ----
    chunksum_k<<<NCH,512>>>(kp, qkv, rm, zz, kv);
    {
        dim3 gp(KVSTRIDE/512, BH);
        prefix_k<<<gp,512>>>(zz, kv);
    }
    chunkout_k<<<NCH,512>>>(qp, kp, qkv, rm, zz, kv, o);

    // ---- Wo GEMM (k-split x2) + residual ----
    splitA_k<<<1536,256>>>(o, afh, afl, ROWS, DD);
    splitB_k<<<576,256>>>(Wo, wfh, wfl, DD, DD, 0);
    {
        dim3 gg(DD/128, ROWS/128, 2);
        gemm_tc<3><<<gg,256,GEMM_SMEM>>>(afh, afl, wfh, wfl, nullptr, nullptr, part,
                                         nullptr, nullptr, DD/16, DD/32, DD);
        reduceK_k<2><<<(ROWS*DD/4+255)/256,256>>>(part, bo, x, x1, DD);
    }

    // ---- LN2 -> fragments, FFN ----
    lnfrag_k<<<ROWS/16,256>>>(x1, ln2g, ln2b, afh, afl);
    splitB_k<<<2304,256>>>(W1, wfh, wfl, DD, FFD, 0);
    {
        dim3 gg(FFD/128, ROWS/128);
        gemm_tc<1><<<gg,256,GEMM_SMEM>>>(afh, afl, wfh, wfl, b1, nullptr, nullptr,
                                         af2h, af2l, DD/16, DD/16, FFD);
    }
    splitB_k<<<2304,256>>>(W2, wfh, wfl, FFD, DD, 0);
    {
        dim3 gg(DD/128, ROWS/128, 4);
        gemm_tc<3><<<gg,256,GEMM_SMEM>>>(af2h, af2l, wfh, wfl, nullptr, nullptr, part,
                                         nullptr, nullptr, FFD/16, FFD/64, DD);
        reduceK_k<4><<<(ROWS*DD/4+255)/256,256>>>(part, b2, x1, out, DD);
    }
}

// round 11
// speedup vs baseline: 8.9338x; 1.0616x over previous
#include <cuda_runtime.h>
#include <cuda_bf16.h>
#include <math.h>
#include <stdint.h>

// ---------------- problem constants ----------------
#define BB   2
#define NN   2048
#define DD   768
#define HH   12
#define MM   266
#define MP2  288
#define GM   36
#define FFD  3072
#define ROWS (BB*NN)
#define RIDS (BB*HH*NN)
#define BH   (BB*HH)
#define CHK  128
#define NC   (NN/CHK)
#define NCH  (BH*NC)
#define TT   8
#define NTILE (CHK/TT)
#define KVSTRIDE (MP2*64)
#define QKVS 2304

#define DN_SCALE   0.35355339059327f
#define RATIO_SC   0.061313689f
#define EPS_KER    1e-4f
#define EPS_DEN    1e-6f

// ---------------- scratch ----------------
__device__ float g_qkv[(size_t)ROWS*QKVS];
__device__ float g_o [ROWS*DD];
__device__ float g_x1[ROWS*DD];
__device__ float g_qp[(size_t)RIDS*MP2];
__device__ float g_kp[(size_t)RIDS*MP2];
__device__ float g_rm[RIDS];
__device__ float g_Z [(size_t)NCH*MP2];
__device__ float g_KV[(size_t)NCH*KVSTRIDE];
__device__ unsigned g_kmax_u;
__device__ float g_bqkv[QKVS];
__device__ float g_part[(size_t)4*ROWS*DD];   // k-split partials
// fragment-ordered bf16 hi/lo buffers
__device__ uint4 g_afh[(size_t)(ROWS/16)*(DD/16)*32];
__device__ uint4 g_afl[(size_t)(ROWS/16)*(DD/16)*32];
__device__ uint4 g_af2h[(size_t)(ROWS/16)*(FFD/16)*32];
__device__ uint4 g_af2l[(size_t)(ROWS/16)*(FFD/16)*32];
__device__ uint2 g_wfh[(size_t)(FFD/16)*(FFD/8)*32];
__device__ uint2 g_wfl[(size_t)(FFD/16)*(FFD/8)*32];

__device__ __forceinline__ unsigned enc_f(float f){
    unsigned u = __float_as_uint(f);
    return (u & 0x80000000u) ? ~u : (u | 0x80000000u);
}
__device__ __forceinline__ float dec_f(unsigned u){
    return (u & 0x80000000u) ? __uint_as_float(u ^ 0x80000000u) : __uint_as_float(~u);
}

__global__ void init_k(){ g_kmax_u = 0x00800000u; }

__device__ __forceinline__ void pack2(float x, float y, unsigned &h, unsigned &l){
    __nv_bfloat162 hv = __floats2bfloat162_rn(x, y);
    float hx = __low2float(hv), hy = __high2float(hv);
    __nv_bfloat162 lv = __floats2bfloat162_rn(x - hx, y - hy);
    h = *reinterpret_cast<unsigned*>(&hv);
    l = *reinterpret_cast<unsigned*>(&lv);
}

// ---------------- LayerNorm emitting A-fragments (16 rows/CTA) ----------------
__global__ __launch_bounds__(256) void lnfrag_k(const float* __restrict__ X,
                                                const float* __restrict__ G,
                                                const float* __restrict__ Bv,
                                                uint4* __restrict__ H,
                                                uint4* __restrict__ L){
    const int blk = blockIdx.x;
    const int tid = threadIdx.x;
    const int r = tid >> 4, c16 = tid & 15;
    __shared__ float mu_s[16], rs_s[16];
    const float* xr = X + ((size_t)blk*16 + r)*DD;
    float s = 0.f, ss = 0.f;
    #pragma unroll
    for (int j=0;j<12;j++){
        float4 v = *(const float4*)(xr + c16*4 + j*64);
        s  += v.x+v.y+v.z+v.w;
        ss += v.x*v.x+v.y*v.y+v.z*v.z+v.w*v.w;
    }
    #pragma unroll
    for (int o=8;o;o>>=1){
        s  += __shfl_xor_sync(0xffffffffu, s, o, 16);
        ss += __shfl_xor_sync(0xffffffffu, ss, o, 16);
    }
    if (c16==0){
        float mu = s*(1.0f/DD);
        float var = ss*(1.0f/DD) - mu*mu;
        mu_s[r]=mu; rs_s[r]=rsqrtf(var + 1e-5f);
    }
    __syncthreads();
    #pragma unroll
    for (int i=0;i<6;i++){
        int it = tid + i*256;
        int ak = it>>5, lane = it&31;
        int g = lane>>2, l = lane&3;
        float mu0 = mu_s[g],  r0 = rs_s[g];
        float mu1 = mu_s[g+8],r1 = rs_s[g+8];
        int c = ak*16 + 2*l;
        const float* row0 = X + ((size_t)blk*16 + g)*DD;
        const float* row1 = X + ((size_t)blk*16 + g + 8)*DD;
        float2 ga = *(const float2*)(G + c),  gb = *(const float2*)(G + c + 8);
        float2 ba = *(const float2*)(Bv + c), bb = *(const float2*)(Bv + c + 8);
        float2 v0 = *(const float2*)(row0 + c);
        float2 v1 = *(const float2*)(row1 + c);
        float2 v2 = *(const float2*)(row0 + c + 8);
        float2 v3 = *(const float2*)(row1 + c + 8);
        uint4 h, lo;
        pack2((v0.x-mu0)*r0*ga.x+ba.x, (v0.y-mu0)*r0*ga.y+ba.y, h.x, lo.x);
        pack2((v1.x-mu1)*r1*ga.x+ba.x, (v1.y-mu1)*r1*ga.y+ba.y, h.y, lo.y);
        pack2((v2.x-mu0)*r0*gb.x+bb.x, (v2.y-mu0)*r0*gb.y+bb.y, h.z, lo.z);
        pack2((v3.x-mu1)*r1*gb.x+bb.x, (v3.y-mu1)*r1*gb.y+bb.y, h.w, lo.w);
        size_t gidx = ((size_t)blk*48 + ak)*32 + lane;
        H[gidx]=h; L[gidx]=lo;
    }
}

// ---------------- bf16 split kernels ----------------
__global__ void splitA_k(const float* __restrict__ X, uint4* __restrict__ H,
                         uint4* __restrict__ L, int R, int C){
    int idx = blockIdx.x*256 + threadIdx.x;
    int K16 = C>>4;
    int total = (R>>4)*K16*32;
    if (idx >= total) return;
    int lane = idx & 31, atom = idx >> 5;
    int am = atom / K16, ak = atom % K16;
    int g = lane>>2, l = lane&3;
    const float* p = X + (size_t)(am*16+g)*C + ak*16 + 2*l;
    float2 v0 = *(const float2*)(p);
    float2 v1 = *(const float2*)(p + (size_t)8*C);
    float2 v2 = *(const float2*)(p + 8);
    float2 v3 = *(const float2*)(p + (size_t)8*C + 8);
    uint4 h, lo;
    pack2(v0.x, v0.y, h.x, lo.x);
    pack2(v1.x, v1.y, h.y, lo.y);
    pack2(v2.x, v2.y, h.z, lo.z);
    pack2(v3.x, v3.y, h.w, lo.w);
    H[idx] = h; L[idx] = lo;
}

__device__ __forceinline__ void splitB_core(const float* __restrict__ W,
                                            uint2* __restrict__ H, uint2* __restrict__ L,
                                            int idx, int K, int N, int anBase){
    int lane = idx & 31, atom = idx >> 5;
    int K16 = K>>4;
    int an = atom / K16, ak = atom % K16;
    int g = lane>>2, l = lane&3;
    const float* p = W + (size_t)(ak*16 + 2*l)*N + an*8 + g;
    float b00 = p[0],            b01 = p[N];
    float b10 = p[(size_t)8*N],  b11 = p[(size_t)9*N];
    uint2 h, lo;
    pack2(b00, b01, h.x, lo.x);
    pack2(b10, b11, h.y, lo.y);
    int outi = ((anBase + an)*K16 + ak)*32 + lane;
    H[outi] = h; L[outi] = lo;
}

__global__ void splitB_k(const float* __restrict__ W, uint2* __restrict__ H,
                         uint2* __restrict__ L, int K, int N, int anBase){
    int idx = blockIdx.x*256 + threadIdx.x;
    int total = (K>>4)*(N>>3)*32;
    if (idx >= total) return;
    splitB_core(W, H, L, idx, K, N, anBase);
}

// merged QKV weight split (3 x [768x768])
__global__ void splitB3_k(const float* __restrict__ Wq, const float* __restrict__ Wk,
                          const float* __restrict__ Wv, uint2* __restrict__ H,
                          uint2* __restrict__ L){
    const int per = (DD>>4)*(DD>>3)*32;   // 147456
    int idx = blockIdx.x*256 + threadIdx.x;
    if (idx >= 3*per) return;
    int which = idx / per, rem = idx - which*per;
    const float* W = (which==0)?Wq:(which==1)?Wk:Wv;
    splitB_core(W, H, L, rem, DD, DD, which*(DD>>3));
}

__global__ void packb_k(const float* __restrict__ bq, const float* __restrict__ bk,
                        const float* __restrict__ bv, float* __restrict__ o){
    int i = blockIdx.x*256 + threadIdx.x;
    if (i < DD){ o[i]=bq[i]; o[DD+i]=bk[i]; o[2*DD+i]=bv[i]; }
}

// ---------------- cp.async helpers ----------------
__device__ __forceinline__ void cpasync16(void* smem, const void* gmem){
    unsigned s = (unsigned)__cvta_generic_to_shared(smem);
    asm volatile("cp.async.ca.shared.global [%0], [%1], 16;\n" :: "r"(s), "l"(gmem));
}
#define CP_COMMIT asm volatile("cp.async.commit_group;\n" ::: "memory")
#define CP_WAIT0  asm volatile("cp.async.wait_group 0;\n" ::: "memory")
#define CP_WAIT1  asm volatile("cp.async.wait_group 1;\n" ::: "memory")

// ---------------- bf16x3 tensor-core GEMM ----------------
__device__ __forceinline__ void mma16(float* d, const uint4& a, const uint2& b){
    asm volatile("mma.sync.aligned.m16n8k16.row.col.f32.bf16.bf16.f32 "
        "{%0,%1,%2,%3},{%4,%5,%6,%7},{%8,%9},{%0,%1,%2,%3};"
        : "+f"(d[0]),"+f"(d[1]),"+f"(d[2]),"+f"(d[3])
        : "r"(a.x),"r"(a.y),"r"(a.z),"r"(a.w),"r"(b.x),"r"(b.y));
}

// EPI: 0=bias->float, 1=bias+gelu->FRAGMENTS, 2=bias+residual->float, 3=raw partial (k-split)
// 3-stage cp.async pipeline (stage = BK32 = 2 k16-atoms, 32KB each).
template<int EPI>
__global__ __launch_bounds__(256, 2) void gemm_tc(const uint4* __restrict__ Ah,
                                               const uint4* __restrict__ Al,
                                               const uint2* __restrict__ Bh,
                                               const uint2* __restrict__ Bl,
                                               const float* __restrict__ bias,
                                               const float* __restrict__ R,
                                               float* __restrict__ C,
                                               uint4* __restrict__ FH,
                                               uint4* __restrict__ FL,
                                               int K16s, int nk16, int N){
    extern __shared__ char smem[];
    const int tid = threadIdx.x, lane = tid & 31, warp = tid >> 5;
    const int wm = warp >> 2, wn = warp & 3;
    const int bm = blockIdx.y, bn = blockIdx.x;
    const int kz = blockIdx.z * nk16;

    float acc[4][4][4];
    #pragma unroll
    for (int a=0;a<4;a++)
        #pragma unroll
        for (int b=0;b<4;b++)
            #pragma unroll
            for (int c=0;c<4;c++) acc[a][b][c]=0.f;

    auto stage_copy = [&](int s, int kb){
        char* base = smem + s*32768;
        #pragma unroll
        for (int i=0;i<2;i++){
            int e = tid + i*256;
            int ma = e>>6, ra = e&63;
            int ka = ra>>5, ln = ra&31;
            size_t ga = ((size_t)(bm*8+ma)*K16s + kz + kb + ka)*32 + ln;
            cpasync16(base + e*16,         Ah + ga);
            cpasync16(base + 8192 + e*16,  Al + ga);
            int na = e>>5, rb = e&31;
            int kb2 = rb>>4, lp = rb&15;
            size_t gb = ((size_t)(bn*16+na)*K16s + kz + kb + kb2)*32 + lp*2;
            cpasync16(base + 16384 + e*16, Bh + gb);
            cpasync16(base + 24576 + e*16, Bl + gb);
        }
    };

    const int nk = nk16 >> 1;
    stage_copy(0, 0); CP_COMMIT;
    if (nk > 1){ stage_copy(1, 2); CP_COMMIT; }

    for (int ks=0; ks<nk; ks++){
        if (ks+1 < nk) { CP_WAIT1; } else { CP_WAIT0; }
        __syncthreads();
        if (ks+2 < nk){ stage_copy((ks+2)%3, (ks+2)*2); CP_COMMIT; }
        const int st = ks % 3;
        const uint4* sAh = (const uint4*)(smem + st*32768);
        const uint4* sAl = (const uint4*)(smem + st*32768 + 8192);
        const uint2* sBh = (const uint2*)(smem + st*32768 + 16384);
        const uint2* sBl = (const uint2*)(smem + st*32768 + 24576);
        #pragma unroll
        for (int ka=0; ka<2; ka++){
            uint4 Afh[4], Afl[4];
            uint2 Bfh[4], Bfl[4];
            #pragma unroll
            for (int mi=0;mi<4;mi++){
                int off = ((wm*4+mi)*2 + ka)*32 + lane;
                Afh[mi] = sAh[off];
                Afl[mi] = sAl[off];
            }
            #pragma unroll
            for (int ni=0;ni<4;ni++){
                int off = ((wn*4+ni)*2 + ka)*32 + lane;
                Bfh[ni] = sBh[off];
                Bfl[ni] = sBl[off];
            }
            #pragma unroll
            for (int mi=0;mi<4;mi++)
                #pragma unroll
                for (int ni=0;ni<4;ni++){
                    mma16(acc[mi][ni], Afh[mi], Bfh[ni]);
                    mma16(acc[mi][ni], Afh[mi], Bfl[ni]);
                    mma16(acc[mi][ni], Afl[mi], Bfh[ni]);
                }
        }
    }

    const int g = lane>>2, l = lane&3;
    if (EPI==1){
        const int K16n = N >> 4;
        #pragma unroll
        for (int mi=0;mi<4;mi++){
            int am = bm*8 + wm*4 + mi;
            #pragma unroll
            for (int np=0;np<2;np++){
                float vv[2][4];
                #pragma unroll
                for (int half=0; half<2; half++){
                    int ni = 2*np + half;
                    int col = bn*128 + wn*32 + ni*8 + 2*l;
                    float b0 = bias[col], b1 = bias[col+1];
                    float v0 = acc[mi][ni][0]+b0, v1 = acc[mi][ni][1]+b1;
                    float v2 = acc[mi][ni][2]+b0, v3 = acc[mi][ni][3]+b1;
                    vv[half][0] = 0.5f*v0*(1.0f + erff(v0*0.70710678118654752f));
                    vv[half][1] = 0.5f*v1*(1.0f + erff(v1*0.70710678118654752f));
                    vv[half][2] = 0.5f*v2*(1.0f + erff(v2*0.70710678118654752f));
                    vv[half][3] = 0.5f*v3*(1.0f + erff(v3*0.70710678118654752f));
                }
                uint4 h, lo;
                pack2(vv[0][0], vv[0][1], h.x, lo.x);
                pack2(vv[0][2], vv[0][3], h.y, lo.y);
                pack2(vv[1][0], vv[1][1], h.z, lo.z);
                pack2(vv[1][2], vv[1][3], h.w, lo.w);
                size_t ga = ((size_t)am*K16n + (bn*8 + wn*2 + np))*32 + lane;
                FH[ga] = h; FL[ga] = lo;
            }
        }
    } else {
        float* Cp = C;
        if (EPI==3) Cp = C + (size_t)blockIdx.z * (size_t)(gridDim.y*128) * N;
        #pragma unroll
        for (int mi=0;mi<4;mi++){
            int row = bm*128 + wm*64 + mi*16 + g;
            #pragma unroll
            for (int ni=0;ni<4;ni++){
                int col = bn*128 + wn*32 + ni*8 + 2*l;
                float b0 = (EPI==3) ? 0.f : bias[col];
                float b1 = (EPI==3) ? 0.f : bias[col+1];
                float v0 = acc[mi][ni][0]+b0, v1 = acc[mi][ni][1]+b1;
                float v2 = acc[mi][ni][2]+b0, v3 = acc[mi][ni][3]+b1;
                if (EPI==2){
                    float2 r0 = *(const float2*)(R + (size_t)row*N + col);
                    float2 r1 = *(const float2*)(R + (size_t)(row+8)*N + col);
                    v0 += r0.x; v1 += r0.y; v2 += r1.x; v3 += r1.y;
                }
                *(float2*)(Cp + (size_t)row*N + col)     = make_float2(v0, v1);
                *(float2*)(Cp + (size_t)(row+8)*N + col) = make_float2(v2, v3);
            }
        }
    }
}

// ---------------- k-split reduce ----------------
template<int S>
__global__ void reduceK_k(const float* __restrict__ P, const float* __restrict__ bias,
                          const float* __restrict__ R, float* __restrict__ C, int N){
    const size_t stride4 = (size_t)ROWS*DD/4;
    size_t i = (size_t)blockIdx.x*256 + threadIdx.x;
    if (i >= stride4) return;
    float4 a = ((const float4*)P)[i];
    #pragma unroll
    for (int s=1;s<S;s++){
        float4 b = ((const float4*)P)[s*stride4 + i];
        a.x+=b.x; a.y+=b.y; a.z+=b.z; a.w+=b.w;
    }
    int col4 = (int)(i % (N/4));
    float4 bb = ((const float4*)bias)[col4];
    float4 rr = ((const float4*)R)[i];
    a.x += bb.x + rr.x; a.y += bb.y + rr.y;
    a.z += bb.z + rr.z; a.w += bb.w + rr.w;
    ((float4*)C)[i] = a;
}

// ---------------- FAVOR+ feature maps as GEMM ----------------
__global__ __launch_bounds__(256) void featgemm_k(const float* __restrict__ QKV,
                                                  const float* __restrict__ proj,
                                                  float* __restrict__ QP,
                                                  float* __restrict__ KP,
                                                  float* __restrict__ RM){
    const int isK = blockIdx.z;
    const int bh = blockIdx.y;
    const int n0 = blockIdx.x*32;
    const int b = bh/HH, h = bh%HH;
    const float* A = QKV + (size_t)(b*NN + n0)*QKVS + (isK ? DD : 0) + h*64;

    __shared__ float Ps[32][292];
    __shared__ float At[32][33];
    __shared__ float diag_s[32];
    __shared__ float wmx[8];

    int tid = threadIdx.x;
    int tx = tid & 31, ty = tid >> 5;
    float acc[4][9];
    #pragma unroll
    for (int i=0;i<4;i++)
        #pragma unroll
        for (int j=0;j<9;j++) acc[i][j]=0.f;

    #pragma unroll
    for (int ks=0; ks<2; ks++){
        {
            int t = tid>>3, d4 = (tid&7)<<2;
            float4 a4 = *(const float4*)(A + (size_t)t*QKVS + ks*32 + d4);
            At[d4+0][t]=a4.x; At[d4+1][t]=a4.y; At[d4+2][t]=a4.z; At[d4+3][t]=a4.w;
        }
        {
            int d4 = (tid&7)<<2, mb = tid>>3;
            #pragma unroll
            for (int it=0; it<9; it++){
                int m = mb + it*32;
                float4 p4 = (m < MM) ? *(const float4*)(proj + (size_t)m*64 + ks*32 + d4)
                                     : make_float4(0.f,0.f,0.f,0.f);
                Ps[d4+0][m]=p4.x; Ps[d4+1][m]=p4.y; Ps[d4+2][m]=p4.z; Ps[d4+3][m]=p4.w;
            }
        }
        __syncthreads();
        if (tid < 32){
            float s = (ks==0) ? 0.f : diag_s[tid];
            #pragma unroll
            for (int d=0; d<32; d++){ float a = At[d][tid]; s += a*a; }
            diag_s[tid] = s;
        }
        #pragma unroll
        for (int d=0; d<32; d++){
            float a0 = At[d][ty*4+0];
            float a1 = At[d][ty*4+1];
            float a2 = At[d][ty*4+2];
            float a3 = At[d][ty*4+3];
            #pragma unroll
            for (int j=0;j<9;j++){
                float p = Ps[d][tx*9+j];
                acc[0][j] += a0*p;
                acc[1][j] += a1*p;
                acc[2][j] += a2*p;
                acc[3][j] += a3*p;
            }
        }
        __syncthreads();
    }

    float mx[4];
    #pragma unroll
    for (int i=0;i<4;i++){
        float m_ = -3.4e38f;
        #pragma unroll
        for (int j=0;j<9;j++){
            float v = acc[i][j]*DN_SCALE;
            acc[i][j] = v;
            if (tx*9+j < MM) m_ = fmaxf(m_, v);
        }
        #pragma unroll
        for (int o=16;o;o>>=1) m_ = fmaxf(m_, __shfl_xor_sync(0xffffffffu, m_, o));
        mx[i] = m_;
    }

    if (!isK){
        #pragma unroll
        for (int i=0;i<4;i++){
            int t = ty*4+i;
            float dg = diag_s[t]*0.0625f;
            float* out = QP + ((size_t)(bh*NN + n0 + t))*MP2;
            #pragma unroll
            for (int j=0;j<9;j++){
                int m = tx*9+j;
                out[m] = (m < MM) ? RATIO_SC*(__expf(acc[i][j]-dg-mx[i]) + EPS_KER) : 0.f;
            }
        }
    } else {
        float bm_ = -3.4e38f;
        #pragma unroll
        for (int i=0;i<4;i++){
            int t = ty*4+i;
            float dg = diag_s[t]*0.0625f;
            float* out = KP + ((size_t)(bh*NN + n0 + t))*MP2;
            #pragma unroll
            for (int j=0;j<9;j++){
                int m = tx*9+j;
                out[m] = (m < MM) ? __expf(acc[i][j]-dg-mx[i]) : 0.f;
            }
            if (tx==0) RM[bh*NN + n0 + t] = mx[i];
            bm_ = fmaxf(bm_, mx[i]);
        }
        if (tx==0) wmx[ty] = bm_;
        __syncthreads();
        if (tid==0){
            float B = wmx[0];
            #pragma unroll
            for (int w=1;w<8;w++) B = fmaxf(B, wmx[w]);
            atomicMax(&g_kmax_u, enc_f(B));
        }
    }
}

// ---------------- chunked causal linear attention ----------------
__global__ __launch_bounds__(512) void chunksum_k(const float* __restrict__ KP,
                                                  const float* __restrict__ QKV,
                                                  const float* __restrict__ RM,
                                                  float* __restrict__ Z,
                                                  float* __restrict__ KV){
    int bhc = blockIdx.x;
    int bh = bhc / NC, c = bhc % NC;
    int b = bh / HH, h = bh % HH;
    int tid = threadIdx.x, g = tid>>6, e = tid&63;
    const int m0 = g*GM;
    __shared__ __align__(16) float kt[2][TT][MP2];
    __shared__ __align__(16) float vt[2][TT][64];
    __shared__ float scs[CHK];
    float S[GM];
    #pragma unroll
    for (int i=0;i<GM;i++) S[i]=0.f;
    float zacc = 0.f;
    const float* kb = KP + ((size_t)bh*NN + c*CHK)*MP2;
    const float* vb = QKV + (size_t)(b*NN + c*CHK)*QKVS + 2*DD + h*64;

    float gmax = dec_f(g_kmax_u);
    for (int i=tid; i<CHK; i+=512)
        scs[i] = __expf(RM[bh*NN + c*CHK + i] - gmax);

    auto load = [&](int buf, int tile){
        const float* kb_ = kb + (size_t)tile*TT*MP2;
        const float* vb_ = vb + (size_t)tile*TT*QKVS;
        for (int idx=tid; idx<704; idx+=512){
            if (idx < 576){ int tok=idx/72, f=(idx%72)*4; cpasync16(&kt[buf][tok][f], kb_ + (size_t)tok*MP2 + f); }
            else { int r=idx-576; int tok=r/16, f=(r%16)*4; cpasync16(&vt[buf][tok][f], vb_ + (size_t)tok*QKVS + f); }
        }
    };
    load(0,0); CP_COMMIT;
    for (int tile=0; tile<NTILE; tile++){
        int buf = tile&1;
        CP_WAIT0;
        __syncthreads();
        if (tile+1 < NTILE) load(buf^1, tile+1);
        CP_COMMIT;
        {
            const int tb = tile*TT;
            for (int idx=tid; idx<TT*MP2; idx+=512){
                int tok = idx/MP2, m = idx - tok*MP2;
                float f = kt[buf][tok][m];
                kt[buf][tok][m] = (m < MM) ? RATIO_SC*(f*scs[tb+tok] + EPS_KER) : 0.f;
            }
        }
        __syncthreads();
        #pragma unroll
        for (int tt=0; tt<TT; tt++){
            float vv = vt[buf][tt][e];
            const float4* kr = (const float4*)(&kt[buf][tt][m0]);
            #pragma unroll
            for (int i4=0;i4<9;i4++){
                float4 kk = kr[i4];
                S[i4*4+0] += kk.x*vv;
                S[i4*4+1] += kk.y*vv;
                S[i4*4+2] += kk.z*vv;
                S[i4*4+3] += kk.w*vv;
            }
            if (tid < MP2) zacc += kt[buf][tt][tid];
        }
    }
    if (tid < MP2) Z[(size_t)bhc*MP2 + tid] = zacc;
    float* kvout = KV + (size_t)bhc*KVSTRIDE;
    #pragma unroll
    for (int i=0;i<GM;i++) kvout[(size_t)(m0+i)*64 + e] = S[i];
}

__global__ __launch_bounds__(512) void prefix_k(float* __restrict__ Z, float* __restrict__ KV){
    int bh = blockIdx.y;
    int base = bh*NC;
    int idx = blockIdx.x*512 + threadIdx.x;
    float run = 0.f;
    #pragma unroll
    for (int c=0;c<NC;c++){
        float* p = KV + (size_t)(base+c)*KVSTRIDE + idx;
        float t = *p; *p = run; run += t;
    }
    if (blockIdx.x==0 && threadIdx.x < MP2){
        float rz = 0.f;
        #pragma unroll
        for (int c=0;c<NC;c++){
            float* p = Z + (size_t)(base+c)*MP2 + threadIdx.x;
            float t = *p; *p = rz; rz += t;
        }
    }
}

// chunkout with dynamic smem + batched per-tile reductions (3 syncs/tile)
#define CO_KT(b,t,m)  dsm[((b)*TT+(t))*MP2+(m)]
#define CO_QT(b,t,m)  dsm[QOFF + ((b)*TT+(t))*MP2+(m)]
#define CO_VT(b,t,e)  dsm[VOFF + ((b)*TT+(t))*64+(e)]
#define CO_PART(t,g,e) dsm[POFF + ((t)*8+(g))*64+(e)]
#define CO_DRED(t,w)  dsm[DOFF + (t)*16+(w)]
#define CO_SCS(i)     dsm[SOFF + (i)]
#define QOFF (2*TT*MP2)
#define VOFF (4*TT*MP2)
#define POFF (4*TT*MP2 + 2*TT*64)
#define DOFF (POFF + TT*8*64)
#define SOFF (DOFF + TT*16)
#define CO_SMEM ((SOFF + CHK)*4)

__global__ __launch_bounds__(512) void chunkout_k(const float* __restrict__ QP,
                                                  const float* __restrict__ KP,
                                                  const float* __restrict__ QKV,
                                                  const float* __restrict__ RM,
                                                  const float* __restrict__ Z,
                                                  const float* __restrict__ KV,
                                                  float* __restrict__ O){
    extern __shared__ __align__(16) float dsm[];
    int bhc = blockIdx.x;
    int bh = bhc / NC, c = bhc % NC;
    int b = bh / HH, h = bh % HH;
    int tid = threadIdx.x, g = tid>>6, e = tid&63;
    const int m0 = g*GM;

    float S[GM];
    const float* kvin = KV + (size_t)bhc*KVSTRIDE;
    #pragma unroll
    for (int i=0;i<GM;i++) S[i] = kvin[(size_t)(m0+i)*64 + e];
    float zreg = (tid < MP2) ? Z[(size_t)bhc*MP2 + tid] : 0.f;

    const float* kb = KP + ((size_t)bh*NN + c*CHK)*MP2;
    const float* qb = QP + ((size_t)bh*NN + c*CHK)*MP2;
    const float* vb = QKV + (size_t)(b*NN + c*CHK)*QKVS + 2*DD + h*64;

    float gmax = dec_f(g_kmax_u);
    for (int i=tid; i<CHK; i+=512)
        CO_SCS(i) = __expf(RM[bh*NN + c*CHK + i] - gmax);

    auto load = [&](int buf, int tile){
        const float* kb_ = kb + (size_t)tile*TT*MP2;
        const float* qb_ = qb + (size_t)tile*TT*MP2;
        const float* vb_ = vb + (size_t)tile*TT*QKVS;
        for (int idx=tid; idx<1280; idx+=512){
            if (idx < 576){ int tok=idx/72, f=(idx%72)*4; cpasync16(&CO_KT(buf,tok,f), kb_ + (size_t)tok*MP2 + f); }
            else if (idx < 1152){ int r=idx-576; int tok=r/72, f=(r%72)*4; cpasync16(&CO_QT(buf,tok,f), qb_ + (size_t)tok*MP2 + f); }
            else { int r=idx-1152; int tok=r/16, f=(r%16)*4; cpasync16(&CO_VT(buf,tok,f), vb_ + (size_t)tok*QKVS + f); }
        }
    };
    load(0,0); CP_COMMIT;

    for (int tile=0; tile<NTILE; tile++){
        int buf = tile&1;
        CP_WAIT0;
        __syncthreads();
        if (tile+1 < NTILE) load(buf^1, tile+1);
        CP_COMMIT;
        // k rescale in place
        {
            const int tb = tile*TT;
            for (int idx=tid; idx<TT*MP2; idx+=512){
                int tok = idx/MP2, m = idx - tok*MP2;
                float f = CO_KT(buf,tok,m);
                CO_KT(buf,tok,m) = (m < MM) ? RATIO_SC*(f*CO_SCS(tb+tok) + EPS_KER) : 0.f;
            }
        }
        __syncthreads();
        // 8 tokens: numerator partials (per-group) — no intra-token syncs
        #pragma unroll
        for (int tt=0; tt<TT; tt++){
            float vv = CO_VT(buf,tt,e);
            const float4* kr = (const float4*)(&CO_KT(buf,tt,m0));
            const float4* qr = (const float4*)(&CO_QT(buf,tt,m0));
            float acc = 0.f;
            #pragma unroll
            for (int i4=0;i4<9;i4++){
                float4 kk = kr[i4];
                float4 qq = qr[i4];
                S[i4*4+0] += kk.x*vv;  acc += qq.x*S[i4*4+0];
                S[i4*4+1] += kk.y*vv;  acc += qq.y*S[i4*4+1];
                S[i4*4+2] += kk.z*vv;  acc += qq.z*S[i4*4+2];
                S[i4*4+3] += kk.w*vv;  acc += qq.w*S[i4*4+3];
            }
            CO_PART(tt,g,e) = acc;
        }
        // denominators: thread owns feature m=tid across all 8 tokens (sequential z)
        if (tid < MP2){
            float dp[TT];
            #pragma unroll
            for (int tt=0; tt<TT; tt++){
                float kv = CO_KT(buf,tt,tid);
                zreg += kv;
                dp[tt] = CO_QT(buf,tt,tid)*(zreg + EPS_DEN);
            }
            #pragma unroll
            for (int tt=0; tt<TT; tt++){
                float d = dp[tt];
                #pragma unroll
                for (int o=16;o;o>>=1) d += __shfl_xor_sync(0xffffffffu, d, o);
                if ((tid&31)==0) CO_DRED(tt, tid>>5) = d;
            }
        }
        __syncthreads();
        // combined output: 512 threads = 8 tokens x 64 dims
        {
            int tok = tid>>6, e2 = tid&63;
            float s = 0.f;
            #pragma unroll
            for (int gg=0; gg<8; gg++) s += CO_PART(tok,gg,e2);
            float den = 0.f;
            #pragma unroll
            for (int w=0; w<9; w++) den += CO_DRED(tok,w);
            int t = c*CHK + tile*TT + tok;
            O[((size_t)(b*NN + t))*DD + h*64 + e2] = s / den;
        }
    }
}

// ---------------- launch ----------------
#define GEMM_SMEM 98304

extern "C" void kernel_launch(void* const* d_in, const int* in_sizes, int n_in,
                              void* d_out, int out_size){
    (void)in_sizes; (void)n_in; (void)out_size;
    const float* x    = (const float*)d_in[0];
    const float* ln1g = (const float*)d_in[1];
    const float* ln1b = (const float*)d_in[2];
    const float* Wq   = (const float*)d_in[3];
    const float* bq   = (const float*)d_in[4];
    const float* Wk   = (const float*)d_in[5];
    const float* bk   = (const float*)d_in[6];
    const float* Wv   = (const float*)d_in[7];
    const float* bv   = (const float*)d_in[8];
    const float* Wo   = (const float*)d_in[9];
    const float* bo   = (const float*)d_in[10];
    const float* proj = (const float*)d_in[11];
    const float* ln2g = (const float*)d_in[12];
    const float* ln2b = (const float*)d_in[13];
    const float* W1   = (const float*)d_in[14];
    const float* b1   = (const float*)d_in[15];
    const float* W2   = (const float*)d_in[16];
    const float* b2   = (const float*)d_in[17];
    float* out = (float*)d_out;

    float *qkv,*qp,*kp,*rm,*o,*x1,*zz,*kv,*bqkv,*part;
    uint4 *afh,*afl,*af2h,*af2l;
    uint2 *wfh,*wfl;
    cudaGetSymbolAddress((void**)&qkv, g_qkv);
    cudaGetSymbolAddress((void**)&qp,  g_qp);
    cudaGetSymbolAddress((void**)&kp,  g_kp);
    cudaGetSymbolAddress((void**)&rm,  g_rm);
    cudaGetSymbolAddress((void**)&o,   g_o);
    cudaGetSymbolAddress((void**)&x1,  g_x1);
    cudaGetSymbolAddress((void**)&zz,  g_Z);
    cudaGetSymbolAddress((void**)&kv,  g_KV);
    cudaGetSymbolAddress((void**)&bqkv,g_bqkv);
    cudaGetSymbolAddress((void**)&part,g_part);
    cudaGetSymbolAddress((void**)&afh, g_afh);
    cudaGetSymbolAddress((void**)&afl, g_afl);
    cudaGetSymbolAddress((void**)&af2h,g_af2h);
    cudaGetSymbolAddress((void**)&af2l,g_af2l);
    cudaGetSymbolAddress((void**)&wfh, g_wfh);
    cudaGetSymbolAddress((void**)&wfl, g_wfl);

    cudaFuncSetAttribute(gemm_tc<0>, cudaFuncAttributeMaxDynamicSharedMemorySize, GEMM_SMEM);
    cudaFuncSetAttribute(gemm_tc<1>, cudaFuncAttributeMaxDynamicSharedMemorySize, GEMM_SMEM);
    cudaFuncSetAttribute(gemm_tc<2>, cudaFuncAttributeMaxDynamicSharedMemorySize, GEMM_SMEM);
    cudaFuncSetAttribute(gemm_tc<3>, cudaFuncAttributeMaxDynamicSharedMemorySize, GEMM_SMEM);
    cudaFuncSetAttribute(chunkout_k, cudaFuncAttributeMaxDynamicSharedMemorySize, CO_SMEM);

    init_k<<<1,1>>>();
    packb_k<<<3,256>>>(bq, bk, bv, bqkv);
    lnfrag_k<<<ROWS/16,256>>>(x, ln1g, ln1b, afh, afl);
    splitB3_k<<<1728,256>>>(Wq, Wk, Wv, wfh, wfl);
    {
        dim3 gq(QKVS/128, ROWS/128);
        gemm_tc<0><<<gq,256,GEMM_SMEM>>>(afh, afl, wfh, wfl, bqkv, nullptr, qkv,
                                         nullptr, nullptr, DD/16, DD/16, QKVS);
    }

    // ---- feature maps ----
    dim3 gfeat(NN/32, BH, 2);
    featgemm_k<<<gfeat,256>>>(qkv, proj, qp, kp, rm);

    // ---- scan ----
    chunksum_k<<<NCH,512>>>(kp, qkv, rm, zz, kv);
    {
        dim3 gp(KVSTRIDE/512, BH);
        prefix_k<<<gp,512>>>(zz, kv);
    }
    chunkout_k<<<NCH,512,CO_SMEM>>>(qp, kp, qkv, rm, zz, kv, o);

    // ---- Wo GEMM (k-split x2) + residual ----
    splitA_k<<<1536,256>>>(o, afh, afl, ROWS, DD);
    splitB_k<<<576,256>>>(Wo, wfh, wfl, DD, DD, 0);
    {
        dim3 gg(DD/128, ROWS/128, 2);
        gemm_tc<3><<<gg,256,GEMM_SMEM>>>(afh, afl, wfh, wfl, nullptr, nullptr, part,
                                         nullptr, nullptr, DD/16, DD/32, DD);
        reduceK_k<2><<<(ROWS*DD/4+255)/256,256>>>(part, bo, x, x1, DD);
    }

    // ---- LN2 -> fragments, FFN ----
    lnfrag_k<<<ROWS/16,256>>>(x1, ln2g, ln2b, afh, afl);
    splitB_k<<<2304,256>>>(W1, wfh, wfl, DD, FFD, 0);
    {
        dim3 gg(FFD/128, ROWS/128);
        gemm_tc<1><<<gg,256,GEMM_SMEM>>>(afh, afl, wfh, wfl, b1, nullptr, nullptr,
                                         af2h, af2l, DD/16, DD/16, FFD);
    }
    splitB_k<<<2304,256>>>(W2, wfh, wfl, FFD, DD, 0);
    {
        dim3 gg(DD/128, ROWS/128, 4);
        gemm_tc<3><<<gg,256,GEMM_SMEM>>>(af2h, af2l, wfh, wfl, nullptr, nullptr, part,
                                         nullptr, nullptr, FFD/16, FFD/64, DD);
        reduceK_k<4><<<(ROWS*DD/4+255)/256,256>>>(part, b2, x1, out, DD);
    }
}

// round 12
// speedup vs baseline: 10.3632x; 1.1600x over previous
#include <cuda_runtime.h>
#include <cuda_bf16.h>
#include <cuda_fp16.h>
#include <math.h>
#include <stdint.h>

// ---------------- problem constants ----------------
#define BB   2
#define NN   2048
#define DD   768
#define HH   12
#define MM   266
#define MP2  288
#define GM   36
#define FFD  3072
#define ROWS (BB*NN)
#define RIDS (BB*HH*NN)
#define BH   (BB*HH)
#define CHK  128
#define NC   (NN/CHK)
#define NCH  (BH*NC)
#define TT   8
#define NTILE (CHK/TT)
#define KVSTRIDE (MP2*64)
#define QKVS 2304

#define DN_SCALE   0.35355339059327f
#define RATIO_SC   0.061313689f
#define EPS_KER    1e-4f
#define EPS_DEN    1e-6f

// ---------------- scratch ----------------
__device__ float g_qkv[(size_t)ROWS*QKVS];
__device__ float g_o [ROWS*DD];
__device__ float g_x1[ROWS*DD];
__device__ float g_qp[(size_t)RIDS*MP2];
__device__ float g_kp[(size_t)RIDS*MP2];
__device__ float g_rm[RIDS];
__device__ float g_Z [(size_t)NCH*MP2];
__device__ float g_KV[(size_t)NCH*KVSTRIDE];
__device__ unsigned g_kmax_u;
__device__ float g_bqkv[QKVS];
__device__ float g_part[(size_t)4*ROWS*DD];   // k-split partials
// fragment-ordered fp16 buffers (A: hi only; B: hi+lo)
__device__ uint4 g_afh[(size_t)(ROWS/16)*(DD/16)*32];
__device__ uint4 g_af2h[(size_t)(ROWS/16)*(FFD/16)*32];
__device__ uint2 g_wfh[(size_t)(FFD/16)*(FFD/8)*32];
__device__ uint2 g_wfl[(size_t)(FFD/16)*(FFD/8)*32];

__device__ __forceinline__ unsigned enc_f(float f){
    unsigned u = __float_as_uint(f);
    return (u & 0x80000000u) ? ~u : (u | 0x80000000u);
}
__device__ __forceinline__ float dec_f(unsigned u){
    return (u & 0x80000000u) ? __uint_as_float(u ^ 0x80000000u) : __uint_as_float(~u);
}

__global__ void init_k(){ g_kmax_u = 0x00800000u; }

// fp16 pack helpers
__device__ __forceinline__ unsigned packh(float x, float y){
    __half2 hv = __floats2half2_rn(x, y);
    return *reinterpret_cast<unsigned*>(&hv);
}
__device__ __forceinline__ void pack2h(float x, float y, unsigned &h, unsigned &l){
    __half2 hv = __floats2half2_rn(x, y);
    float hx = __low2float(hv), hy = __high2float(hv);
    __half2 lv = __floats2half2_rn(x - hx, y - hy);
    h = *reinterpret_cast<unsigned*>(&hv);
    l = *reinterpret_cast<unsigned*>(&lv);
}

// ---------------- LayerNorm emitting A-hi fragments (16 rows/CTA) ----------------
__global__ __launch_bounds__(256) void lnfrag_k(const float* __restrict__ X,
                                                const float* __restrict__ G,
                                                const float* __restrict__ Bv,
                                                uint4* __restrict__ H){
    const int blk = blockIdx.x;
    const int tid = threadIdx.x;
    const int r = tid >> 4, c16 = tid & 15;
    __shared__ float mu_s[16], rs_s[16];
    const float* xr = X + ((size_t)blk*16 + r)*DD;
    float s = 0.f, ss = 0.f;
    #pragma unroll
    for (int j=0;j<12;j++){
        float4 v = *(const float4*)(xr + c16*4 + j*64);
        s  += v.x+v.y+v.z+v.w;
        ss += v.x*v.x+v.y*v.y+v.z*v.z+v.w*v.w;
    }
    #pragma unroll
    for (int o=8;o;o>>=1){
        s  += __shfl_xor_sync(0xffffffffu, s, o, 16);
        ss += __shfl_xor_sync(0xffffffffu, ss, o, 16);
    }
    if (c16==0){
        float mu = s*(1.0f/DD);
        float var = ss*(1.0f/DD) - mu*mu;
        mu_s[r]=mu; rs_s[r]=rsqrtf(var + 1e-5f);
    }
    __syncthreads();
    #pragma unroll
    for (int i=0;i<6;i++){
        int it = tid + i*256;
        int ak = it>>5, lane = it&31;
        int g = lane>>2, l = lane&3;
        float mu0 = mu_s[g],  r0 = rs_s[g];
        float mu1 = mu_s[g+8],r1 = rs_s[g+8];
        int c = ak*16 + 2*l;
        const float* row0 = X + ((size_t)blk*16 + g)*DD;
        const float* row1 = X + ((size_t)blk*16 + g + 8)*DD;
        float2 ga = *(const float2*)(G + c),  gb = *(const float2*)(G + c + 8);
        float2 ba = *(const float2*)(Bv + c), bb = *(const float2*)(Bv + c + 8);
        float2 v0 = *(const float2*)(row0 + c);
        float2 v1 = *(const float2*)(row1 + c);
        float2 v2 = *(const float2*)(row0 + c + 8);
        float2 v3 = *(const float2*)(row1 + c + 8);
        uint4 h;
        h.x = packh((v0.x-mu0)*r0*ga.x+ba.x, (v0.y-mu0)*r0*ga.y+ba.y);
        h.y = packh((v1.x-mu1)*r1*ga.x+ba.x, (v1.y-mu1)*r1*ga.y+ba.y);
        h.z = packh((v2.x-mu0)*r0*gb.x+bb.x, (v2.y-mu0)*r0*gb.y+bb.y);
        h.w = packh((v3.x-mu1)*r1*gb.x+bb.x, (v3.y-mu1)*r1*gb.y+bb.y);
        size_t gidx = ((size_t)blk*48 + ak)*32 + lane;
        H[gidx]=h;
    }
}

// ---------------- fp16 split kernels ----------------
__global__ void splitA_k(const float* __restrict__ X, uint4* __restrict__ H,
                         int R, int C){
    int idx = blockIdx.x*256 + threadIdx.x;
    int K16 = C>>4;
    int total = (R>>4)*K16*32;
    if (idx >= total) return;
    int lane = idx & 31, atom = idx >> 5;
    int am = atom / K16, ak = atom % K16;
    int g = lane>>2, l = lane&3;
    const float* p = X + (size_t)(am*16+g)*C + ak*16 + 2*l;
    float2 v0 = *(const float2*)(p);
    float2 v1 = *(const float2*)(p + (size_t)8*C);
    float2 v2 = *(const float2*)(p + 8);
    float2 v3 = *(const float2*)(p + (size_t)8*C + 8);
    uint4 h;
    h.x = packh(v0.x, v0.y);
    h.y = packh(v1.x, v1.y);
    h.z = packh(v2.x, v2.y);
    h.w = packh(v3.x, v3.y);
    H[idx] = h;
}

__device__ __forceinline__ void splitB_core(const float* __restrict__ W,
                                            uint2* __restrict__ H, uint2* __restrict__ L,
                                            int idx, int K, int N, int anBase){
    int lane = idx & 31, atom = idx >> 5;
    int K16 = K>>4;
    int an = atom / K16, ak = atom % K16;
    int g = lane>>2, l = lane&3;
    const float* p = W + (size_t)(ak*16 + 2*l)*N + an*8 + g;
    float b00 = p[0],            b01 = p[N];
    float b10 = p[(size_t)8*N],  b11 = p[(size_t)9*N];
    uint2 h, lo;
    pack2h(b00, b01, h.x, lo.x);
    pack2h(b10, b11, h.y, lo.y);
    int outi = ((anBase + an)*K16 + ak)*32 + lane;
    H[outi] = h; L[outi] = lo;
}

__global__ void splitB_k(const float* __restrict__ W, uint2* __restrict__ H,
                         uint2* __restrict__ L, int K, int N, int anBase){
    int idx = blockIdx.x*256 + threadIdx.x;
    int total = (K>>4)*(N>>3)*32;
    if (idx >= total) return;
    splitB_core(W, H, L, idx, K, N, anBase);
}

__global__ void splitB3_k(const float* __restrict__ Wq, const float* __restrict__ Wk,
                          const float* __restrict__ Wv, uint2* __restrict__ H,
                          uint2* __restrict__ L){
    const int per = (DD>>4)*(DD>>3)*32;
    int idx = blockIdx.x*256 + threadIdx.x;
    if (idx >= 3*per) return;
    int which = idx / per, rem = idx - which*per;
    const float* W = (which==0)?Wq:(which==1)?Wk:Wv;
    splitB_core(W, H, L, rem, DD, DD, which*(DD>>3));
}

__global__ void packb_k(const float* __restrict__ bq, const float* __restrict__ bk,
                        const float* __restrict__ bv, float* __restrict__ o){
    int i = blockIdx.x*256 + threadIdx.x;
    if (i < DD){ o[i]=bq[i]; o[DD+i]=bk[i]; o[2*DD+i]=bv[i]; }
}

// ---------------- cp.async helpers ----------------
__device__ __forceinline__ void cpasync16(void* smem, const void* gmem){
    unsigned s = (unsigned)__cvta_generic_to_shared(smem);
    asm volatile("cp.async.ca.shared.global [%0], [%1], 16;\n" :: "r"(s), "l"(gmem));
}
#define CP_COMMIT asm volatile("cp.async.commit_group;\n" ::: "memory")
#define CP_WAIT0  asm volatile("cp.async.wait_group 0;\n" ::: "memory")
#define CP_WAIT1  asm volatile("cp.async.wait_group 1;\n" ::: "memory")

// ---------------- fp16x2 tensor-core GEMM ----------------
__device__ __forceinline__ void mma16(float* d, const uint4& a, const uint2& b){
    asm volatile("mma.sync.aligned.m16n8k16.row.col.f32.f16.f16.f32 "
        "{%0,%1,%2,%3},{%4,%5,%6,%7},{%8,%9},{%0,%1,%2,%3};"
        : "+f"(d[0]),"+f"(d[1]),"+f"(d[2]),"+f"(d[3])
        : "r"(a.x),"r"(a.y),"r"(a.z),"r"(a.w),"r"(b.x),"r"(b.y));
}

// EPI: 0=bias->float, 1=bias+gelu->FRAGMENTS, 2=bias+residual->float, 3=raw partial (k-split)
// 3-stage cp.async pipeline; stage = BK32 = 2 k16-atoms = 24KB (A-hi, B-hi, B-lo).
#define STG 24576
template<int EPI>
__global__ __launch_bounds__(256, 2) void gemm_tc(const uint4* __restrict__ Ah,
                                               const uint2* __restrict__ Bh,
                                               const uint2* __restrict__ Bl,
                                               const float* __restrict__ bias,
                                               const float* __restrict__ R,
                                               float* __restrict__ C,
                                               uint4* __restrict__ FH,
                                               int K16s, int nk16, int N){
    extern __shared__ char smem[];
    const int tid = threadIdx.x, lane = tid & 31, warp = tid >> 5;
    const int wm = warp >> 2, wn = warp & 3;
    const int bm = blockIdx.y, bn = blockIdx.x;
    const int kz = blockIdx.z * nk16;

    float acc[4][4][4];
    #pragma unroll
    for (int a=0;a<4;a++)
        #pragma unroll
        for (int b=0;b<4;b++)
            #pragma unroll
            for (int c=0;c<4;c++) acc[a][b][c]=0.f;

    auto stage_copy = [&](int s, int kb){
        char* base = smem + s*STG;
        #pragma unroll
        for (int i=0;i<2;i++){
            int e = tid + i*256;
            int ma = e>>6, ra = e&63;
            int ka = ra>>5, ln = ra&31;
            size_t ga = ((size_t)(bm*8+ma)*K16s + kz + kb + ka)*32 + ln;
            cpasync16(base + e*16, Ah + ga);
            int na = e>>5, rb = e&31;
            int kb2 = rb>>4, lp = rb&15;
            size_t gb = ((size_t)(bn*16+na)*K16s + kz + kb + kb2)*32 + lp*2;
            cpasync16(base + 8192 + e*16,  Bh + gb);
            cpasync16(base + 16384 + e*16, Bl + gb);
        }
    };

    const int nk = nk16 >> 1;
    stage_copy(0, 0); CP_COMMIT;
    if (nk > 1){ stage_copy(1, 2); CP_COMMIT; }

    for (int ks=0; ks<nk; ks++){
        if (ks+1 < nk) { CP_WAIT1; } else { CP_WAIT0; }
        __syncthreads();
        if (ks+2 < nk){ stage_copy((ks+2)%3, (ks+2)*2); CP_COMMIT; }
        const int st = ks % 3;
        const uint4* sAh = (const uint4*)(smem + st*STG);
        const uint2* sBh = (const uint2*)(smem + st*STG + 8192);
        const uint2* sBl = (const uint2*)(smem + st*STG + 16384);
        #pragma unroll
        for (int ka=0; ka<2; ka++){
            uint4 Afh[4];
            uint2 Bfh[4], Bfl[4];
            #pragma unroll
            for (int mi=0;mi<4;mi++){
                int off = ((wm*4+mi)*2 + ka)*32 + lane;
                Afh[mi] = sAh[off];
            }
            #pragma unroll
            for (int ni=0;ni<4;ni++){
                int off = ((wn*4+ni)*2 + ka)*32 + lane;
                Bfh[ni] = sBh[off];
                Bfl[ni] = sBl[off];
            }
            #pragma unroll
            for (int mi=0;mi<4;mi++)
                #pragma unroll
                for (int ni=0;ni<4;ni++){
                    mma16(acc[mi][ni], Afh[mi], Bfh[ni]);
                    mma16(acc[mi][ni], Afh[mi], Bfl[ni]);
                }
        }
    }

    const int g = lane>>2, l = lane&3;
    if (EPI==1){
        const int K16n = N >> 4;
        #pragma unroll
        for (int mi=0;mi<4;mi++){
            int am = bm*8 + wm*4 + mi;
            #pragma unroll
            for (int np=0;np<2;np++){
                float vv[2][4];
                #pragma unroll
                for (int half=0; half<2; half++){
                    int ni = 2*np + half;
                    int col = bn*128 + wn*32 + ni*8 + 2*l;
                    float b0 = bias[col], b1 = bias[col+1];
                    float v0 = acc[mi][ni][0]+b0, v1 = acc[mi][ni][1]+b1;
                    float v2 = acc[mi][ni][2]+b0, v3 = acc[mi][ni][3]+b1;
                    vv[half][0] = 0.5f*v0*(1.0f + erff(v0*0.70710678118654752f));
                    vv[half][1] = 0.5f*v1*(1.0f + erff(v1*0.70710678118654752f));
                    vv[half][2] = 0.5f*v2*(1.0f + erff(v2*0.70710678118654752f));
                    vv[half][3] = 0.5f*v3*(1.0f + erff(v3*0.70710678118654752f));
                }
                uint4 h;
                h.x = packh(vv[0][0], vv[0][1]);
                h.y = packh(vv[0][2], vv[0][3]);
                h.z = packh(vv[1][0], vv[1][1]);
                h.w = packh(vv[1][2], vv[1][3]);
                size_t ga = ((size_t)am*K16n + (bn*8 + wn*2 + np))*32 + lane;
                FH[ga] = h;
            }
        }
    } else {
        float* Cp = C;
        if (EPI==3) Cp = C + (size_t)blockIdx.z * (size_t)(gridDim.y*128) * N;
        #pragma unroll
        for (int mi=0;mi<4;mi++){
            int row = bm*128 + wm*64 + mi*16 + g;
            #pragma unroll
            for (int ni=0;ni<4;ni++){
                int col = bn*128 + wn*32 + ni*8 + 2*l;
                float b0 = (EPI==3) ? 0.f : bias[col];
                float b1 = (EPI==3) ? 0.f : bias[col+1];
                float v0 = acc[mi][ni][0]+b0, v1 = acc[mi][ni][1]+b1;
                float v2 = acc[mi][ni][2]+b0, v3 = acc[mi][ni][3]+b1;
                if (EPI==2){
                    float2 r0 = *(const float2*)(R + (size_t)row*N + col);
                    float2 r1 = *(const float2*)(R + (size_t)(row+8)*N + col);
                    v0 += r0.x; v1 += r0.y; v2 += r1.x; v3 += r1.y;
                }
                *(float2*)(Cp + (size_t)row*N + col)     = make_float2(v0, v1);
                *(float2*)(Cp + (size_t)(row+8)*N + col) = make_float2(v2, v3);
            }
        }
    }
}

// ---------------- k-split reduce ----------------
template<int S>
__global__ void reduceK_k(const float* __restrict__ P, const float* __restrict__ bias,
                          const float* __restrict__ R, float* __restrict__ C, int N){
    const size_t stride4 = (size_t)ROWS*DD/4;
    size_t i = (size_t)blockIdx.x*256 + threadIdx.x;
    if (i >= stride4) return;
    float4 a = ((const float4*)P)[i];
    #pragma unroll
    for (int s=1;s<S;s++){
        float4 b = ((const float4*)P)[s*stride4 + i];
        a.x+=b.x; a.y+=b.y; a.z+=b.z; a.w+=b.w;
    }
    int col4 = (int)(i % (N/4));
    float4 bb = ((const float4*)bias)[col4];
    float4 rr = ((const float4*)R)[i];
    a.x += bb.x + rr.x; a.y += bb.y + rr.y;
    a.z += bb.z + rr.z; a.w += bb.w + rr.w;
    ((float4*)C)[i] = a;
}

// ---------------- FAVOR+ feature maps as GEMM ----------------
__global__ __launch_bounds__(256) void featgemm_k(const float* __restrict__ QKV,
                                                  const float* __restrict__ proj,
                                                  float* __restrict__ QP,
                                                  float* __restrict__ KP,
                                                  float* __restrict__ RM){
    const int isK = blockIdx.z;
    const int bh = blockIdx.y;
    const int n0 = blockIdx.x*32;
    const int b = bh/HH, h = bh%HH;
    const float* A = QKV + (size_t)(b*NN + n0)*QKVS + (isK ? DD : 0) + h*64;

    __shared__ float Ps[32][292];
    __shared__ float At[32][33];
    __shared__ float diag_s[32];
    __shared__ float wmx[8];

    int tid = threadIdx.x;
    int tx = tid & 31, ty = tid >> 5;
    float acc[4][9];
    #pragma unroll
    for (int i=0;i<4;i++)
        #pragma unroll
        for (int j=0;j<9;j++) acc[i][j]=0.f;

    #pragma unroll
    for (int ks=0; ks<2; ks++){
        {
            int t = tid>>3, d4 = (tid&7)<<2;
            float4 a4 = *(const float4*)(A + (size_t)t*QKVS + ks*32 + d4);
            At[d4+0][t]=a4.x; At[d4+1][t]=a4.y; At[d4+2][t]=a4.z; At[d4+3][t]=a4.w;
        }
        {
            int d4 = (tid&7)<<2, mb = tid>>3;
            #pragma unroll
            for (int it=0; it<9; it++){
                int m = mb + it*32;
                float4 p4 = (m < MM) ? *(const float4*)(proj + (size_t)m*64 + ks*32 + d4)
                                     : make_float4(0.f,0.f,0.f,0.f);
                Ps[d4+0][m]=p4.x; Ps[d4+1][m]=p4.y; Ps[d4+2][m]=p4.z; Ps[d4+3][m]=p4.w;
            }
        }
        __syncthreads();
        if (tid < 32){
            float s = (ks==0) ? 0.f : diag_s[tid];
            #pragma unroll
            for (int d=0; d<32; d++){ float a = At[d][tid]; s += a*a; }
            diag_s[tid] = s;
        }
        #pragma unroll
        for (int d=0; d<32; d++){
            float a0 = At[d][ty*4+0];
            float a1 = At[d][ty*4+1];
            float a2 = At[d][ty*4+2];
            float a3 = At[d][ty*4+3];
            #pragma unroll
            for (int j=0;j<9;j++){
                float p = Ps[d][tx*9+j];
                acc[0][j] += a0*p;
                acc[1][j] += a1*p;
                acc[2][j] += a2*p;
                acc[3][j] += a3*p;
            }
        }
        __syncthreads();
    }

    float mx[4];
    #pragma unroll
    for (int i=0;i<4;i++){
        float m_ = -3.4e38f;
        #pragma unroll
        for (int j=0;j<9;j++){
            float v = acc[i][j]*DN_SCALE;
            acc[i][j] = v;
            if (tx*9+j < MM) m_ = fmaxf(m_, v);
        }
        #pragma unroll
        for (int o=16;o;o>>=1) m_ = fmaxf(m_, __shfl_xor_sync(0xffffffffu, m_, o));
        mx[i] = m_;
    }

    if (!isK){
        #pragma unroll
        for (int i=0;i<4;i++){
            int t = ty*4+i;
            float dg = diag_s[t]*0.0625f;
            float* out = QP + ((size_t)(bh*NN + n0 + t))*MP2;
            #pragma unroll
            for (int j=0;j<9;j++){
                int m = tx*9+j;
                out[m] = (m < MM) ? RATIO_SC*(__expf(acc[i][j]-dg-mx[i]) + EPS_KER) : 0.f;
            }
        }
    } else {
        float bm_ = -3.4e38f;
        #pragma unroll
        for (int i=0;i<4;i++){
            int t = ty*4+i;
            float dg = diag_s[t]*0.0625f;
            float* out = KP + ((size_t)(bh*NN + n0 + t))*MP2;
            #pragma unroll
            for (int j=0;j<9;j++){
                int m = tx*9+j;
                out[m] = (m < MM) ? __expf(acc[i][j]-dg-mx[i]) : 0.f;
            }
            if (tx==0) RM[bh*NN + n0 + t] = mx[i];
            bm_ = fmaxf(bm_, mx[i]);
        }
        if (tx==0) wmx[ty] = bm_;
        __syncthreads();
        if (tid==0){
            float B = wmx[0];
            #pragma unroll
            for (int w=1;w<8;w++) B = fmaxf(B, wmx[w]);
            atomicMax(&g_kmax_u, enc_f(B));
        }
    }
}

// ---------------- chunked causal linear attention ----------------
__global__ __launch_bounds__(512) void chunksum_k(const float* __restrict__ KP,
                                                  const float* __restrict__ QKV,
                                                  const float* __restrict__ RM,
                                                  float* __restrict__ Z,
                                                  float* __restrict__ KV){
    int bhc = blockIdx.x;
    int bh = bhc / NC, c = bhc % NC;
    int b = bh / HH, h = bh % HH;
    int tid = threadIdx.x, g = tid>>6, e = tid&63;
    const int m0 = g*GM;
    __shared__ __align__(16) float kt[2][TT][MP2];
    __shared__ __align__(16) float vt[2][TT][64];
    __shared__ float scs[CHK];
    float S[GM];
    #pragma unroll
    for (int i=0;i<GM;i++) S[i]=0.f;
    float zacc = 0.f;
    const float* kb = KP + ((size_t)bh*NN + c*CHK)*MP2;
    const float* vb = QKV + (size_t)(b*NN + c*CHK)*QKVS + 2*DD + h*64;

    float gmax = dec_f(g_kmax_u);
    for (int i=tid; i<CHK; i+=512)
        scs[i] = __expf(RM[bh*NN + c*CHK + i] - gmax);

    auto load = [&](int buf, int tile){
        const float* kb_ = kb + (size_t)tile*TT*MP2;
        const float* vb_ = vb + (size_t)tile*TT*QKVS;
        for (int idx=tid; idx<704; idx+=512){
            if (idx < 576){ int tok=idx/72, f=(idx%72)*4; cpasync16(&kt[buf][tok][f], kb_ + (size_t)tok*MP2 + f); }
            else { int r=idx-576; int tok=r/16, f=(r%16)*4; cpasync16(&vt[buf][tok][f], vb_ + (size_t)tok*QKVS + f); }
        }
    };
    load(0,0); CP_COMMIT;
    for (int tile=0; tile<NTILE; tile++){
        int buf = tile&1;
        CP_WAIT0;
        __syncthreads();
        if (tile+1 < NTILE) load(buf^1, tile+1);
        CP_COMMIT;
        {
            const int tb = tile*TT;
            for (int idx=tid; idx<TT*MP2; idx+=512){
                int tok = idx/MP2, m = idx - tok*MP2;
                float f = kt[buf][tok][m];
                kt[buf][tok][m] = (m < MM) ? RATIO_SC*(f*scs[tb+tok] + EPS_KER) : 0.f;
            }
        }
        __syncthreads();
        #pragma unroll
        for (int tt=0; tt<TT; tt++){
            float vv = vt[buf][tt][e];
            const float4* kr = (const float4*)(&kt[buf][tt][m0]);
            #pragma unroll
            for (int i4=0;i4<9;i4++){
                float4 kk = kr[i4];
                S[i4*4+0] += kk.x*vv;
                S[i4*4+1] += kk.y*vv;
                S[i4*4+2] += kk.z*vv;
                S[i4*4+3] += kk.w*vv;
            }
            if (tid < MP2) zacc += kt[buf][tt][tid];
        }
    }
    if (tid < MP2) Z[(size_t)bhc*MP2 + tid] = zacc;
    float* kvout = KV + (size_t)bhc*KVSTRIDE;
    #pragma unroll
    for (int i=0;i<GM;i++) kvout[(size_t)(m0+i)*64 + e] = S[i];
}

__global__ __launch_bounds__(512) void prefix_k(float* __restrict__ Z, float* __restrict__ KV){
    int bh = blockIdx.y;
    int base = bh*NC;
    int idx = blockIdx.x*512 + threadIdx.x;
    float run = 0.f;
    #pragma unroll
    for (int c=0;c<NC;c++){
        float* p = KV + (size_t)(base+c)*KVSTRIDE + idx;
        float t = *p; *p = run; run += t;
    }
    if (blockIdx.x==0 && threadIdx.x < MP2){
        float rz = 0.f;
        #pragma unroll
        for (int c=0;c<NC;c++){
            float* p = Z + (size_t)(base+c)*MP2 + threadIdx.x;
            float t = *p; *p = rz; rz += t;
        }
    }
}

// chunkout with dynamic smem + batched per-tile reductions
#define CO_KT(b,t,m)  dsm[((b)*TT+(t))*MP2+(m)]
#define CO_QT(b,t,m)  dsm[QOFF + ((b)*TT+(t))*MP2+(m)]
#define CO_VT(b,t,e)  dsm[VOFF + ((b)*TT+(t))*64+(e)]
#define CO_PART(t,g,e) dsm[POFF + ((t)*8+(g))*64+(e)]
#define CO_DRED(t,w)  dsm[DOFF + (t)*16+(w)]
#define CO_SCS(i)     dsm[SOFF + (i)]
#define QOFF (2*TT*MP2)
#define VOFF (4*TT*MP2)
#define POFF (4*TT*MP2 + 2*TT*64)
#define DOFF (POFF + TT*8*64)
#define SOFF (DOFF + TT*16)
#define CO_SMEM ((SOFF + CHK)*4)

__global__ __launch_bounds__(512) void chunkout_k(const float* __restrict__ QP,
                                                  const float* __restrict__ KP,
                                                  const float* __restrict__ QKV,
                                                  const float* __restrict__ RM,
                                                  const float* __restrict__ Z,
                                                  const float* __restrict__ KV,
                                                  float* __restrict__ O){
    extern __shared__ __align__(16) float dsm[];
    int bhc = blockIdx.x;
    int bh = bhc / NC, c = bhc % NC;
    int b = bh / HH, h = bh % HH;
    int tid = threadIdx.x, g = tid>>6, e = tid&63;
    const int m0 = g*GM;

    float S[GM];
    const float* kvin = KV + (size_t)bhc*KVSTRIDE;
    #pragma unroll
    for (int i=0;i<GM;i++) S[i] = kvin[(size_t)(m0+i)*64 + e];
    float zreg = (tid < MP2) ? Z[(size_t)bhc*MP2 + tid] : 0.f;

    const float* kb = KP + ((size_t)bh*NN + c*CHK)*MP2;
    const float* qb = QP + ((size_t)bh*NN + c*CHK)*MP2;
    const float* vb = QKV + (size_t)(b*NN + c*CHK)*QKVS + 2*DD + h*64;

    float gmax = dec_f(g_kmax_u);
    for (int i=tid; i<CHK; i+=512)
        CO_SCS(i) = __expf(RM[bh*NN + c*CHK + i] - gmax);

    auto load = [&](int buf, int tile){
        const float* kb_ = kb + (size_t)tile*TT*MP2;
        const float* qb_ = qb + (size_t)tile*TT*MP2;
        const float* vb_ = vb + (size_t)tile*TT*QKVS;
        for (int idx=tid; idx<1280; idx+=512){
            if (idx < 576){ int tok=idx/72, f=(idx%72)*4; cpasync16(&CO_KT(buf,tok,f), kb_ + (size_t)tok*MP2 + f); }
            else if (idx < 1152){ int r=idx-576; int tok=r/72, f=(r%72)*4; cpasync16(&CO_QT(buf,tok,f), qb_ + (size_t)tok*MP2 + f); }
            else { int r=idx-1152; int tok=r/16, f=(r%16)*4; cpasync16(&CO_VT(buf,tok,f), vb_ + (size_t)tok*QKVS + f); }
        }
    };
    load(0,0); CP_COMMIT;

    for (int tile=0; tile<NTILE; tile++){
        int buf = tile&1;
        CP_WAIT0;
        __syncthreads();
        if (tile+1 < NTILE) load(buf^1, tile+1);
        CP_COMMIT;
        {
            const int tb = tile*TT;
            for (int idx=tid; idx<TT*MP2; idx+=512){
                int tok = idx/MP2, m = idx - tok*MP2;
                float f = CO_KT(buf,tok,m);
                CO_KT(buf,tok,m) = (m < MM) ? RATIO_SC*(f*CO_SCS(tb+tok) + EPS_KER) : 0.f;
            }
        }
        __syncthreads();
        #pragma unroll
        for (int tt=0; tt<TT; tt++){
            float vv = CO_VT(buf,tt,e);
            const float4* kr = (const float4*)(&CO_KT(buf,tt,m0));
            const float4* qr = (const float4*)(&CO_QT(buf,tt,m0));
            float acc = 0.f;
            #pragma unroll
            for (int i4=0;i4<9;i4++){
                float4 kk = kr[i4];
                float4 qq = qr[i4];
                S[i4*4+0] += kk.x*vv;  acc += qq.x*S[i4*4+0];
                S[i4*4+1] += kk.y*vv;  acc += qq.y*S[i4*4+1];
                S[i4*4+2] += kk.z*vv;  acc += qq.z*S[i4*4+2];
                S[i4*4+3] += kk.w*vv;  acc += qq.w*S[i4*4+3];
            }
            CO_PART(tt,g,e) = acc;
        }
        if (tid < MP2){
            float dp[TT];
            #pragma unroll
            for (int tt=0; tt<TT; tt++){
                float kv = CO_KT(buf,tt,tid);
                zreg += kv;
                dp[tt] = CO_QT(buf,tt,tid)*(zreg + EPS_DEN);
            }
            #pragma unroll
            for (int tt=0; tt<TT; tt++){
                float d = dp[tt];
                #pragma unroll
                for (int o=16;o;o>>=1) d += __shfl_xor_sync(0xffffffffu, d, o);
                if ((tid&31)==0) CO_DRED(tt, tid>>5) = d;
            }
        }
        __syncthreads();
        {
            int tok = tid>>6, e2 = tid&63;
            float s = 0.f;
            #pragma unroll
            for (int gg=0; gg<8; gg++) s += CO_PART(tok,gg,e2);
            float den = 0.f;
            #pragma unroll
            for (int w=0; w<9; w++) den += CO_DRED(tok,w);
            int t = c*CHK + tile*TT + tok;
            O[((size_t)(b*NN + t))*DD + h*64 + e2] = s / den;
        }
    }
}

// ---------------- launch ----------------
#define GEMM_SMEM (3*STG)

extern "C" void kernel_launch(void* const* d_in, const int* in_sizes, int n_in,
                              void* d_out, int out_size){
    (void)in_sizes; (void)n_in; (void)out_size;
    const float* x    = (const float*)d_in[0];
    const float* ln1g = (const float*)d_in[1];
    const float* ln1b = (const float*)d_in[2];
    const float* Wq   = (const float*)d_in[3];
    const float* bq   = (const float*)d_in[4];
    const float* Wk   = (const float*)d_in[5];
    const float* bk   = (const float*)d_in[6];
    const float* Wv   = (const float*)d_in[7];
    const float* bv   = (const float*)d_in[8];
    const float* Wo   = (const float*)d_in[9];
    const float* bo   = (const float*)d_in[10];
    const float* proj = (const float*)d_in[11];
    const float* ln2g = (const float*)d_in[12];
    const float* ln2b = (const float*)d_in[13];
    const float* W1   = (const float*)d_in[14];
    const float* b1   = (const float*)d_in[15];
    const float* W2   = (const float*)d_in[16];
    const float* b2   = (const float*)d_in[17];
    float* out = (float*)d_out;

    float *qkv,*qp,*kp,*rm,*o,*x1,*zz,*kv,*bqkv,*part;
    uint4 *afh,*af2h;
    uint2 *wfh,*wfl;
    cudaGetSymbolAddress((void**)&qkv, g_qkv);
    cudaGetSymbolAddress((void**)&qp,  g_qp);
    cudaGetSymbolAddress((void**)&kp,  g_kp);
    cudaGetSymbolAddress((void**)&rm,  g_rm);
    cudaGetSymbolAddress((void**)&o,   g_o);
    cudaGetSymbolAddress((void**)&x1,  g_x1);
    cudaGetSymbolAddress((void**)&zz,  g_Z);
    cudaGetSymbolAddress((void**)&kv,  g_KV);
    cudaGetSymbolAddress((void**)&bqkv,g_bqkv);
    cudaGetSymbolAddress((void**)&part,g_part);
    cudaGetSymbolAddress((void**)&afh, g_afh);
    cudaGetSymbolAddress((void**)&af2h,g_af2h);
    cudaGetSymbolAddress((void**)&wfh, g_wfh);
    cudaGetSymbolAddress((void**)&wfl, g_wfl);

    cudaFuncSetAttribute(gemm_tc<0>, cudaFuncAttributeMaxDynamicSharedMemorySize, GEMM_SMEM);
    cudaFuncSetAttribute(gemm_tc<1>, cudaFuncAttributeMaxDynamicSharedMemorySize, GEMM_SMEM);
    cudaFuncSetAttribute(gemm_tc<2>, cudaFuncAttributeMaxDynamicSharedMemorySize, GEMM_SMEM);
    cudaFuncSetAttribute(gemm_tc<3>, cudaFuncAttributeMaxDynamicSharedMemorySize, GEMM_SMEM);
    cudaFuncSetAttribute(chunkout_k, cudaFuncAttributeMaxDynamicSharedMemorySize, CO_SMEM);

    init_k<<<1,1>>>();
    packb_k<<<3,256>>>(bq, bk, bv, bqkv);
    lnfrag_k<<<ROWS/16,256>>>(x, ln1g, ln1b, afh);
    splitB3_k<<<1728,256>>>(Wq, Wk, Wv, wfh, wfl);
    {
        dim3 gq(QKVS/128, ROWS/128);
        gemm_tc<0><<<gq,256,GEMM_SMEM>>>(afh, wfh, wfl, bqkv, nullptr, qkv,
                                         nullptr, DD/16, DD/16, QKVS);
    }

    // ---- feature maps ----
    dim3 gfeat(NN/32, BH, 2);
    featgemm_k<<<gfeat,256>>>(qkv, proj, qp, kp, rm);

    // ---- scan ----
    chunksum_k<<<NCH,512>>>(kp, qkv, rm, zz, kv);
    {
        dim3 gp(KVSTRIDE/512, BH);
        prefix_k<<<gp,512>>>(zz, kv);
    }
    chunkout_k<<<NCH,512,CO_SMEM>>>(qp, kp, qkv, rm, zz, kv, o);

    // ---- Wo GEMM (k-split x2) + residual ----
    splitA_k<<<1536,256>>>(o, afh, ROWS, DD);
    splitB_k<<<576,256>>>(Wo, wfh, wfl, DD, DD, 0);
    {
        dim3 gg(DD/128, ROWS/128, 2);
        gemm_tc<3><<<gg,256,GEMM_SMEM>>>(afh, wfh, wfl, nullptr, nullptr, part,
                                         nullptr, DD/16, DD/32, DD);
        reduceK_k<2><<<(ROWS*DD/4+255)/256,256>>>(part, bo, x, x1, DD);
    }

    // ---- LN2 -> fragments, FFN ----
    lnfrag_k<<<ROWS/16,256>>>(x1, ln2g, ln2b, afh);
    splitB_k<<<2304,256>>>(W1, wfh, wfl, DD, FFD, 0);
    {
        dim3 gg(FFD/128, ROWS/128);
        gemm_tc<1><<<gg,256,GEMM_SMEM>>>(afh, wfh, wfl, b1, nullptr, nullptr,
                                         af2h, DD/16, DD/16, FFD);
    }
    splitB_k<<<2304,256>>>(W2, wfh, wfl, FFD, DD, 0);
    {
        dim3 gg(DD/128, ROWS/128, 4);
        gemm_tc<3><<<gg,256,GEMM_SMEM>>>(af2h, wfh, wfl, nullptr, nullptr, part,
                                         nullptr, FFD/16, FFD/64, DD);
        reduceK_k<4><<<(ROWS*DD/4+255)/256,256>>>(part, b2, x1, out, DD);
    }
}

// round 14
// speedup vs baseline: 10.4085x; 1.0044x over previous
#include <cuda_runtime.h>
#include <cuda_bf16.h>
#include <cuda_fp16.h>
#include <math.h>
#include <stdint.h>

// ---------------- problem constants ----------------
#define BB   2
#define NN   2048
#define DD   768
#define HH   12
#define MM   266
#define MP2  288
#define GM   36
#define FFD  3072
#define ROWS (BB*NN)
#define RIDS (BB*HH*NN)
#define BH   (BB*HH)
#define CHK  128
#define NC   (NN/CHK)
#define NCH  (BH*NC)
#define TT   8
#define NTILE (CHK/TT)
#define KVSTRIDE (MP2*64)
#define QKVS 2304

#define DN_SCALE   0.35355339059327f
#define RATIO_SC   0.061313689f
#define EPS_KER    1e-4f
#define EPS_DEN    1e-6f

// ---------------- scratch ----------------
__device__ float g_qkv[(size_t)ROWS*QKVS];
__device__ float g_o [ROWS*DD];
__device__ float g_x1[ROWS*DD];
__device__ float g_qp[(size_t)RIDS*MP2];
__device__ float g_kp[(size_t)RIDS*MP2];
__device__ float g_rm[RIDS];
__device__ float g_Z [(size_t)NCH*MP2];
__device__ float g_KV[(size_t)NCH*KVSTRIDE];
__device__ unsigned g_kmax_u;
__device__ float g_bqkv[QKVS];
__device__ float g_part[(size_t)4*ROWS*DD];
// fp16 operand buffers (A: hi only; B: hi+lo)
__device__ uint4 g_afh[(size_t)(ROWS/16)*(DD/16)*32];
__device__ uint4 g_af2h[(size_t)(ROWS/16)*(FFD/16)*32];
__device__ uint2 g_wfh[(size_t)(FFD/16)*(FFD/8)*32];
__device__ uint2 g_wfl[(size_t)(FFD/16)*(FFD/8)*32];

__device__ __forceinline__ unsigned enc_f(float f){
    unsigned u = __float_as_uint(f);
    return (u & 0x80000000u) ? ~u : (u | 0x80000000u);
}
__device__ __forceinline__ float dec_f(unsigned u){
    return (u & 0x80000000u) ? __uint_as_float(u ^ 0x80000000u) : __uint_as_float(~u);
}

// fp16 pack helpers
__device__ __forceinline__ unsigned packh(float x, float y){
    __half2 hv = __floats2half2_rn(x, y);
    return *reinterpret_cast<unsigned*>(&hv);
}
__device__ __forceinline__ void pack2h(float x, float y, unsigned &h, unsigned &l){
    __half2 hv = __floats2half2_rn(x, y);
    float hx = __low2float(hv), hy = __high2float(hv);
    __half2 lv = __floats2half2_rn(x - hx, y - hy);
    h = *reinterpret_cast<unsigned*>(&hv);
    l = *reinterpret_cast<unsigned*>(&lv);
}

// ---------------- LayerNorm emitting A-hi fragments (16 rows/CTA) ----------------
__global__ __launch_bounds__(256) void lnfrag_k(const float* __restrict__ X,
                                                const float* __restrict__ G,
                                                const float* __restrict__ Bv,
                                                uint4* __restrict__ H){
    const int blk = blockIdx.x;
    const int tid = threadIdx.x;
    const int r = tid >> 4, c16 = tid & 15;
    __shared__ float mu_s[16], rs_s[16];
    const float* xr = X + ((size_t)blk*16 + r)*DD;
    float s = 0.f, ss = 0.f;
    #pragma unroll
    for (int j=0;j<12;j++){
        float4 v = *(const float4*)(xr + c16*4 + j*64);
        s  += v.x+v.y+v.z+v.w;
        ss += v.x*v.x+v.y*v.y+v.z*v.z+v.w*v.w;
    }
    #pragma unroll
    for (int o=8;o;o>>=1){
        s  += __shfl_xor_sync(0xffffffffu, s, o, 16);
        ss += __shfl_xor_sync(0xffffffffu, ss, o, 16);
    }
    if (c16==0){
        float mu = s*(1.0f/DD);
        float var = ss*(1.0f/DD) - mu*mu;
        mu_s[r]=mu; rs_s[r]=rsqrtf(var + 1e-5f);
    }
    __syncthreads();
    #pragma unroll
    for (int i=0;i<6;i++){
        int it = tid + i*256;
        int ak = it>>5, lane = it&31;
        int g = lane>>2, l = lane&3;
        float mu0 = mu_s[g],  r0 = rs_s[g];
        float mu1 = mu_s[g+8],r1 = rs_s[g+8];
        int c = ak*16 + 2*l;
        const float* row0 = X + ((size_t)blk*16 + g)*DD;
        const float* row1 = X + ((size_t)blk*16 + g + 8)*DD;
        float2 ga = *(const float2*)(G + c),  gb = *(const float2*)(G + c + 8);
        float2 ba = *(const float2*)(Bv + c), bb = *(const float2*)(Bv + c + 8);
        float2 v0 = *(const float2*)(row0 + c);
        float2 v1 = *(const float2*)(row1 + c);
        float2 v2 = *(const float2*)(row0 + c + 8);
        float2 v3 = *(const float2*)(row1 + c + 8);
        uint4 h;
        h.x = packh((v0.x-mu0)*r0*ga.x+ba.x, (v0.y-mu0)*r0*ga.y+ba.y);
        h.y = packh((v1.x-mu1)*r1*ga.x+ba.x, (v1.y-mu1)*r1*ga.y+ba.y);
        h.z = packh((v2.x-mu0)*r0*gb.x+bb.x, (v2.y-mu0)*r0*gb.y+bb.y);
        h.w = packh((v3.x-mu1)*r1*gb.x+bb.x, (v3.y-mu1)*r1*gb.y+bb.y);
        size_t gidx = ((size_t)blk*48 + ak)*32 + lane;
        H[gidx]=h;
    }
}

// ---------------- fused k-split reduce + residual + LN2 + fragment emit ----------------
#define SXS 772
#define FLN_SMEM ((16*SXS + 32)*4)
__global__ __launch_bounds__(256) void fusedln_k(const float* __restrict__ P,
                                                 const float* __restrict__ bias,
                                                 const float* __restrict__ xres,
                                                 float* __restrict__ X1,
                                                 const float* __restrict__ G,
                                                 const float* __restrict__ Bv,
                                                 uint4* __restrict__ H){
    extern __shared__ float sx[];
    float* mu_s = sx + 16*SXS;
    float* rs_s = mu_s + 16;
    const int blk = blockIdx.x, tid = threadIdx.x;
    const int r = tid >> 4, c16 = tid & 15;
    const size_t stride = (size_t)ROWS*DD;
    const size_t rowoff = ((size_t)blk*16 + r)*DD;
    float s = 0.f, ss = 0.f;
    #pragma unroll
    for (int j=0;j<12;j++){
        int col = c16*4 + j*64;
        float4 p0 = *(const float4*)(P + rowoff + col);
        float4 p1 = *(const float4*)(P + stride + rowoff + col);
        float4 rr = *(const float4*)(xres + rowoff + col);
        float4 bb = *(const float4*)(bias + col);
        float4 v;
        v.x = p0.x+p1.x+rr.x+bb.x; v.y = p0.y+p1.y+rr.y+bb.y;
        v.z = p0.z+p1.z+rr.z+bb.z; v.w = p0.w+p1.w+rr.w+bb.w;
        *(float4*)(X1 + rowoff + col) = v;
        *(float4*)(sx + r*SXS + col) = v;
        s  += v.x+v.y+v.z+v.w;
        ss += v.x*v.x+v.y*v.y+v.z*v.z+v.w*v.w;
    }
    #pragma unroll
    for (int o=8;o;o>>=1){
        s  += __shfl_xor_sync(0xffffffffu, s, o, 16);
        ss += __shfl_xor_sync(0xffffffffu, ss, o, 16);
    }
    if (c16==0){
        float mu = s*(1.0f/DD);
        float var = ss*(1.0f/DD) - mu*mu;
        mu_s[r]=mu; rs_s[r]=rsqrtf(var + 1e-5f);
    }
    __syncthreads();
    #pragma unroll
    for (int i=0;i<6;i++){
        int it = tid + i*256;
        int ak = it>>5, lane = it&31;
        int g = lane>>2, l = lane&3;
        float mu0 = mu_s[g],  r0 = rs_s[g];
        float mu1 = mu_s[g+8],r1 = rs_s[g+8];
        int c = ak*16 + 2*l;
        const float* row0 = sx + g*SXS;
        const float* row1 = sx + (g+8)*SXS;
        float2 ga = *(const float2*)(G + c),  gb = *(const float2*)(G + c + 8);
        float2 ba = *(const float2*)(Bv + c), bb = *(const float2*)(Bv + c + 8);
        float2 v0 = *(const float2*)(row0 + c);
        float2 v1 = *(const float2*)(row1 + c);
        float2 v2 = *(const float2*)(row0 + c + 8);
        float2 v3 = *(const float2*)(row1 + c + 8);
        uint4 h;
        h.x = packh((v0.x-mu0)*r0*ga.x+ba.x, (v0.y-mu0)*r0*ga.y+ba.y);
        h.y = packh((v1.x-mu1)*r1*ga.x+ba.x, (v1.y-mu1)*r1*ga.y+ba.y);
        h.z = packh((v2.x-mu0)*r0*gb.x+bb.x, (v2.y-mu0)*r0*gb.y+bb.y);
        h.w = packh((v3.x-mu1)*r1*gb.x+bb.x, (v3.y-mu1)*r1*gb.y+bb.y);
        size_t gidx = ((size_t)blk*48 + ak)*32 + lane;
        H[gidx]=h;
    }
}

// ---------------- fp16 split cores ----------------
__device__ __forceinline__ void splitA_core(const float* __restrict__ X,
                                            uint4* __restrict__ H,
                                            int idx, int R, int C){
    int K16 = C>>4;
    int lane = idx & 31, atom = idx >> 5;
    int am = atom / K16, ak = atom % K16;
    int g = lane>>2, l = lane&3;
    const float* p = X + (size_t)(am*16+g)*C + ak*16 + 2*l;
    float2 v0 = *(const float2*)(p);
    float2 v1 = *(const float2*)(p + (size_t)8*C);
    float2 v2 = *(const float2*)(p + 8);
    float2 v3 = *(const float2*)(p + (size_t)8*C + 8);
    uint4 h;
    h.x = packh(v0.x, v0.y);
    h.y = packh(v1.x, v1.y);
    h.z = packh(v2.x, v2.y);
    h.w = packh(v3.x, v3.y);
    H[idx] = h;
}

__device__ __forceinline__ void splitB_core(const float* __restrict__ W,
                                            uint2* __restrict__ H, uint2* __restrict__ L,
                                            int idx, int K, int N, int anBase){
    int lane = idx & 31, atom = idx >> 5;
    int K16 = K>>4;
    int an = atom / K16, ak = atom % K16;
    int g = lane>>2, l = lane&3;
    const float* p = W + (size_t)(ak*16 + 2*l)*N + an*8 + g;
    float b00 = p[0],            b01 = p[N];
    float b10 = p[(size_t)8*N],  b11 = p[(size_t)9*N];
    uint2 h, lo;
    pack2h(b00, b01, h.x, lo.x);
    pack2h(b10, b11, h.y, lo.y);
    int outi = ((anBase + an)*K16 + ak)*32 + lane;
    H[outi] = h; L[outi] = lo;
}

// merged QKV weight split + bias pack + kmax init
__global__ void splitB3_k(const float* __restrict__ Wq, const float* __restrict__ Wk,
                          const float* __restrict__ Wv, uint2* __restrict__ H,
                          uint2* __restrict__ L,
                          const float* __restrict__ bq, const float* __restrict__ bk,
                          const float* __restrict__ bv, float* __restrict__ bo){
    const int per = (DD>>4)*(DD>>3)*32;   // 147456
    int idx = blockIdx.x*256 + threadIdx.x;
    if (idx < 3*per){
        int which = idx / per, rem = idx - which*per;
        const float* W = (which==0)?Wq:(which==1)?Wk:Wv;
        splitB_core(W, H, L, rem, DD, DD, which*(DD>>3));
    } else if (idx < 3*per + DD){
        int i = idx - 3*per;
        bo[i]=bq[i]; bo[DD+i]=bk[i]; bo[2*DD+i]=bv[i];
    } else if (idx == 3*per + DD){
        g_kmax_u = 0x00800000u;
    }
}

// merged splitA(o) + splitB(Wo)   (params renamed: no macro collisions)
__global__ void splitAB_k(const float* __restrict__ O, const float* __restrict__ Wo,
                          uint4* __restrict__ AHo, uint2* __restrict__ BHo,
                          uint2* __restrict__ BLo){
    const int atot = (ROWS/16)*(DD/16)*32;   // 393216
    const int btot = (DD>>4)*(DD>>3)*32;     // 147456
    int idx = blockIdx.x*256 + threadIdx.x;
    if (idx < atot) splitA_core(O, AHo, idx, ROWS, DD);
    else if (idx < atot + btot) splitB_core(Wo, BHo, BLo, idx - atot, DD, DD, 0);
}

// merged splitB(W1) + splitB(W2); W2 region at offset W2OFF
#define W2OFF (48*384*32)
__global__ void splitB12_k(const float* __restrict__ W1, const float* __restrict__ W2,
                           uint2* __restrict__ H, uint2* __restrict__ L){
    const int p1 = 48*384*32;    // W1: K16=48, N/8=384
    const int p2 = 192*96*32;    // W2: K16=192, N/8=96
    int idx = blockIdx.x*256 + threadIdx.x;
    if (idx < p1) splitB_core(W1, H, L, idx, DD, FFD, 0);
    else if (idx < p1 + p2) splitB_core(W2, H + W2OFF, L + W2OFF, idx - p1, FFD, DD, 0);
}

// ---------------- cp.async helpers ----------------
__device__ __forceinline__ void cpasync16(void* smem, const void* gmem){
    unsigned s = (unsigned)__cvta_generic_to_shared(smem);
    asm volatile("cp.async.ca.shared.global [%0], [%1], 16;\n" :: "r"(s), "l"(gmem));
}
#define CP_COMMIT asm volatile("cp.async.commit_group;\n" ::: "memory")
#define CP_WAIT0  asm volatile("cp.async.wait_group 0;\n" ::: "memory")
#define CP_WAIT1  asm volatile("cp.async.wait_group 1;\n" ::: "memory")
#define CP_WAIT2  asm volatile("cp.async.wait_group 2;\n" ::: "memory")

// ---------------- fp16x2 tensor-core GEMM ----------------
__device__ __forceinline__ void mma16(float* d, const uint4& a, const uint2& b){
    asm volatile("mma.sync.aligned.m16n8k16.row.col.f32.f16.f16.f32 "
        "{%0,%1,%2,%3},{%4,%5,%6,%7},{%8,%9},{%0,%1,%2,%3};"
        : "+f"(d[0]),"+f"(d[1]),"+f"(d[2]),"+f"(d[3])
        : "r"(a.x),"r"(a.y),"r"(a.z),"r"(a.w),"r"(b.x),"r"(b.y));
}

// EPI: 0=bias->float, 1=bias+gelu->FRAGMENTS, 3=raw partial (k-split)
// 4-stage cp.async pipeline; stage = BK32 = 2 k16-atoms = 24KB.
#define STG 24576
template<int EPI>
__global__ __launch_bounds__(256, 2) void gemm_tc(const uint4* __restrict__ Ah,
                                               const uint2* __restrict__ Bh,
                                               const uint2* __restrict__ Bl,
                                               const float* __restrict__ bias,
                                               const float* __restrict__ R,
                                               float* __restrict__ C,
                                               uint4* __restrict__ FH,
                                               int K16s, int nk16, int N){
    extern __shared__ char smem[];
    const int tid = threadIdx.x, lane = tid & 31, warp = tid >> 5;
    const int wm = warp >> 2, wn = warp & 3;
    const int bm = blockIdx.y, bn = blockIdx.x;
    const int kz = blockIdx.z * nk16;

    float acc[4][4][4];
    #pragma unroll
    for (int a=0;a<4;a++)
        #pragma unroll
        for (int b=0;b<4;b++)
            #pragma unroll
            for (int c=0;c<4;c++) acc[a][b][c]=0.f;

    auto stage_copy = [&](int s, int kb){
        char* base = smem + s*STG;
        #pragma unroll
        for (int i=0;i<2;i++){
            int e = tid + i*256;
            int ma = e>>6, ra = e&63;
            int ka = ra>>5, ln = ra&31;
            size_t ga = ((size_t)(bm*8+ma)*K16s + kz + kb + ka)*32 + ln;
            cpasync16(base + e*16, Ah + ga);
            int na = e>>5, rb = e&31;
            int kb2 = rb>>4, lp = rb&15;
            size_t gb = ((size_t)(bn*16+na)*K16s + kz + kb + kb2)*32 + lp*2;
            cpasync16(base + 8192 + e*16,  Bh + gb);
            cpasync16(base + 16384 + e*16, Bl + gb);
        }
    };

    const int nk = nk16 >> 1;
    stage_copy(0, 0); CP_COMMIT;
    if (nk > 1){ stage_copy(1, 2); CP_COMMIT; }
    if (nk > 2){ stage_copy(2, 4); CP_COMMIT; }

    for (int ks=0; ks<nk; ks++){
        int rem = nk - 1 - ks;
        if (rem >= 2)      { CP_WAIT2; }
        else if (rem == 1) { CP_WAIT1; }
        else               { CP_WAIT0; }
        __syncthreads();
        if (ks+3 < nk){ stage_copy((ks+3)&3, (ks+3)*2); CP_COMMIT; }
        const int st = ks & 3;
        const uint4* sAh = (const uint4*)(smem + st*STG);
        const uint2* sBh = (const uint2*)(smem + st*STG + 8192);
        const uint2* sBl = (const uint2*)(smem + st*STG + 16384);
        #pragma unroll
        for (int ka=0; ka<2; ka++){
            uint4 Afh[4];
            uint2 Bfh[4], Bfl[4];
            #pragma unroll
            for (int mi=0;mi<4;mi++){
                int off = ((wm*4+mi)*2 + ka)*32 + lane;
                Afh[mi] = sAh[off];
            }
            #pragma unroll
            for (int ni=0;ni<4;ni++){
                int off = ((wn*4+ni)*2 + ka)*32 + lane;
                Bfh[ni] = sBh[off];
                Bfl[ni] = sBl[off];
            }
            #pragma unroll
            for (int mi=0;mi<4;mi++)
                #pragma unroll
                for (int ni=0;ni<4;ni++){
                    mma16(acc[mi][ni], Afh[mi], Bfh[ni]);
                    mma16(acc[mi][ni], Afh[mi], Bfl[ni]);
                }
        }
    }

    const int g = lane>>2, l = lane&3;
    if (EPI==1){
        const int K16n = N >> 4;
        #pragma unroll
        for (int mi=0;mi<4;mi++){
            int am = bm*8 + wm*4 + mi;
            #pragma unroll
            for (int np=0;np<2;np++){
                float vv[2][4];
                #pragma unroll
                for (int half=0; half<2; half++){
                    int ni = 2*np + half;
                    int col = bn*128 + wn*32 + ni*8 + 2*l;
                    float b0 = bias[col], b1 = bias[col+1];
                    float v0 = acc[mi][ni][0]+b0, v1 = acc[mi][ni][1]+b1;
                    float v2 = acc[mi][ni][2]+b0, v3 = acc[mi][ni][3]+b1;
                    vv[half][0] = 0.5f*v0*(1.0f + erff(v0*0.70710678118654752f));
                    vv[half][1] = 0.5f*v1*(1.0f + erff(v1*0.70710678118654752f));
                    vv[half][2] = 0.5f*v2*(1.0f + erff(v2*0.70710678118654752f));
                    vv[half][3] = 0.5f*v3*(1.0f + erff(v3*0.70710678118654752f));
                }
                uint4 h;
                h.x = packh(vv[0][0], vv[0][1]);
                h.y = packh(vv[0][2], vv[0][3]);
                h.z = packh(vv[1][0], vv[1][1]);
                h.w = packh(vv[1][2], vv[1][3]);
                size_t ga = ((size_t)am*K16n + (bn*8 + wn*2 + np))*32 + lane;
                FH[ga] = h;
            }
        }
    } else {
        float* Cp = C;
        if (EPI==3) Cp = C + (size_t)blockIdx.z * (size_t)(gridDim.y*128) * N;
        #pragma unroll
        for (int mi=0;mi<4;mi++){
            int row = bm*128 + wm*64 + mi*16 + g;
            #pragma unroll
            for (int ni=0;ni<4;ni++){
                int col = bn*128 + wn*32 + ni*8 + 2*l;
                float b0 = (EPI==3) ? 0.f : bias[col];
                float b1 = (EPI==3) ? 0.f : bias[col+1];
                float v0 = acc[mi][ni][0]+b0, v1 = acc[mi][ni][1]+b1;
                float v2 = acc[mi][ni][2]+b0, v3 = acc[mi][ni][3]+b1;
                *(float2*)(Cp + (size_t)row*N + col)     = make_float2(v0, v1);
                *(float2*)(Cp + (size_t)(row+8)*N + col) = make_float2(v2, v3);
            }
        }
    }
}

// ---------------- k-split reduce (final output) ----------------
template<int S>
__global__ void reduceK_k(const float* __restrict__ P, const float* __restrict__ bias,
                          const float* __restrict__ R, float* __restrict__ C, int N){
    const size_t stride4 = (size_t)ROWS*DD/4;
    size_t i = (size_t)blockIdx.x*256 + threadIdx.x;
    if (i >= stride4) return;
    float4 a = ((const float4*)P)[i];
    #pragma unroll
    for (int s=1;s<S;s++){
        float4 b = ((const float4*)P)[s*stride4 + i];
        a.x+=b.x; a.y+=b.y; a.z+=b.z; a.w+=b.w;
    }
    int col4 = (int)(i % (N/4));
    float4 bb = ((const float4*)bias)[col4];
    float4 rr = ((const float4*)R)[i];
    a.x += bb.x + rr.x; a.y += bb.y + rr.y;
    a.z += bb.z + rr.z; a.w += bb.w + rr.w;
    ((float4*)C)[i] = a;
}

// ---------------- FAVOR+ feature maps as GEMM ----------------
__global__ __launch_bounds__(256) void featgemm_k(const float* __restrict__ QKV,
                                                  const float* __restrict__ proj,
                                                  float* __restrict__ QP,
                                                  float* __restrict__ KP,
                                                  float* __restrict__ RM){
    const int isK = blockIdx.z;
    const int bh = blockIdx.y;
    const int n0 = blockIdx.x*32;
    const int b = bh/HH, h = bh%HH;
    const float* A = QKV + (size_t)(b*NN + n0)*QKVS + (isK ? DD : 0) + h*64;

    __shared__ float Ps[32][292];
    __shared__ float At[32][33];
    __shared__ float diag_s[32];
    __shared__ float wmx[8];

    int tid = threadIdx.x;
    int tx = tid & 31, ty = tid >> 5;
    float acc[4][9];
    #pragma unroll
    for (int i=0;i<4;i++)
        #pragma unroll
        for (int j=0;j<9;j++) acc[i][j]=0.f;

    #pragma unroll
    for (int ks=0; ks<2; ks++){
        {
            int t = tid>>3, d4 = (tid&7)<<2;
            float4 a4 = *(const float4*)(A + (size_t)t*QKVS + ks*32 + d4);
            At[d4+0][t]=a4.x; At[d4+1][t]=a4.y; At[d4+2][t]=a4.z; At[d4+3][t]=a4.w;
        }
        {
            int d4 = (tid&7)<<2, mb = tid>>3;
            #pragma unroll
            for (int it=0; it<9; it++){
                int m = mb + it*32;
                float4 p4 = (m < MM) ? *(const float4*)(proj + (size_t)m*64 + ks*32 + d4)
                                     : make_float4(0.f,0.f,0.f,0.f);
                Ps[d4+0][m]=p4.x; Ps[d4+1][m]=p4.y; Ps[d4+2][m]=p4.z; Ps[d4+3][m]=p4.w;
            }
        }
        __syncthreads();
        if (tid < 32){
            float s = (ks==0) ? 0.f : diag_s[tid];
            #pragma unroll
            for (int d=0; d<32; d++){ float a = At[d][tid]; s += a*a; }
            diag_s[tid] = s;
        }
        #pragma unroll
        for (int d=0; d<32; d++){
            float a0 = At[d][ty*4+0];
            float a1 = At[d][ty*4+1];
            float a2 = At[d][ty*4+2];
            float a3 = At[d][ty*4+3];
            #pragma unroll
            for (int j=0;j<9;j++){
                float p = Ps[d][tx*9+j];
                acc[0][j] += a0*p;
                acc[1][j] += a1*p;
                acc[2][j] += a2*p;
                acc[3][j] += a3*p;
            }
        }
        __syncthreads();
    }

    float mx[4];
    #pragma unroll
    for (int i=0;i<4;i++){
        float m_ = -3.4e38f;
        #pragma unroll
        for (int j=0;j<9;j++){
            float v = acc[i][j]*DN_SCALE;
            acc[i][j] = v;
            if (tx*9+j < MM) m_ = fmaxf(m_, v);
        }
        #pragma unroll
        for (int o=16;o;o>>=1) m_ = fmaxf(m_, __shfl_xor_sync(0xffffffffu, m_, o));
        mx[i] = m_;
    }

    if (!isK){
        #pragma unroll
        for (int i=0;i<4;i++){
            int t = ty*4+i;
            float dg = diag_s[t]*0.0625f;
            float* out = QP + ((size_t)(bh*NN + n0 + t))*MP2;
            #pragma unroll
            for (int j=0;j<9;j++){
                int m = tx*9+j;
                out[m] = (m < MM) ? RATIO_SC*(__expf(acc[i][j]-dg-mx[i]) + EPS_KER) : 0.f;
            }
        }
    } else {
        float bm_ = -3.4e38f;
        #pragma unroll
        for (int i=0;i<4;i++){
            int t = ty*4+i;
            float dg = diag_s[t]*0.0625f;
            float* out = KP + ((size_t)(bh*NN + n0 + t))*MP2;
            #pragma unroll
            for (int j=0;j<9;j++){
                int m = tx*9+j;
                out[m] = (m < MM) ? __expf(acc[i][j]-dg-mx[i]) : 0.f;
            }
            if (tx==0) RM[bh*NN + n0 + t] = mx[i];
            bm_ = fmaxf(bm_, mx[i]);
        }
        if (tx==0) wmx[ty] = bm_;
        __syncthreads();
        if (tid==0){
            float B = wmx[0];
            #pragma unroll
            for (int w=1;w<8;w++) B = fmaxf(B, wmx[w]);
            atomicMax(&g_kmax_u, enc_f(B));
        }
    }
}

// ---------------- chunked causal linear attention ----------------
__global__ __launch_bounds__(512) void chunksum_k(const float* __restrict__ KP,
                                                  const float* __restrict__ QKV,
                                                  const float* __restrict__ RM,
                                                  float* __restrict__ Z,
                                                  float* __restrict__ KV){
    int bhc = blockIdx.x;
    int bh = bhc / NC, c = bhc % NC;
    int b = bh / HH, h = bh % HH;
    int tid = threadIdx.x, g = tid>>6, e = tid&63;
    const int m0 = g*GM;
    __shared__ __align__(16) float kt[2][TT][MP2];
    __shared__ __align__(16) float vt[2][TT][64];
    __shared__ float scs[CHK];
    float S[GM];
    #pragma unroll
    for (int i=0;i<GM;i++) S[i]=0.f;
    float zacc = 0.f;
    const float* kb = KP + ((size_t)bh*NN + c*CHK)*MP2;
    const float* vb = QKV + (size_t)(b*NN + c*CHK)*QKVS + 2*DD + h*64;

    float gmax = dec_f(g_kmax_u);
    for (int i=tid; i<CHK; i+=512)
        scs[i] = __expf(RM[bh*NN + c*CHK + i] - gmax);

    auto load = [&](int buf, int tile){
        const float* kb_ = kb + (size_t)tile*TT*MP2;
        const float* vb_ = vb + (size_t)tile*TT*QKVS;
        for (int idx=tid; idx<704; idx+=512){
            if (idx < 576){ int tok=idx/72, f=(idx%72)*4; cpasync16(&kt[buf][tok][f], kb_ + (size_t)tok*MP2 + f); }
            else { int r=idx-576; int tok=r/16, f=(r%16)*4; cpasync16(&vt[buf][tok][f], vb_ + (size_t)tok*QKVS + f); }
        }
    };
    load(0,0); CP_COMMIT;
    for (int tile=0; tile<NTILE; tile++){
        int buf = tile&1;
        CP_WAIT0;
        __syncthreads();
        if (tile+1 < NTILE) load(buf^1, tile+1);
        CP_COMMIT;
        {
            const int tb = tile*TT;
            for (int idx=tid; idx<TT*MP2; idx+=512){
                int tok = idx/MP2, m = idx - tok*MP2;
                float f = kt[buf][tok][m];
                kt[buf][tok][m] = (m < MM) ? RATIO_SC*(f*scs[tb+tok] + EPS_KER) : 0.f;
            }
        }
        __syncthreads();
        #pragma unroll
        for (int tt=0; tt<TT; tt++){
            float vv = vt[buf][tt][e];
            const float4* kr = (const float4*)(&kt[buf][tt][m0]);
            #pragma unroll
            for (int i4=0;i4<9;i4++){
                float4 kk = kr[i4];
                S[i4*4+0] += kk.x*vv;
                S[i4*4+1] += kk.y*vv;
                S[i4*4+2] += kk.z*vv;
                S[i4*4+3] += kk.w*vv;
            }
            if (tid < MP2) zacc += kt[buf][tt][tid];
        }
    }
    if (tid < MP2) Z[(size_t)bhc*MP2 + tid] = zacc;
    float* kvout = KV + (size_t)bhc*KVSTRIDE;
    #pragma unroll
    for (int i=0;i<GM;i++) kvout[(size_t)(m0+i)*64 + e] = S[i];
}

__global__ __launch_bounds__(512) void prefix_k(float* __restrict__ Z, float* __restrict__ KV){
    int bh = blockIdx.y;
    int base = bh*NC;
    int idx = blockIdx.x*512 + threadIdx.x;
    float run = 0.f;
    #pragma unroll
    for (int c=0;c<NC;c++){
        float* p = KV + (size_t)(base+c)*KVSTRIDE + idx;
        float t = *p; *p = run; run += t;
    }
    if (blockIdx.x==0 && threadIdx.x < MP2){
        float rz = 0.f;
        #pragma unroll
        for (int c=0;c<NC;c++){
            float* p = Z + (size_t)(base+c)*MP2 + threadIdx.x;
            float t = *p; *p = rz; rz += t;
        }
    }
}

// chunkout with dynamic smem + batched per-tile reductions
#define CO_KT(b,t,m)  dsm[((b)*TT+(t))*MP2+(m)]
#define CO_QT(b,t,m)  dsm[QOFF + ((b)*TT+(t))*MP2+(m)]
#define CO_VT(b,t,e)  dsm[VOFF + ((b)*TT+(t))*64+(e)]
#define CO_PART(t,g,e) dsm[POFF + ((t)*8+(g))*64+(e)]
#define CO_DRED(t,w)  dsm[DOFF + (t)*16+(w)]
#define CO_SCS(i)     dsm[SOFF + (i)]
#define QOFF (2*TT*MP2)
#define VOFF (4*TT*MP2)
#define POFF (4*TT*MP2 + 2*TT*64)
#define DOFF (POFF + TT*8*64)
#define SOFF (DOFF + TT*16)
#define CO_SMEM ((SOFF + CHK)*4)

__global__ __launch_bounds__(512) void chunkout_k(const float* __restrict__ QP,
                                                  const float* __restrict__ KP,
                                                  const float* __restrict__ QKV,
                                                  const float* __restrict__ RM,
                                                  const float* __restrict__ Z,
                                                  const float* __restrict__ KV,
                                                  float* __restrict__ O){
    extern __shared__ __align__(16) float dsm[];
    int bhc = blockIdx.x;
    int bh = bhc / NC, c = bhc % NC;
    int b = bh / HH, h = bh % HH;
    int tid = threadIdx.x, g = tid>>6, e = tid&63;
    const int m0 = g*GM;

    float S[GM];
    const float* kvin = KV + (size_t)bhc*KVSTRIDE;
    #pragma unroll
    for (int i=0;i<GM;i++) S[i] = kvin[(size_t)(m0+i)*64 + e];
    float zreg = (tid < MP2) ? Z[(size_t)bhc*MP2 + tid] : 0.f;

    const float* kb = KP + ((size_t)bh*NN + c*CHK)*MP2;
    const float* qb = QP + ((size_t)bh*NN + c*CHK)*MP2;
    const float* vb = QKV + (size_t)(b*NN + c*CHK)*QKVS + 2*DD + h*64;

    float gmax = dec_f(g_kmax_u);
    for (int i=tid; i<CHK; i+=512)
        CO_SCS(i) = __expf(RM[bh*NN + c*CHK + i] - gmax);

    auto load = [&](int buf, int tile){
        const float* kb_ = kb + (size_t)tile*TT*MP2;
        const float* qb_ = qb + (size_t)tile*TT*MP2;
        const float* vb_ = vb + (size_t)tile*TT*QKVS;
        for (int idx=tid; idx<1280; idx+=512){
            if (idx < 576){ int tok=idx/72, f=(idx%72)*4; cpasync16(&CO_KT(buf,tok,f), kb_ + (size_t)tok*MP2 + f); }
            else if (idx < 1152){ int r=idx-576; int tok=r/72, f=(r%72)*4; cpasync16(&CO_QT(buf,tok,f), qb_ + (size_t)tok*MP2 + f); }
            else { int r=idx-1152; int tok=r/16, f=(r%16)*4; cpasync16(&CO_VT(buf,tok,f), vb_ + (size_t)tok*QKVS + f); }
        }
    };
    load(0,0); CP_COMMIT;

    for (int tile=0; tile<NTILE; tile++){
        int buf = tile&1;
        CP_WAIT0;
        __syncthreads();
        if (tile+1 < NTILE) load(buf^1, tile+1);
        CP_COMMIT;
        {
            const int tb = tile*TT;
            for (int idx=tid; idx<TT*MP2; idx+=512){
                int tok = idx/MP2, m = idx - tok*MP2;
                float f = CO_KT(buf,tok,m);
                CO_KT(buf,tok,m) = (m < MM) ? RATIO_SC*(f*CO_SCS(tb+tok) + EPS_KER) : 0.f;
            }
        }
        __syncthreads();
        #pragma unroll
        for (int tt=0; tt<TT; tt++){
            float vv = CO_VT(buf,tt,e);
            const float4* kr = (const float4*)(&CO_KT(buf,tt,m0));
            const float4* qr = (const float4*)(&CO_QT(buf,tt,m0));
            float acc = 0.f;
            #pragma unroll
            for (int i4=0;i4<9;i4++){
                float4 kk = kr[i4];
                float4 qq = qr[i4];
                S[i4*4+0] += kk.x*vv;  acc += qq.x*S[i4*4+0];
                S[i4*4+1] += kk.y*vv;  acc += qq.y*S[i4*4+1];
                S[i4*4+2] += kk.z*vv;  acc += qq.z*S[i4*4+2];
                S[i4*4+3] += kk.w*vv;  acc += qq.w*S[i4*4+3];
            }
            CO_PART(tt,g,e) = acc;
        }
        if (tid < MP2){
            float dp[TT];
            #pragma unroll
            for (int tt=0; tt<TT; tt++){
                float kv = CO_KT(buf,tt,tid);
                zreg += kv;
                dp[tt] = CO_QT(buf,tt,tid)*(zreg + EPS_DEN);
            }
            #pragma unroll
            for (int tt=0; tt<TT; tt++){
                float d = dp[tt];
                #pragma unroll
                for (int o=16;o;o>>=1) d += __shfl_xor_sync(0xffffffffu, d, o);
                if ((tid&31)==0) CO_DRED(tt, tid>>5) = d;
            }
        }
        __syncthreads();
        {
            int tok = tid>>6, e2 = tid&63;
            float s = 0.f;
            #pragma unroll
            for (int gg=0; gg<8; gg++) s += CO_PART(tok,gg,e2);
            float den = 0.f;
            #pragma unroll
            for (int w=0; w<9; w++) den += CO_DRED(tok,w);
            int t = c*CHK + tile*TT + tok;
            O[((size_t)(b*NN + t))*DD + h*64 + e2] = s / den;
        }
    }
}

// ---------------- launch ----------------
#define GEMM_SMEM (4*STG)

extern "C" void kernel_launch(void* const* d_in, const int* in_sizes, int n_in,
                              void* d_out, int out_size){
    (void)in_sizes; (void)n_in; (void)out_size;
    const float* x    = (const float*)d_in[0];
    const float* ln1g = (const float*)d_in[1];
    const float* ln1b = (const float*)d_in[2];
    const float* Wq   = (const float*)d_in[3];
    const float* bq   = (const float*)d_in[4];
    const float* Wk   = (const float*)d_in[5];
    const float* bk   = (const float*)d_in[6];
    const float* Wv   = (const float*)d_in[7];
    const float* bv   = (const float*)d_in[8];
    const float* Wo   = (const float*)d_in[9];
    const float* bo   = (const float*)d_in[10];
    const float* proj = (const float*)d_in[11];
    const float* ln2g = (const float*)d_in[12];
    const float* ln2b = (const float*)d_in[13];
    const float* W1   = (const float*)d_in[14];
    const float* b1   = (const float*)d_in[15];
    const float* W2   = (const float*)d_in[16];
    const float* b2   = (const float*)d_in[17];
    float* out = (float*)d_out;

    float *qkv,*qp,*kp,*rm,*o,*x1,*zz,*kv,*bqkv,*part;
    uint4 *afh,*af2h;
    uint2 *wfh,*wfl;
    cudaGetSymbolAddress((void**)&qkv, g_qkv);
    cudaGetSymbolAddress((void**)&qp,  g_qp);
    cudaGetSymbolAddress((void**)&kp,  g_kp);
    cudaGetSymbolAddress((void**)&rm,  g_rm);
    cudaGetSymbolAddress((void**)&o,   g_o);
    cudaGetSymbolAddress((void**)&x1,  g_x1);
    cudaGetSymbolAddress((void**)&zz,  g_Z);
    cudaGetSymbolAddress((void**)&kv,  g_KV);
    cudaGetSymbolAddress((void**)&bqkv,g_bqkv);
    cudaGetSymbolAddress((void**)&part,g_part);
    cudaGetSymbolAddress((void**)&afh, g_afh);
    cudaGetSymbolAddress((void**)&af2h,g_af2h);
    cudaGetSymbolAddress((void**)&wfh, g_wfh);
    cudaGetSymbolAddress((void**)&wfl, g_wfl);

    cudaFuncSetAttribute(gemm_tc<0>, cudaFuncAttributeMaxDynamicSharedMemorySize, GEMM_SMEM);
    cudaFuncSetAttribute(gemm_tc<1>, cudaFuncAttributeMaxDynamicSharedMemorySize, GEMM_SMEM);
    cudaFuncSetAttribute(gemm_tc<3>, cudaFuncAttributeMaxDynamicSharedMemorySize, GEMM_SMEM);
    cudaFuncSetAttribute(chunkout_k, cudaFuncAttributeMaxDynamicSharedMemorySize, CO_SMEM);
    cudaFuncSetAttribute(fusedln_k,  cudaFuncAttributeMaxDynamicSharedMemorySize, FLN_SMEM);

    // 1: weight split + bias pack + kmax init
    splitB3_k<<<1731,256>>>(Wq, Wk, Wv, wfh, wfl, bq, bk, bv, bqkv);
    // 2: LN1 -> fp16 fragments
    lnfrag_k<<<ROWS/16,256>>>(x, ln1g, ln1b, afh);
    // 3: QKV fused GEMM
    {
        dim3 gq(QKVS/128, ROWS/128);
        gemm_tc<0><<<gq,256,GEMM_SMEM>>>(afh, wfh, wfl, bqkv, nullptr, qkv,
                                         nullptr, DD/16, DD/16, QKVS);
    }
    // 4: feature maps
    dim3 gfeat(NN/32, BH, 2);
    featgemm_k<<<gfeat,256>>>(qkv, proj, qp, kp, rm);
    // 5-7: scan
    chunksum_k<<<NCH,512>>>(kp, qkv, rm, zz, kv);
    {
        dim3 gp(KVSTRIDE/512, BH);
        prefix_k<<<gp,512>>>(zz, kv);
    }
    chunkout_k<<<NCH,512,CO_SMEM>>>(qp, kp, qkv, rm, zz, kv, o);
    // 8: split o + Wo
    splitAB_k<<<2112,256>>>(o, Wo, afh, wfh, wfl);
    // 9: Wo GEMM (k-split x2)
    {
        dim3 gg(DD/128, ROWS/128, 2);
        gemm_tc<3><<<gg,256,GEMM_SMEM>>>(afh, wfh, wfl, nullptr, nullptr, part,
                                         nullptr, DD/16, DD/32, DD);
    }
    // 10: fused reduce + residual + LN2 + fragment emit
    fusedln_k<<<ROWS/16,256,FLN_SMEM>>>(part, bo, x, x1, ln2g, ln2b, afh);
    // 11: split W1 + W2
    splitB12_k<<<4608,256>>>(W1, W2, wfh, wfl);
    // 12: W1 GEMM + gelu -> fragments
    {
        dim3 gg(FFD/128, ROWS/128);
        gemm_tc<1><<<gg,256,GEMM_SMEM>>>(afh, wfh, wfl, b1, nullptr, nullptr,
                                         af2h, DD/16, DD/16, FFD);
    }
    // 13: W2 GEMM (k-split x4)
    {
        dim3 gg(DD/128, ROWS/128, 4);
        gemm_tc<3><<<gg,256,GEMM_SMEM>>>(af2h, wfh + W2OFF, wfl + W2OFF, nullptr, nullptr, part,
                                         nullptr, FFD/16, FFD/64, DD);
    }
    // 14: final reduce + bias + residual
    reduceK_k<4><<<(ROWS*DD/4+255)/256,256>>>(part, b2, x1, out, DD);
}

// round 15
// speedup vs baseline: 12.2636x; 1.1782x over previous
#include <cuda_runtime.h>
#include <cuda_bf16.h>
#include <cuda_fp16.h>
#include <math.h>
#include <stdint.h>

// ---------------- problem constants ----------------
#define BB   2
#define NN   2048
#define DD   768
#define HH   12
#define MM   266
#define MP2  288
#define GM   36
#define FFD  3072
#define ROWS (BB*NN)
#define RIDS (BB*HH*NN)
#define BH   (BB*HH)
#define CHK  128
#define NC   (NN/CHK)
#define NCH  (BH*NC)
#define TT   8
#define NTILE (CHK/TT)
#define KVSTRIDE (MP2*64)
#define QKVS 2304

#define DN_SCALE   0.35355339059327f
#define RATIO_SC   0.061313689f
#define EPS_KER    1e-4f
#define EPS_DEN    1e-6f

// ---------------- scratch ----------------
__device__ float g_qkv[(size_t)ROWS*QKVS];
__device__ float g_o [ROWS*DD];
__device__ float g_x1[ROWS*DD];
__device__ float g_qp[(size_t)RIDS*MP2];
__device__ float g_kp[(size_t)RIDS*MP2];
__device__ float g_rm[RIDS];
__device__ float g_Z [(size_t)NCH*MP2];
__device__ float g_KV[(size_t)NCH*KVSTRIDE];
__device__ unsigned g_kmax_u;
__device__ float g_bqkv[QKVS];
__device__ float g_part[(size_t)4*ROWS*DD];
// fp16 operand buffers (A: hi only; B: hi+lo)
__device__ uint4 g_afh[(size_t)(ROWS/16)*(DD/16)*32];
__device__ uint4 g_af2h[(size_t)(ROWS/16)*(FFD/16)*32];
__device__ uint2 g_wfh[(size_t)(FFD/16)*(FFD/8)*32];
__device__ uint2 g_wfl[(size_t)(FFD/16)*(FFD/8)*32];
// proj B-fragments (36 n-atoms x 4 k-atoms x 32 lanes), hi+lo
__device__ uint2 g_pfh[36*4*32];
__device__ uint2 g_pfl[36*4*32];

__device__ __forceinline__ unsigned enc_f(float f){
    unsigned u = __float_as_uint(f);
    return (u & 0x80000000u) ? ~u : (u | 0x80000000u);
}
__device__ __forceinline__ float dec_f(unsigned u){
    return (u & 0x80000000u) ? __uint_as_float(u ^ 0x80000000u) : __uint_as_float(~u);
}

// fp16 pack helpers
__device__ __forceinline__ unsigned packh(float x, float y){
    __half2 hv = __floats2half2_rn(x, y);
    return *reinterpret_cast<unsigned*>(&hv);
}
__device__ __forceinline__ void pack2h(float x, float y, unsigned &h, unsigned &l){
    __half2 hv = __floats2half2_rn(x, y);
    float hx = __low2float(hv), hy = __high2float(hv);
    __half2 lv = __floats2half2_rn(x - hx, y - hy);
    h = *reinterpret_cast<unsigned*>(&hv);
    l = *reinterpret_cast<unsigned*>(&lv);
}

// ---------------- LayerNorm emitting A-hi fragments (16 rows/CTA) ----------------
__global__ __launch_bounds__(256) void lnfrag_k(const float* __restrict__ X,
                                                const float* __restrict__ G,
                                                const float* __restrict__ Bv,
                                                uint4* __restrict__ H){
    const int blk = blockIdx.x;
    const int tid = threadIdx.x;
    const int r = tid >> 4, c16 = tid & 15;
    __shared__ float mu_s[16], rs_s[16];
    const float* xr = X + ((size_t)blk*16 + r)*DD;
    float s = 0.f, ss = 0.f;
    #pragma unroll
    for (int j=0;j<12;j++){
        float4 v = *(const float4*)(xr + c16*4 + j*64);
        s  += v.x+v.y+v.z+v.w;
        ss += v.x*v.x+v.y*v.y+v.z*v.z+v.w*v.w;
    }
    #pragma unroll
    for (int o=8;o;o>>=1){
        s  += __shfl_xor_sync(0xffffffffu, s, o, 16);
        ss += __shfl_xor_sync(0xffffffffu, ss, o, 16);
    }
    if (c16==0){
        float mu = s*(1.0f/DD);
        float var = ss*(1.0f/DD) - mu*mu;
        mu_s[r]=mu; rs_s[r]=rsqrtf(var + 1e-5f);
    }
    __syncthreads();
    #pragma unroll
    for (int i=0;i<6;i++){
        int it = tid + i*256;
        int ak = it>>5, lane = it&31;
        int g = lane>>2, l = lane&3;
        float mu0 = mu_s[g],  r0 = rs_s[g];
        float mu1 = mu_s[g+8],r1 = rs_s[g+8];
        int c = ak*16 + 2*l;
        const float* row0 = X + ((size_t)blk*16 + g)*DD;
        const float* row1 = X + ((size_t)blk*16 + g + 8)*DD;
        float2 ga = *(const float2*)(G + c),  gb = *(const float2*)(G + c + 8);
        float2 ba = *(const float2*)(Bv + c), bb = *(const float2*)(Bv + c + 8);
        float2 v0 = *(const float2*)(row0 + c);
        float2 v1 = *(const float2*)(row1 + c);
        float2 v2 = *(const float2*)(row0 + c + 8);
        float2 v3 = *(const float2*)(row1 + c + 8);
        uint4 h;
        h.x = packh((v0.x-mu0)*r0*ga.x+ba.x, (v0.y-mu0)*r0*ga.y+ba.y);
        h.y = packh((v1.x-mu1)*r1*ga.x+ba.x, (v1.y-mu1)*r1*ga.y+ba.y);
        h.z = packh((v2.x-mu0)*r0*gb.x+bb.x, (v2.y-mu0)*r0*gb.y+bb.y);
        h.w = packh((v3.x-mu1)*r1*gb.x+bb.x, (v3.y-mu1)*r1*gb.y+bb.y);
        size_t gidx = ((size_t)blk*48 + ak)*32 + lane;
        H[gidx]=h;
    }
}

// ---------------- fused k-split reduce + residual + LN2 + fragment emit ----------------
#define SXS 772
#define FLN_SMEM ((16*SXS + 32)*4)
__global__ __launch_bounds__(256) void fusedln_k(const float* __restrict__ P,
                                                 const float* __restrict__ bias,
                                                 const float* __restrict__ xres,
                                                 float* __restrict__ X1,
                                                 const float* __restrict__ G,
                                                 const float* __restrict__ Bv,
                                                 uint4* __restrict__ H){
    extern __shared__ float sx[];
    float* mu_s = sx + 16*SXS;
    float* rs_s = mu_s + 16;
    const int blk = blockIdx.x, tid = threadIdx.x;
    const int r = tid >> 4, c16 = tid & 15;
    const size_t stride = (size_t)ROWS*DD;
    const size_t rowoff = ((size_t)blk*16 + r)*DD;
    float s = 0.f, ss = 0.f;
    #pragma unroll
    for (int j=0;j<12;j++){
        int col = c16*4 + j*64;
        float4 p0 = *(const float4*)(P + rowoff + col);
        float4 p1 = *(const float4*)(P + stride + rowoff + col);
        float4 rr = *(const float4*)(xres + rowoff + col);
        float4 bb = *(const float4*)(bias + col);
        float4 v;
        v.x = p0.x+p1.x+rr.x+bb.x; v.y = p0.y+p1.y+rr.y+bb.y;
        v.z = p0.z+p1.z+rr.z+bb.z; v.w = p0.w+p1.w+rr.w+bb.w;
        *(float4*)(X1 + rowoff + col) = v;
        *(float4*)(sx + r*SXS + col) = v;
        s  += v.x+v.y+v.z+v.w;
        ss += v.x*v.x+v.y*v.y+v.z*v.z+v.w*v.w;
    }
    #pragma unroll
    for (int o=8;o;o>>=1){
        s  += __shfl_xor_sync(0xffffffffu, s, o, 16);
        ss += __shfl_xor_sync(0xffffffffu, ss, o, 16);
    }
    if (c16==0){
        float mu = s*(1.0f/DD);
        float var = ss*(1.0f/DD) - mu*mu;
        mu_s[r]=mu; rs_s[r]=rsqrtf(var + 1e-5f);
    }
    __syncthreads();
    #pragma unroll
    for (int i=0;i<6;i++){
        int it = tid + i*256;
        int ak = it>>5, lane = it&31;
        int g = lane>>2, l = lane&3;
        float mu0 = mu_s[g],  r0 = rs_s[g];
        float mu1 = mu_s[g+8],r1 = rs_s[g+8];
        int c = ak*16 + 2*l;
        const float* row0 = sx + g*SXS;
        const float* row1 = sx + (g+8)*SXS;
        float2 ga = *(const float2*)(G + c),  gb = *(const float2*)(G + c + 8);
        float2 ba = *(const float2*)(Bv + c), bb = *(const float2*)(Bv + c + 8);
        float2 v0 = *(const float2*)(row0 + c);
        float2 v1 = *(const float2*)(row1 + c);
        float2 v2 = *(const float2*)(row0 + c + 8);
        float2 v3 = *(const float2*)(row1 + c + 8);
        uint4 h;
        h.x = packh((v0.x-mu0)*r0*ga.x+ba.x, (v0.y-mu0)*r0*ga.y+ba.y);
        h.y = packh((v1.x-mu1)*r1*ga.x+ba.x, (v1.y-mu1)*r1*ga.y+ba.y);
        h.z = packh((v2.x-mu0)*r0*gb.x+bb.x, (v2.y-mu0)*r0*gb.y+bb.y);
        h.w = packh((v3.x-mu1)*r1*gb.x+bb.x, (v3.y-mu1)*r1*gb.y+bb.y);
        size_t gidx = ((size_t)blk*48 + ak)*32 + lane;
        H[gidx]=h;
    }
}

// ---------------- fp16 split cores ----------------
__device__ __forceinline__ void splitA_core(const float* __restrict__ X,
                                            uint4* __restrict__ H,
                                            int idx, int R, int C){
    int K16 = C>>4;
    int lane = idx & 31, atom = idx >> 5;
    int am = atom / K16, ak = atom % K16;
    int g = lane>>2, l = lane&3;
    const float* p = X + (size_t)(am*16+g)*C + ak*16 + 2*l;
    float2 v0 = *(const float2*)(p);
    float2 v1 = *(const float2*)(p + (size_t)8*C);
    float2 v2 = *(const float2*)(p + 8);
    float2 v3 = *(const float2*)(p + (size_t)8*C + 8);
    uint4 h;
    h.x = packh(v0.x, v0.y);
    h.y = packh(v1.x, v1.y);
    h.z = packh(v2.x, v2.y);
    h.w = packh(v3.x, v3.y);
    H[idx] = h;
}

__device__ __forceinline__ void splitB_core(const float* __restrict__ W,
                                            uint2* __restrict__ H, uint2* __restrict__ L,
                                            int idx, int K, int N, int anBase){
    int lane = idx & 31, atom = idx >> 5;
    int K16 = K>>4;
    int an = atom / K16, ak = atom % K16;
    int g = lane>>2, l = lane&3;
    const float* p = W + (size_t)(ak*16 + 2*l)*N + an*8 + g;
    float b00 = p[0],            b01 = p[N];
    float b10 = p[(size_t)8*N],  b11 = p[(size_t)9*N];
    uint2 h, lo;
    pack2h(b00, b01, h.x, lo.x);
    pack2h(b10, b11, h.y, lo.y);
    int outi = ((anBase + an)*K16 + ak)*32 + lane;
    H[outi] = h; L[outi] = lo;
}

// merged QKV weight split + bias pack + kmax init + proj B-fragment split
__global__ void splitB3_k(const float* __restrict__ Wq, const float* __restrict__ Wk,
                          const float* __restrict__ Wv, uint2* __restrict__ H,
                          uint2* __restrict__ L,
                          const float* __restrict__ bq, const float* __restrict__ bk,
                          const float* __restrict__ bv, float* __restrict__ bo,
                          const float* __restrict__ proj,
                          uint2* __restrict__ pfh, uint2* __restrict__ pfl){
    const int per = (DD>>4)*(DD>>3)*32;   // 147456
    const int pstart = 3*per + DD + 1;
    int idx = blockIdx.x*256 + threadIdx.x;
    if (idx < 3*per){
        int which = idx / per, rem = idx - which*per;
        const float* W = (which==0)?Wq:(which==1)?Wk:Wv;
        splitB_core(W, H, L, rem, DD, DD, which*(DD>>3));
    } else if (idx < 3*per + DD){
        int i = idx - 3*per;
        bo[i]=bq[i]; bo[DD+i]=bk[i]; bo[2*DD+i]=bv[i];
    } else if (idx == 3*per + DD){
        g_kmax_u = 0x00800000u;
    } else if (idx < pstart + 36*4*32){
        int i2 = idx - pstart;
        int lane = i2 & 31, atom = i2 >> 5;    // atom = an*4+ak
        int an = atom >> 2, ak = atom & 3;
        int g = lane>>2, l = lane&3;
        int n = an*8 + g;
        float b00=0.f,b01=0.f,b10=0.f,b11=0.f;
        if (n < MM){
            const float* p = proj + (size_t)n*64 + ak*16 + 2*l;
            b00=p[0]; b01=p[1]; b10=p[8]; b11=p[9];
        }
        uint2 h, lo;
        pack2h(b00,b01,h.x,lo.x);
        pack2h(b10,b11,h.y,lo.y);
        pfh[atom*32+lane]=h; pfl[atom*32+lane]=lo;
    }
}

// merged splitA(o) + splitB(Wo)
__global__ void splitAB_k(const float* __restrict__ O, const float* __restrict__ Wo,
                          uint4* __restrict__ AHo, uint2* __restrict__ BHo,
                          uint2* __restrict__ BLo){
    const int atot = (ROWS/16)*(DD/16)*32;   // 393216
    const int btot = (DD>>4)*(DD>>3)*32;     // 147456
    int idx = blockIdx.x*256 + threadIdx.x;
    if (idx < atot) splitA_core(O, AHo, idx, ROWS, DD);
    else if (idx < atot + btot) splitB_core(Wo, BHo, BLo, idx - atot, DD, DD, 0);
}

// merged splitB(W1) + splitB(W2); W2 region at offset W2OFF
#define W2OFF (48*384*32)
__global__ void splitB12_k(const float* __restrict__ W1, const float* __restrict__ W2,
                           uint2* __restrict__ H, uint2* __restrict__ L){
    const int p1 = 48*384*32;
    const int p2 = 192*96*32;
    int idx = blockIdx.x*256 + threadIdx.x;
    if (idx < p1) splitB_core(W1, H, L, idx, DD, FFD, 0);
    else if (idx < p1 + p2) splitB_core(W2, H + W2OFF, L + W2OFF, idx - p1, FFD, DD, 0);
}

// ---------------- cp.async helpers ----------------
__device__ __forceinline__ void cpasync16(void* smem, const void* gmem){
    unsigned s = (unsigned)__cvta_generic_to_shared(smem);
    asm volatile("cp.async.ca.shared.global [%0], [%1], 16;\n" :: "r"(s), "l"(gmem));
}
#define CP_COMMIT asm volatile("cp.async.commit_group;\n" ::: "memory")
#define CP_WAIT0  asm volatile("cp.async.wait_group 0;\n" ::: "memory")
#define CP_WAIT1  asm volatile("cp.async.wait_group 1;\n" ::: "memory")
#define CP_WAIT2  asm volatile("cp.async.wait_group 2;\n" ::: "memory")

// ---------------- fp16x2 tensor-core GEMM ----------------
__device__ __forceinline__ void mma16(float* d, const uint4& a, const uint2& b){
    asm volatile("mma.sync.aligned.m16n8k16.row.col.f32.f16.f16.f32 "
        "{%0,%1,%2,%3},{%4,%5,%6,%7},{%8,%9},{%0,%1,%2,%3};"
        : "+f"(d[0]),"+f"(d[1]),"+f"(d[2]),"+f"(d[3])
        : "r"(a.x),"r"(a.y),"r"(a.z),"r"(a.w),"r"(b.x),"r"(b.y));
}

// EPI: 0=bias->float, 1=bias+gelu->FRAGMENTS, 3=raw partial (k-split)
#define STG 24576
template<int EPI>
__global__ __launch_bounds__(256, 2) void gemm_tc(const uint4* __restrict__ Ah,
                                               const uint2* __restrict__ Bh,
                                               const uint2* __restrict__ Bl,
                                               const float* __restrict__ bias,
                                               const float* __restrict__ R,
                                               float* __restrict__ C,
                                               uint4* __restrict__ FH,
                                               int K16s, int nk16, int N){
    extern __shared__ char smem[];
    const int tid = threadIdx.x, lane = tid & 31, warp = tid >> 5;
    const int wm = warp >> 2, wn = warp & 3;
    const int bm = blockIdx.y, bn = blockIdx.x;
    const int kz = blockIdx.z * nk16;

    float acc[4][4][4];
    #pragma unroll
    for (int a=0;a<4;a++)
        #pragma unroll
        for (int b=0;b<4;b++)
            #pragma unroll
            for (int c=0;c<4;c++) acc[a][b][c]=0.f;

    auto stage_copy = [&](int s, int kb){
        char* base = smem + s*STG;
        #pragma unroll
        for (int i=0;i<2;i++){
            int e = tid + i*256;
            int ma = e>>6, ra = e&63;
            int ka = ra>>5, ln = ra&31;
            size_t ga = ((size_t)(bm*8+ma)*K16s + kz + kb + ka)*32 + ln;
            cpasync16(base + e*16, Ah + ga);
            int na = e>>5, rb = e&31;
            int kb2 = rb>>4, lp = rb&15;
            size_t gb = ((size_t)(bn*16+na)*K16s + kz + kb + kb2)*32 + lp*2;
            cpasync16(base + 8192 + e*16,  Bh + gb);
            cpasync16(base + 16384 + e*16, Bl + gb);
        }
    };

    const int nk = nk16 >> 1;
    stage_copy(0, 0); CP_COMMIT;
    if (nk > 1){ stage_copy(1, 2); CP_COMMIT; }
    if (nk > 2){ stage_copy(2, 4); CP_COMMIT; }

    for (int ks=0; ks<nk; ks++){
        int rem = nk - 1 - ks;
        if (rem >= 2)      { CP_WAIT2; }
        else if (rem == 1) { CP_WAIT1; }
        else               { CP_WAIT0; }
        __syncthreads();
        if (ks+3 < nk){ stage_copy((ks+3)&3, (ks+3)*2); CP_COMMIT; }
        const int st = ks & 3;
        const uint4* sAh = (const uint4*)(smem + st*STG);
        const uint2* sBh = (const uint2*)(smem + st*STG + 8192);
        const uint2* sBl = (const uint2*)(smem + st*STG + 16384);
        #pragma unroll
        for (int ka=0; ka<2; ka++){
            uint4 Afh[4];
            uint2 Bfh[4], Bfl[4];
            #pragma unroll
            for (int mi=0;mi<4;mi++){
                int off = ((wm*4+mi)*2 + ka)*32 + lane;
                Afh[mi] = sAh[off];
            }
            #pragma unroll
            for (int ni=0;ni<4;ni++){
                int off = ((wn*4+ni)*2 + ka)*32 + lane;
                Bfh[ni] = sBh[off];
                Bfl[ni] = sBl[off];
            }
            #pragma unroll
            for (int mi=0;mi<4;mi++)
                #pragma unroll
                for (int ni=0;ni<4;ni++){
                    mma16(acc[mi][ni], Afh[mi], Bfh[ni]);
                    mma16(acc[mi][ni], Afh[mi], Bfl[ni]);
                }
        }
    }

    const int g = lane>>2, l = lane&3;
    if (EPI==1){
        const int K16n = N >> 4;
        #pragma unroll
        for (int mi=0;mi<4;mi++){
            int am = bm*8 + wm*4 + mi;
            #pragma unroll
            for (int np=0;np<2;np++){
                float vv[2][4];
                #pragma unroll
                for (int half=0; half<2; half++){
                    int ni = 2*np + half;
                    int col = bn*128 + wn*32 + ni*8 + 2*l;
                    float b0 = bias[col], b1 = bias[col+1];
                    float v0 = acc[mi][ni][0]+b0, v1 = acc[mi][ni][1]+b1;
                    float v2 = acc[mi][ni][2]+b0, v3 = acc[mi][ni][3]+b1;
                    vv[half][0] = 0.5f*v0*(1.0f + erff(v0*0.70710678118654752f));
                    vv[half][1] = 0.5f*v1*(1.0f + erff(v1*0.70710678118654752f));
                    vv[half][2] = 0.5f*v2*(1.0f + erff(v2*0.70710678118654752f));
                    vv[half][3] = 0.5f*v3*(1.0f + erff(v3*0.70710678118654752f));
                }
                uint4 h;
                h.x = packh(vv[0][0], vv[0][1]);
                h.y = packh(vv[0][2], vv[0][3]);
                h.z = packh(vv[1][0], vv[1][1]);
                h.w = packh(vv[1][2], vv[1][3]);
                size_t ga = ((size_t)am*K16n + (bn*8 + wn*2 + np))*32 + lane;
                FH[ga] = h;
            }
        }
    } else {
        float* Cp = C;
        if (EPI==3) Cp = C + (size_t)blockIdx.z * (size_t)(gridDim.y*128) * N;
        #pragma unroll
        for (int mi=0;mi<4;mi++){
            int row = bm*128 + wm*64 + mi*16 + g;
            #pragma unroll
            for (int ni=0;ni<4;ni++){
                int col = bn*128 + wn*32 + ni*8 + 2*l;
                float b0 = (EPI==3) ? 0.f : bias[col];
                float b1 = (EPI==3) ? 0.f : bias[col+1];
                float v0 = acc[mi][ni][0]+b0, v1 = acc[mi][ni][1]+b1;
                float v2 = acc[mi][ni][2]+b0, v3 = acc[mi][ni][3]+b1;
                *(float2*)(Cp + (size_t)row*N + col)     = make_float2(v0, v1);
                *(float2*)(Cp + (size_t)(row+8)*N + col) = make_float2(v2, v3);
            }
        }
    }
}

// ---------------- k-split reduce (final output) ----------------
template<int S>
__global__ void reduceK_k(const float* __restrict__ P, const float* __restrict__ bias,
                          const float* __restrict__ R, float* __restrict__ C, int N){
    const size_t stride4 = (size_t)ROWS*DD/4;
    size_t i = (size_t)blockIdx.x*256 + threadIdx.x;
    if (i >= stride4) return;
    float4 a = ((const float4*)P)[i];
    #pragma unroll
    for (int s=1;s<S;s++){
        float4 b = ((const float4*)P)[s*stride4 + i];
        a.x+=b.x; a.y+=b.y; a.z+=b.z; a.w+=b.w;
    }
    int col4 = (int)(i % (N/4));
    float4 bb = ((const float4*)bias)[col4];
    float4 rr = ((const float4*)R)[i];
    a.x += bb.x + rr.x; a.y += bb.y + rr.y;
    a.z += bb.z + rr.z; a.w += bb.w + rr.w;
    ((float4*)C)[i] = a;
}

// ---------------- FAVOR+ feature maps: tensor-core version ----------------
// CTA: 32 tokens x 288 features. 8 warps: wm=warp&1 (m-atom), wg=warp>>1 (9 n-atoms).
// A (q rows) fp16 hi/lo built in-register; B (proj) fragments preloaded to smem.
#define FG_QS    0
#define FG_PBH   8704
#define FG_PBL   45568
#define FG_MISC  82432
#define FG_SMEM  (82432 + 1024)
__global__ __launch_bounds__(256, 2) void featgemm_tc(const float* __restrict__ QKV,
                                                      const uint2* __restrict__ PFH,
                                                      const uint2* __restrict__ PFL,
                                                      float* __restrict__ QP,
                                                      float* __restrict__ KP,
                                                      float* __restrict__ RM){
    extern __shared__ char fsm[];
    float* qs   = (float*)(fsm + FG_QS);        // [32][68]
    uint2* pbh  = (uint2*)(fsm + FG_PBH);       // 4608
    uint2* pbl  = (uint2*)(fsm + FG_PBL);       // 4608
    float* diag_s   = (float*)(fsm + FG_MISC);  // 32
    float* rowmax_s = diag_s + 32;              // 32
    float* pm       = rowmax_s + 32;            // [4][32]

    const int isK = blockIdx.z;
    const int bh = blockIdx.y;
    const int t0 = blockIdx.x*32;
    const int b = bh/HH, h = bh%HH;
    const int tid = threadIdx.x, lane = tid&31, warp = tid>>5;
    const int wm = warp & 1, wg = warp >> 1;
    const float* A = QKV + (size_t)(b*NN + t0)*QKVS + (isK ? DD : 0) + h*64;

    // loads: q tile (32x64 floats) + proj fragments (hi/lo)
    for (int i = tid; i < 512; i += 256){
        int tok = i>>4, c4 = (i&15)*4;
        cpasync16(&qs[tok*68 + c4], A + (size_t)tok*QKVS + c4);
    }
    for (int i = tid; i < 2304; i += 256){
        cpasync16(&pbh[i*2], PFH + i*2);
        cpasync16(&pbl[i*2], PFL + i*2);
    }
    CP_COMMIT; CP_WAIT0;
    __syncthreads();

    // diag: 8 threads per token
    {
        int tok = tid>>3, sl = tid&7;
        float ssq = 0.f;
        #pragma unroll
        for (int d=0; d<8; d++){ float q = qs[tok*68 + sl*8 + d]; ssq += q*q; }
        #pragma unroll
        for (int o=4;o;o>>=1) ssq += __shfl_xor_sync(0xffffffffu, ssq, o, 8);
        if (sl==0) diag_s[tok] = ssq*0.0625f;
    }

    const int g = lane>>2, l = lane&3;
    float acc[9][4];
    #pragma unroll
    for (int j=0;j<9;j++)
        #pragma unroll
        for (int q_=0;q_<4;q_++) acc[j][q_]=0.f;

    #pragma unroll
    for (int ak=0; ak<4; ak++){
        const float* r0 = &qs[(wm*16+g)*68 + ak*16];
        const float* r1 = &qs[(wm*16+g+8)*68 + ak*16];
        uint4 Ah_, Al_;
        pack2h(r0[2*l],   r0[2*l+1], Ah_.x, Al_.x);
        pack2h(r1[2*l],   r1[2*l+1], Ah_.y, Al_.y);
        pack2h(r0[2*l+8], r0[2*l+9], Ah_.z, Al_.z);
        pack2h(r1[2*l+8], r1[2*l+9], Ah_.w, Al_.w);
        #pragma unroll
        for (int j=0;j<9;j++){
            int atom = (wg*9+j)*4 + ak;
            uint2 Bh_ = pbh[atom*32 + lane];
            uint2 Bl_ = pbl[atom*32 + lane];
            mma16(acc[j], Ah_, Bh_);
            mma16(acc[j], Ah_, Bl_);
            mma16(acc[j], Al_, Bh_);
        }
    }

    // scale + masked row max
    float mx0 = -3.4e38f, mx1 = -3.4e38f;
    #pragma unroll
    for (int j=0;j<9;j++){
        #pragma unroll
        for (int q_=0;q_<4;q_++) acc[j][q_] *= DN_SCALE;
        int c0 = (wg*9+j)*8 + 2*l;
        if (c0 < MM)   { mx0 = fmaxf(mx0, acc[j][0]); mx1 = fmaxf(mx1, acc[j][2]); }
        if (c0+1 < MM) { mx0 = fmaxf(mx0, acc[j][1]); mx1 = fmaxf(mx1, acc[j][3]); }
    }
    #pragma unroll
    for (int o=1;o<=2;o<<=1){
        mx0 = fmaxf(mx0, __shfl_xor_sync(0xffffffffu, mx0, o));
        mx1 = fmaxf(mx1, __shfl_xor_sync(0xffffffffu, mx1, o));
    }
    if (l==0){
        pm[wg*32 + wm*16 + g]     = mx0;
        pm[wg*32 + wm*16 + 8 + g] = mx1;
    }
    __syncthreads();
    if (tid < 32){
        float m_ = fmaxf(fmaxf(pm[tid], pm[32+tid]), fmaxf(pm[64+tid], pm[96+tid]));
        rowmax_s[tid] = m_;
        if (isK){
            RM[bh*NN + t0 + tid] = m_;
            float bmv = m_;
            #pragma unroll
            for (int o=16;o;o>>=1) bmv = fmaxf(bmv, __shfl_xor_sync(0xffffffffu, bmv, o));
            if (tid==0) atomicMax(&g_kmax_u, enc_f(bmv));
        }
    }
    __syncthreads();

    float* OUT = (isK ? KP : QP) + ((size_t)(bh*NN + t0))*MP2;
    int tokA = wm*16 + g, tokB = tokA + 8;
    float dA = diag_s[tokA] + rowmax_s[tokA];
    float dB = diag_s[tokB] + rowmax_s[tokB];
    #pragma unroll
    for (int j=0;j<9;j++){
        int c0 = (wg*9+j)*8 + 2*l;
        float v0,v1,v2,v3;
        if (isK){
            v0 = (c0   < MM) ? __expf(acc[j][0]-dA) : 0.f;
            v1 = (c0+1 < MM) ? __expf(acc[j][1]-dA) : 0.f;
            v2 = (c0   < MM) ? __expf(acc[j][2]-dB) : 0.f;
            v3 = (c0+1 < MM) ? __expf(acc[j][3]-dB) : 0.f;
        } else {
            v0 = (c0   < MM) ? RATIO_SC*(__expf(acc[j][0]-dA)+EPS_KER) : 0.f;
            v1 = (c0+1 < MM) ? RATIO_SC*(__expf(acc[j][1]-dA)+EPS_KER) : 0.f;
            v2 = (c0   < MM) ? RATIO_SC*(__expf(acc[j][2]-dB)+EPS_KER) : 0.f;
            v3 = (c0+1 < MM) ? RATIO_SC*(__expf(acc[j][3]-dB)+EPS_KER) : 0.f;
        }
        *(float2*)(OUT + (size_t)tokA*MP2 + c0) = make_float2(v0,v1);
        *(float2*)(OUT + (size_t)tokB*MP2 + c0) = make_float2(v2,v3);
    }
}

// ---------------- chunked causal linear attention ----------------
__global__ __launch_bounds__(512) void chunksum_k(const float* __restrict__ KP,
                                                  const float* __restrict__ QKV,
                                                  const float* __restrict__ RM,
                                                  float* __restrict__ Z,
                                                  float* __restrict__ KV){
    int bhc = blockIdx.x;
    int bh = bhc / NC, c = bhc % NC;
    int b = bh / HH, h = bh % HH;
    int tid = threadIdx.x, g = tid>>6, e = tid&63;
    const int m0 = g*GM;
    __shared__ __align__(16) float kt[2][TT][MP2];
    __shared__ __align__(16) float vt[2][TT][64];
    __shared__ float scs[CHK];
    float S[GM];
    #pragma unroll
    for (int i=0;i<GM;i++) S[i]=0.f;
    float zacc = 0.f;
    const float* kb = KP + ((size_t)bh*NN + c*CHK)*MP2;
    const float* vb = QKV + (size_t)(b*NN + c*CHK)*QKVS + 2*DD + h*64;

    float gmax = dec_f(g_kmax_u);
    for (int i=tid; i<CHK; i+=512)
        scs[i] = __expf(RM[bh*NN + c*CHK + i] - gmax);

    auto load = [&](int buf, int tile){
        const float* kb_ = kb + (size_t)tile*TT*MP2;
        const float* vb_ = vb + (size_t)tile*TT*QKVS;
        for (int idx=tid; idx<704; idx+=512){
            if (idx < 576){ int tok=idx/72, f=(idx%72)*4; cpasync16(&kt[buf][tok][f], kb_ + (size_t)tok*MP2 + f); }
            else { int r=idx-576; int tok=r/16, f=(r%16)*4; cpasync16(&vt[buf][tok][f], vb_ + (size_t)tok*QKVS + f); }
        }
    };
    load(0,0); CP_COMMIT;
    for (int tile=0; tile<NTILE; tile++){
        int buf = tile&1;
        CP_WAIT0;
        __syncthreads();
        if (tile+1 < NTILE) load(buf^1, tile+1);
        CP_COMMIT;
        {
            const int tb = tile*TT;
            for (int idx=tid; idx<TT*MP2; idx+=512){
                int tok = idx/MP2, m = idx - tok*MP2;
                float f = kt[buf][tok][m];
                kt[buf][tok][m] = (m < MM) ? RATIO_SC*(f*scs[tb+tok] + EPS_KER) : 0.f;
            }
        }
        __syncthreads();
        #pragma unroll
        for (int tt=0; tt<TT; tt++){
            float vv = vt[buf][tt][e];
            const float4* kr = (const float4*)(&kt[buf][tt][m0]);
            #pragma unroll
            for (int i4=0;i4<9;i4++){
                float4 kk = kr[i4];
                S[i4*4+0] += kk.x*vv;
                S[i4*4+1] += kk.y*vv;
                S[i4*4+2] += kk.z*vv;
                S[i4*4+3] += kk.w*vv;
            }
            if (tid < MP2) zacc += kt[buf][tt][tid];
        }
    }
    if (tid < MP2) Z[(size_t)bhc*MP2 + tid] = zacc;
    float* kvout = KV + (size_t)bhc*KVSTRIDE;
    #pragma unroll
    for (int i=0;i<GM;i++) kvout[(size_t)(m0+i)*64 + e] = S[i];
}

__global__ __launch_bounds__(512) void prefix_k(float* __restrict__ Z, float* __restrict__ KV){
    int bh = blockIdx.y;
    int base = bh*NC;
    int idx = blockIdx.x*512 + threadIdx.x;
    float run = 0.f;
    #pragma unroll
    for (int c=0;c<NC;c++){
        float* p = KV + (size_t)(base+c)*KVSTRIDE + idx;
        float t = *p; *p = run; run += t;
    }
    if (blockIdx.x==0 && threadIdx.x < MP2){
        float rz = 0.f;
        #pragma unroll
        for (int c=0;c<NC;c++){
            float* p = Z + (size_t)(base+c)*MP2 + threadIdx.x;
            float t = *p; *p = rz; rz += t;
        }
    }
}

// chunkout with dynamic smem + batched per-tile reductions
#define CO_KT(b,t,m)  dsm[((b)*TT+(t))*MP2+(m)]
#define CO_QT(b,t,m)  dsm[QOFF + ((b)*TT+(t))*MP2+(m)]
#define CO_VT(b,t,e)  dsm[VOFF + ((b)*TT+(t))*64+(e)]
#define CO_PART(t,g,e) dsm[POFF + ((t)*8+(g))*64+(e)]
#define CO_DRED(t,w)  dsm[DOFF + (t)*16+(w)]
#define CO_SCS(i)     dsm[SOFF + (i)]
#define QOFF (2*TT*MP2)
#define VOFF (4*TT*MP2)
#define POFF (4*TT*MP2 + 2*TT*64)
#define DOFF (POFF + TT*8*64)
#define SOFF (DOFF + TT*16)
#define CO_SMEM ((SOFF + CHK)*4)

__global__ __launch_bounds__(512) void chunkout_k(const float* __restrict__ QP,
                                                  const float* __restrict__ KP,
                                                  const float* __restrict__ QKV,
                                                  const float* __restrict__ RM,
                                                  const float* __restrict__ Z,
                                                  const float* __restrict__ KV,
                                                  float* __restrict__ O){
    extern __shared__ __align__(16) float dsm[];
    int bhc = blockIdx.x;
    int bh = bhc / NC, c = bhc % NC;
    int b = bh / HH, h = bh % HH;
    int tid = threadIdx.x, g = tid>>6, e = tid&63;
    const int m0 = g*GM;

    float S[GM];
    const float* kvin = KV + (size_t)bhc*KVSTRIDE;
    #pragma unroll
    for (int i=0;i<GM;i++) S[i] = kvin[(size_t)(m0+i)*64 + e];
    float zreg = (tid < MP2) ? Z[(size_t)bhc*MP2 + tid] : 0.f;

    const float* kb = KP + ((size_t)bh*NN + c*CHK)*MP2;
    const float* qb = QP + ((size_t)bh*NN + c*CHK)*MP2;
    const float* vb = QKV + (size_t)(b*NN + c*CHK)*QKVS + 2*DD + h*64;

    float gmax = dec_f(g_kmax_u);
    for (int i=tid; i<CHK; i+=512)
        CO_SCS(i) = __expf(RM[bh*NN + c*CHK + i] - gmax);

    auto load = [&](int buf, int tile){
        const float* kb_ = kb + (size_t)tile*TT*MP2;
        const float* qb_ = qb + (size_t)tile*TT*MP2;
        const float* vb_ = vb + (size_t)tile*TT*QKVS;
        for (int idx=tid; idx<1280; idx+=512){
            if (idx < 576){ int tok=idx/72, f=(idx%72)*4; cpasync16(&CO_KT(buf,tok,f), kb_ + (size_t)tok*MP2 + f); }
            else if (idx < 1152){ int r=idx-576; int tok=r/72, f=(r%72)*4; cpasync16(&CO_QT(buf,tok,f), qb_ + (size_t)tok*MP2 + f); }
            else { int r=idx-1152; int tok=r/16, f=(r%16)*4; cpasync16(&CO_VT(buf,tok,f), vb_ + (size_t)tok*QKVS + f); }
        }
    };
    load(0,0); CP_COMMIT;

    for (int tile=0; tile<NTILE; tile++){
        int buf = tile&1;
        CP_WAIT0;
        __syncthreads();
        if (tile+1 < NTILE) load(buf^1, tile+1);
        CP_COMMIT;
        {
            const int tb = tile*TT;
            for (int idx=tid; idx<TT*MP2; idx+=512){
                int tok = idx/MP2, m = idx - tok*MP2;
                float f = CO_KT(buf,tok,m);
                CO_KT(buf,tok,m) = (m < MM) ? RATIO_SC*(f*CO_SCS(tb+tok) + EPS_KER) : 0.f;
            }
        }
        __syncthreads();
        #pragma unroll
        for (int tt=0; tt<TT; tt++){
            float vv = CO_VT(buf,tt,e);
            const float4* kr = (const float4*)(&CO_KT(buf,tt,m0));
            const float4* qr = (const float4*)(&CO_QT(buf,tt,m0));
            float acc = 0.f;
            #pragma unroll
            for (int i4=0;i4<9;i4++){
                float4 kk = kr[i4];
                float4 qq = qr[i4];
                S[i4*4+0] += kk.x*vv;  acc += qq.x*S[i4*4+0];
                S[i4*4+1] += kk.y*vv;  acc += qq.y*S[i4*4+1];
                S[i4*4+2] += kk.z*vv;  acc += qq.z*S[i4*4+2];
                S[i4*4+3] += kk.w*vv;  acc += qq.w*S[i4*4+3];
            }
            CO_PART(tt,g,e) = acc;
        }
        if (tid < MP2){
            float dp[TT];
            #pragma unroll
            for (int tt=0; tt<TT; tt++){
                float kv = CO_KT(buf,tt,tid);
                zreg += kv;
                dp[tt] = CO_QT(buf,tt,tid)*(zreg + EPS_DEN);
            }
            #pragma unroll
            for (int tt=0; tt<TT; tt++){
                float d = dp[tt];
                #pragma unroll
                for (int o=16;o;o>>=1) d += __shfl_xor_sync(0xffffffffu, d, o);
                if ((tid&31)==0) CO_DRED(tt, tid>>5) = d;
            }
        }
        __syncthreads();
        {
            int tok = tid>>6, e2 = tid&63;
            float s = 0.f;
            #pragma unroll
            for (int gg=0; gg<8; gg++) s += CO_PART(tok,gg,e2);
            float den = 0.f;
            #pragma unroll
            for (int w=0; w<9; w++) den += CO_DRED(tok,w);
            int t = c*CHK + tile*TT + tok;
            O[((size_t)(b*NN + t))*DD + h*64 + e2] = s / den;
        }
    }
}

// ---------------- launch ----------------
#define GEMM_SMEM (4*STG)

extern "C" void kernel_launch(void* const* d_in, const int* in_sizes, int n_in,
                              void* d_out, int out_size){
    (void)in_sizes; (void)n_in; (void)out_size;
    const float* x    = (const float*)d_in[0];
    const float* ln1g = (const float*)d_in[1];
    const float* ln1b = (const float*)d_in[2];
    const float* Wq   = (const float*)d_in[3];
    const float* bq   = (const float*)d_in[4];
    const float* Wk   = (const float*)d_in[5];
    const float* bk   = (const float*)d_in[6];
    const float* Wv   = (const float*)d_in[7];
    const float* bv   = (const float*)d_in[8];
    const float* Wo   = (const float*)d_in[9];
    const float* bo   = (const float*)d_in[10];
    const float* proj = (const float*)d_in[11];
    const float* ln2g = (const float*)d_in[12];
    const float* ln2b = (const float*)d_in[13];
    const float* W1   = (const float*)d_in[14];
    const float* b1   = (const float*)d_in[15];
    const float* W2   = (const float*)d_in[16];
    const float* b2   = (const float*)d_in[17];
    float* out = (float*)d_out;

    float *qkv,*qp,*kp,*rm,*o,*x1,*zz,*kv,*bqkv,*part;
    uint4 *afh,*af2h;
    uint2 *wfh,*wfl,*pfh,*pfl;
    cudaGetSymbolAddress((void**)&qkv, g_qkv);
    cudaGetSymbolAddress((void**)&qp,  g_qp);
    cudaGetSymbolAddress((void**)&kp,  g_kp);
    cudaGetSymbolAddress((void**)&rm,  g_rm);
    cudaGetSymbolAddress((void**)&o,   g_o);
    cudaGetSymbolAddress((void**)&x1,  g_x1);
    cudaGetSymbolAddress((void**)&zz,  g_Z);
    cudaGetSymbolAddress((void**)&kv,  g_KV);
    cudaGetSymbolAddress((void**)&bqkv,g_bqkv);
    cudaGetSymbolAddress((void**)&part,g_part);
    cudaGetSymbolAddress((void**)&afh, g_afh);
    cudaGetSymbolAddress((void**)&af2h,g_af2h);
    cudaGetSymbolAddress((void**)&wfh, g_wfh);
    cudaGetSymbolAddress((void**)&wfl, g_wfl);
    cudaGetSymbolAddress((void**)&pfh, g_pfh);
    cudaGetSymbolAddress((void**)&pfl, g_pfl);

    cudaFuncSetAttribute(gemm_tc<0>, cudaFuncAttributeMaxDynamicSharedMemorySize, GEMM_SMEM);
    cudaFuncSetAttribute(gemm_tc<1>, cudaFuncAttributeMaxDynamicSharedMemorySize, GEMM_SMEM);
    cudaFuncSetAttribute(gemm_tc<3>, cudaFuncAttributeMaxDynamicSharedMemorySize, GEMM_SMEM);
    cudaFuncSetAttribute(chunkout_k, cudaFuncAttributeMaxDynamicSharedMemorySize, CO_SMEM);
    cudaFuncSetAttribute(fusedln_k,  cudaFuncAttributeMaxDynamicSharedMemorySize, FLN_SMEM);
    cudaFuncSetAttribute(featgemm_tc, cudaFuncAttributeMaxDynamicSharedMemorySize, FG_SMEM);

    // 1: weight split + bias pack + kmax init + proj fragments
    splitB3_k<<<1750,256>>>(Wq, Wk, Wv, wfh, wfl, bq, bk, bv, bqkv, proj, pfh, pfl);
    // 2: LN1 -> fp16 fragments
    lnfrag_k<<<ROWS/16,256>>>(x, ln1g, ln1b, afh);
    // 3: QKV fused GEMM
    {
        dim3 gq(QKVS/128, ROWS/128);
        gemm_tc<0><<<gq,256,GEMM_SMEM>>>(afh, wfh, wfl, bqkv, nullptr, qkv,
                                         nullptr, DD/16, DD/16, QKVS);
    }
    // 4: feature maps (tensor-core)
    {
        dim3 gfeat(NN/32, BH, 2);
        featgemm_tc<<<gfeat,256,FG_SMEM>>>(qkv, pfh, pfl, qp, kp, rm);
    }
    // 5-7: scan
    chunksum_k<<<NCH,512>>>(kp, qkv, rm, zz, kv);
    {
        dim3 gp(KVSTRIDE/512, BH);
        prefix_k<<<gp,512>>>(zz, kv);
    }
    chunkout_k<<<NCH,512,CO_SMEM>>>(qp, kp, qkv, rm, zz, kv, o);
    // 8: split o + Wo
    splitAB_k<<<2112,256>>>(o, Wo, afh, wfh, wfl);
    // 9: Wo GEMM (k-split x2)
    {
        dim3 gg(DD/128, ROWS/128, 2);
        gemm_tc<3><<<gg,256,GEMM_SMEM>>>(afh, wfh, wfl, nullptr, nullptr, part,
                                         nullptr, DD/16, DD/32, DD);
    }
    // 10: fused reduce + residual + LN2 + fragment emit
    fusedln_k<<<ROWS/16,256,FLN_SMEM>>>(part, bo, x, x1, ln2g, ln2b, afh);
    // 11: split W1 + W2
    splitB12_k<<<4608,256>>>(W1, W2, wfh, wfl);
    // 12: W1 GEMM + gelu -> fragments
    {
        dim3 gg(FFD/128, ROWS/128);
        gemm_tc<1><<<gg,256,GEMM_SMEM>>>(afh, wfh, wfl, b1, nullptr, nullptr,
                                         af2h, DD/16, DD/16, FFD);
    }
    // 13: W2 GEMM (k-split x4)
    {
        dim3 gg(DD/128, ROWS/128, 4);
        gemm_tc<3><<<gg,256,GEMM_SMEM>>>(af2h, wfh + W2OFF, wfl + W2OFF, nullptr, nullptr, part,
                                         nullptr, FFD/16, FFD/64, DD);
    }
    // 14: final reduce + bias + residual
    reduceK_k<4><<<(ROWS*DD/4+255)/256,256>>>(part, b2, x1, out, DD);
}

// round 17
// speedup vs baseline: 12.2710x; 1.0006x over previous
#include <cuda_runtime.h>
#include <cuda_bf16.h>
#include <cuda_fp16.h>
#include <math.h>
#include <stdint.h>

// ---------------- problem constants ----------------
#define BB   2
#define NN   2048
#define DD   768
#define HH   12
#define MM   266
#define MP2  288
#define GM   36
#define FFD  3072
#define ROWS (BB*NN)
#define RIDS (BB*HH*NN)
#define BH   (BB*HH)
#define CHK  128
#define NC   (NN/CHK)
#define NCH  (BH*NC)
#define TT   8
#define NTILE (CHK/TT)
#define KVSTRIDE (MP2*64)
#define QKVS 2304

#define DN_SCALE   0.35355339059327f
#define RATIO_SC   0.061313689f
#define EPS_KER    1e-4f
#define EPS_DEN    1e-6f

// ---------------- scratch ----------------
__device__ float g_qkv[(size_t)ROWS*QKVS];
__device__ float g_o [ROWS*DD];
__device__ float g_x1[ROWS*DD];
__device__ float g_qp[(size_t)RIDS*MP2];
__device__ float g_kp[(size_t)RIDS*MP2];
__device__ float g_rm[RIDS];
__device__ float g_Z [(size_t)NCH*MP2];
__device__ float g_KV[(size_t)NCH*KVSTRIDE];
__device__ unsigned g_kmax_u;
__device__ float g_bqkv[QKVS];
__device__ float g_part[(size_t)4*ROWS*DD];
// fp16 operand buffers (A: hi only; B: hi+lo)
__device__ uint4 g_afh[(size_t)(ROWS/16)*(DD/16)*32];
__device__ uint4 g_af2h[(size_t)(ROWS/16)*(FFD/16)*32];
__device__ uint2 g_wfh[(size_t)(FFD/16)*(FFD/8)*32];
__device__ uint2 g_wfl[(size_t)(FFD/16)*(FFD/8)*32];
// proj B-fragments (36 n-atoms x 4 k-atoms x 32 lanes), hi+lo
__device__ uint2 g_pfh[36*4*32];
__device__ uint2 g_pfl[36*4*32];

__device__ __forceinline__ unsigned enc_f(float f){
    unsigned u = __float_as_uint(f);
    return (u & 0x80000000u) ? ~u : (u | 0x80000000u);
}
__device__ __forceinline__ float dec_f(unsigned u){
    return (u & 0x80000000u) ? __uint_as_float(u ^ 0x80000000u) : __uint_as_float(~u);
}

// fp16 pack helpers
__device__ __forceinline__ unsigned packh(float x, float y){
    __half2 hv = __floats2half2_rn(x, y);
    return *reinterpret_cast<unsigned*>(&hv);
}
__device__ __forceinline__ void pack2h(float x, float y, unsigned &h, unsigned &l){
    __half2 hv = __floats2half2_rn(x, y);
    float hx = __low2float(hv), hy = __high2float(hv);
    __half2 lv = __floats2half2_rn(x - hx, y - hy);
    h = *reinterpret_cast<unsigned*>(&hv);
    l = *reinterpret_cast<unsigned*>(&lv);
}

// ---------------- LayerNorm emitting A-hi fragments (16 rows/CTA) ----------------
__global__ __launch_bounds__(256) void lnfrag_k(const float* __restrict__ X,
                                                const float* __restrict__ G,
                                                const float* __restrict__ Bv,
                                                uint4* __restrict__ H){
    const int blk = blockIdx.x;
    const int tid = threadIdx.x;
    const int r = tid >> 4, c16 = tid & 15;
    __shared__ float mu_s[16], rs_s[16];
    const float* xr = X + ((size_t)blk*16 + r)*DD;
    float s = 0.f, ss = 0.f;
    #pragma unroll
    for (int j=0;j<12;j++){
        float4 v = *(const float4*)(xr + c16*4 + j*64);
        s  += v.x+v.y+v.z+v.w;
        ss += v.x*v.x+v.y*v.y+v.z*v.z+v.w*v.w;
    }
    #pragma unroll
    for (int o=8;o;o>>=1){
        s  += __shfl_xor_sync(0xffffffffu, s, o, 16);
        ss += __shfl_xor_sync(0xffffffffu, ss, o, 16);
    }
    if (c16==0){
        float mu = s*(1.0f/DD);
        float var = ss*(1.0f/DD) - mu*mu;
        mu_s[r]=mu; rs_s[r]=rsqrtf(var + 1e-5f);
    }
    __syncthreads();
    #pragma unroll
    for (int i=0;i<6;i++){
        int it = tid + i*256;
        int ak = it>>5, lane = it&31;
        int g = lane>>2, l = lane&3;
        float mu0 = mu_s[g],  r0 = rs_s[g];
        float mu1 = mu_s[g+8],r1 = rs_s[g+8];
        int c = ak*16 + 2*l;
        const float* row0 = X + ((size_t)blk*16 + g)*DD;
        const float* row1 = X + ((size_t)blk*16 + g + 8)*DD;
        float2 ga = *(const float2*)(G + c),  gb = *(const float2*)(G + c + 8);
        float2 ba = *(const float2*)(Bv + c), bb = *(const float2*)(Bv + c + 8);
        float2 v0 = *(const float2*)(row0 + c);
        float2 v1 = *(const float2*)(row1 + c);
        float2 v2 = *(const float2*)(row0 + c + 8);
        float2 v3 = *(const float2*)(row1 + c + 8);
        uint4 h;
        h.x = packh((v0.x-mu0)*r0*ga.x+ba.x, (v0.y-mu0)*r0*ga.y+ba.y);
        h.y = packh((v1.x-mu1)*r1*ga.x+ba.x, (v1.y-mu1)*r1*ga.y+ba.y);
        h.z = packh((v2.x-mu0)*r0*gb.x+bb.x, (v2.y-mu0)*r0*gb.y+bb.y);
        h.w = packh((v3.x-mu1)*r1*gb.x+bb.x, (v3.y-mu1)*r1*gb.y+bb.y);
        size_t gidx = ((size_t)blk*48 + ak)*32 + lane;
        H[gidx]=h;
    }
}

// ---------------- fused k-split reduce + residual + LN2 + fragment emit ----------------
#define SXS 772
#define FLN_SMEM ((16*SXS + 32)*4)
__global__ __launch_bounds__(256) void fusedln_k(const float* __restrict__ P,
                                                 const float* __restrict__ bias,
                                                 const float* __restrict__ xres,
                                                 float* __restrict__ X1,
                                                 const float* __restrict__ G,
                                                 const float* __restrict__ Bv,
                                                 uint4* __restrict__ H){
    extern __shared__ float sx[];
    float* mu_s = sx + 16*SXS;
    float* rs_s = mu_s + 16;
    const int blk = blockIdx.x, tid = threadIdx.x;
    const int r = tid >> 4, c16 = tid & 15;
    const size_t stride = (size_t)ROWS*DD;
    const size_t rowoff = ((size_t)blk*16 + r)*DD;
    float s = 0.f, ss = 0.f;
    #pragma unroll
    for (int j=0;j<12;j++){
        int col = c16*4 + j*64;
        float4 p0 = *(const float4*)(P + rowoff + col);
        float4 p1 = *(const float4*)(P + stride + rowoff + col);
        float4 rr = *(const float4*)(xres + rowoff + col);
        float4 bb = *(const float4*)(bias + col);
        float4 v;
        v.x = p0.x+p1.x+rr.x+bb.x; v.y = p0.y+p1.y+rr.y+bb.y;
        v.z = p0.z+p1.z+rr.z+bb.z; v.w = p0.w+p1.w+rr.w+bb.w;
        *(float4*)(X1 + rowoff + col) = v;
        *(float4*)(sx + r*SXS + col) = v;
        s  += v.x+v.y+v.z+v.w;
        ss += v.x*v.x+v.y*v.y+v.z*v.z+v.w*v.w;
    }
    #pragma unroll
    for (int o=8;o;o>>=1){
        s  += __shfl_xor_sync(0xffffffffu, s, o, 16);
        ss += __shfl_xor_sync(0xffffffffu, ss, o, 16);
    }
    if (c16==0){
        float mu = s*(1.0f/DD);
        float var = ss*(1.0f/DD) - mu*mu;
        mu_s[r]=mu; rs_s[r]=rsqrtf(var + 1e-5f);
    }
    __syncthreads();
    #pragma unroll
    for (int i=0;i<6;i++){
        int it = tid + i*256;
        int ak = it>>5, lane = it&31;
        int g = lane>>2, l = lane&3;
        float mu0 = mu_s[g],  r0 = rs_s[g];
        float mu1 = mu_s[g+8],r1 = rs_s[g+8];
        int c = ak*16 + 2*l;
        const float* row0 = sx + g*SXS;
        const float* row1 = sx + (g+8)*SXS;
        float2 ga = *(const float2*)(G + c),  gb = *(const float2*)(G + c + 8);
        float2 ba = *(const float2*)(Bv + c), bb = *(const float2*)(Bv + c + 8);
        float2 v0 = *(const float2*)(row0 + c);
        float2 v1 = *(const float2*)(row1 + c);
        float2 v2 = *(const float2*)(row0 + c + 8);
        float2 v3 = *(const float2*)(row1 + c + 8);
        uint4 h;
        h.x = packh((v0.x-mu0)*r0*ga.x+ba.x, (v0.y-mu0)*r0*ga.y+ba.y);
        h.y = packh((v1.x-mu1)*r1*ga.x+ba.x, (v1.y-mu1)*r1*ga.y+ba.y);
        h.z = packh((v2.x-mu0)*r0*gb.x+bb.x, (v2.y-mu0)*r0*gb.y+bb.y);
        h.w = packh((v3.x-mu1)*r1*gb.x+bb.x, (v3.y-mu1)*r1*gb.y+bb.y);
        size_t gidx = ((size_t)blk*48 + ak)*32 + lane;
        H[gidx]=h;
    }
}

// ---------------- fp16 split cores ----------------
__device__ __forceinline__ void splitA_core(const float* __restrict__ X,
                                            uint4* __restrict__ H,
                                            int idx, int R, int C){
    int K16 = C>>4;
    int lane = idx & 31, atom = idx >> 5;
    int am = atom / K16, ak = atom % K16;
    int g = lane>>2, l = lane&3;
    const float* p = X + (size_t)(am*16+g)*C + ak*16 + 2*l;
    float2 v0 = *(const float2*)(p);
    float2 v1 = *(const float2*)(p + (size_t)8*C);
    float2 v2 = *(const float2*)(p + 8);
    float2 v3 = *(const float2*)(p + (size_t)8*C + 8);
    uint4 h;
    h.x = packh(v0.x, v0.y);
    h.y = packh(v1.x, v1.y);
    h.z = packh(v2.x, v2.y);
    h.w = packh(v3.x, v3.y);
    H[idx] = h;
}

__device__ __forceinline__ void splitB_core(const float* __restrict__ W,
                                            uint2* __restrict__ H, uint2* __restrict__ L,
                                            int idx, int K, int N, int anBase){
    int lane = idx & 31, atom = idx >> 5;
    int K16 = K>>4;
    int an = atom / K16, ak = atom % K16;
    int g = lane>>2, l = lane&3;
    const float* p = W + (size_t)(ak*16 + 2*l)*N + an*8 + g;
    float b00 = p[0],            b01 = p[N];
    float b10 = p[(size_t)8*N],  b11 = p[(size_t)9*N];
    uint2 h, lo;
    pack2h(b00, b01, h.x, lo.x);
    pack2h(b10, b11, h.y, lo.y);
    int outi = ((anBase + an)*K16 + ak)*32 + lane;
    H[outi] = h; L[outi] = lo;
}

// merged QKV weight split + bias pack + kmax init + proj B-fragment split
__global__ void splitB3_k(const float* __restrict__ Wq, const float* __restrict__ Wk,
                          const float* __restrict__ Wv, uint2* __restrict__ H,
                          uint2* __restrict__ L,
                          const float* __restrict__ bq, const float* __restrict__ bk,
                          const float* __restrict__ bv, float* __restrict__ bo,
                          const float* __restrict__ proj,
                          uint2* __restrict__ pfh, uint2* __restrict__ pfl){
    const int per = (DD>>4)*(DD>>3)*32;   // 147456
    const int pstart = 3*per + DD + 1;
    int idx = blockIdx.x*256 + threadIdx.x;
    if (idx < 3*per){
        int which = idx / per, rem = idx - which*per;
        const float* W = (which==0)?Wq:(which==1)?Wk:Wv;
        splitB_core(W, H, L, rem, DD, DD, which*(DD>>3));
    } else if (idx < 3*per + DD){
        int i = idx - 3*per;
        bo[i]=bq[i]; bo[DD+i]=bk[i]; bo[2*DD+i]=bv[i];
    } else if (idx == 3*per + DD){
        g_kmax_u = 0x00800000u;
    } else if (idx < pstart + 36*4*32){
        int i2 = idx - pstart;
        int lane = i2 & 31, atom = i2 >> 5;
        int an = atom >> 2, ak = atom & 3;
        int g = lane>>2, l = lane&3;
        int n = an*8 + g;
        float b00=0.f,b01=0.f,b10=0.f,b11=0.f;
        if (n < MM){
            const float* p = proj + (size_t)n*64 + ak*16 + 2*l;
            b00=p[0]; b01=p[1]; b10=p[8]; b11=p[9];
        }
        uint2 h, lo;
        pack2h(b00,b01,h.x,lo.x);
        pack2h(b10,b11,h.y,lo.y);
        pfh[atom*32+lane]=h; pfl[atom*32+lane]=lo;
    }
}

// merged splitA(o) + splitB(Wo)
__global__ void splitAB_k(const float* __restrict__ O, const float* __restrict__ Wo,
                          uint4* __restrict__ AHo, uint2* __restrict__ BHo,
                          uint2* __restrict__ BLo){
    const int atot = (ROWS/16)*(DD/16)*32;
    const int btot = (DD>>4)*(DD>>3)*32;
    int idx = blockIdx.x*256 + threadIdx.x;
    if (idx < atot) splitA_core(O, AHo, idx, ROWS, DD);
    else if (idx < atot + btot) splitB_core(Wo, BHo, BLo, idx - atot, DD, DD, 0);
}

// merged splitB(W1) + splitB(W2); W2 region at offset W2OFF
#define W2OFF (48*384*32)
__global__ void splitB12_k(const float* __restrict__ W1, const float* __restrict__ W2,
                           uint2* __restrict__ H, uint2* __restrict__ L){
    const int p1 = 48*384*32;
    const int p2 = 192*96*32;
    int idx = blockIdx.x*256 + threadIdx.x;
    if (idx < p1) splitB_core(W1, H, L, idx, DD, FFD, 0);
    else if (idx < p1 + p2) splitB_core(W2, H + W2OFF, L + W2OFF, idx - p1, FFD, DD, 0);
}

// ---------------- cp.async helpers ----------------
__device__ __forceinline__ void cpasync16(void* smem, const void* gmem){
    unsigned s = (unsigned)__cvta_generic_to_shared(smem);
    asm volatile("cp.async.ca.shared.global [%0], [%1], 16;\n" :: "r"(s), "l"(gmem));
}
#define CP_COMMIT asm volatile("cp.async.commit_group;\n" ::: "memory")
#define CP_WAIT0  asm volatile("cp.async.wait_group 0;\n" ::: "memory")
#define CP_WAIT1  asm volatile("cp.async.wait_group 1;\n" ::: "memory")
#define CP_WAIT2  asm volatile("cp.async.wait_group 2;\n" ::: "memory")

// ---------------- fp16x2 tensor-core GEMM ----------------
__device__ __forceinline__ void mma16(float* d, const uint4& a, const uint2& b){
    asm volatile("mma.sync.aligned.m16n8k16.row.col.f32.f16.f16.f32 "
        "{%0,%1,%2,%3},{%4,%5,%6,%7},{%8,%9},{%0,%1,%2,%3};"
        : "+f"(d[0]),"+f"(d[1]),"+f"(d[2]),"+f"(d[3])
        : "r"(a.x),"r"(a.y),"r"(a.z),"r"(a.w),"r"(b.x),"r"(b.y));
}

// EPI: 0=bias->float, 1=bias+gelu->FRAGMENTS, 3=raw partial (k-split)
#define STG 24576
template<int EPI>
__global__ __launch_bounds__(256, 2) void gemm_tc(const uint4* __restrict__ Ah,
                                               const uint2* __restrict__ Bh,
                                               const uint2* __restrict__ Bl,
                                               const float* __restrict__ bias,
                                               const float* __restrict__ R,
                                               float* __restrict__ C,
                                               uint4* __restrict__ FH,
                                               int K16s, int nk16, int N){
    extern __shared__ char smem[];
    const int tid = threadIdx.x, lane = tid & 31, warp = tid >> 5;
    const int wm = warp >> 2, wn = warp & 3;
    const int bm = blockIdx.y, bn = blockIdx.x;
    const int kz = blockIdx.z * nk16;

    float acc[4][4][4];
    #pragma unroll
    for (int a=0;a<4;a++)
        #pragma unroll
        for (int b=0;b<4;b++)
            #pragma unroll
            for (int c=0;c<4;c++) acc[a][b][c]=0.f;

    auto stage_copy = [&](int s, int kb){
        char* base = smem + s*STG;
        #pragma unroll
        for (int i=0;i<2;i++){
            int e = tid + i*256;
            int ma = e>>6, ra = e&63;
            int ka = ra>>5, ln = ra&31;
            size_t ga = ((size_t)(bm*8+ma)*K16s + kz + kb + ka)*32 + ln;
            cpasync16(base + e*16, Ah + ga);
            int na = e>>5, rb = e&31;
            int kb2 = rb>>4, lp = rb&15;
            size_t gb = ((size_t)(bn*16+na)*K16s + kz + kb + kb2)*32 + lp*2;
            cpasync16(base + 8192 + e*16,  Bh + gb);
            cpasync16(base + 16384 + e*16, Bl + gb);
        }
    };

    const int nk = nk16 >> 1;
    stage_copy(0, 0); CP_COMMIT;
    if (nk > 1){ stage_copy(1, 2); CP_COMMIT; }
    if (nk > 2){ stage_copy(2, 4); CP_COMMIT; }

    for (int ks=0; ks<nk; ks++){
        int rem = nk - 1 - ks;
        if (rem >= 2)      { CP_WAIT2; }
        else if (rem == 1) { CP_WAIT1; }
        else               { CP_WAIT0; }
        __syncthreads();
        if (ks+3 < nk){ stage_copy((ks+3)&3, (ks+3)*2); CP_COMMIT; }
        const int st = ks & 3;
        const uint4* sAh = (const uint4*)(smem + st*STG);
        const uint2* sBh = (const uint2*)(smem + st*STG + 8192);
        const uint2* sBl = (const uint2*)(smem + st*STG + 16384);
        #pragma unroll
        for (int ka=0; ka<2; ka++){
            uint4 Afh[4];
            uint2 Bfh[4], Bfl[4];
            #pragma unroll
            for (int mi=0;mi<4;mi++){
                int off = ((wm*4+mi)*2 + ka)*32 + lane;
                Afh[mi] = sAh[off];
            }
            #pragma unroll
            for (int ni=0;ni<4;ni++){
                int off = ((wn*4+ni)*2 + ka)*32 + lane;
                Bfh[ni] = sBh[off];
                Bfl[ni] = sBl[off];
            }
            #pragma unroll
            for (int mi=0;mi<4;mi++)
                #pragma unroll
                for (int ni=0;ni<4;ni++){
                    mma16(acc[mi][ni], Afh[mi], Bfh[ni]);
                    mma16(acc[mi][ni], Afh[mi], Bfl[ni]);
                }
        }
    }

    const int g = lane>>2, l = lane&3;
    if (EPI==1){
        const int K16n = N >> 4;
        #pragma unroll
        for (int mi=0;mi<4;mi++){
            int am = bm*8 + wm*4 + mi;
            #pragma unroll
            for (int np=0;np<2;np++){
                float vv[2][4];
                #pragma unroll
                for (int half=0; half<2; half++){
                    int ni = 2*np + half;
                    int col = bn*128 + wn*32 + ni*8 + 2*l;
                    float b0 = bias[col], b1 = bias[col+1];
                    float v0 = acc[mi][ni][0]+b0, v1 = acc[mi][ni][1]+b1;
                    float v2 = acc[mi][ni][2]+b0, v3 = acc[mi][ni][3]+b1;
                    vv[half][0] = 0.5f*v0*(1.0f + erff(v0*0.70710678118654752f));
                    vv[half][1] = 0.5f*v1*(1.0f + erff(v1*0.70710678118654752f));
                    vv[half][2] = 0.5f*v2*(1.0f + erff(v2*0.70710678118654752f));
                    vv[half][3] = 0.5f*v3*(1.0f + erff(v3*0.70710678118654752f));
                }
                uint4 h;
                h.x = packh(vv[0][0], vv[0][1]);
                h.y = packh(vv[0][2], vv[0][3]);
                h.z = packh(vv[1][0], vv[1][1]);
                h.w = packh(vv[1][2], vv[1][3]);
                size_t ga = ((size_t)am*K16n + (bn*8 + wn*2 + np))*32 + lane;
                FH[ga] = h;
            }
        }
    } else {
        float* Cp = C;
        if (EPI==3) Cp = C + (size_t)blockIdx.z * (size_t)(gridDim.y*128) * N;
        #pragma unroll
        for (int mi=0;mi<4;mi++){
            int row = bm*128 + wm*64 + mi*16 + g;
            #pragma unroll
            for (int ni=0;ni<4;ni++){
                int col = bn*128 + wn*32 + ni*8 + 2*l;
                float b0 = (EPI==3) ? 0.f : bias[col];
                float b1 = (EPI==3) ? 0.f : bias[col+1];
                float v0 = acc[mi][ni][0]+b0, v1 = acc[mi][ni][1]+b1;
                float v2 = acc[mi][ni][2]+b0, v3 = acc[mi][ni][3]+b1;
                *(float2*)(Cp + (size_t)row*N + col)     = make_float2(v0, v1);
                *(float2*)(Cp + (size_t)(row+8)*N + col) = make_float2(v2, v3);
            }
        }
    }
}

// ---------------- k-split reduce (final output) ----------------
template<int S>
__global__ void reduceK_k(const float* __restrict__ P, const float* __restrict__ bias,
                          const float* __restrict__ R, float* __restrict__ C, int N){
    const size_t stride4 = (size_t)ROWS*DD/4;
    size_t i = (size_t)blockIdx.x*256 + threadIdx.x;
    if (i >= stride4) return;
    float4 a = ((const float4*)P)[i];
    #pragma unroll
    for (int s=1;s<S;s++){
        float4 b = ((const float4*)P)[s*stride4 + i];
        a.x+=b.x; a.y+=b.y; a.z+=b.z; a.w+=b.w;
    }
    int col4 = (int)(i % (N/4));
    float4 bb = ((const float4*)bias)[col4];
    float4 rr = ((const float4*)R)[i];
    a.x += bb.x + rr.x; a.y += bb.y + rr.y;
    a.z += bb.z + rr.z; a.w += bb.w + rr.w;
    ((float4*)C)[i] = a;
}

// ---------------- FAVOR+ feature maps: tensor-core, 64 tokens + Q&K per CTA ----------------
// smem: qs[64][68] | ks[64][68] | pbh[4608] | pbl[4608] | misc
#define FG2_QS    0
#define FG2_KS    17408
#define FG2_PBH   34816
#define FG2_PBL   71680
#define FG2_MISC  108544
#define FG2_SMEM  (108544 + 1024)
__global__ __launch_bounds__(256, 2) void featgemm_tc(const float* __restrict__ QKV,
                                                      const uint2* __restrict__ PFH,
                                                      const uint2* __restrict__ PFL,
                                                      float* __restrict__ QP,
                                                      float* __restrict__ KP,
                                                      float* __restrict__ RM){
    extern __shared__ char fsm[];
    float* qs   = (float*)(fsm + FG2_QS);       // [64][68]
    float* ksm  = (float*)(fsm + FG2_KS);       // [64][68]
    uint2* pbh  = (uint2*)(fsm + FG2_PBH);
    uint2* pbl  = (uint2*)(fsm + FG2_PBL);
    float* diag_s   = (float*)(fsm + FG2_MISC); // 32 (per pass)
    float* rowmax_s = diag_s + 32;              // 32
    float* pm       = rowmax_s + 32;            // [4][32]

    const int bh = blockIdx.y;
    const int t0 = blockIdx.x*64;
    const int b = bh/HH, h = bh%HH;
    const int tid = threadIdx.x, lane = tid&31, warp = tid>>5;
    const int wm = warp & 1, wg = warp >> 1;
    const float* Aq = QKV + (size_t)(b*NN + t0)*QKVS + h*64;
    const float* Ak = Aq + DD;

    // loads: q tile + k tile (64x64 floats each) + proj fragments
    for (int i = tid; i < 1024; i += 256){
        int tok = i>>4, c4 = (i&15)*4;
        cpasync16(&qs [tok*68 + c4], Aq + (size_t)tok*QKVS + c4);
        cpasync16(&ksm[tok*68 + c4], Ak + (size_t)tok*QKVS + c4);
    }
    for (int i = tid; i < 2304; i += 256){
        cpasync16(&pbh[i*2], PFH + i*2);
        cpasync16(&pbl[i*2], PFL + i*2);
    }
    CP_COMMIT; CP_WAIT0;
    __syncthreads();

    const int g = lane>>2, l = lane&3;

    #pragma unroll 1
    for (int pass=0; pass<4; pass++){
        const int isK = pass >> 1;
        const int mh  = pass & 1;
        float* tile = (isK ? ksm : qs) + mh*32*68;

        __syncthreads();   // protect diag_s/pm reuse across passes
        // diag: 8 threads per token (32 tokens of this pass)
        {
            int tok = tid>>3, sl = tid&7;
            float ssq = 0.f;
            #pragma unroll
            for (int d=0; d<8; d++){ float q = tile[tok*68 + sl*8 + d]; ssq += q*q; }
            #pragma unroll
            for (int o=4;o;o>>=1) ssq += __shfl_xor_sync(0xffffffffu, ssq, o, 8);
            if (sl==0) diag_s[tok] = ssq*0.0625f;
        }

        float acc[9][4];
        #pragma unroll
        for (int j=0;j<9;j++)
            #pragma unroll
            for (int q_=0;q_<4;q_++) acc[j][q_]=0.f;

        #pragma unroll
        for (int ak=0; ak<4; ak++){
            const float* r0 = &tile[(wm*16+g)*68 + ak*16];
            const float* r1 = &tile[(wm*16+g+8)*68 + ak*16];
            uint4 Ah_, Al_;
            pack2h(r0[2*l],   r0[2*l+1], Ah_.x, Al_.x);
            pack2h(r1[2*l],   r1[2*l+1], Ah_.y, Al_.y);
            pack2h(r0[2*l+8], r0[2*l+9], Ah_.z, Al_.z);
            pack2h(r1[2*l+8], r1[2*l+9], Ah_.w, Al_.w);
            #pragma unroll
            for (int j=0;j<9;j++){
                int atom = (wg*9+j)*4 + ak;
                uint2 Bh_ = pbh[atom*32 + lane];
                uint2 Bl_ = pbl[atom*32 + lane];
                mma16(acc[j], Ah_, Bh_);
                mma16(acc[j], Ah_, Bl_);
                mma16(acc[j], Al_, Bh_);
            }
        }

        // scale + masked row max
        float mx0 = -3.4e38f, mx1 = -3.4e38f;
        #pragma unroll
        for (int j=0;j<9;j++){
            #pragma unroll
            for (int q_=0;q_<4;q_++) acc[j][q_] *= DN_SCALE;
            int c0 = (wg*9+j)*8 + 2*l;
            if (c0 < MM)   { mx0 = fmaxf(mx0, acc[j][0]); mx1 = fmaxf(mx1, acc[j][2]); }
            if (c0+1 < MM) { mx0 = fmaxf(mx0, acc[j][1]); mx1 = fmaxf(mx1, acc[j][3]); }
        }
        #pragma unroll
        for (int o=1;o<=2;o<<=1){
            mx0 = fmaxf(mx0, __shfl_xor_sync(0xffffffffu, mx0, o));
            mx1 = fmaxf(mx1, __shfl_xor_sync(0xffffffffu, mx1, o));
        }
        if (l==0){
            pm[wg*32 + wm*16 + g]     = mx0;
            pm[wg*32 + wm*16 + 8 + g] = mx1;
        }
        __syncthreads();
        if (tid < 32){
            float m_ = fmaxf(fmaxf(pm[tid], pm[32+tid]), fmaxf(pm[64+tid], pm[96+tid]));
            rowmax_s[tid] = m_;
            if (isK){
                RM[bh*NN + t0 + mh*32 + tid] = m_;
                float bmv = m_;
                #pragma unroll
                for (int o=16;o;o>>=1) bmv = fmaxf(bmv, __shfl_xor_sync(0xffffffffu, bmv, o));
                if (tid==0) atomicMax(&g_kmax_u, enc_f(bmv));
            }
        }
        __syncthreads();

        float* OUT = (isK ? KP : QP) + ((size_t)(bh*NN + t0 + mh*32))*MP2;
        int tokA = wm*16 + g, tokB = tokA + 8;
        float dA = diag_s[tokA] + rowmax_s[tokA];
        float dB = diag_s[tokB] + rowmax_s[tokB];
        #pragma unroll
        for (int j=0;j<9;j++){
            int c0 = (wg*9+j)*8 + 2*l;
            float v0,v1,v2,v3;
            if (isK){
                v0 = (c0   < MM) ? __expf(acc[j][0]-dA) : 0.f;
                v1 = (c0+1 < MM) ? __expf(acc[j][1]-dA) : 0.f;
                v2 = (c0   < MM) ? __expf(acc[j][2]-dB) : 0.f;
                v3 = (c0+1 < MM) ? __expf(acc[j][3]-dB) : 0.f;
            } else {
                v0 = (c0   < MM) ? RATIO_SC*(__expf(acc[j][0]-dA)+EPS_KER) : 0.f;
                v1 = (c0+1 < MM) ? RATIO_SC*(__expf(acc[j][1]-dA)+EPS_KER) : 0.f;
                v2 = (c0   < MM) ? RATIO_SC*(__expf(acc[j][2]-dB)+EPS_KER) : 0.f;
                v3 = (c0+1 < MM) ? RATIO_SC*(__expf(acc[j][3]-dB)+EPS_KER) : 0.f;
            }
            *(float2*)(OUT + (size_t)tokA*MP2 + c0) = make_float2(v0,v1);
            *(float2*)(OUT + (size_t)tokB*MP2 + c0) = make_float2(v2,v3);
        }
    }
}

// ---------------- chunked causal linear attention ----------------
__global__ __launch_bounds__(512) void chunksum_k(const float* __restrict__ KP,
                                                  const float* __restrict__ QKV,
                                                  const float* __restrict__ RM,
                                                  float* __restrict__ Z,
                                                  float* __restrict__ KV){
    int bhc = blockIdx.x;
    int bh = bhc / NC, c = bhc % NC;
    int b = bh / HH, h = bh % HH;
    int tid = threadIdx.x, g = tid>>6, e = tid&63;
    const int m0 = g*GM;
    __shared__ __align__(16) float kt[2][TT][MP2];
    __shared__ __align__(16) float vt[2][TT][64];
    __shared__ float scs[CHK];
    float S[GM];
    #pragma unroll
    for (int i=0;i<GM;i++) S[i]=0.f;
    float zacc = 0.f;
    const float* kb = KP + ((size_t)bh*NN + c*CHK)*MP2;
    const float* vb = QKV + (size_t)(b*NN + c*CHK)*QKVS + 2*DD + h*64;

    float gmax = dec_f(g_kmax_u);
    for (int i=tid; i<CHK; i+=512)
        scs[i] = __expf(RM[bh*NN + c*CHK + i] - gmax);

    auto load = [&](int buf, int tile){
        const float* kb_ = kb + (size_t)tile*TT*MP2;
        const float* vb_ = vb + (size_t)tile*TT*QKVS;
        for (int idx=tid; idx<704; idx+=512){
            if (idx < 576){ int tok=idx/72, f=(idx%72)*4; cpasync16(&kt[buf][tok][f], kb_ + (size_t)tok*MP2 + f); }
            else { int r=idx-576; int tok=r/16, f=(r%16)*4; cpasync16(&vt[buf][tok][f], vb_ + (size_t)tok*QKVS + f); }
        }
    };
    load(0,0); CP_COMMIT;
    for (int tile=0; tile<NTILE; tile++){
        int buf = tile&1;
        CP_WAIT0;
        __syncthreads();
        if (tile+1 < NTILE) load(buf^1, tile+1);
        CP_COMMIT;
        {
            const int tb = tile*TT;
            for (int idx=tid; idx<TT*MP2; idx+=512){
                int tok = idx/MP2, m = idx - tok*MP2;
                float f = kt[buf][tok][m];
                kt[buf][tok][m] = (m < MM) ? RATIO_SC*(f*scs[tb+tok] + EPS_KER) : 0.f;
            }
        }
        __syncthreads();
        #pragma unroll
        for (int tt=0; tt<TT; tt++){
            float vv = vt[buf][tt][e];
            const float4* kr = (const float4*)(&kt[buf][tt][m0]);
            #pragma unroll
            for (int i4=0;i4<9;i4++){
                float4 kk = kr[i4];
                S[i4*4+0] += kk.x*vv;
                S[i4*4+1] += kk.y*vv;
                S[i4*4+2] += kk.z*vv;
                S[i4*4+3] += kk.w*vv;
            }
            if (tid < MP2) zacc += kt[buf][tt][tid];
        }
    }
    if (tid < MP2) Z[(size_t)bhc*MP2 + tid] = zacc;
    float* kvout = KV + (size_t)bhc*KVSTRIDE;
    #pragma unroll
    for (int i=0;i<GM;i++) kvout[(size_t)(m0+i)*64 + e] = S[i];
}

__global__ __launch_bounds__(512) void prefix_k(float* __restrict__ Z, float* __restrict__ KV){
    int bh = blockIdx.y;
    int base = bh*NC;
    int idx = blockIdx.x*512 + threadIdx.x;
    float run = 0.f;
    #pragma unroll
    for (int c=0;c<NC;c++){
        float* p = KV + (size_t)(base+c)*KVSTRIDE + idx;
        float t = *p; *p = run; run += t;
    }
    if (blockIdx.x==0 && threadIdx.x < MP2){
        float rz = 0.f;
        #pragma unroll
        for (int c=0;c<NC;c++){
            float* p = Z + (size_t)(base+c)*MP2 + threadIdx.x;
            float t = *p; *p = rz; rz += t;
        }
    }
}

// chunkout with dynamic smem + batched per-tile reductions
#define CO_KT(b,t,m)  dsm[((b)*TT+(t))*MP2+(m)]
#define CO_QT(b,t,m)  dsm[QOFF + ((b)*TT+(t))*MP2+(m)]
#define CO_VT(b,t,e)  dsm[VOFF + ((b)*TT+(t))*64+(e)]
#define CO_PART(t,g,e) dsm[POFF + ((t)*8+(g))*64+(e)]
#define CO_DRED(t,w)  dsm[DOFF + (t)*16+(w)]
#define CO_SCS(i)     dsm[SOFF + (i)]
#define QOFF (2*TT*MP2)
#define VOFF (4*TT*MP2)
#define POFF (4*TT*MP2 + 2*TT*64)
#define DOFF (POFF + TT*8*64)
#define SOFF (DOFF + TT*16)
#define CO_SMEM ((SOFF + CHK)*4)

__global__ __launch_bounds__(512) void chunkout_k(const float* __restrict__ QP,
                                                  const float* __restrict__ KP,
                                                  const float* __restrict__ QKV,
                                                  const float* __restrict__ RM,
                                                  const float* __restrict__ Z,
                                                  const float* __restrict__ KV,
                                                  float* __restrict__ O){
    extern __shared__ __align__(16) float dsm[];
    int bhc = blockIdx.x;
    int bh = bhc / NC, c = bhc % NC;
    int b = bh / HH, h = bh % HH;
    int tid = threadIdx.x, g = tid>>6, e = tid&63;
    const int m0 = g*GM;

    float S[GM];
    const float* kvin = KV + (size_t)bhc*KVSTRIDE;
    #pragma unroll
    for (int i=0;i<GM;i++) S[i] = kvin[(size_t)(m0+i)*64 + e];
    float zreg = (tid < MP2) ? Z[(size_t)bhc*MP2 + tid] : 0.f;

    const float* kb = KP + ((size_t)bh*NN + c*CHK)*MP2;
    const float* qb = QP + ((size_t)bh*NN + c*CHK)*MP2;
    const float* vb = QKV + (size_t)(b*NN + c*CHK)*QKVS + 2*DD + h*64;

    float gmax = dec_f(g_kmax_u);
    for (int i=tid; i<CHK; i+=512)
        CO_SCS(i) = __expf(RM[bh*NN + c*CHK + i] - gmax);

    auto load = [&](int buf, int tile){
        const float* kb_ = kb + (size_t)tile*TT*MP2;
        const float* qb_ = qb + (size_t)tile*TT*MP2;
        const float* vb_ = vb + (size_t)tile*TT*QKVS;
        for (int idx=tid; idx<1280; idx+=512){
            if (idx < 576){ int tok=idx/72, f=(idx%72)*4; cpasync16(&CO_KT(buf,tok,f), kb_ + (size_t)tok*MP2 + f); }
            else if (idx < 1152){ int r=idx-576; int tok=r/72, f=(r%72)*4; cpasync16(&CO_QT(buf,tok,f), qb_ + (size_t)tok*MP2 + f); }
            else { int r=idx-1152; int tok=r/16, f=(r%16)*4; cpasync16(&CO_VT(buf,tok,f), vb_ + (size_t)tok*QKVS + f); }
        }
    };
    load(0,0); CP_COMMIT;

    for (int tile=0; tile<NTILE; tile++){
        int buf = tile&1;
        CP_WAIT0;
        __syncthreads();
        if (tile+1 < NTILE) load(buf^1, tile+1);
        CP_COMMIT;
        {
            const int tb = tile*TT;
            for (int idx=tid; idx<TT*MP2; idx+=512){
                int tok = idx/MP2, m = idx - tok*MP2;
                float f = CO_KT(buf,tok,m);
                CO_KT(buf,tok,m) = (m < MM) ? RATIO_SC*(f*CO_SCS(tb+tok) + EPS_KER) : 0.f;
            }
        }
        __syncthreads();
        #pragma unroll
        for (int tt=0; tt<TT; tt++){
            float vv = CO_VT(buf,tt,e);
            const float4* kr = (const float4*)(&CO_KT(buf,tt,m0));
            const float4* qr = (const float4*)(&CO_QT(buf,tt,m0));
            float acc = 0.f;
            #pragma unroll
            for (int i4=0;i4<9;i4++){
                float4 kk = kr[i4];
                float4 qq = qr[i4];
                S[i4*4+0] += kk.x*vv;  acc += qq.x*S[i4*4+0];
                S[i4*4+1] += kk.y*vv;  acc += qq.y*S[i4*4+1];
                S[i4*4+2] += kk.z*vv;  acc += qq.z*S[i4*4+2];
                S[i4*4+3] += kk.w*vv;  acc += qq.w*S[i4*4+3];
            }
            CO_PART(tt,g,e) = acc;
        }
        if (tid < MP2){
            float dp[TT];
            #pragma unroll
            for (int tt=0; tt<TT; tt++){
                float kv = CO_KT(buf,tt,tid);
                zreg += kv;
                dp[tt] = CO_QT(buf,tt,tid)*(zreg + EPS_DEN);
            }
            #pragma unroll
            for (int tt=0; tt<TT; tt++){
                float d = dp[tt];
                #pragma unroll
                for (int o=16;o;o>>=1) d += __shfl_xor_sync(0xffffffffu, d, o);
                if ((tid&31)==0) CO_DRED(tt, tid>>5) = d;
            }
        }
        __syncthreads();
        {
            int tok = tid>>6, e2 = tid&63;
            float s = 0.f;
            #pragma unroll
            for (int gg=0; gg<8; gg++) s += CO_PART(tok,gg,e2);
            float den = 0.f;
            #pragma unroll
            for (int w=0; w<9; w++) den += CO_DRED(tok,w);
            int t = c*CHK + tile*TT + tok;
            O[((size_t)(b*NN + t))*DD + h*64 + e2] = s / den;
        }
    }
}

// ---------------- launch ----------------
#define GEMM_SMEM (4*STG)

extern "C" void kernel_launch(void* const* d_in, const int* in_sizes, int n_in,
                              void* d_out, int out_size){
    (void)in_sizes; (void)n_in; (void)out_size;
    const float* x    = (const float*)d_in[0];
    const float* ln1g = (const float*)d_in[1];
    const float* ln1b = (const float*)d_in[2];
    const float* Wq   = (const float*)d_in[3];
    const float* bq   = (const float*)d_in[4];
    const float* Wk   = (const float*)d_in[5];
    const float* bk   = (const float*)d_in[6];
    const float* Wv   = (const float*)d_in[7];
    const float* bv   = (const float*)d_in[8];
    const float* Wo   = (const float*)d_in[9];
    const float* bo   = (const float*)d_in[10];
    const float* proj = (const float*)d_in[11];
    const float* ln2g = (const float*)d_in[12];
    const float* ln2b = (const float*)d_in[13];
    const float* W1   = (const float*)d_in[14];
    const float* b1   = (const float*)d_in[15];
    const float* W2   = (const float*)d_in[16];
    const float* b2   = (const float*)d_in[17];
    float* out = (float*)d_out;

    float *qkv,*qp,*kp,*rm,*o,*x1,*zz,*kv,*bqkv,*part;
    uint4 *afh,*af2h;
    uint2 *wfh,*wfl,*pfh,*pfl;
    cudaGetSymbolAddress((void**)&qkv, g_qkv);
    cudaGetSymbolAddress((void**)&qp,  g_qp);
    cudaGetSymbolAddress((void**)&kp,  g_kp);
    cudaGetSymbolAddress((void**)&rm,  g_rm);
    cudaGetSymbolAddress((void**)&o,   g_o);
    cudaGetSymbolAddress((void**)&x1,  g_x1);
    cudaGetSymbolAddress((void**)&zz,  g_Z);
    cudaGetSymbolAddress((void**)&kv,  g_KV);
    cudaGetSymbolAddress((void**)&bqkv,g_bqkv);
    cudaGetSymbolAddress((void**)&part,g_part);
    cudaGetSymbolAddress((void**)&afh, g_afh);
    cudaGetSymbolAddress((void**)&af2h,g_af2h);
    cudaGetSymbolAddress((void**)&wfh, g_wfh);
    cudaGetSymbolAddress((void**)&wfl, g_wfl);
    cudaGetSymbolAddress((void**)&pfh, g_pfh);
    cudaGetSymbolAddress((void**)&pfl, g_pfl);

    cudaFuncSetAttribute(gemm_tc<0>, cudaFuncAttributeMaxDynamicSharedMemorySize, GEMM_SMEM);
    cudaFuncSetAttribute(gemm_tc<1>, cudaFuncAttributeMaxDynamicSharedMemorySize, GEMM_SMEM);
    cudaFuncSetAttribute(gemm_tc<3>, cudaFuncAttributeMaxDynamicSharedMemorySize, GEMM_SMEM);
    cudaFuncSetAttribute(chunkout_k, cudaFuncAttributeMaxDynamicSharedMemorySize, CO_SMEM);
    cudaFuncSetAttribute(fusedln_k,  cudaFuncAttributeMaxDynamicSharedMemorySize, FLN_SMEM);
    cudaFuncSetAttribute(featgemm_tc, cudaFuncAttributeMaxDynamicSharedMemorySize, FG2_SMEM);

    // 1: weight split + bias pack + kmax init + proj fragments
    splitB3_k<<<1750,256>>>(Wq, Wk, Wv, wfh, wfl, bq, bk, bv, bqkv, proj, pfh, pfl);
    // 2: LN1 -> fp16 fragments
    lnfrag_k<<<ROWS/16,256>>>(x, ln1g, ln1b, afh);
    // 3: QKV fused GEMM
    {
        dim3 gq(QKVS/128, ROWS/128);
        gemm_tc<0><<<gq,256,GEMM_SMEM>>>(afh, wfh, wfl, bqkv, nullptr, qkv,
                                         nullptr, DD/16, DD/16, QKVS);
    }
    // 4: feature maps (tensor-core, 64 tokens + Q&K per CTA)
    {
        dim3 gfeat(NN/64, BH);
        featgemm_tc<<<gfeat,256,FG2_SMEM>>>(qkv, pfh, pfl, qp, kp, rm);
    }
    // 5-7: scan
    chunksum_k<<<NCH,512>>>(kp, qkv, rm, zz, kv);
    {
        dim3 gp(KVSTRIDE/512, BH);
        prefix_k<<<gp,512>>>(zz, kv);
    }
    chunkout_k<<<NCH,512,CO_SMEM>>>(qp, kp, qkv, rm, zz, kv, o);
    // 8: split o + Wo
    splitAB_k<<<2112,256>>>(o, Wo, afh, wfh, wfl);
    // 9: Wo GEMM (k-split x2)
    {
        dim3 gg(DD/128, ROWS/128, 2);
        gemm_tc<3><<<gg,256,GEMM_SMEM>>>(afh, wfh, wfl, nullptr, nullptr, part,
                                         nullptr, DD/16, DD/32, DD);
    }
    // 10: fused reduce + residual + LN2 + fragment emit
    fusedln_k<<<ROWS/16,256,FLN_SMEM>>>(part, bo, x, x1, ln2g, ln2b, afh);
    // 11: split W1 + W2
    splitB12_k<<<4608,256>>>(W1, W2, wfh, wfl);
    // 12: W1 GEMM + gelu -> fragments
    {
        dim3 gg(FFD/128, ROWS/128);
        gemm_tc<1><<<gg,256,GEMM_SMEM>>>(afh, wfh, wfl, b1, nullptr, nullptr,
                                         af2h, DD/16, DD/16, FFD);
    }
    // 13: W2 GEMM (k-split x4)
    {
        dim3 gg(DD/128, ROWS/128, 4);
        gemm_tc<3><<<gg,256,GEMM_SMEM>>>(af2h, wfh + W2OFF, wfl + W2OFF, nullptr, nullptr, part,
                                         nullptr, FFD/16, FFD/64, DD);
    }
    // 14: final reduce + bias + residual
    reduceK_k<4><<<(ROWS*DD/4+255)/256,256>>>(part, b2, x1, out, DD);
}